// round 9
// baseline (speedup 1.0000x reference)
#include <cuda_runtime.h>
#include <cuda_bf16.h>
#include <cstdint>
#include <math.h>

// ---------------- dimensions ----------------
#define N_IMG 17
#define H0 383
#define W0 287
#define H0P 387
#define W0P 291
#define C1o 64
#define H1 95
#define W1 71
#define P1H 47
#define P1W 35
#define P1HP 51
#define P1WP 39
#define C2o 192
#define H2 47
#define W2 35
#define P2H 23
#define P2W 17
#define P2HP 25
#define P2WP 19
#define C3o 384
#define C4o 256
#define C5o 256
#define H5 23
#define W5 17
#define P5H 11
#define P5W 8
#define MM 88
#define TT 16
#define TMN 1408
#define TAILPAD 4096

// ---------------- scratch (device globals; no allocation) ----------------
__device__ float g_in [N_IMG*3*H0P*W0P + TAILPAD];
__device__ float g_c1 [N_IMG*C1o*H1*W1];
__device__ float g_p1 [N_IMG*C1o*P1HP*P1WP + TAILPAD];
__device__ float g_c2 [N_IMG*C2o*H2*W2];
__device__ float g_p2 [N_IMG*C2o*P2HP*P2WP + TAILPAD];
__device__ float g_c3 [N_IMG*C3o*P2HP*P2WP + TAILPAD];
__device__ float g_c4 [N_IMG*C4o*P2HP*P2WP + TAILPAD];
__device__ float g_c5 [N_IMG*C5o*H5*W5];
__device__ float g_p5 [N_IMG*C5o*MM];
__device__ float g_xc [256*88];
__device__ float g_v  [256];
__device__ float g_xhat[256*88];
__device__ float g_nodes[TMN*256];
__device__ float g_Y1 [TMN*512];
__device__ float g_S  [16*512];
__device__ float g_h1 [TMN*512];
__device__ float g_Y2 [TMN*256];
__device__ float g_h2 [TMN*256];
__device__ float g_V1 [256*88];
__device__ float g_V1t[88*256];
__device__ float g_Vx [256*88];
__device__ float g_G  [256*88];
__device__ float g_Hh [256*88];
__device__ float g_A2 [88*88];
__device__ float g_xw [88*384];
__device__ float g_c1m[88*384];
__device__ float g_cw [88*256];
__device__ float g_V2t[88*256];

// bf16 split matrices for tensor-core conv GEMMs (also reused as NHWC maps)
__device__ __nv_bfloat16 g_Ahi[384*3456];
__device__ __nv_bfloat16 g_Alo[384*3456];
__device__ __nv_bfloat16 g_Bhi[44800000];
__device__ __nv_bfloat16 g_Blo[44800000];

// ---------------- mma / cp.async helpers (baseline PTX, sm_80+) ----------------
__device__ __forceinline__ uint32_t smem_u32(const void* p)
{
    uint32_t a;
    asm("{ .reg .u64 t; cvta.to.shared.u64 t, %1; cvt.u32.u64 %0, t; }" : "=r"(a) : "l"(p));
    return a;
}
__device__ __forceinline__ void ldsm_x4(uint32_t& r0, uint32_t& r1, uint32_t& r2, uint32_t& r3,
                                        uint32_t addr)
{
    asm volatile("ldmatrix.sync.aligned.m8n8.x4.shared.b16 {%0,%1,%2,%3}, [%4];"
                 : "=r"(r0), "=r"(r1), "=r"(r2), "=r"(r3) : "r"(addr));
}
__device__ __forceinline__ void mma16816(float* d, const uint32_t* a, uint32_t b0, uint32_t b1)
{
    asm volatile("mma.sync.aligned.m16n8k16.row.col.f32.bf16.bf16.f32 "
                 "{%0,%1,%2,%3}, {%4,%5,%6,%7}, {%8,%9}, {%0,%1,%2,%3};"
                 : "+f"(d[0]), "+f"(d[1]), "+f"(d[2]), "+f"(d[3])
                 : "r"(a[0]), "r"(a[1]), "r"(a[2]), "r"(a[3]), "r"(b0), "r"(b1));
}
__device__ __forceinline__ void cp16(uint32_t dst, const void* src, bool pred)
{
    int sz = pred ? 16 : 0;
    asm volatile("cp.async.cg.shared.global [%0], [%1], 16, %2;"
                 :: "r"(dst), "l"(src), "r"(sz));
}
#define CP_COMMIT() asm volatile("cp.async.commit_group;" ::: "memory")
#define CP_WAIT(n)  asm volatile("cp.async.wait_group %0;" :: "n"(n) : "memory")

// ---------------- prep kernels ----------------
// weight split, original k order (ci*KK + kk) with K padding — used by conv1
__global__ void wsplit_pad_k(const float* __restrict__ w, __nv_bfloat16* __restrict__ hi,
                             __nv_bfloat16* __restrict__ lo, int M, int Kreal, int KPAD)
{
    int i = blockIdx.x * blockDim.x + threadIdx.x;
    if (i >= M * KPAD) return;
    int m = i / KPAD, k = i - m * KPAD;
    float x = (k < Kreal) ? w[(size_t)m * Kreal + k] : 0.f;
    __nv_bfloat16 h = __float2bfloat16_rn(x);
    hi[i] = h;
    lo[i] = __float2bfloat16_rn(x - __bfloat162float(h));
}

// weight split + reorder to k = (kh*KD+kw)*CIN + ci (patch-pos outer, channel inner)
__global__ void wsplit_reorder_k(const float* __restrict__ w, __nv_bfloat16* __restrict__ hi,
                                 __nv_bfloat16* __restrict__ lo, int M, int CIN, int KK)
{
    int K = CIN * KK;
    int i = blockIdx.x * blockDim.x + threadIdx.x;
    if (i >= M * K) return;
    int m = i / K, kidx = i - m * K;
    int pos = kidx / CIN, ci = kidx - pos * CIN;
    float x = w[((size_t)m * CIN + ci) * KK + pos];
    __nv_bfloat16 h = __float2bfloat16_rn(x);
    hi[i] = h;
    lo[i] = __float2bfloat16_rn(x - __bfloat162float(h));
}

// NCHW fp32 (padded) -> NHWC bf16 hi/lo via smem transpose. C multiple of 32.
__global__ void nchw2nhwc_k(const float* __restrict__ in,
                            __nv_bfloat16* __restrict__ hi, __nv_bfloat16* __restrict__ lo,
                            int C, int NPIX)
{
    __shared__ float t[32][33];
    int img = blockIdx.z;
    int p0 = blockIdx.x * 32, c0 = blockIdx.y * 32;
    int tx = threadIdx.x, ty = threadIdx.y;
    const float* src = in + (size_t)img * C * NPIX;
    #pragma unroll
    for (int i = 0; i < 4; i++) {
        int c = c0 + ty + i * 8, p = p0 + tx;
        if (p < NPIX) t[ty + i * 8][tx] = src[(size_t)c * NPIX + p];
    }
    __syncthreads();
    #pragma unroll
    for (int i = 0; i < 4; i++) {
        int p = p0 + ty + i * 8, c = c0 + tx;
        if (p < NPIX) {
            float x = t[tx][ty + i * 8];
            __nv_bfloat16 h = __float2bfloat16_rn(x);
            size_t o = ((size_t)img * NPIX + p) * C + c;
            hi[o] = h;
            lo[o] = __float2bfloat16_rn(x - __bfloat162float(h));
        }
    }
}

// vectorized explicit im2col for conv1: each thread emits 8 consecutive k as one uint4
template<int CIN, int KD, int S, int HinP, int WinP, int Hout, int Wout, int KPAD>
__global__ void im2col_v8_t(const float* __restrict__ in,
                            __nv_bfloat16* __restrict__ bhi, __nv_bfloat16* __restrict__ blo)
{
    constexpr int KK = KD * KD;
    constexpr int KREAL = CIN * KK;
    constexpr int HW = Hout * Wout;
    constexpr int NPIX = N_IMG * HW;
    constexpr int KQ = KPAD / 8;
    int idx = blockIdx.x * blockDim.x + threadIdx.x;
    if (idx >= NPIX * KQ) return;
    int p  = idx / KQ;
    int k0 = (idx - p * KQ) * 8;
    int img = p / HW;
    int rr  = p - img * HW;
    int oh  = rr / Wout;
    int ow  = rr - oh * Wout;
    const float* base = in + ((size_t)img * CIN * HinP + oh * S) * WinP + ow * S;

    __nv_bfloat16 hv[8], lv[8];
    #pragma unroll
    for (int j = 0; j < 8; j++) {
        int k = k0 + j;
        float x = 0.f;
        if (k < KREAL) {
            int ci = k / KK;
            int r  = k - ci * KK;
            int kh = r / KD;
            int kw = r - kh * KD;
            x = base[((size_t)ci * HinP + kh) * WinP + kw];
        }
        __nv_bfloat16 h = __float2bfloat16_rn(x);
        hv[j] = h;
        lv[j] = __float2bfloat16_rn(x - __bfloat162float(h));
    }
    size_t o = (size_t)p * KPAD + k0;
    *(uint4*)(bhi + o) = *(const uint4*)hv;
    *(uint4*)(blo + o) = *(const uint4*)lv;
}

// ---------------- tensor-core conv GEMMs (3-stage cp.async, 1 barrier/iter) ----------------
#define ASTR 72

// -------- explicit-B GEMM, 64(M) x 128(N) tile — conv1 only --------
#define A1_SZ (64 * ASTR * 2)
#define B1_SZ (128 * ASTR * 2)
#define ST1_SZ (A1_SZ + B1_SZ)
#define SMEM_G1 (3 * ST1_SZ)
__global__ void __launch_bounds__(256)
mmaconv64_k(const __nv_bfloat16* __restrict__ Ahi, const __nv_bfloat16* __restrict__ Alo,
            const __nv_bfloat16* __restrict__ Bhi, const __nv_bfloat16* __restrict__ Blo,
            const float* __restrict__ bias, float* __restrict__ out,
            int M, int Npix, int K, int Hout, int Wout,
            int HoP, int WoP, int opad)
{
    extern __shared__ char smem[];
    uint32_t sb = smem_u32(smem);
    uint32_t aOff[3] = { sb, sb + ST1_SZ, sb + 2 * ST1_SZ };
    uint32_t bOff[3] = { sb + A1_SZ, sb + ST1_SZ + A1_SZ, sb + 2 * ST1_SZ + A1_SZ };

    int tid  = threadIdx.x;
    int lane = tid & 31;
    int wid  = tid >> 5;
    int wm   = wid & 1;
    int wn   = wid >> 1;

    int m0 = 0;
    int n0 = blockIdx.x * 128;

    float d[2][4][4];
    #pragma unroll
    for (int i = 0; i < 2; i++)
        #pragma unroll
        for (int j = 0; j < 4; j++)
            #pragma unroll
            for (int r = 0; r < 4; r++) d[i][j][r] = 0.f;

    int aj = lane >> 3, ar = lane & 7;
    uint32_t aAddrOff = (uint32_t)(((aj & 1) * 8 + ar) * ASTR + (aj >> 1) * 8) * 2;
    uint32_t bAddrOff = (uint32_t)(((aj >> 1) * 8 + ar) * ASTR + (aj & 1) * 8) * 2;

    int per = K >> 6;
    int itK = 3 * per;

    int arow[2], aq[2];
    #pragma unroll
    for (int j = 0; j < 2; j++) { int i = tid + j * 256; arow[j] = i >> 3; aq[j] = i & 7; }
    int brow[4], bq[4];
    #pragma unroll
    for (int j = 0; j < 4; j++) { int i = tid + j * 256; brow[j] = i >> 3; bq[j] = i & 7; }

    auto load_stage = [&](int st, int it) {
        int seg = it / per;
        int kof = (it - seg * per) << 6;
        const __nv_bfloat16* As = (seg < 2) ? Ahi : Alo;
        const __nv_bfloat16* Bs = (seg == 1) ? Blo : Bhi;
        #pragma unroll
        for (int j = 0; j < 2; j++) {
            uint32_t dst = aOff[st] + (uint32_t)(arow[j] * ASTR + aq[j] * 8) * 2;
            cp16(dst, As + (size_t)(m0 + arow[j]) * K + kof + aq[j] * 8, m0 + arow[j] < M);
        }
        #pragma unroll
        for (int j = 0; j < 4; j++) {
            uint32_t dst = bOff[st] + (uint32_t)(brow[j] * ASTR + bq[j] * 8) * 2;
            cp16(dst, Bs + (size_t)(n0 + brow[j]) * K + kof + bq[j] * 8, n0 + brow[j] < Npix);
        }
        CP_COMMIT();
    };

    load_stage(0, 0);
    if (itK > 1) load_stage(1, 1);

    for (int it = 0; it < itK; it++) {
        int st = it % 3;
        if (it + 1 < itK) { CP_WAIT(1); } else { CP_WAIT(0); }
        __syncthreads();
        if (it + 2 < itK) load_stage((it + 2) % 3, it + 2);

        #pragma unroll
        for (int kk = 0; kk < 4; kk++) {
            uint32_t a[2][4];
            #pragma unroll
            for (int mi = 0; mi < 2; mi++) {
                uint32_t ad = aOff[st] + aAddrOff
                            + (uint32_t)((wm * 32 + mi * 16) * ASTR + kk * 16) * 2;
                ldsm_x4(a[mi][0], a[mi][1], a[mi][2], a[mi][3], ad);
            }
            uint32_t b[4][2];
            #pragma unroll
            for (int q = 0; q < 2; q++) {
                uint32_t bd = bOff[st] + bAddrOff
                            + (uint32_t)((wn * 32 + q * 16) * ASTR + kk * 16) * 2;
                uint32_t r0, r1, r2, r3;
                ldsm_x4(r0, r1, r2, r3, bd);
                b[q * 2][0] = r0;  b[q * 2][1] = r1;
                b[q * 2 + 1][0] = r2;  b[q * 2 + 1][1] = r3;
            }
            #pragma unroll
            for (int mi = 0; mi < 2; mi++)
                #pragma unroll
                for (int nj = 0; nj < 4; nj++)
                    mma16816(d[mi][nj], a[mi], b[nj][0], b[nj][1]);
        }
    }

    int HW = Hout * Wout;
    #pragma unroll
    for (int mi = 0; mi < 2; mi++) {
        #pragma unroll
        for (int r2 = 0; r2 < 2; r2++) {
            int co = m0 + wm * 32 + mi * 16 + (lane >> 2) + r2 * 8;
            if (co >= M) continue;
            float bv = bias[co];
            #pragma unroll
            for (int nj = 0; nj < 4; nj++) {
                #pragma unroll
                for (int c = 0; c < 2; c++) {
                    int p = n0 + wn * 32 + nj * 8 + (lane & 3) * 2 + c;
                    if (p >= Npix) continue;
                    float v = d[mi][nj][r2 * 2 + c] + bv;
                    int img = p / HW;
                    int rr  = p - img * HW;
                    int oh  = rr / Wout;
                    int ow  = rr - oh * Wout;
                    out[((size_t)(img * M + co) * HoP + oh + opad) * WoP + ow + opad]
                        = fmaxf(v, 0.f);
                }
            }
        }
    }
}

// -------- implicit-B GEMM, 128(M) x 64(N), B gathered from NHWC map --------
#define A2_SZ (128 * ASTR * 2)
#define B2_SZ (64 * ASTR * 2)
#define ST2_SZ (A2_SZ + B2_SZ)
#define SMEM_G2 (3 * ST2_SZ)
__global__ void __launch_bounds__(256)
mmaconv_imp_k(const __nv_bfloat16* __restrict__ Ahi, const __nv_bfloat16* __restrict__ Alo,
              const __nv_bfloat16* __restrict__ Xhi, const __nv_bfloat16* __restrict__ Xlo,
              const float* __restrict__ bias, float* __restrict__ out,
              int M, int Npix, int K, int CIN, int KD,
              int HinP, int WinP, int Hout, int Wout,
              int HoP, int WoP, int opad)
{
    extern __shared__ char smem[];
    uint32_t sb = smem_u32(smem);
    uint32_t aOff[3] = { sb, sb + ST2_SZ, sb + 2 * ST2_SZ };
    uint32_t bOff[3] = { sb + A2_SZ, sb + ST2_SZ + A2_SZ, sb + 2 * ST2_SZ + A2_SZ };

    int tid  = threadIdx.x;
    int lane = tid & 31;
    int wid  = tid >> 5;
    int wm   = wid & 3;
    int wn   = wid >> 2;

    int m0 = blockIdx.y * 128;
    int n0 = blockIdx.x * 64;

    float d[2][4][4];
    #pragma unroll
    for (int i = 0; i < 2; i++)
        #pragma unroll
        for (int j = 0; j < 4; j++)
            #pragma unroll
            for (int r = 0; r < 4; r++) d[i][j][r] = 0.f;

    int aj = lane >> 3, ar = lane & 7;
    uint32_t aAddrOff = (uint32_t)(((aj & 1) * 8 + ar) * ASTR + (aj >> 1) * 8) * 2;
    uint32_t bAddrOff = (uint32_t)(((aj >> 1) * 8 + ar) * ASTR + (aj & 1) * 8) * 2;

    int per = K >> 6;
    int itK = 3 * per;
    int cPer = CIN >> 6;
    int HW = Hout * Wout;

    int arow[4], aq[4];
    #pragma unroll
    for (int j = 0; j < 4; j++) { int i = tid + j * 256; arow[j] = i >> 3; aq[j] = i & 7; }
    int brow[2], bq[2];
    long bbase[2];
    bool bval[2];
    #pragma unroll
    for (int j = 0; j < 2; j++) {
        int i = tid + j * 256;
        brow[j] = i >> 3; bq[j] = i & 7;
        int p = n0 + brow[j];
        bval[j] = p < Npix;
        if (!bval[j]) p = 0;
        int img = p / HW;
        int rr  = p - img * HW;
        int oh  = rr / Wout;
        int ow  = rr - oh * Wout;
        bbase[j] = ((long)(img * HinP + oh) * WinP + ow) * CIN;
    }

    auto load_stage = [&](int st, int it) {
        int seg = it / per;
        int c   = it - seg * per;
        int pos = c / cPer;
        int cioff = (c - pos * cPer) << 6;
        int kh = pos / KD, kw = pos - kh * KD;
        int kofA = c << 6;
        long boff = (long)(kh * WinP + kw) * CIN + cioff;
        const __nv_bfloat16* As = (seg < 2) ? Ahi : Alo;
        const __nv_bfloat16* Bs = (seg == 1) ? Xlo : Xhi;
        #pragma unroll
        for (int j = 0; j < 4; j++) {
            uint32_t dst = aOff[st] + (uint32_t)(arow[j] * ASTR + aq[j] * 8) * 2;
            cp16(dst, As + (size_t)(m0 + arow[j]) * K + kofA + aq[j] * 8, m0 + arow[j] < M);
        }
        #pragma unroll
        for (int j = 0; j < 2; j++) {
            uint32_t dst = bOff[st] + (uint32_t)(brow[j] * ASTR + bq[j] * 8) * 2;
            cp16(dst, Bs + bbase[j] + boff + bq[j] * 8, bval[j]);
        }
        CP_COMMIT();
    };

    load_stage(0, 0);
    if (itK > 1) load_stage(1, 1);

    for (int it = 0; it < itK; it++) {
        int st = it % 3;
        if (it + 1 < itK) { CP_WAIT(1); } else { CP_WAIT(0); }
        __syncthreads();
        if (it + 2 < itK) load_stage((it + 2) % 3, it + 2);

        #pragma unroll
        for (int kk = 0; kk < 4; kk++) {
            uint32_t a[2][4];
            #pragma unroll
            for (int mi = 0; mi < 2; mi++) {
                uint32_t ad = aOff[st] + aAddrOff
                            + (uint32_t)((wm * 32 + mi * 16) * ASTR + kk * 16) * 2;
                ldsm_x4(a[mi][0], a[mi][1], a[mi][2], a[mi][3], ad);
            }
            uint32_t b[4][2];
            #pragma unroll
            for (int q = 0; q < 2; q++) {
                uint32_t bd = bOff[st] + bAddrOff
                            + (uint32_t)((wn * 32 + q * 16) * ASTR + kk * 16) * 2;
                uint32_t r0, r1, r2, r3;
                ldsm_x4(r0, r1, r2, r3, bd);
                b[q * 2][0] = r0;  b[q * 2][1] = r1;
                b[q * 2 + 1][0] = r2;  b[q * 2 + 1][1] = r3;
            }
            #pragma unroll
            for (int mi = 0; mi < 2; mi++)
                #pragma unroll
                for (int nj = 0; nj < 4; nj++)
                    mma16816(d[mi][nj], a[mi], b[nj][0], b[nj][1]);
        }
    }

    #pragma unroll
    for (int mi = 0; mi < 2; mi++) {
        #pragma unroll
        for (int r2 = 0; r2 < 2; r2++) {
            int co = m0 + wm * 32 + mi * 16 + (lane >> 2) + r2 * 8;
            if (co >= M) continue;
            float bv = bias[co];
            #pragma unroll
            for (int nj = 0; nj < 4; nj++) {
                #pragma unroll
                for (int c = 0; c < 2; c++) {
                    int p = n0 + wn * 32 + nj * 8 + (lane & 3) * 2 + c;
                    if (p >= Npix) continue;
                    float v = d[mi][nj][r2 * 2 + c] + bv;
                    int img = p / HW;
                    int rr  = p - img * HW;
                    int oh  = rr / Wout;
                    int ow  = rr - oh * Wout;
                    out[((size_t)(img * M + co) * HoP + oh + opad) * WoP + ow + opad]
                        = fmaxf(v, 0.f);
                }
            }
        }
    }
}

// ---------------- scalar kernels (rest of network) ----------------

__global__ void pad_copy_k(const float* __restrict__ src, float* __restrict__ dst,
                           int nimg, int boff)
{
    int idx = blockIdx.x * blockDim.x + threadIdx.x;
    int total = nimg * 3 * H0 * W0;
    if (idx >= total) return;
    int w = idx % W0; int t = idx / W0;
    int h = t % H0;   t /= H0;
    int c = t % 3;    int n = t / 3;
    dst[(((size_t)(boff + n) * 3 + c) * H0P + h + 2) * W0P + (w + 2)] = src[idx];
}

__global__ void maxpool_k(const float* __restrict__ in, float* __restrict__ out,
                          int NC, int Hin, int Win, int Ho, int Wo,
                          int HoP, int WoP, int opad)
{
    int idx = blockIdx.x * blockDim.x + threadIdx.x;
    int total = NC * Ho * Wo;
    if (idx >= total) return;
    int ow = idx % Wo; int t = idx / Wo;
    int oh = t % Ho;   int nc = t / Ho;
    const float* ip = in + ((size_t)nc * Hin + oh * 2) * Win + ow * 2;
    float m = -INFINITY;
    #pragma unroll
    for (int kh = 0; kh < 3; kh++)
        #pragma unroll
        for (int kw = 0; kw < 3; kw++)
            m = fmaxf(m, ip[kh * Win + kw]);
    out[((size_t)nc * HoP + oh + opad) * WoP + ow + opad] = m;
}

__global__ void cd_conv_k(const float* __restrict__ Xf, const float* __restrict__ wcd,
                          const float* __restrict__ bcd, float* __restrict__ xc)
{
    int p = blockIdx.x;
    int o = threadIdx.x;
    float acc = bcd[o];
    for (int i = 0; i < 256; i++) {
        const float* wr = wcd + (o * 256 + i) * 3;
        const float* xr = Xf + i * 88;
        if (p > 0)  acc += xr[p - 1] * wr[0];
        acc += xr[p] * wr[1];
        if (p < 87) acc += xr[p + 1] * wr[2];
    }
    xc[o * 88 + p] = acc;
}

__global__ void cd_max_k(const float* __restrict__ xc, float* __restrict__ v)
{
    int o = threadIdx.x;
    float m = -INFINITY;
    for (int p = 0; p < 88; p++) m = fmaxf(m, xc[o * 88 + p]);
    v[o] = m;
}

__global__ void xhat_k(const float* __restrict__ v, const float* __restrict__ wt,
                       const float* __restrict__ bt, float* __restrict__ xhat)
{
    __shared__ float sv[256];
    int o = blockIdx.x;
    int k = threadIdx.x;
    for (int i = threadIdx.x; i < 256; i += blockDim.x) sv[i] = v[i];
    __syncthreads();
    float acc = bt[o];
    for (int i = 0; i < 256; i++)
        acc += sv[i] * wt[((size_t)i * 256 + o) * 88 + k];
    xhat[o * 88 + k] = acc;
}

__global__ void gather_nodes_k(const float* __restrict__ p5, float* __restrict__ nodes)
{
    int idx = blockIdx.x * blockDim.x + threadIdx.x;
    if (idx >= TMN * 256) return;
    int d = idx % 256;
    int n = idx / 256;
    int t = n % 16, m = n / 16;
    nodes[idx] = p5[((size_t)t * 256 + d) * 88 + m];
}

__global__ __launch_bounds__(256)
void rbgemm_k(const float* __restrict__ A, const float* __restrict__ B,
              const float* __restrict__ bias, float* __restrict__ C,
              int M, int N, int K, int flags)
{
    __shared__ float As[16][65];
    __shared__ float Bs[16][64];
    int tid = threadIdx.x;
    int tx = tid & 15;
    int ty = tid >> 4;
    int m0 = blockIdx.y * 64;
    int n0 = blockIdx.x * 64;

    float acc[4][4] = {};

    for (int k0 = 0; k0 < K; k0 += 16) {
        #pragma unroll
        for (int i = 0; i < 4; i++) {
            int e  = tid + i * 256;
            int kk = e & 15;
            int mm = e >> 4;
            int gm = m0 + mm, gk = k0 + kk;
            As[kk][mm] = (gm < M && gk < K) ? A[(size_t)gm * K + gk] : 0.f;
        }
        #pragma unroll
        for (int i = 0; i < 4; i++) {
            int nn = tid & 63;
            int kk = (tid >> 6) + i * 4;
            int gk = k0 + kk, gn = n0 + nn;
            Bs[kk][nn] = (gk < K && gn < N) ? B[(size_t)gk * N + gn] : 0.f;
        }
        __syncthreads();
        #pragma unroll
        for (int kk = 0; kk < 16; kk++) {
            float ra[4], rb[4];
            #pragma unroll
            for (int i = 0; i < 4; i++) ra[i] = As[kk][ty * 4 + i];
            #pragma unroll
            for (int j = 0; j < 4; j++) rb[j] = Bs[kk][tx * 4 + j];
            #pragma unroll
            for (int i = 0; i < 4; i++)
                #pragma unroll
                for (int j = 0; j < 4; j++)
                    acc[i][j] += ra[i] * rb[j];
        }
        __syncthreads();
    }

    #pragma unroll
    for (int i = 0; i < 4; i++) {
        int gm = m0 + ty * 4 + i;
        if (gm >= M) continue;
        #pragma unroll
        for (int j = 0; j < 4; j++) {
            int gn = n0 + tx * 4 + j;
            if (gn >= N) continue;
            float v = acc[i][j];
            if (flags & 1) v += bias[gm];
            if (flags & 2) v += bias[gn];
            if (flags & 4) v = v >= 0.f ? v : 0.01f * v;
            C[(size_t)gm * N + gn] = v;
        }
    }
}

__global__ void a1_reduce_k(const float* __restrict__ Y, float* __restrict__ S, int F)
{
    int f = blockIdx.x * blockDim.x + threadIdx.x;
    int t = blockIdx.y;
    if (f >= F) return;
    float s = 0.f;
    for (int m = 0; m < 88; m++) s += Y[(size_t)(m * 16 + t) * F + f];
    S[t * F + f] = s;
}

__global__ void a1_apply_k(const float* __restrict__ Y, const float* __restrict__ S,
                           const float* __restrict__ bias, float* __restrict__ h, int F)
{
    int idx = blockIdx.x * blockDim.x + threadIdx.x;
    if (idx >= TMN * F) return;
    int f = idx % F;
    int n = idx / F;
    int t = n % 16;
    float val = S[t * F + f] + bias[f];
    if (t == 0) val -= Y[idx];
    h[idx] = val >= 0.f ? val : 0.01f * val;
}

__global__ void v1_k(const float* __restrict__ h2, const float* __restrict__ xhat,
                     float* __restrict__ V1, float* __restrict__ V1t, float* __restrict__ Vx)
{
    int idx = blockIdx.x * blockDim.x + threadIdx.x;
    if (idx >= 256 * 88) return;
    int d = idx % 256;
    int m = idx / 256;
    float mx = -INFINITY;
    #pragma unroll
    for (int t = 0; t < 16; t++) mx = fmaxf(mx, h2[(size_t)(m * 16 + t) * 256 + d]);
    V1[d * 88 + m] = mx;
    V1t[m * 256 + d] = mx;
    Vx[d * 88 + m] = mx + xhat[d * 88 + m];
}

__global__ void attn_k(const float* __restrict__ G, const float* __restrict__ Hh,
                       float* __restrict__ A2)
{
    __shared__ float red[128];
    int j = blockIdx.x;
    int i = threadIdx.x;
    float s = 0.f;
    if (i < 88) {
        for (int d = 0; d < 256; d++) s += Hh[d * 88 + j] * G[d * 88 + i];
    }
    red[i] = (i < 88) ? s : -INFINITY;
    __syncthreads();
    for (int st = 64; st > 0; st >>= 1) {
        if (i < st) red[i] = fmaxf(red[i], red[i + st]);
        __syncthreads();
    }
    float mx = red[0];
    __syncthreads();
    float e = (i < 88) ? expf(s - mx) : 0.f;
    red[i] = e;
    __syncthreads();
    for (int st = 64; st > 0; st >>= 1) {
        if (i < st) red[i] += red[i + st];
        __syncthreads();
    }
    float sum = red[0];
    if (i < 88) A2[j * 88 + i] = e / sum;
}

__global__ void final_dot_k(const float* __restrict__ Xf, const float* __restrict__ V2t,
                            float* __restrict__ out)
{
    __shared__ float red[256];
    float acc = 0.f;
    for (int e = threadIdx.x; e < 256 * 88; e += 256) {
        int d = e / 88, m = e % 88;
        acc += Xf[e] * V2t[m * 256 + d];
    }
    red[threadIdx.x] = acc;
    __syncthreads();
    for (int st = 128; st > 0; st >>= 1) {
        if (threadIdx.x < st) red[threadIdx.x] += red[threadIdx.x + st];
        __syncthreads();
    }
    if (threadIdx.x == 0) out[0] = red[0];
}

// ---------------- host ----------------
static float* symaddr(const void* s)
{
    void* p = nullptr;
    cudaGetSymbolAddress(&p, s);
    return (float*)p;
}
static __nv_bfloat16* symaddr_bf(const void* s)
{
    void* p = nullptr;
    cudaGetSymbolAddress(&p, s);
    return (__nv_bfloat16*)p;
}

extern "C" void kernel_launch(void* const* d_in, const int* in_sizes, int n_in,
                              void* d_out, int out_size)
{
    const float* search    = (const float*)d_in[0];
    const float* exemplars = (const float*)d_in[1];
    const float* aw1 = (const float*)d_in[2];  const float* ab1 = (const float*)d_in[3];
    const float* aw2 = (const float*)d_in[4];  const float* ab2 = (const float*)d_in[5];
    const float* aw3 = (const float*)d_in[6];  const float* ab3 = (const float*)d_in[7];
    const float* aw4 = (const float*)d_in[8];  const float* ab4 = (const float*)d_in[9];
    const float* aw5 = (const float*)d_in[10]; const float* ab5 = (const float*)d_in[11];
    const float* wcd = (const float*)d_in[12]; const float* bcd = (const float*)d_in[13];
    const float* wt  = (const float*)d_in[14]; const float* bt  = (const float*)d_in[15];
    const float* ws1 = (const float*)d_in[16]; const float* bs1 = (const float*)d_in[17];
    const float* ws2 = (const float*)d_in[18]; const float* bs2 = (const float*)d_in[19];
    const float* wg  = (const float*)d_in[20]; const float* bg  = (const float*)d_in[21];
    const float* wh  = (const float*)d_in[22]; const float* bh  = (const float*)d_in[23];
    const float* wc1 = (const float*)d_in[24]; const float* bc1 = (const float*)d_in[25];
    const float* wc2 = (const float*)d_in[26]; const float* bc2 = (const float*)d_in[27];

    float* p_in  = symaddr(g_in);
    float* p_c1  = symaddr(g_c1);
    float* p_p1  = symaddr(g_p1);
    float* p_c2  = symaddr(g_c2);
    float* p_p2  = symaddr(g_p2);
    float* p_c3  = symaddr(g_c3);
    float* p_c4  = symaddr(g_c4);
    float* p_c5  = symaddr(g_c5);
    float* p_p5  = symaddr(g_p5);
    float* p_xc  = symaddr(g_xc);
    float* p_v   = symaddr(g_v);
    float* p_xh  = symaddr(g_xhat);
    float* p_nd  = symaddr(g_nodes);
    float* p_Y1  = symaddr(g_Y1);
    float* p_S   = symaddr(g_S);
    float* p_h1  = symaddr(g_h1);
    float* p_Y2  = symaddr(g_Y2);
    float* p_h2  = symaddr(g_h2);
    float* p_V1  = symaddr(g_V1);
    float* p_V1t = symaddr(g_V1t);
    float* p_Vx  = symaddr(g_Vx);
    float* p_G   = symaddr(g_G);
    float* p_Hh  = symaddr(g_Hh);
    float* p_A2  = symaddr(g_A2);
    float* p_xw  = symaddr(g_xw);
    float* p_c1m = symaddr(g_c1m);
    float* p_cw  = symaddr(g_cw);
    float* p_V2t = symaddr(g_V2t);
    __nv_bfloat16* pAhi = symaddr_bf(g_Ahi);
    __nv_bfloat16* pAlo = symaddr_bf(g_Alo);
    __nv_bfloat16* pBhi = symaddr_bf(g_Bhi);
    __nv_bfloat16* pBlo = symaddr_bf(g_Blo);

    cudaFuncSetAttribute(mmaconv64_k, cudaFuncAttributeMaxDynamicSharedMemorySize, SMEM_G1);
    cudaFuncSetAttribute(mmaconv_imp_k, cudaFuncAttributeMaxDynamicSharedMemorySize, SMEM_G2);

    // zero padded buffers (borders must be 0 every replay)
    cudaMemsetAsync(p_in, 0, sizeof(float) * ((size_t)N_IMG * 3 * H0P * W0P + TAILPAD), 0);
    cudaMemsetAsync(p_p1, 0, sizeof(float) * ((size_t)N_IMG * C1o * P1HP * P1WP + TAILPAD), 0);
    cudaMemsetAsync(p_p2, 0, sizeof(float) * ((size_t)N_IMG * C2o * P2HP * P2WP + TAILPAD), 0);
    cudaMemsetAsync(p_c3, 0, sizeof(float) * ((size_t)N_IMG * C3o * P2HP * P2WP + TAILPAD), 0);
    cudaMemsetAsync(p_c4, 0, sizeof(float) * ((size_t)N_IMG * C4o * P2HP * P2WP + TAILPAD), 0);

    // assemble padded input batch
    {
        int tot = 16 * 3 * H0 * W0;
        pad_copy_k<<<(tot + 127) / 128, 128>>>(exemplars, p_in, 16, 0);
        tot = 3 * H0 * W0;
        pad_copy_k<<<(tot + 127) / 128, 128>>>(search, p_in, 1, 16);
    }

    // ---- conv1 (vectorized im2col, 64x128 tile GEMM): M=64, K=384(pad) ----
    {
        const int KP = 384, NP = N_IMG * H1 * W1;
        wsplit_pad_k<<<(C1o * KP + 255) / 256, 256>>>(aw1, pAhi, pAlo, C1o, 363, KP);
        int tot = NP * (KP / 8);
        im2col_v8_t<3, 11, 4, H0P, W0P, H1, W1, 384><<<(tot + 255) / 256, 256>>>(p_in, pBhi, pBlo);
        mmaconv64_k<<<(NP + 127) / 128, 256, SMEM_G1>>>(
            pAhi, pAlo, pBhi, pBlo, ab1, p_c1, C1o, NP, KP, H1, W1, H1, W1, 0);
    }
    {
        int tot = N_IMG * C1o * P1H * P1W;
        maxpool_k<<<(tot + 127) / 128, 128>>>(p_c1, p_p1, N_IMG * C1o, H1, W1, P1H, P1W, P1HP, P1WP, 2);
    }

    // ---- p1 -> NHWC bf16 ----
    {
        const int NPIX = P1HP * P1WP;
        nchw2nhwc_k<<<dim3((NPIX + 31) / 32, C1o / 32, N_IMG), dim3(32, 8)>>>(p_p1, pBhi, pBlo, C1o, NPIX);
    }

    // ---- conv2 (implicit): M=192, K=1600, CIN=64, KD=5 ----
    {
        const int K = 1600, NP = N_IMG * H2 * W2;
        wsplit_reorder_k<<<(C2o * K + 255) / 256, 256>>>(aw2, pAhi, pAlo, C2o, 64, 25);
        mmaconv_imp_k<<<dim3((NP + 63) / 64, 2), 256, SMEM_G2>>>(
            pAhi, pAlo, pBhi, pBlo, ab2, p_c2, C2o, NP, K, 64, 5,
            P1HP, P1WP, H2, W2, H2, W2, 0);
    }
    {
        int tot = N_IMG * C2o * P2H * P2W;
        maxpool_k<<<(tot + 127) / 128, 128>>>(p_c2, p_p2, N_IMG * C2o, H2, W2, P2H, P2W, P2HP, P2WP, 1);
    }

    // ---- p2 -> NHWC ----
    {
        const int NPIX = P2HP * P2WP;
        nchw2nhwc_k<<<dim3((NPIX + 31) / 32, C2o / 32, N_IMG), dim3(32, 8)>>>(p_p2, pBhi, pBlo, C2o, NPIX);
    }

    // ---- conv3 (implicit): M=384, K=1728, CIN=192 ----
    {
        const int K = 1728, NP = N_IMG * P2H * P2W;
        wsplit_reorder_k<<<(C3o * K + 255) / 256, 256>>>(aw3, pAhi, pAlo, C3o, 192, 9);
        mmaconv_imp_k<<<dim3((NP + 63) / 64, 3), 256, SMEM_G2>>>(
            pAhi, pAlo, pBhi, pBlo, ab3, p_c3, C3o, NP, K, 192, 3,
            P2HP, P2WP, P2H, P2W, P2HP, P2WP, 1);
    }

    // ---- c3 -> NHWC ----
    {
        const int NPIX = P2HP * P2WP;
        nchw2nhwc_k<<<dim3((NPIX + 31) / 32, C3o / 32, N_IMG), dim3(32, 8)>>>(p_c3, pBhi, pBlo, C3o, NPIX);
    }

    // ---- conv4 (implicit): M=256, K=3456, CIN=384 ----
    {
        const int K = 3456, NP = N_IMG * P2H * P2W;
        wsplit_reorder_k<<<(C4o * K + 255) / 256, 256>>>(aw4, pAhi, pAlo, C4o, 384, 9);
        mmaconv_imp_k<<<dim3((NP + 63) / 64, 2), 256, SMEM_G2>>>(
            pAhi, pAlo, pBhi, pBlo, ab4, p_c4, C4o, NP, K, 384, 3,
            P2HP, P2WP, P2H, P2W, P2HP, P2WP, 1);
    }

    // ---- c4 -> NHWC ----
    {
        const int NPIX = P2HP * P2WP;
        nchw2nhwc_k<<<dim3((NPIX + 31) / 32, C4o / 32, N_IMG), dim3(32, 8)>>>(p_c4, pBhi, pBlo, C4o, NPIX);
    }

    // ---- conv5 (implicit): M=256, K=2304, CIN=256, out unpadded ----
    {
        const int K = 2304, NP = N_IMG * P2H * P2W;
        wsplit_reorder_k<<<(C5o * K + 255) / 256, 256>>>(aw5, pAhi, pAlo, C5o, 256, 9);
        mmaconv_imp_k<<<dim3((NP + 63) / 64, 2), 256, SMEM_G2>>>(
            pAhi, pAlo, pBhi, pBlo, ab5, p_c5, C5o, NP, K, 256, 3,
            P2HP, P2WP, P2H, P2W, H5, W5, 0);
    }
    {
        int tot = N_IMG * C5o * P5H * P5W;
        maxpool_k<<<(tot + 127) / 128, 128>>>(p_c5, p_p5, N_IMG * C5o, H5, W5, P5H, P5W, P5H, P5W, 0);
    }

    const float* Xf = p_p5 + (size_t)16 * 256 * 88;

    // ---- conv_deconv branch ----
    cd_conv_k<<<88, 256>>>(Xf, wcd, bcd, p_xc);
    cd_max_k<<<1, 256>>>(p_xc, p_v);
    xhat_k<<<256, 88>>>(p_v, wt, bt, p_xh);

    // ---- spatiotemporal GCN ----
    gather_nodes_k<<<(TMN * 256 + 127) / 128, 128>>>(p_p5, p_nd);
    rbgemm_k<<<dim3(512 / 64, TMN / 64), 256>>>(p_nd, ws1, nullptr, p_Y1, TMN, 512, 256, 0);
    a1_reduce_k<<<dim3(4, 16), 128>>>(p_Y1, p_S, 512);
    a1_apply_k<<<(TMN * 512 + 255) / 256, 256>>>(p_Y1, p_S, bs1, p_h1, 512);
    rbgemm_k<<<dim3(256 / 64, TMN / 64), 256>>>(p_h1, ws2, nullptr, p_Y2, TMN, 256, 512, 0);
    a1_reduce_k<<<dim3(2, 16), 128>>>(p_Y2, p_S, 256);
    a1_apply_k<<<(TMN * 256 + 255) / 256, 256>>>(p_Y2, p_S, bs2, p_h2, 256);
    v1_k<<<(256 * 88 + 255) / 256, 256>>>(p_h2, p_xh, p_V1, p_V1t, p_Vx);

    // ---- dynamic cross-track graph ----
    rbgemm_k<<<dim3((88 + 63) / 64, 256 / 64), 256>>>(wg, p_Vx, bg, p_G, 256, 88, 256, 1);
    rbgemm_k<<<dim3((88 + 63) / 64, 256 / 64), 256>>>(wh, p_Vx, bh, p_Hh, 256, 88, 256, 1);
    attn_k<<<88, 128>>>(p_G, p_Hh, p_A2);

    // ---- ct GCN ----
    rbgemm_k<<<dim3(384 / 64, (88 + 63) / 64), 256>>>(p_V1t, wc1, nullptr, p_xw, 88, 384, 256, 0);
    rbgemm_k<<<dim3(384 / 64, (88 + 63) / 64), 256>>>(p_A2, p_xw, bc1, p_c1m, 88, 384, 88, 2 | 4);
    rbgemm_k<<<dim3(256 / 64, (88 + 63) / 64), 256>>>(p_c1m, wc2, nullptr, p_cw, 88, 256, 384, 0);
    rbgemm_k<<<dim3(256 / 64, (88 + 63) / 64), 256>>>(p_A2, p_cw, bc2, p_V2t, 88, 256, 88, 2 | 4);

    // ---- final correlation ----
    final_dot_k<<<1, 256>>>(Xf, p_V2t, (float*)d_out);
}

// round 10
// speedup vs baseline: 1.0590x; 1.0590x over previous
#include <cuda_runtime.h>
#include <cuda_bf16.h>
#include <cstdint>
#include <math.h>

// ---------------- dimensions ----------------
#define N_IMG 17
#define H0 383
#define W0 287
#define H0P 387
#define W0P 291
#define C1o 64
#define H1 95
#define W1 71
#define P1H 47
#define P1W 35
#define P1HP 51
#define P1WP 39
#define C2o 192
#define H2 47
#define W2 35
#define P2H 23
#define P2W 17
#define P2HP 25
#define P2WP 19
#define C3o 384
#define C4o 256
#define C5o 256
#define H5 23
#define W5 17
#define P5H 11
#define P5W 8
#define MM 88
#define TT 16
#define TMN 1408
#define TAILPAD 4096

// ---------------- scratch (device globals; no allocation) ----------------
__device__ float g_in [N_IMG*3*H0P*W0P + TAILPAD];
__device__ float g_c1 [N_IMG*C1o*H1*W1];
__device__ float g_p1 [N_IMG*C1o*P1HP*P1WP + TAILPAD];
__device__ float g_c2 [N_IMG*C2o*H2*W2];
__device__ float g_p2 [N_IMG*C2o*P2HP*P2WP + TAILPAD];
__device__ float g_c3 [N_IMG*C3o*P2HP*P2WP + TAILPAD];
__device__ float g_c4 [N_IMG*C4o*P2HP*P2WP + TAILPAD];
__device__ float g_c5 [N_IMG*C5o*H5*W5];
__device__ float g_p5 [N_IMG*C5o*MM];
__device__ float g_xc [256*88];
__device__ float g_v  [256];
__device__ float g_xhat[256*88];
__device__ float g_nodes[TMN*256];
__device__ float g_Y1 [TMN*512];
__device__ float g_S  [16*512];
__device__ float g_h1 [TMN*512];
__device__ float g_Y2 [TMN*256];
__device__ float g_h2 [TMN*256];
__device__ float g_V1 [256*88];
__device__ float g_V1t[88*256];
__device__ float g_Vx [256*88];
__device__ float g_G  [256*88];
__device__ float g_Hh [256*88];
__device__ float g_A2 [88*88];
__device__ float g_xw [88*384];
__device__ float g_c1m[88*384];
__device__ float g_cw [88*256];
__device__ float g_V2t[88*256];

// bf16 split matrices for tensor-core conv GEMMs (also reused as NHWC maps)
__device__ __nv_bfloat16 g_Ahi[384*3456];
__device__ __nv_bfloat16 g_Alo[384*3456];
__device__ __nv_bfloat16 g_Bhi[44800000];
__device__ __nv_bfloat16 g_Blo[44800000];

// ---------------- mma / cp.async helpers (baseline PTX, sm_80+) ----------------
__device__ __forceinline__ uint32_t smem_u32(const void* p)
{
    uint32_t a;
    asm("{ .reg .u64 t; cvta.to.shared.u64 t, %1; cvt.u32.u64 %0, t; }" : "=r"(a) : "l"(p));
    return a;
}
__device__ __forceinline__ void ldsm_x4(uint32_t& r0, uint32_t& r1, uint32_t& r2, uint32_t& r3,
                                        uint32_t addr)
{
    asm volatile("ldmatrix.sync.aligned.m8n8.x4.shared.b16 {%0,%1,%2,%3}, [%4];"
                 : "=r"(r0), "=r"(r1), "=r"(r2), "=r"(r3) : "r"(addr));
}
__device__ __forceinline__ void mma16816(float* d, const uint32_t* a, uint32_t b0, uint32_t b1)
{
    asm volatile("mma.sync.aligned.m16n8k16.row.col.f32.bf16.bf16.f32 "
                 "{%0,%1,%2,%3}, {%4,%5,%6,%7}, {%8,%9}, {%0,%1,%2,%3};"
                 : "+f"(d[0]), "+f"(d[1]), "+f"(d[2]), "+f"(d[3])
                 : "r"(a[0]), "r"(a[1]), "r"(a[2]), "r"(a[3]), "r"(b0), "r"(b1));
}
__device__ __forceinline__ void cp16(uint32_t dst, const void* src, bool pred)
{
    int sz = pred ? 16 : 0;
    asm volatile("cp.async.cg.shared.global [%0], [%1], 16, %2;"
                 :: "r"(dst), "l"(src), "r"(sz));
}
#define CP_COMMIT() asm volatile("cp.async.commit_group;" ::: "memory")
#define CP_WAIT(n)  asm volatile("cp.async.wait_group %0;" :: "n"(n) : "memory")

// ---------------- prep kernels ----------------
// weight split, original k order (ci*KK + kk) with K padding — used by conv1
__global__ void wsplit_pad_k(const float* __restrict__ w, __nv_bfloat16* __restrict__ hi,
                             __nv_bfloat16* __restrict__ lo, int M, int Kreal, int KPAD)
{
    int i = blockIdx.x * blockDim.x + threadIdx.x;
    if (i >= M * KPAD) return;
    int m = i / KPAD, k = i - m * KPAD;
    float x = (k < Kreal) ? w[(size_t)m * Kreal + k] : 0.f;
    __nv_bfloat16 h = __float2bfloat16_rn(x);
    hi[i] = h;
    lo[i] = __float2bfloat16_rn(x - __bfloat162float(h));
}

// weight split + reorder to k = (kh*KD+kw)*CIN + ci (patch-pos outer, channel inner)
__global__ void wsplit_reorder_k(const float* __restrict__ w, __nv_bfloat16* __restrict__ hi,
                                 __nv_bfloat16* __restrict__ lo, int M, int CIN, int KK)
{
    int K = CIN * KK;
    int i = blockIdx.x * blockDim.x + threadIdx.x;
    if (i >= M * K) return;
    int m = i / K, kidx = i - m * K;
    int pos = kidx / CIN, ci = kidx - pos * CIN;
    float x = w[((size_t)m * CIN + ci) * KK + pos];
    __nv_bfloat16 h = __float2bfloat16_rn(x);
    hi[i] = h;
    lo[i] = __float2bfloat16_rn(x - __bfloat162float(h));
}

// NCHW fp32 (padded) -> NHWC bf16 hi/lo via smem transpose. C multiple of 32.
__global__ void nchw2nhwc_k(const float* __restrict__ in,
                            __nv_bfloat16* __restrict__ hi, __nv_bfloat16* __restrict__ lo,
                            int C, int NPIX)
{
    __shared__ float t[32][33];
    int img = blockIdx.z;
    int p0 = blockIdx.x * 32, c0 = blockIdx.y * 32;
    int tx = threadIdx.x, ty = threadIdx.y;
    const float* src = in + (size_t)img * C * NPIX;
    #pragma unroll
    for (int i = 0; i < 4; i++) {
        int c = c0 + ty + i * 8, p = p0 + tx;
        if (p < NPIX) t[ty + i * 8][tx] = src[(size_t)c * NPIX + p];
    }
    __syncthreads();
    #pragma unroll
    for (int i = 0; i < 4; i++) {
        int p = p0 + ty + i * 8, c = c0 + tx;
        if (p < NPIX) {
            float x = t[tx][ty + i * 8];
            __nv_bfloat16 h = __float2bfloat16_rn(x);
            size_t o = ((size_t)img * NPIX + p) * C + c;
            hi[o] = h;
            lo[o] = __float2bfloat16_rn(x - __bfloat162float(h));
        }
    }
}

// vectorized explicit im2col for conv1: each thread emits 8 consecutive k as one uint4
template<int CIN, int KD, int S, int HinP, int WinP, int Hout, int Wout, int KPAD>
__global__ void im2col_v8_t(const float* __restrict__ in,
                            __nv_bfloat16* __restrict__ bhi, __nv_bfloat16* __restrict__ blo)
{
    constexpr int KK = KD * KD;
    constexpr int KREAL = CIN * KK;
    constexpr int HW = Hout * Wout;
    constexpr int NPIX = N_IMG * HW;
    constexpr int KQ = KPAD / 8;
    int idx = blockIdx.x * blockDim.x + threadIdx.x;
    if (idx >= NPIX * KQ) return;
    int p  = idx / KQ;
    int k0 = (idx - p * KQ) * 8;
    int img = p / HW;
    int rr  = p - img * HW;
    int oh  = rr / Wout;
    int ow  = rr - oh * Wout;
    const float* base = in + ((size_t)img * CIN * HinP + oh * S) * WinP + ow * S;

    __nv_bfloat16 hv[8], lv[8];
    #pragma unroll
    for (int j = 0; j < 8; j++) {
        int k = k0 + j;
        float x = 0.f;
        if (k < KREAL) {
            int ci = k / KK;
            int r  = k - ci * KK;
            int kh = r / KD;
            int kw = r - kh * KD;
            x = base[((size_t)ci * HinP + kh) * WinP + kw];
        }
        __nv_bfloat16 h = __float2bfloat16_rn(x);
        hv[j] = h;
        lv[j] = __float2bfloat16_rn(x - __bfloat162float(h));
    }
    size_t o = (size_t)p * KPAD + k0;
    *(uint4*)(bhi + o) = *(const uint4*)hv;
    *(uint4*)(blo + o) = *(const uint4*)lv;
}

// ---------------- tensor-core conv GEMMs (2-stage cp.async, round-8 structure) ----------------
#define ASTR 72

// -------- explicit-B GEMM, 64(M) x 128(N) tile — conv1 only --------
#define A1_SZ (64 * ASTR * 2)
#define B1_SZ (128 * ASTR * 2)
#define SMEM_G1 (2 * A1_SZ + 2 * B1_SZ)
__global__ void __launch_bounds__(256)
mmaconv64_k(const __nv_bfloat16* __restrict__ Ahi, const __nv_bfloat16* __restrict__ Alo,
            const __nv_bfloat16* __restrict__ Bhi, const __nv_bfloat16* __restrict__ Blo,
            const float* __restrict__ bias, float* __restrict__ out,
            int M, int Npix, int K, int Hout, int Wout,
            int HoP, int WoP, int opad)
{
    extern __shared__ char smem[];
    uint32_t sb = smem_u32(smem);
    uint32_t aOff[2] = { sb, sb + A1_SZ };
    uint32_t bOff[2] = { sb + 2 * A1_SZ, sb + 2 * A1_SZ + B1_SZ };

    int tid  = threadIdx.x;
    int lane = tid & 31;
    int wid  = tid >> 5;
    int wm   = wid & 1;
    int wn   = wid >> 1;

    int m0 = 0;
    int n0 = blockIdx.x * 128;

    float d[2][4][4];
    #pragma unroll
    for (int i = 0; i < 2; i++)
        #pragma unroll
        for (int j = 0; j < 4; j++)
            #pragma unroll
            for (int r = 0; r < 4; r++) d[i][j][r] = 0.f;

    int aj = lane >> 3, ar = lane & 7;
    uint32_t aAddrOff = (uint32_t)(((aj & 1) * 8 + ar) * ASTR + (aj >> 1) * 8) * 2;
    uint32_t bAddrOff = (uint32_t)(((aj >> 1) * 8 + ar) * ASTR + (aj & 1) * 8) * 2;

    int per = K >> 6;
    int itK = 3 * per;

    int arow[2], aq[2];
    #pragma unroll
    for (int j = 0; j < 2; j++) { int i = tid + j * 256; arow[j] = i >> 3; aq[j] = i & 7; }
    int brow[4], bq[4];
    #pragma unroll
    for (int j = 0; j < 4; j++) { int i = tid + j * 256; brow[j] = i >> 3; bq[j] = i & 7; }

    auto load_stage = [&](int st, int it) {
        int seg = it / per;
        int kof = (it - seg * per) << 6;
        const __nv_bfloat16* As = (seg < 2) ? Ahi : Alo;
        const __nv_bfloat16* Bs = (seg == 1) ? Blo : Bhi;
        #pragma unroll
        for (int j = 0; j < 2; j++) {
            uint32_t dst = aOff[st] + (uint32_t)(arow[j] * ASTR + aq[j] * 8) * 2;
            cp16(dst, As + (size_t)(m0 + arow[j]) * K + kof + aq[j] * 8, m0 + arow[j] < M);
        }
        #pragma unroll
        for (int j = 0; j < 4; j++) {
            uint32_t dst = bOff[st] + (uint32_t)(brow[j] * ASTR + bq[j] * 8) * 2;
            cp16(dst, Bs + (size_t)(n0 + brow[j]) * K + kof + bq[j] * 8, n0 + brow[j] < Npix);
        }
        CP_COMMIT();
    };

    load_stage(0, 0);

    for (int it = 0; it < itK; it++) {
        int st = it & 1;
        if (it + 1 < itK) { load_stage(st ^ 1, it + 1); CP_WAIT(1); }
        else              { CP_WAIT(0); }
        __syncthreads();

        #pragma unroll
        for (int kk = 0; kk < 4; kk++) {
            uint32_t a[2][4];
            #pragma unroll
            for (int mi = 0; mi < 2; mi++) {
                uint32_t ad = aOff[st] + aAddrOff
                            + (uint32_t)((wm * 32 + mi * 16) * ASTR + kk * 16) * 2;
                ldsm_x4(a[mi][0], a[mi][1], a[mi][2], a[mi][3], ad);
            }
            uint32_t b[4][2];
            #pragma unroll
            for (int q = 0; q < 2; q++) {
                uint32_t bd = bOff[st] + bAddrOff
                            + (uint32_t)((wn * 32 + q * 16) * ASTR + kk * 16) * 2;
                uint32_t r0, r1, r2, r3;
                ldsm_x4(r0, r1, r2, r3, bd);
                b[q * 2][0] = r0;  b[q * 2][1] = r1;
                b[q * 2 + 1][0] = r2;  b[q * 2 + 1][1] = r3;
            }
            #pragma unroll
            for (int mi = 0; mi < 2; mi++)
                #pragma unroll
                for (int nj = 0; nj < 4; nj++)
                    mma16816(d[mi][nj], a[mi], b[nj][0], b[nj][1]);
        }
        __syncthreads();
    }

    int HW = Hout * Wout;
    #pragma unroll
    for (int mi = 0; mi < 2; mi++) {
        #pragma unroll
        for (int r2 = 0; r2 < 2; r2++) {
            int co = m0 + wm * 32 + mi * 16 + (lane >> 2) + r2 * 8;
            if (co >= M) continue;
            float bv = bias[co];
            #pragma unroll
            for (int nj = 0; nj < 4; nj++) {
                #pragma unroll
                for (int c = 0; c < 2; c++) {
                    int p = n0 + wn * 32 + nj * 8 + (lane & 3) * 2 + c;
                    if (p >= Npix) continue;
                    float v = d[mi][nj][r2 * 2 + c] + bv;
                    int img = p / HW;
                    int rr  = p - img * HW;
                    int oh  = rr / Wout;
                    int ow  = rr - oh * Wout;
                    out[((size_t)(img * M + co) * HoP + oh + opad) * WoP + ow + opad]
                        = fmaxf(v, 0.f);
                }
            }
        }
    }
}

// -------- implicit-B GEMM, 128(M) x 64(N), B gathered from NHWC map --------
#define A2_SZ (128 * ASTR * 2)
#define B2_SZ (64 * ASTR * 2)
#define SMEM_G2 (2 * A2_SZ + 2 * B2_SZ)
__global__ void __launch_bounds__(256)
mmaconv_imp_k(const __nv_bfloat16* __restrict__ Ahi, const __nv_bfloat16* __restrict__ Alo,
              const __nv_bfloat16* __restrict__ Xhi, const __nv_bfloat16* __restrict__ Xlo,
              const float* __restrict__ bias, float* __restrict__ out,
              int M, int Npix, int K, int CIN, int KD,
              int HinP, int WinP, int Hout, int Wout,
              int HoP, int WoP, int opad)
{
    extern __shared__ char smem[];
    uint32_t sb = smem_u32(smem);
    uint32_t aOff[2] = { sb, sb + A2_SZ };
    uint32_t bOff[2] = { sb + 2 * A2_SZ, sb + 2 * A2_SZ + B2_SZ };

    int tid  = threadIdx.x;
    int lane = tid & 31;
    int wid  = tid >> 5;
    int wm   = wid & 3;
    int wn   = wid >> 2;

    int m0 = blockIdx.y * 128;
    int n0 = blockIdx.x * 64;

    float d[2][4][4];
    #pragma unroll
    for (int i = 0; i < 2; i++)
        #pragma unroll
        for (int j = 0; j < 4; j++)
            #pragma unroll
            for (int r = 0; r < 4; r++) d[i][j][r] = 0.f;

    int aj = lane >> 3, ar = lane & 7;
    uint32_t aAddrOff = (uint32_t)(((aj & 1) * 8 + ar) * ASTR + (aj >> 1) * 8) * 2;
    uint32_t bAddrOff = (uint32_t)(((aj >> 1) * 8 + ar) * ASTR + (aj & 1) * 8) * 2;

    int per = K >> 6;
    int itK = 3 * per;
    int cPer = CIN >> 6;
    int HW = Hout * Wout;

    int arow[4], aq[4];
    #pragma unroll
    for (int j = 0; j < 4; j++) { int i = tid + j * 256; arow[j] = i >> 3; aq[j] = i & 7; }
    int brow[2], bq[2];
    long bbase[2];
    bool bval[2];
    #pragma unroll
    for (int j = 0; j < 2; j++) {
        int i = tid + j * 256;
        brow[j] = i >> 3; bq[j] = i & 7;
        int p = n0 + brow[j];
        bval[j] = p < Npix;
        if (!bval[j]) p = 0;
        int img = p / HW;
        int rr  = p - img * HW;
        int oh  = rr / Wout;
        int ow  = rr - oh * Wout;
        bbase[j] = ((long)(img * HinP + oh) * WinP + ow) * CIN;
    }

    auto load_stage = [&](int st, int it) {
        int seg = it / per;
        int c   = it - seg * per;
        int pos = c / cPer;
        int cioff = (c - pos * cPer) << 6;
        int kh = pos / KD, kw = pos - kh * KD;
        int kofA = c << 6;
        long boff = (long)(kh * WinP + kw) * CIN + cioff;
        const __nv_bfloat16* As = (seg < 2) ? Ahi : Alo;
        const __nv_bfloat16* Bs = (seg == 1) ? Xlo : Xhi;
        #pragma unroll
        for (int j = 0; j < 4; j++) {
            uint32_t dst = aOff[st] + (uint32_t)(arow[j] * ASTR + aq[j] * 8) * 2;
            cp16(dst, As + (size_t)(m0 + arow[j]) * K + kofA + aq[j] * 8, m0 + arow[j] < M);
        }
        #pragma unroll
        for (int j = 0; j < 2; j++) {
            uint32_t dst = bOff[st] + (uint32_t)(brow[j] * ASTR + bq[j] * 8) * 2;
            cp16(dst, Bs + bbase[j] + boff + bq[j] * 8, bval[j]);
        }
        CP_COMMIT();
    };

    load_stage(0, 0);

    for (int it = 0; it < itK; it++) {
        int st = it & 1;
        if (it + 1 < itK) { load_stage(st ^ 1, it + 1); CP_WAIT(1); }
        else              { CP_WAIT(0); }
        __syncthreads();

        #pragma unroll
        for (int kk = 0; kk < 4; kk++) {
            uint32_t a[2][4];
            #pragma unroll
            for (int mi = 0; mi < 2; mi++) {
                uint32_t ad = aOff[st] + aAddrOff
                            + (uint32_t)((wm * 32 + mi * 16) * ASTR + kk * 16) * 2;
                ldsm_x4(a[mi][0], a[mi][1], a[mi][2], a[mi][3], ad);
            }
            uint32_t b[4][2];
            #pragma unroll
            for (int q = 0; q < 2; q++) {
                uint32_t bd = bOff[st] + bAddrOff
                            + (uint32_t)((wn * 32 + q * 16) * ASTR + kk * 16) * 2;
                uint32_t r0, r1, r2, r3;
                ldsm_x4(r0, r1, r2, r3, bd);
                b[q * 2][0] = r0;  b[q * 2][1] = r1;
                b[q * 2 + 1][0] = r2;  b[q * 2 + 1][1] = r3;
            }
            #pragma unroll
            for (int mi = 0; mi < 2; mi++)
                #pragma unroll
                for (int nj = 0; nj < 4; nj++)
                    mma16816(d[mi][nj], a[mi], b[nj][0], b[nj][1]);
        }
        __syncthreads();
    }

    #pragma unroll
    for (int mi = 0; mi < 2; mi++) {
        #pragma unroll
        for (int r2 = 0; r2 < 2; r2++) {
            int co = m0 + wm * 32 + mi * 16 + (lane >> 2) + r2 * 8;
            if (co >= M) continue;
            float bv = bias[co];
            #pragma unroll
            for (int nj = 0; nj < 4; nj++) {
                #pragma unroll
                for (int c = 0; c < 2; c++) {
                    int p = n0 + wn * 32 + nj * 8 + (lane & 3) * 2 + c;
                    if (p >= Npix) continue;
                    float v = d[mi][nj][r2 * 2 + c] + bv;
                    int img = p / HW;
                    int rr  = p - img * HW;
                    int oh  = rr / Wout;
                    int ow  = rr - oh * Wout;
                    out[((size_t)(img * M + co) * HoP + oh + opad) * WoP + ow + opad]
                        = fmaxf(v, 0.f);
                }
            }
        }
    }
}

// ---------------- scalar kernels (rest of network) ----------------

__global__ void pad_copy_k(const float* __restrict__ src, float* __restrict__ dst,
                           int nimg, int boff)
{
    int idx = blockIdx.x * blockDim.x + threadIdx.x;
    int total = nimg * 3 * H0 * W0;
    if (idx >= total) return;
    int w = idx % W0; int t = idx / W0;
    int h = t % H0;   t /= H0;
    int c = t % 3;    int n = t / 3;
    dst[(((size_t)(boff + n) * 3 + c) * H0P + h + 2) * W0P + (w + 2)] = src[idx];
}

__global__ void maxpool_k(const float* __restrict__ in, float* __restrict__ out,
                          int NC, int Hin, int Win, int Ho, int Wo,
                          int HoP, int WoP, int opad)
{
    int idx = blockIdx.x * blockDim.x + threadIdx.x;
    int total = NC * Ho * Wo;
    if (idx >= total) return;
    int ow = idx % Wo; int t = idx / Wo;
    int oh = t % Ho;   int nc = t / Ho;
    const float* ip = in + ((size_t)nc * Hin + oh * 2) * Win + ow * 2;
    float m = -INFINITY;
    #pragma unroll
    for (int kh = 0; kh < 3; kh++)
        #pragma unroll
        for (int kw = 0; kw < 3; kw++)
            m = fmaxf(m, ip[kh * Win + kw]);
    out[((size_t)nc * HoP + oh + opad) * WoP + ow + opad] = m;
}

__global__ void cd_conv_k(const float* __restrict__ Xf, const float* __restrict__ wcd,
                          const float* __restrict__ bcd, float* __restrict__ xc)
{
    int p = blockIdx.x;
    int o = threadIdx.x;
    float acc = bcd[o];
    for (int i = 0; i < 256; i++) {
        const float* wr = wcd + (o * 256 + i) * 3;
        const float* xr = Xf + i * 88;
        if (p > 0)  acc += xr[p - 1] * wr[0];
        acc += xr[p] * wr[1];
        if (p < 87) acc += xr[p + 1] * wr[2];
    }
    xc[o * 88 + p] = acc;
}

__global__ void cd_max_k(const float* __restrict__ xc, float* __restrict__ v)
{
    int o = threadIdx.x;
    float m = -INFINITY;
    for (int p = 0; p < 88; p++) m = fmaxf(m, xc[o * 88 + p]);
    v[o] = m;
}

__global__ void xhat_k(const float* __restrict__ v, const float* __restrict__ wt,
                       const float* __restrict__ bt, float* __restrict__ xhat)
{
    __shared__ float sv[256];
    int o = blockIdx.x;
    int k = threadIdx.x;
    for (int i = threadIdx.x; i < 256; i += blockDim.x) sv[i] = v[i];
    __syncthreads();
    float acc = bt[o];
    for (int i = 0; i < 256; i++)
        acc += sv[i] * wt[((size_t)i * 256 + o) * 88 + k];
    xhat[o * 88 + k] = acc;
}

__global__ void gather_nodes_k(const float* __restrict__ p5, float* __restrict__ nodes)
{
    int idx = blockIdx.x * blockDim.x + threadIdx.x;
    if (idx >= TMN * 256) return;
    int d = idx % 256;
    int n = idx / 256;
    int t = n % 16, m = n / 16;
    nodes[idx] = p5[((size_t)t * 256 + d) * 88 + m];
}

__global__ __launch_bounds__(256)
void rbgemm_k(const float* __restrict__ A, const float* __restrict__ B,
              const float* __restrict__ bias, float* __restrict__ C,
              int M, int N, int K, int flags)
{
    __shared__ float As[16][65];
    __shared__ float Bs[16][64];
    int tid = threadIdx.x;
    int tx = tid & 15;
    int ty = tid >> 4;
    int m0 = blockIdx.y * 64;
    int n0 = blockIdx.x * 64;

    float acc[4][4] = {};

    for (int k0 = 0; k0 < K; k0 += 16) {
        #pragma unroll
        for (int i = 0; i < 4; i++) {
            int e  = tid + i * 256;
            int kk = e & 15;
            int mm = e >> 4;
            int gm = m0 + mm, gk = k0 + kk;
            As[kk][mm] = (gm < M && gk < K) ? A[(size_t)gm * K + gk] : 0.f;
        }
        #pragma unroll
        for (int i = 0; i < 4; i++) {
            int nn = tid & 63;
            int kk = (tid >> 6) + i * 4;
            int gk = k0 + kk, gn = n0 + nn;
            Bs[kk][nn] = (gk < K && gn < N) ? B[(size_t)gk * N + gn] : 0.f;
        }
        __syncthreads();
        #pragma unroll
        for (int kk = 0; kk < 16; kk++) {
            float ra[4], rb[4];
            #pragma unroll
            for (int i = 0; i < 4; i++) ra[i] = As[kk][ty * 4 + i];
            #pragma unroll
            for (int j = 0; j < 4; j++) rb[j] = Bs[kk][tx * 4 + j];
            #pragma unroll
            for (int i = 0; i < 4; i++)
                #pragma unroll
                for (int j = 0; j < 4; j++)
                    acc[i][j] += ra[i] * rb[j];
        }
        __syncthreads();
    }

    #pragma unroll
    for (int i = 0; i < 4; i++) {
        int gm = m0 + ty * 4 + i;
        if (gm >= M) continue;
        #pragma unroll
        for (int j = 0; j < 4; j++) {
            int gn = n0 + tx * 4 + j;
            if (gn >= N) continue;
            float v = acc[i][j];
            if (flags & 1) v += bias[gm];
            if (flags & 2) v += bias[gn];
            if (flags & 4) v = v >= 0.f ? v : 0.01f * v;
            C[(size_t)gm * N + gn] = v;
        }
    }
}

__global__ void a1_reduce_k(const float* __restrict__ Y, float* __restrict__ S, int F)
{
    int f = blockIdx.x * blockDim.x + threadIdx.x;
    int t = blockIdx.y;
    if (f >= F) return;
    float s = 0.f;
    for (int m = 0; m < 88; m++) s += Y[(size_t)(m * 16 + t) * F + f];
    S[t * F + f] = s;
}

__global__ void a1_apply_k(const float* __restrict__ Y, const float* __restrict__ S,
                           const float* __restrict__ bias, float* __restrict__ h, int F)
{
    int idx = blockIdx.x * blockDim.x + threadIdx.x;
    if (idx >= TMN * F) return;
    int f = idx % F;
    int n = idx / F;
    int t = n % 16;
    float val = S[t * F + f] + bias[f];
    if (t == 0) val -= Y[idx];
    h[idx] = val >= 0.f ? val : 0.01f * val;
}

__global__ void v1_k(const float* __restrict__ h2, const float* __restrict__ xhat,
                     float* __restrict__ V1, float* __restrict__ V1t, float* __restrict__ Vx)
{
    int idx = blockIdx.x * blockDim.x + threadIdx.x;
    if (idx >= 256 * 88) return;
    int d = idx % 256;
    int m = idx / 256;
    float mx = -INFINITY;
    #pragma unroll
    for (int t = 0; t < 16; t++) mx = fmaxf(mx, h2[(size_t)(m * 16 + t) * 256 + d]);
    V1[d * 88 + m] = mx;
    V1t[m * 256 + d] = mx;
    Vx[d * 88 + m] = mx + xhat[d * 88 + m];
}

__global__ void attn_k(const float* __restrict__ G, const float* __restrict__ Hh,
                       float* __restrict__ A2)
{
    __shared__ float red[128];
    int j = blockIdx.x;
    int i = threadIdx.x;
    float s = 0.f;
    if (i < 88) {
        for (int d = 0; d < 256; d++) s += Hh[d * 88 + j] * G[d * 88 + i];
    }
    red[i] = (i < 88) ? s : -INFINITY;
    __syncthreads();
    for (int st = 64; st > 0; st >>= 1) {
        if (i < st) red[i] = fmaxf(red[i], red[i + st]);
        __syncthreads();
    }
    float mx = red[0];
    __syncthreads();
    float e = (i < 88) ? expf(s - mx) : 0.f;
    red[i] = e;
    __syncthreads();
    for (int st = 64; st > 0; st >>= 1) {
        if (i < st) red[i] += red[i + st];
        __syncthreads();
    }
    float sum = red[0];
    if (i < 88) A2[j * 88 + i] = e / sum;
}

__global__ void final_dot_k(const float* __restrict__ Xf, const float* __restrict__ V2t,
                            float* __restrict__ out)
{
    __shared__ float red[256];
    float acc = 0.f;
    for (int e = threadIdx.x; e < 256 * 88; e += 256) {
        int d = e / 88, m = e % 88;
        acc += Xf[e] * V2t[m * 256 + d];
    }
    red[threadIdx.x] = acc;
    __syncthreads();
    for (int st = 128; st > 0; st >>= 1) {
        if (threadIdx.x < st) red[threadIdx.x] += red[threadIdx.x + st];
        __syncthreads();
    }
    if (threadIdx.x == 0) out[0] = red[0];
}

// ---------------- host ----------------
static float* symaddr(const void* s)
{
    void* p = nullptr;
    cudaGetSymbolAddress(&p, s);
    return (float*)p;
}
static __nv_bfloat16* symaddr_bf(const void* s)
{
    void* p = nullptr;
    cudaGetSymbolAddress(&p, s);
    return (__nv_bfloat16*)p;
}

extern "C" void kernel_launch(void* const* d_in, const int* in_sizes, int n_in,
                              void* d_out, int out_size)
{
    const float* search    = (const float*)d_in[0];
    const float* exemplars = (const float*)d_in[1];
    const float* aw1 = (const float*)d_in[2];  const float* ab1 = (const float*)d_in[3];
    const float* aw2 = (const float*)d_in[4];  const float* ab2 = (const float*)d_in[5];
    const float* aw3 = (const float*)d_in[6];  const float* ab3 = (const float*)d_in[7];
    const float* aw4 = (const float*)d_in[8];  const float* ab4 = (const float*)d_in[9];
    const float* aw5 = (const float*)d_in[10]; const float* ab5 = (const float*)d_in[11];
    const float* wcd = (const float*)d_in[12]; const float* bcd = (const float*)d_in[13];
    const float* wt  = (const float*)d_in[14]; const float* bt  = (const float*)d_in[15];
    const float* ws1 = (const float*)d_in[16]; const float* bs1 = (const float*)d_in[17];
    const float* ws2 = (const float*)d_in[18]; const float* bs2 = (const float*)d_in[19];
    const float* wg  = (const float*)d_in[20]; const float* bg  = (const float*)d_in[21];
    const float* wh  = (const float*)d_in[22]; const float* bh  = (const float*)d_in[23];
    const float* wc1 = (const float*)d_in[24]; const float* bc1 = (const float*)d_in[25];
    const float* wc2 = (const float*)d_in[26]; const float* bc2 = (const float*)d_in[27];

    float* p_in  = symaddr(g_in);
    float* p_c1  = symaddr(g_c1);
    float* p_p1  = symaddr(g_p1);
    float* p_c2  = symaddr(g_c2);
    float* p_p2  = symaddr(g_p2);
    float* p_c3  = symaddr(g_c3);
    float* p_c4  = symaddr(g_c4);
    float* p_c5  = symaddr(g_c5);
    float* p_p5  = symaddr(g_p5);
    float* p_xc  = symaddr(g_xc);
    float* p_v   = symaddr(g_v);
    float* p_xh  = symaddr(g_xhat);
    float* p_nd  = symaddr(g_nodes);
    float* p_Y1  = symaddr(g_Y1);
    float* p_S   = symaddr(g_S);
    float* p_h1  = symaddr(g_h1);
    float* p_Y2  = symaddr(g_Y2);
    float* p_h2  = symaddr(g_h2);
    float* p_V1  = symaddr(g_V1);
    float* p_V1t = symaddr(g_V1t);
    float* p_Vx  = symaddr(g_Vx);
    float* p_G   = symaddr(g_G);
    float* p_Hh  = symaddr(g_Hh);
    float* p_A2  = symaddr(g_A2);
    float* p_xw  = symaddr(g_xw);
    float* p_c1m = symaddr(g_c1m);
    float* p_cw  = symaddr(g_cw);
    float* p_V2t = symaddr(g_V2t);
    __nv_bfloat16* pAhi = symaddr_bf(g_Ahi);
    __nv_bfloat16* pAlo = symaddr_bf(g_Alo);
    __nv_bfloat16* pBhi = symaddr_bf(g_Bhi);
    __nv_bfloat16* pBlo = symaddr_bf(g_Blo);

    cudaFuncSetAttribute(mmaconv64_k, cudaFuncAttributeMaxDynamicSharedMemorySize, SMEM_G1);
    cudaFuncSetAttribute(mmaconv_imp_k, cudaFuncAttributeMaxDynamicSharedMemorySize, SMEM_G2);

    // zero padded buffers (borders must be 0 every replay)
    cudaMemsetAsync(p_in, 0, sizeof(float) * ((size_t)N_IMG * 3 * H0P * W0P + TAILPAD), 0);
    cudaMemsetAsync(p_p1, 0, sizeof(float) * ((size_t)N_IMG * C1o * P1HP * P1WP + TAILPAD), 0);
    cudaMemsetAsync(p_p2, 0, sizeof(float) * ((size_t)N_IMG * C2o * P2HP * P2WP + TAILPAD), 0);
    cudaMemsetAsync(p_c3, 0, sizeof(float) * ((size_t)N_IMG * C3o * P2HP * P2WP + TAILPAD), 0);
    cudaMemsetAsync(p_c4, 0, sizeof(float) * ((size_t)N_IMG * C4o * P2HP * P2WP + TAILPAD), 0);

    // assemble padded input batch
    {
        int tot = 16 * 3 * H0 * W0;
        pad_copy_k<<<(tot + 127) / 128, 128>>>(exemplars, p_in, 16, 0);
        tot = 3 * H0 * W0;
        pad_copy_k<<<(tot + 127) / 128, 128>>>(search, p_in, 1, 16);
    }

    // ---- conv1 (vectorized im2col, 64x128 tile GEMM): M=64, K=384(pad) ----
    {
        const int KP = 384, NP = N_IMG * H1 * W1;
        wsplit_pad_k<<<(C1o * KP + 255) / 256, 256>>>(aw1, pAhi, pAlo, C1o, 363, KP);
        int tot = NP * (KP / 8);
        im2col_v8_t<3, 11, 4, H0P, W0P, H1, W1, 384><<<(tot + 255) / 256, 256>>>(p_in, pBhi, pBlo);
        mmaconv64_k<<<(NP + 127) / 128, 256, SMEM_G1>>>(
            pAhi, pAlo, pBhi, pBlo, ab1, p_c1, C1o, NP, KP, H1, W1, H1, W1, 0);
    }
    {
        int tot = N_IMG * C1o * P1H * P1W;
        maxpool_k<<<(tot + 127) / 128, 128>>>(p_c1, p_p1, N_IMG * C1o, H1, W1, P1H, P1W, P1HP, P1WP, 2);
    }

    // ---- p1 -> NHWC bf16 ----
    {
        const int NPIX = P1HP * P1WP;
        nchw2nhwc_k<<<dim3((NPIX + 31) / 32, C1o / 32, N_IMG), dim3(32, 8)>>>(p_p1, pBhi, pBlo, C1o, NPIX);
    }

    // ---- conv2 (implicit): M=192, K=1600, CIN=64, KD=5 ----
    {
        const int K = 1600, NP = N_IMG * H2 * W2;
        wsplit_reorder_k<<<(C2o * K + 255) / 256, 256>>>(aw2, pAhi, pAlo, C2o, 64, 25);
        mmaconv_imp_k<<<dim3((NP + 63) / 64, 2), 256, SMEM_G2>>>(
            pAhi, pAlo, pBhi, pBlo, ab2, p_c2, C2o, NP, K, 64, 5,
            P1HP, P1WP, H2, W2, H2, W2, 0);
    }
    {
        int tot = N_IMG * C2o * P2H * P2W;
        maxpool_k<<<(tot + 127) / 128, 128>>>(p_c2, p_p2, N_IMG * C2o, H2, W2, P2H, P2W, P2HP, P2WP, 1);
    }

    // ---- p2 -> NHWC ----
    {
        const int NPIX = P2HP * P2WP;
        nchw2nhwc_k<<<dim3((NPIX + 31) / 32, C2o / 32, N_IMG), dim3(32, 8)>>>(p_p2, pBhi, pBlo, C2o, NPIX);
    }

    // ---- conv3 (implicit): M=384, K=1728, CIN=192 ----
    {
        const int K = 1728, NP = N_IMG * P2H * P2W;
        wsplit_reorder_k<<<(C3o * K + 255) / 256, 256>>>(aw3, pAhi, pAlo, C3o, 192, 9);
        mmaconv_imp_k<<<dim3((NP + 63) / 64, 3), 256, SMEM_G2>>>(
            pAhi, pAlo, pBhi, pBlo, ab3, p_c3, C3o, NP, K, 192, 3,
            P2HP, P2WP, P2H, P2W, P2HP, P2WP, 1);
    }

    // ---- c3 -> NHWC ----
    {
        const int NPIX = P2HP * P2WP;
        nchw2nhwc_k<<<dim3((NPIX + 31) / 32, C3o / 32, N_IMG), dim3(32, 8)>>>(p_c3, pBhi, pBlo, C3o, NPIX);
    }

    // ---- conv4 (implicit): M=256, K=3456, CIN=384 ----
    {
        const int K = 3456, NP = N_IMG * P2H * P2W;
        wsplit_reorder_k<<<(C4o * K + 255) / 256, 256>>>(aw4, pAhi, pAlo, C4o, 384, 9);
        mmaconv_imp_k<<<dim3((NP + 63) / 64, 2), 256, SMEM_G2>>>(
            pAhi, pAlo, pBhi, pBlo, ab4, p_c4, C4o, NP, K, 384, 3,
            P2HP, P2WP, P2H, P2W, P2HP, P2WP, 1);
    }

    // ---- c4 -> NHWC ----
    {
        const int NPIX = P2HP * P2WP;
        nchw2nhwc_k<<<dim3((NPIX + 31) / 32, C4o / 32, N_IMG), dim3(32, 8)>>>(p_c4, pBhi, pBlo, C4o, NPIX);
    }

    // ---- conv5 (implicit): M=256, K=2304, CIN=256, out unpadded ----
    {
        const int K = 2304, NP = N_IMG * P2H * P2W;
        wsplit_reorder_k<<<(C5o * K + 255) / 256, 256>>>(aw5, pAhi, pAlo, C5o, 256, 9);
        mmaconv_imp_k<<<dim3((NP + 63) / 64, 2), 256, SMEM_G2>>>(
            pAhi, pAlo, pBhi, pBlo, ab5, p_c5, C5o, NP, K, 256, 3,
            P2HP, P2WP, P2H, P2W, H5, W5, 0);
    }
    {
        int tot = N_IMG * C5o * P5H * P5W;
        maxpool_k<<<(tot + 127) / 128, 128>>>(p_c5, p_p5, N_IMG * C5o, H5, W5, P5H, P5W, P5H, P5W, 0);
    }

    const float* Xf = p_p5 + (size_t)16 * 256 * 88;

    // ---- conv_deconv branch ----
    cd_conv_k<<<88, 256>>>(Xf, wcd, bcd, p_xc);
    cd_max_k<<<1, 256>>>(p_xc, p_v);
    xhat_k<<<256, 88>>>(p_v, wt, bt, p_xh);

    // ---- spatiotemporal GCN ----
    gather_nodes_k<<<(TMN * 256 + 127) / 128, 128>>>(p_p5, p_nd);
    rbgemm_k<<<dim3(512 / 64, TMN / 64), 256>>>(p_nd, ws1, nullptr, p_Y1, TMN, 512, 256, 0);
    a1_reduce_k<<<dim3(4, 16), 128>>>(p_Y1, p_S, 512);
    a1_apply_k<<<(TMN * 512 + 255) / 256, 256>>>(p_Y1, p_S, bs1, p_h1, 512);
    rbgemm_k<<<dim3(256 / 64, TMN / 64), 256>>>(p_h1, ws2, nullptr, p_Y2, TMN, 256, 512, 0);
    a1_reduce_k<<<dim3(2, 16), 128>>>(p_Y2, p_S, 256);
    a1_apply_k<<<(TMN * 256 + 255) / 256, 256>>>(p_Y2, p_S, bs2, p_h2, 256);
    v1_k<<<(256 * 88 + 255) / 256, 256>>>(p_h2, p_xh, p_V1, p_V1t, p_Vx);

    // ---- dynamic cross-track graph ----
    rbgemm_k<<<dim3((88 + 63) / 64, 256 / 64), 256>>>(wg, p_Vx, bg, p_G, 256, 88, 256, 1);
    rbgemm_k<<<dim3((88 + 63) / 64, 256 / 64), 256>>>(wh, p_Vx, bh, p_Hh, 256, 88, 256, 1);
    attn_k<<<88, 128>>>(p_G, p_Hh, p_A2);

    // ---- ct GCN ----
    rbgemm_k<<<dim3(384 / 64, (88 + 63) / 64), 256>>>(p_V1t, wc1, nullptr, p_xw, 88, 384, 256, 0);
    rbgemm_k<<<dim3(384 / 64, (88 + 63) / 64), 256>>>(p_A2, p_xw, bc1, p_c1m, 88, 384, 88, 2 | 4);
    rbgemm_k<<<dim3(256 / 64, (88 + 63) / 64), 256>>>(p_c1m, wc2, nullptr, p_cw, 88, 256, 384, 0);
    rbgemm_k<<<dim3(256 / 64, (88 + 63) / 64), 256>>>(p_A2, p_cw, bc2, p_V2t, 88, 256, 88, 2 | 4);

    // ---- final correlation ----
    final_dot_k<<<1, 256>>>(Xf, p_V2t, (float*)d_out);
}

// round 11
// speedup vs baseline: 1.1492x; 1.0852x over previous
#include <cuda_runtime.h>
#include <cuda_bf16.h>
#include <cstdint>
#include <math.h>

// ---------------- dimensions ----------------
#define N_IMG 17
#define H0 383
#define W0 287
#define H0P 387
#define W0P 291
#define C1o 64
#define H1 95
#define W1 71
#define P1H 47
#define P1W 35
#define P1HP 51
#define P1WP 39
#define C2o 192
#define H2 47
#define W2 35
#define P2H 23
#define P2W 17
#define P2HP 25
#define P2WP 19
#define C3o 384
#define C4o 256
#define C5o 256
#define H5 23
#define W5 17
#define P5H 11
#define P5W 8
#define MM 88
#define TT 16
#define TMN 1408
#define TAILPAD 4096

// ---------------- scratch (device globals; no allocation) ----------------
__device__ float g_in [N_IMG*3*H0P*W0P + TAILPAD];
__device__ float g_c1 [N_IMG*C1o*H1*W1];
__device__ float g_p1 [N_IMG*C1o*P1HP*P1WP + TAILPAD];
__device__ float g_c2 [N_IMG*C2o*H2*W2];
__device__ float g_p2 [N_IMG*C2o*P2HP*P2WP + TAILPAD];
__device__ float g_c3 [N_IMG*C3o*P2HP*P2WP + TAILPAD];
__device__ float g_c4 [N_IMG*C4o*P2HP*P2WP + TAILPAD];
__device__ float g_c5 [N_IMG*C5o*H5*W5];
__device__ float g_p5 [N_IMG*C5o*MM];
__device__ float g_xc [256*88];
__device__ float g_v  [256];
__device__ float g_xhat[256*88];
__device__ float g_nodes[TMN*256];
__device__ float g_Y1 [TMN*512];
__device__ float g_S  [16*512];
__device__ float g_h1 [TMN*512];
__device__ float g_Y2 [TMN*256];
__device__ float g_h2 [TMN*256];
__device__ float g_V1 [256*88];
__device__ float g_V1t[88*256];
__device__ float g_Vx [256*88];
__device__ float g_G  [256*88];
__device__ float g_Hh [256*88];
__device__ float g_A2 [88*88];
__device__ float g_xw [88*384];
__device__ float g_c1m[88*384];
__device__ float g_cw [88*256];
__device__ float g_V2t[88*256];

// bf16 split matrices for tensor-core conv GEMMs (also reused as NHWC maps)
__device__ __nv_bfloat16 g_Ahi[384*3456];
__device__ __nv_bfloat16 g_Alo[384*3456];
__device__ __nv_bfloat16 g_Bhi[44800000];
__device__ __nv_bfloat16 g_Blo[44800000];

// ---------------- mma / cp.async helpers (baseline PTX, sm_80+) ----------------
__device__ __forceinline__ uint32_t smem_u32(const void* p)
{
    uint32_t a;
    asm("{ .reg .u64 t; cvta.to.shared.u64 t, %1; cvt.u32.u64 %0, t; }" : "=r"(a) : "l"(p));
    return a;
}
__device__ __forceinline__ void ldsm_x4(uint32_t& r0, uint32_t& r1, uint32_t& r2, uint32_t& r3,
                                        uint32_t addr)
{
    asm volatile("ldmatrix.sync.aligned.m8n8.x4.shared.b16 {%0,%1,%2,%3}, [%4];"
                 : "=r"(r0), "=r"(r1), "=r"(r2), "=r"(r3) : "r"(addr));
}
__device__ __forceinline__ void mma16816(float* d, const uint32_t* a, uint32_t b0, uint32_t b1)
{
    asm volatile("mma.sync.aligned.m16n8k16.row.col.f32.bf16.bf16.f32 "
                 "{%0,%1,%2,%3}, {%4,%5,%6,%7}, {%8,%9}, {%0,%1,%2,%3};"
                 : "+f"(d[0]), "+f"(d[1]), "+f"(d[2]), "+f"(d[3])
                 : "r"(a[0]), "r"(a[1]), "r"(a[2]), "r"(a[3]), "r"(b0), "r"(b1));
}
__device__ __forceinline__ void cp16(uint32_t dst, const void* src, bool pred)
{
    int sz = pred ? 16 : 0;
    asm volatile("cp.async.cg.shared.global [%0], [%1], 16, %2;"
                 :: "r"(dst), "l"(src), "r"(sz));
}
#define CP_COMMIT() asm volatile("cp.async.commit_group;" ::: "memory")
#define CP_WAIT(n)  asm volatile("cp.async.wait_group %0;" :: "n"(n) : "memory")

// ---------------- prep kernels ----------------
__global__ void wsplit_pad_k(const float* __restrict__ w, __nv_bfloat16* __restrict__ hi,
                             __nv_bfloat16* __restrict__ lo, int M, int Kreal, int KPAD)
{
    int i = blockIdx.x * blockDim.x + threadIdx.x;
    if (i >= M * KPAD) return;
    int m = i / KPAD, k = i - m * KPAD;
    float x = (k < Kreal) ? w[(size_t)m * Kreal + k] : 0.f;
    __nv_bfloat16 h = __float2bfloat16_rn(x);
    hi[i] = h;
    lo[i] = __float2bfloat16_rn(x - __bfloat162float(h));
}

__global__ void wsplit_reorder_k(const float* __restrict__ w, __nv_bfloat16* __restrict__ hi,
                                 __nv_bfloat16* __restrict__ lo, int M, int CIN, int KK)
{
    int K = CIN * KK;
    int i = blockIdx.x * blockDim.x + threadIdx.x;
    if (i >= M * K) return;
    int m = i / K, kidx = i - m * K;
    int pos = kidx / CIN, ci = kidx - pos * CIN;
    float x = w[((size_t)m * CIN + ci) * KK + pos];
    __nv_bfloat16 h = __float2bfloat16_rn(x);
    hi[i] = h;
    lo[i] = __float2bfloat16_rn(x - __bfloat162float(h));
}

__global__ void nchw2nhwc_k(const float* __restrict__ in,
                            __nv_bfloat16* __restrict__ hi, __nv_bfloat16* __restrict__ lo,
                            int C, int NPIX)
{
    __shared__ float t[32][33];
    int img = blockIdx.z;
    int p0 = blockIdx.x * 32, c0 = blockIdx.y * 32;
    int tx = threadIdx.x, ty = threadIdx.y;
    const float* src = in + (size_t)img * C * NPIX;
    #pragma unroll
    for (int i = 0; i < 4; i++) {
        int c = c0 + ty + i * 8, p = p0 + tx;
        if (p < NPIX) t[ty + i * 8][tx] = src[(size_t)c * NPIX + p];
    }
    __syncthreads();
    #pragma unroll
    for (int i = 0; i < 4; i++) {
        int p = p0 + ty + i * 8, c = c0 + tx;
        if (p < NPIX) {
            float x = t[tx][ty + i * 8];
            __nv_bfloat16 h = __float2bfloat16_rn(x);
            size_t o = ((size_t)img * NPIX + p) * C + c;
            hi[o] = h;
            lo[o] = __float2bfloat16_rn(x - __bfloat162float(h));
        }
    }
}

template<int CIN, int KD, int S, int HinP, int WinP, int Hout, int Wout, int KPAD>
__global__ void im2col_v8_t(const float* __restrict__ in,
                            __nv_bfloat16* __restrict__ bhi, __nv_bfloat16* __restrict__ blo)
{
    constexpr int KK = KD * KD;
    constexpr int KREAL = CIN * KK;
    constexpr int HW = Hout * Wout;
    constexpr int NPIX = N_IMG * HW;
    constexpr int KQ = KPAD / 8;
    int idx = blockIdx.x * blockDim.x + threadIdx.x;
    if (idx >= NPIX * KQ) return;
    int p  = idx / KQ;
    int k0 = (idx - p * KQ) * 8;
    int img = p / HW;
    int rr  = p - img * HW;
    int oh  = rr / Wout;
    int ow  = rr - oh * Wout;
    const float* base = in + ((size_t)img * CIN * HinP + oh * S) * WinP + ow * S;

    __nv_bfloat16 hv[8], lv[8];
    #pragma unroll
    for (int j = 0; j < 8; j++) {
        int k = k0 + j;
        float x = 0.f;
        if (k < KREAL) {
            int ci = k / KK;
            int r  = k - ci * KK;
            int kh = r / KD;
            int kw = r - kh * KD;
            x = base[((size_t)ci * HinP + kh) * WinP + kw];
        }
        __nv_bfloat16 h = __float2bfloat16_rn(x);
        hv[j] = h;
        lv[j] = __float2bfloat16_rn(x - __bfloat162float(h));
    }
    size_t o = (size_t)p * KPAD + k0;
    *(uint4*)(bhi + o) = *(const uint4*)hv;
    *(uint4*)(blo + o) = *(const uint4*)lv;
}

// ---------------- fused-segment tensor-core conv GEMMs ----------------
// Per 64-wide K chunk: load Ahi+Alo and Bhi+Blo tiles once; issue the three MMA
// passes (hi*hi, hi*lo, lo*hi) from the same SMEM tiles. 2-stage cp.async.
#define ASTR 72

// -------- explicit-B GEMM, 64(M) x 128(N) — conv1 --------
#define A1_SZ (64 * ASTR * 2)
#define B1_SZ (128 * ASTR * 2)
#define ST1_SZ (2 * A1_SZ + 2 * B1_SZ)
#define SMEM_G1 (2 * ST1_SZ)
__global__ void __launch_bounds__(256)
mmaconv64_k(const __nv_bfloat16* __restrict__ Ahi, const __nv_bfloat16* __restrict__ Alo,
            const __nv_bfloat16* __restrict__ Bhi, const __nv_bfloat16* __restrict__ Blo,
            const float* __restrict__ bias, float* __restrict__ out,
            int M, int Npix, int K, int Hout, int Wout,
            int HoP, int WoP, int opad)
{
    extern __shared__ char smem[];
    uint32_t sb = smem_u32(smem);
    // stage layout: [AHI][ALO][BHI][BLO]
    uint32_t stg[2] = { sb, sb + ST1_SZ };

    int tid  = threadIdx.x;
    int lane = tid & 31;
    int wid  = tid >> 5;
    int wm   = wid & 1;
    int wn   = wid >> 1;

    int m0 = 0;
    int n0 = blockIdx.x * 128;

    float d[2][4][4];
    #pragma unroll
    for (int i = 0; i < 2; i++)
        #pragma unroll
        for (int j = 0; j < 4; j++)
            #pragma unroll
            for (int r = 0; r < 4; r++) d[i][j][r] = 0.f;

    int aj = lane >> 3, ar = lane & 7;
    uint32_t aAddrOff = (uint32_t)(((aj & 1) * 8 + ar) * ASTR + (aj >> 1) * 8) * 2;
    uint32_t bAddrOff = (uint32_t)(((aj >> 1) * 8 + ar) * ASTR + (aj & 1) * 8) * 2;

    int itK = K >> 6;

    int arow[2], aq[2];
    #pragma unroll
    for (int j = 0; j < 2; j++) { int i = tid + j * 256; arow[j] = i >> 3; aq[j] = i & 7; }
    int brow[4], bq[4];
    #pragma unroll
    for (int j = 0; j < 4; j++) { int i = tid + j * 256; brow[j] = i >> 3; bq[j] = i & 7; }

    auto load_stage = [&](int st, int it) {
        int kof = it << 6;
        uint32_t s = stg[st];
        #pragma unroll
        for (int j = 0; j < 2; j++) {
            size_t go = (size_t)(m0 + arow[j]) * K + kof + aq[j] * 8;
            uint32_t so = (uint32_t)(arow[j] * ASTR + aq[j] * 8) * 2;
            bool pr = m0 + arow[j] < M;
            cp16(s + so, Ahi + go, pr);
            cp16(s + A1_SZ + so, Alo + go, pr);
        }
        #pragma unroll
        for (int j = 0; j < 4; j++) {
            size_t go = (size_t)(n0 + brow[j]) * K + kof + bq[j] * 8;
            uint32_t so = (uint32_t)(brow[j] * ASTR + bq[j] * 8) * 2;
            bool pr = n0 + brow[j] < Npix;
            cp16(s + 2 * A1_SZ + so, Bhi + go, pr);
            cp16(s + 2 * A1_SZ + B1_SZ + so, Blo + go, pr);
        }
        CP_COMMIT();
    };

    load_stage(0, 0);

    for (int it = 0; it < itK; it++) {
        int st = it & 1;
        if (it + 1 < itK) { load_stage(st ^ 1, it + 1); CP_WAIT(1); }
        else              { CP_WAIT(0); }
        __syncthreads();
        uint32_t s = stg[st];

        #pragma unroll
        for (int kk = 0; kk < 4; kk++) {
            uint32_t ah[2][4], al[2][4];
            #pragma unroll
            for (int mi = 0; mi < 2; mi++) {
                uint32_t off = aAddrOff + (uint32_t)((wm * 32 + mi * 16) * ASTR + kk * 16) * 2;
                ldsm_x4(ah[mi][0], ah[mi][1], ah[mi][2], ah[mi][3], s + off);
                ldsm_x4(al[mi][0], al[mi][1], al[mi][2], al[mi][3], s + A1_SZ + off);
            }
            uint32_t bh[4][2], bl[4][2];
            #pragma unroll
            for (int q = 0; q < 2; q++) {
                uint32_t off = bAddrOff + (uint32_t)((wn * 32 + q * 16) * ASTR + kk * 16) * 2;
                uint32_t r0, r1, r2, r3;
                ldsm_x4(r0, r1, r2, r3, s + 2 * A1_SZ + off);
                bh[q * 2][0] = r0; bh[q * 2][1] = r1;
                bh[q * 2 + 1][0] = r2; bh[q * 2 + 1][1] = r3;
                ldsm_x4(r0, r1, r2, r3, s + 2 * A1_SZ + B1_SZ + off);
                bl[q * 2][0] = r0; bl[q * 2][1] = r1;
                bl[q * 2 + 1][0] = r2; bl[q * 2 + 1][1] = r3;
            }
            #pragma unroll
            for (int mi = 0; mi < 2; mi++)
                #pragma unroll
                for (int nj = 0; nj < 4; nj++) {
                    mma16816(d[mi][nj], ah[mi], bh[nj][0], bh[nj][1]);
                    mma16816(d[mi][nj], ah[mi], bl[nj][0], bl[nj][1]);
                    mma16816(d[mi][nj], al[mi], bh[nj][0], bh[nj][1]);
                }
        }
        __syncthreads();
    }

    int HW = Hout * Wout;
    #pragma unroll
    for (int mi = 0; mi < 2; mi++) {
        #pragma unroll
        for (int r2 = 0; r2 < 2; r2++) {
            int co = m0 + wm * 32 + mi * 16 + (lane >> 2) + r2 * 8;
            if (co >= M) continue;
            float bv = bias[co];
            #pragma unroll
            for (int nj = 0; nj < 4; nj++) {
                #pragma unroll
                for (int c = 0; c < 2; c++) {
                    int p = n0 + wn * 32 + nj * 8 + (lane & 3) * 2 + c;
                    if (p >= Npix) continue;
                    float v = d[mi][nj][r2 * 2 + c] + bv;
                    int img = p / HW;
                    int rr  = p - img * HW;
                    int oh  = rr / Wout;
                    int ow  = rr - oh * Wout;
                    out[((size_t)(img * M + co) * HoP + oh + opad) * WoP + ow + opad]
                        = fmaxf(v, 0.f);
                }
            }
        }
    }
}

// -------- implicit-B GEMM, 128(M) x 64(N), B gathered from NHWC map --------
#define A2_SZ (128 * ASTR * 2)
#define B2_SZ (64 * ASTR * 2)
#define ST2_SZ (2 * A2_SZ + 2 * B2_SZ)
#define SMEM_G2 (2 * ST2_SZ)
__global__ void __launch_bounds__(256)
mmaconv_imp_k(const __nv_bfloat16* __restrict__ Ahi, const __nv_bfloat16* __restrict__ Alo,
              const __nv_bfloat16* __restrict__ Xhi, const __nv_bfloat16* __restrict__ Xlo,
              const float* __restrict__ bias, float* __restrict__ out,
              int M, int Npix, int K, int CIN, int KD,
              int HinP, int WinP, int Hout, int Wout,
              int HoP, int WoP, int opad)
{
    extern __shared__ char smem[];
    uint32_t sb = smem_u32(smem);
    uint32_t stg[2] = { sb, sb + ST2_SZ };

    int tid  = threadIdx.x;
    int lane = tid & 31;
    int wid  = tid >> 5;
    int wm   = wid & 3;
    int wn   = wid >> 2;

    int m0 = blockIdx.y * 128;
    int n0 = blockIdx.x * 64;

    float d[2][4][4];
    #pragma unroll
    for (int i = 0; i < 2; i++)
        #pragma unroll
        for (int j = 0; j < 4; j++)
            #pragma unroll
            for (int r = 0; r < 4; r++) d[i][j][r] = 0.f;

    int aj = lane >> 3, ar = lane & 7;
    uint32_t aAddrOff = (uint32_t)(((aj & 1) * 8 + ar) * ASTR + (aj >> 1) * 8) * 2;
    uint32_t bAddrOff = (uint32_t)(((aj >> 1) * 8 + ar) * ASTR + (aj & 1) * 8) * 2;

    int itK = K >> 6;
    int cPer = CIN >> 6;
    int HW = Hout * Wout;

    int arow[4], aq[4];
    #pragma unroll
    for (int j = 0; j < 4; j++) { int i = tid + j * 256; arow[j] = i >> 3; aq[j] = i & 7; }
    int brow[2], bq[2];
    long bbase[2];
    bool bval[2];
    #pragma unroll
    for (int j = 0; j < 2; j++) {
        int i = tid + j * 256;
        brow[j] = i >> 3; bq[j] = i & 7;
        int p = n0 + brow[j];
        bval[j] = p < Npix;
        if (!bval[j]) p = 0;
        int img = p / HW;
        int rr  = p - img * HW;
        int oh  = rr / Wout;
        int ow  = rr - oh * Wout;
        bbase[j] = ((long)(img * HinP + oh) * WinP + ow) * CIN;
    }

    auto load_stage = [&](int st, int it) {
        int pos = it / cPer;
        int cioff = (it - pos * cPer) << 6;
        int kh = pos / KD, kw = pos - kh * KD;
        int kofA = it << 6;
        long boff = (long)(kh * WinP + kw) * CIN + cioff;
        uint32_t s = stg[st];
        #pragma unroll
        for (int j = 0; j < 4; j++) {
            size_t go = (size_t)(m0 + arow[j]) * K + kofA + aq[j] * 8;
            uint32_t so = (uint32_t)(arow[j] * ASTR + aq[j] * 8) * 2;
            bool pr = m0 + arow[j] < M;
            cp16(s + so, Ahi + go, pr);
            cp16(s + A2_SZ + so, Alo + go, pr);
        }
        #pragma unroll
        for (int j = 0; j < 2; j++) {
            long go = bbase[j] + boff + bq[j] * 8;
            uint32_t so = (uint32_t)(brow[j] * ASTR + bq[j] * 8) * 2;
            cp16(s + 2 * A2_SZ + so, Xhi + go, bval[j]);
            cp16(s + 2 * A2_SZ + B2_SZ + so, Xlo + go, bval[j]);
        }
        CP_COMMIT();
    };

    load_stage(0, 0);

    for (int it = 0; it < itK; it++) {
        int st = it & 1;
        if (it + 1 < itK) { load_stage(st ^ 1, it + 1); CP_WAIT(1); }
        else              { CP_WAIT(0); }
        __syncthreads();
        uint32_t s = stg[st];

        #pragma unroll
        for (int kk = 0; kk < 4; kk++) {
            uint32_t ah[2][4], al[2][4];
            #pragma unroll
            for (int mi = 0; mi < 2; mi++) {
                uint32_t off = aAddrOff + (uint32_t)((wm * 32 + mi * 16) * ASTR + kk * 16) * 2;
                ldsm_x4(ah[mi][0], ah[mi][1], ah[mi][2], ah[mi][3], s + off);
                ldsm_x4(al[mi][0], al[mi][1], al[mi][2], al[mi][3], s + A2_SZ + off);
            }
            uint32_t bh[4][2], bl[4][2];
            #pragma unroll
            for (int q = 0; q < 2; q++) {
                uint32_t off = bAddrOff + (uint32_t)((wn * 32 + q * 16) * ASTR + kk * 16) * 2;
                uint32_t r0, r1, r2, r3;
                ldsm_x4(r0, r1, r2, r3, s + 2 * A2_SZ + off);
                bh[q * 2][0] = r0; bh[q * 2][1] = r1;
                bh[q * 2 + 1][0] = r2; bh[q * 2 + 1][1] = r3;
                ldsm_x4(r0, r1, r2, r3, s + 2 * A2_SZ + B2_SZ + off);
                bl[q * 2][0] = r0; bl[q * 2][1] = r1;
                bl[q * 2 + 1][0] = r2; bl[q * 2 + 1][1] = r3;
            }
            #pragma unroll
            for (int mi = 0; mi < 2; mi++)
                #pragma unroll
                for (int nj = 0; nj < 4; nj++) {
                    mma16816(d[mi][nj], ah[mi], bh[nj][0], bh[nj][1]);
                    mma16816(d[mi][nj], ah[mi], bl[nj][0], bl[nj][1]);
                    mma16816(d[mi][nj], al[mi], bh[nj][0], bh[nj][1]);
                }
        }
        __syncthreads();
    }

    #pragma unroll
    for (int mi = 0; mi < 2; mi++) {
        #pragma unroll
        for (int r2 = 0; r2 < 2; r2++) {
            int co = m0 + wm * 32 + mi * 16 + (lane >> 2) + r2 * 8;
            if (co >= M) continue;
            float bv = bias[co];
            #pragma unroll
            for (int nj = 0; nj < 4; nj++) {
                #pragma unroll
                for (int c = 0; c < 2; c++) {
                    int p = n0 + wn * 32 + nj * 8 + (lane & 3) * 2 + c;
                    if (p >= Npix) continue;
                    float v = d[mi][nj][r2 * 2 + c] + bv;
                    int img = p / HW;
                    int rr  = p - img * HW;
                    int oh  = rr / Wout;
                    int ow  = rr - oh * Wout;
                    out[((size_t)(img * M + co) * HoP + oh + opad) * WoP + ow + opad]
                        = fmaxf(v, 0.f);
                }
            }
        }
    }
}

// ---------------- scalar kernels (rest of network) ----------------

__global__ void pad_copy_k(const float* __restrict__ src, float* __restrict__ dst,
                           int nimg, int boff)
{
    int idx = blockIdx.x * blockDim.x + threadIdx.x;
    int total = nimg * 3 * H0 * W0;
    if (idx >= total) return;
    int w = idx % W0; int t = idx / W0;
    int h = t % H0;   t /= H0;
    int c = t % 3;    int n = t / 3;
    dst[(((size_t)(boff + n) * 3 + c) * H0P + h + 2) * W0P + (w + 2)] = src[idx];
}

__global__ void maxpool_k(const float* __restrict__ in, float* __restrict__ out,
                          int NC, int Hin, int Win, int Ho, int Wo,
                          int HoP, int WoP, int opad)
{
    int idx = blockIdx.x * blockDim.x + threadIdx.x;
    int total = NC * Ho * Wo;
    if (idx >= total) return;
    int ow = idx % Wo; int t = idx / Wo;
    int oh = t % Ho;   int nc = t / Ho;
    const float* ip = in + ((size_t)nc * Hin + oh * 2) * Win + ow * 2;
    float m = -INFINITY;
    #pragma unroll
    for (int kh = 0; kh < 3; kh++)
        #pragma unroll
        for (int kw = 0; kw < 3; kw++)
            m = fmaxf(m, ip[kh * Win + kw]);
    out[((size_t)nc * HoP + oh + opad) * WoP + ow + opad] = m;
}

__global__ void cd_conv_k(const float* __restrict__ Xf, const float* __restrict__ wcd,
                          const float* __restrict__ bcd, float* __restrict__ xc)
{
    int p = blockIdx.x;
    int o = threadIdx.x;
    float acc = bcd[o];
    for (int i = 0; i < 256; i++) {
        const float* wr = wcd + (o * 256 + i) * 3;
        const float* xr = Xf + i * 88;
        if (p > 0)  acc += xr[p - 1] * wr[0];
        acc += xr[p] * wr[1];
        if (p < 87) acc += xr[p + 1] * wr[2];
    }
    xc[o * 88 + p] = acc;
}

__global__ void cd_max_k(const float* __restrict__ xc, float* __restrict__ v)
{
    int o = threadIdx.x;
    float m = -INFINITY;
    for (int p = 0; p < 88; p++) m = fmaxf(m, xc[o * 88 + p]);
    v[o] = m;
}

__global__ void xhat_k(const float* __restrict__ v, const float* __restrict__ wt,
                       const float* __restrict__ bt, float* __restrict__ xhat)
{
    __shared__ float sv[256];
    int o = blockIdx.x;
    int k = threadIdx.x;
    for (int i = threadIdx.x; i < 256; i += blockDim.x) sv[i] = v[i];
    __syncthreads();
    float acc = bt[o];
    for (int i = 0; i < 256; i++)
        acc += sv[i] * wt[((size_t)i * 256 + o) * 88 + k];
    xhat[o * 88 + k] = acc;
}

__global__ void gather_nodes_k(const float* __restrict__ p5, float* __restrict__ nodes)
{
    int idx = blockIdx.x * blockDim.x + threadIdx.x;
    if (idx >= TMN * 256) return;
    int d = idx % 256;
    int n = idx / 256;
    int t = n % 16, m = n / 16;
    nodes[idx] = p5[((size_t)t * 256 + d) * 88 + m];
}

__global__ __launch_bounds__(256)
void rbgemm_k(const float* __restrict__ A, const float* __restrict__ B,
              const float* __restrict__ bias, float* __restrict__ C,
              int M, int N, int K, int flags)
{
    __shared__ float As[16][65];
    __shared__ float Bs[16][64];
    int tid = threadIdx.x;
    int tx = tid & 15;
    int ty = tid >> 4;
    int m0 = blockIdx.y * 64;
    int n0 = blockIdx.x * 64;

    float acc[4][4] = {};

    for (int k0 = 0; k0 < K; k0 += 16) {
        #pragma unroll
        for (int i = 0; i < 4; i++) {
            int e  = tid + i * 256;
            int kk = e & 15;
            int mm = e >> 4;
            int gm = m0 + mm, gk = k0 + kk;
            As[kk][mm] = (gm < M && gk < K) ? A[(size_t)gm * K + gk] : 0.f;
        }
        #pragma unroll
        for (int i = 0; i < 4; i++) {
            int nn = tid & 63;
            int kk = (tid >> 6) + i * 4;
            int gk = k0 + kk, gn = n0 + nn;
            Bs[kk][nn] = (gk < K && gn < N) ? B[(size_t)gk * N + gn] : 0.f;
        }
        __syncthreads();
        #pragma unroll
        for (int kk = 0; kk < 16; kk++) {
            float ra[4], rb[4];
            #pragma unroll
            for (int i = 0; i < 4; i++) ra[i] = As[kk][ty * 4 + i];
            #pragma unroll
            for (int j = 0; j < 4; j++) rb[j] = Bs[kk][tx * 4 + j];
            #pragma unroll
            for (int i = 0; i < 4; i++)
                #pragma unroll
                for (int j = 0; j < 4; j++)
                    acc[i][j] += ra[i] * rb[j];
        }
        __syncthreads();
    }

    #pragma unroll
    for (int i = 0; i < 4; i++) {
        int gm = m0 + ty * 4 + i;
        if (gm >= M) continue;
        #pragma unroll
        for (int j = 0; j < 4; j++) {
            int gn = n0 + tx * 4 + j;
            if (gn >= N) continue;
            float v = acc[i][j];
            if (flags & 1) v += bias[gm];
            if (flags & 2) v += bias[gn];
            if (flags & 4) v = v >= 0.f ? v : 0.01f * v;
            C[(size_t)gm * N + gn] = v;
        }
    }
}

__global__ void a1_reduce_k(const float* __restrict__ Y, float* __restrict__ S, int F)
{
    int f = blockIdx.x * blockDim.x + threadIdx.x;
    int t = blockIdx.y;
    if (f >= F) return;
    float s = 0.f;
    for (int m = 0; m < 88; m++) s += Y[(size_t)(m * 16 + t) * F + f];
    S[t * F + f] = s;
}

__global__ void a1_apply_k(const float* __restrict__ Y, const float* __restrict__ S,
                           const float* __restrict__ bias, float* __restrict__ h, int F)
{
    int idx = blockIdx.x * blockDim.x + threadIdx.x;
    if (idx >= TMN * F) return;
    int f = idx % F;
    int n = idx / F;
    int t = n % 16;
    float val = S[t * F + f] + bias[f];
    if (t == 0) val -= Y[idx];
    h[idx] = val >= 0.f ? val : 0.01f * val;
}

__global__ void v1_k(const float* __restrict__ h2, const float* __restrict__ xhat,
                     float* __restrict__ V1, float* __restrict__ V1t, float* __restrict__ Vx)
{
    int idx = blockIdx.x * blockDim.x + threadIdx.x;
    if (idx >= 256 * 88) return;
    int d = idx % 256;
    int m = idx / 256;
    float mx = -INFINITY;
    #pragma unroll
    for (int t = 0; t < 16; t++) mx = fmaxf(mx, h2[(size_t)(m * 16 + t) * 256 + d]);
    V1[d * 88 + m] = mx;
    V1t[m * 256 + d] = mx;
    Vx[d * 88 + m] = mx + xhat[d * 88 + m];
}

__global__ void attn_k(const float* __restrict__ G, const float* __restrict__ Hh,
                       float* __restrict__ A2)
{
    __shared__ float red[128];
    int j = blockIdx.x;
    int i = threadIdx.x;
    float s = 0.f;
    if (i < 88) {
        for (int d = 0; d < 256; d++) s += Hh[d * 88 + j] * G[d * 88 + i];
    }
    red[i] = (i < 88) ? s : -INFINITY;
    __syncthreads();
    for (int st = 64; st > 0; st >>= 1) {
        if (i < st) red[i] = fmaxf(red[i], red[i + st]);
        __syncthreads();
    }
    float mx = red[0];
    __syncthreads();
    float e = (i < 88) ? expf(s - mx) : 0.f;
    red[i] = e;
    __syncthreads();
    for (int st = 64; st > 0; st >>= 1) {
        if (i < st) red[i] += red[i + st];
        __syncthreads();
    }
    float sum = red[0];
    if (i < 88) A2[j * 88 + i] = e / sum;
}

__global__ void final_dot_k(const float* __restrict__ Xf, const float* __restrict__ V2t,
                            float* __restrict__ out)
{
    __shared__ float red[256];
    float acc = 0.f;
    for (int e = threadIdx.x; e < 256 * 88; e += 256) {
        int d = e / 88, m = e % 88;
        acc += Xf[e] * V2t[m * 256 + d];
    }
    red[threadIdx.x] = acc;
    __syncthreads();
    for (int st = 128; st > 0; st >>= 1) {
        if (threadIdx.x < st) red[threadIdx.x] += red[threadIdx.x + st];
        __syncthreads();
    }
    if (threadIdx.x == 0) out[0] = red[0];
}

// ---------------- host ----------------
static float* symaddr(const void* s)
{
    void* p = nullptr;
    cudaGetSymbolAddress(&p, s);
    return (float*)p;
}
static __nv_bfloat16* symaddr_bf(const void* s)
{
    void* p = nullptr;
    cudaGetSymbolAddress(&p, s);
    return (__nv_bfloat16*)p;
}

extern "C" void kernel_launch(void* const* d_in, const int* in_sizes, int n_in,
                              void* d_out, int out_size)
{
    const float* search    = (const float*)d_in[0];
    const float* exemplars = (const float*)d_in[1];
    const float* aw1 = (const float*)d_in[2];  const float* ab1 = (const float*)d_in[3];
    const float* aw2 = (const float*)d_in[4];  const float* ab2 = (const float*)d_in[5];
    const float* aw3 = (const float*)d_in[6];  const float* ab3 = (const float*)d_in[7];
    const float* aw4 = (const float*)d_in[8];  const float* ab4 = (const float*)d_in[9];
    const float* aw5 = (const float*)d_in[10]; const float* ab5 = (const float*)d_in[11];
    const float* wcd = (const float*)d_in[12]; const float* bcd = (const float*)d_in[13];
    const float* wt  = (const float*)d_in[14]; const float* bt  = (const float*)d_in[15];
    const float* ws1 = (const float*)d_in[16]; const float* bs1 = (const float*)d_in[17];
    const float* ws2 = (const float*)d_in[18]; const float* bs2 = (const float*)d_in[19];
    const float* wg  = (const float*)d_in[20]; const float* bg  = (const float*)d_in[21];
    const float* wh  = (const float*)d_in[22]; const float* bh  = (const float*)d_in[23];
    const float* wc1 = (const float*)d_in[24]; const float* bc1 = (const float*)d_in[25];
    const float* wc2 = (const float*)d_in[26]; const float* bc2 = (const float*)d_in[27];

    float* p_in  = symaddr(g_in);
    float* p_c1  = symaddr(g_c1);
    float* p_p1  = symaddr(g_p1);
    float* p_c2  = symaddr(g_c2);
    float* p_p2  = symaddr(g_p2);
    float* p_c3  = symaddr(g_c3);
    float* p_c4  = symaddr(g_c4);
    float* p_c5  = symaddr(g_c5);
    float* p_p5  = symaddr(g_p5);
    float* p_xc  = symaddr(g_xc);
    float* p_v   = symaddr(g_v);
    float* p_xh  = symaddr(g_xhat);
    float* p_nd  = symaddr(g_nodes);
    float* p_Y1  = symaddr(g_Y1);
    float* p_S   = symaddr(g_S);
    float* p_h1  = symaddr(g_h1);
    float* p_Y2  = symaddr(g_Y2);
    float* p_h2  = symaddr(g_h2);
    float* p_V1  = symaddr(g_V1);
    float* p_V1t = symaddr(g_V1t);
    float* p_Vx  = symaddr(g_Vx);
    float* p_G   = symaddr(g_G);
    float* p_Hh  = symaddr(g_Hh);
    float* p_A2  = symaddr(g_A2);
    float* p_xw  = symaddr(g_xw);
    float* p_c1m = symaddr(g_c1m);
    float* p_cw  = symaddr(g_cw);
    float* p_V2t = symaddr(g_V2t);
    __nv_bfloat16* pAhi = symaddr_bf(g_Ahi);
    __nv_bfloat16* pAlo = symaddr_bf(g_Alo);
    __nv_bfloat16* pBhi = symaddr_bf(g_Bhi);
    __nv_bfloat16* pBlo = symaddr_bf(g_Blo);

    cudaFuncSetAttribute(mmaconv64_k, cudaFuncAttributeMaxDynamicSharedMemorySize, SMEM_G1);
    cudaFuncSetAttribute(mmaconv_imp_k, cudaFuncAttributeMaxDynamicSharedMemorySize, SMEM_G2);

    // zero padded buffers (borders must be 0 every replay)
    cudaMemsetAsync(p_in, 0, sizeof(float) * ((size_t)N_IMG * 3 * H0P * W0P + TAILPAD), 0);
    cudaMemsetAsync(p_p1, 0, sizeof(float) * ((size_t)N_IMG * C1o * P1HP * P1WP + TAILPAD), 0);
    cudaMemsetAsync(p_p2, 0, sizeof(float) * ((size_t)N_IMG * C2o * P2HP * P2WP + TAILPAD), 0);
    cudaMemsetAsync(p_c3, 0, sizeof(float) * ((size_t)N_IMG * C3o * P2HP * P2WP + TAILPAD), 0);
    cudaMemsetAsync(p_c4, 0, sizeof(float) * ((size_t)N_IMG * C4o * P2HP * P2WP + TAILPAD), 0);

    // assemble padded input batch
    {
        int tot = 16 * 3 * H0 * W0;
        pad_copy_k<<<(tot + 127) / 128, 128>>>(exemplars, p_in, 16, 0);
        tot = 3 * H0 * W0;
        pad_copy_k<<<(tot + 127) / 128, 128>>>(search, p_in, 1, 16);
    }

    // ---- conv1 (vectorized im2col, fused-segment 64x128 GEMM): M=64, K=384(pad) ----
    {
        const int KP = 384, NP = N_IMG * H1 * W1;
        wsplit_pad_k<<<(C1o * KP + 255) / 256, 256>>>(aw1, pAhi, pAlo, C1o, 363, KP);
        int tot = NP * (KP / 8);
        im2col_v8_t<3, 11, 4, H0P, W0P, H1, W1, 384><<<(tot + 255) / 256, 256>>>(p_in, pBhi, pBlo);
        mmaconv64_k<<<(NP + 127) / 128, 256, SMEM_G1>>>(
            pAhi, pAlo, pBhi, pBlo, ab1, p_c1, C1o, NP, KP, H1, W1, H1, W1, 0);
    }
    {
        int tot = N_IMG * C1o * P1H * P1W;
        maxpool_k<<<(tot + 127) / 128, 128>>>(p_c1, p_p1, N_IMG * C1o, H1, W1, P1H, P1W, P1HP, P1WP, 2);
    }

    // ---- p1 -> NHWC bf16 ----
    {
        const int NPIX = P1HP * P1WP;
        nchw2nhwc_k<<<dim3((NPIX + 31) / 32, C1o / 32, N_IMG), dim3(32, 8)>>>(p_p1, pBhi, pBlo, C1o, NPIX);
    }

    // ---- conv2 (implicit, fused): M=192, K=1600, CIN=64, KD=5 ----
    {
        const int K = 1600, NP = N_IMG * H2 * W2;
        wsplit_reorder_k<<<(C2o * K + 255) / 256, 256>>>(aw2, pAhi, pAlo, C2o, 64, 25);
        mmaconv_imp_k<<<dim3((NP + 63) / 64, 2), 256, SMEM_G2>>>(
            pAhi, pAlo, pBhi, pBlo, ab2, p_c2, C2o, NP, K, 64, 5,
            P1HP, P1WP, H2, W2, H2, W2, 0);
    }
    {
        int tot = N_IMG * C2o * P2H * P2W;
        maxpool_k<<<(tot + 127) / 128, 128>>>(p_c2, p_p2, N_IMG * C2o, H2, W2, P2H, P2W, P2HP, P2WP, 1);
    }

    // ---- p2 -> NHWC ----
    {
        const int NPIX = P2HP * P2WP;
        nchw2nhwc_k<<<dim3((NPIX + 31) / 32, C2o / 32, N_IMG), dim3(32, 8)>>>(p_p2, pBhi, pBlo, C2o, NPIX);
    }

    // ---- conv3 (implicit, fused): M=384, K=1728, CIN=192 ----
    {
        const int K = 1728, NP = N_IMG * P2H * P2W;
        wsplit_reorder_k<<<(C3o * K + 255) / 256, 256>>>(aw3, pAhi, pAlo, C3o, 192, 9);
        mmaconv_imp_k<<<dim3((NP + 63) / 64, 3), 256, SMEM_G2>>>(
            pAhi, pAlo, pBhi, pBlo, ab3, p_c3, C3o, NP, K, 192, 3,
            P2HP, P2WP, P2H, P2W, P2HP, P2WP, 1);
    }

    // ---- c3 -> NHWC ----
    {
        const int NPIX = P2HP * P2WP;
        nchw2nhwc_k<<<dim3((NPIX + 31) / 32, C3o / 32, N_IMG), dim3(32, 8)>>>(p_c3, pBhi, pBlo, C3o, NPIX);
    }

    // ---- conv4 (implicit, fused): M=256, K=3456, CIN=384 ----
    {
        const int K = 3456, NP = N_IMG * P2H * P2W;
        wsplit_reorder_k<<<(C4o * K + 255) / 256, 256>>>(aw4, pAhi, pAlo, C4o, 384, 9);
        mmaconv_imp_k<<<dim3((NP + 63) / 64, 2), 256, SMEM_G2>>>(
            pAhi, pAlo, pBhi, pBlo, ab4, p_c4, C4o, NP, K, 384, 3,
            P2HP, P2WP, P2H, P2W, P2HP, P2WP, 1);
    }

    // ---- c4 -> NHWC ----
    {
        const int NPIX = P2HP * P2WP;
        nchw2nhwc_k<<<dim3((NPIX + 31) / 32, C4o / 32, N_IMG), dim3(32, 8)>>>(p_c4, pBhi, pBlo, C4o, NPIX);
    }

    // ---- conv5 (implicit, fused): M=256, K=2304, CIN=256, out unpadded ----
    {
        const int K = 2304, NP = N_IMG * P2H * P2W;
        wsplit_reorder_k<<<(C5o * K + 255) / 256, 256>>>(aw5, pAhi, pAlo, C5o, 256, 9);
        mmaconv_imp_k<<<dim3((NP + 63) / 64, 2), 256, SMEM_G2>>>(
            pAhi, pAlo, pBhi, pBlo, ab5, p_c5, C5o, NP, K, 256, 3,
            P2HP, P2WP, P2H, P2W, H5, W5, 0);
    }
    {
        int tot = N_IMG * C5o * P5H * P5W;
        maxpool_k<<<(tot + 127) / 128, 128>>>(p_c5, p_p5, N_IMG * C5o, H5, W5, P5H, P5W, P5H, P5W, 0);
    }

    const float* Xf = p_p5 + (size_t)16 * 256 * 88;

    // ---- conv_deconv branch ----
    cd_conv_k<<<88, 256>>>(Xf, wcd, bcd, p_xc);
    cd_max_k<<<1, 256>>>(p_xc, p_v);
    xhat_k<<<256, 88>>>(p_v, wt, bt, p_xh);

    // ---- spatiotemporal GCN ----
    gather_nodes_k<<<(TMN * 256 + 127) / 128, 128>>>(p_p5, p_nd);
    rbgemm_k<<<dim3(512 / 64, TMN / 64), 256>>>(p_nd, ws1, nullptr, p_Y1, TMN, 512, 256, 0);
    a1_reduce_k<<<dim3(4, 16), 128>>>(p_Y1, p_S, 512);
    a1_apply_k<<<(TMN * 512 + 255) / 256, 256>>>(p_Y1, p_S, bs1, p_h1, 512);
    rbgemm_k<<<dim3(256 / 64, TMN / 64), 256>>>(p_h1, ws2, nullptr, p_Y2, TMN, 256, 512, 0);
    a1_reduce_k<<<dim3(2, 16), 128>>>(p_Y2, p_S, 256);
    a1_apply_k<<<(TMN * 256 + 255) / 256, 256>>>(p_Y2, p_S, bs2, p_h2, 256);
    v1_k<<<(256 * 88 + 255) / 256, 256>>>(p_h2, p_xh, p_V1, p_V1t, p_Vx);

    // ---- dynamic cross-track graph ----
    rbgemm_k<<<dim3((88 + 63) / 64, 256 / 64), 256>>>(wg, p_Vx, bg, p_G, 256, 88, 256, 1);
    rbgemm_k<<<dim3((88 + 63) / 64, 256 / 64), 256>>>(wh, p_Vx, bh, p_Hh, 256, 88, 256, 1);
    attn_k<<<88, 128>>>(p_G, p_Hh, p_A2);

    // ---- ct GCN ----
    rbgemm_k<<<dim3(384 / 64, (88 + 63) / 64), 256>>>(p_V1t, wc1, nullptr, p_xw, 88, 384, 256, 0);
    rbgemm_k<<<dim3(384 / 64, (88 + 63) / 64), 256>>>(p_A2, p_xw, bc1, p_c1m, 88, 384, 88, 2 | 4);
    rbgemm_k<<<dim3(256 / 64, (88 + 63) / 64), 256>>>(p_c1m, wc2, nullptr, p_cw, 88, 256, 384, 0);
    rbgemm_k<<<dim3(256 / 64, (88 + 63) / 64), 256>>>(p_A2, p_cw, bc2, p_V2t, 88, 256, 88, 2 | 4);

    // ---- final correlation ----
    final_dot_k<<<1, 256>>>(Xf, p_V2t, (float*)d_out);
}

// round 12
// speedup vs baseline: 1.1922x; 1.0374x over previous
#include <cuda_runtime.h>
#include <cuda_bf16.h>
#include <cstdint>
#include <math.h>

// ---------------- dimensions ----------------
#define N_IMG 17
#define H0 383
#define W0 287
#define H0P 387
#define W0P 291
#define C1o 64
#define H1 95
#define W1 71
#define P1H 47
#define P1W 35
#define P1HP 51
#define P1WP 39
#define C2o 192
#define H2 47
#define W2 35
#define P2H 23
#define P2W 17
#define P2HP 25
#define P2WP 19
#define C3o 384
#define C4o 256
#define C5o 256
#define H5 23
#define W5 17
#define P5H 11
#define P5W 8
#define MM 88
#define TT 16
#define TMN 1408
#define TAILPAD 4096

// ---------------- scratch (device globals; no allocation) ----------------
__device__ float g_in [N_IMG*3*H0P*W0P + TAILPAD];
__device__ float g_c1 [N_IMG*C1o*H1*W1];
__device__ float g_p1 [N_IMG*C1o*P1HP*P1WP + TAILPAD];
__device__ float g_c2 [N_IMG*C2o*H2*W2];
__device__ float g_p2 [N_IMG*C2o*P2HP*P2WP + TAILPAD];
__device__ float g_c3 [N_IMG*C3o*P2HP*P2WP + TAILPAD];
__device__ float g_c4 [N_IMG*C4o*P2HP*P2WP + TAILPAD];
__device__ float g_c5 [N_IMG*C5o*H5*W5];
__device__ float g_p5 [N_IMG*C5o*MM];
__device__ float g_xc [256*88];
__device__ float g_v  [256];
__device__ float g_xhat[256*88];
__device__ float g_Y1 [TMN*512];
__device__ float g_S  [16*512];
__device__ float g_Y2 [TMN*256];
__device__ float g_h2 [TMN*256];
__device__ float g_V1 [256*88];
__device__ float g_V1t[88*256];
__device__ float g_Vx [256*88];
__device__ float g_G  [256*88];
__device__ float g_Hh [256*88];
__device__ float g_A2 [88*88];
__device__ float g_xw [88*384];
__device__ float g_c1m[88*384];
__device__ float g_cw [88*256];
__device__ float g_V2t[88*256];

// bf16 split matrices for tensor-core GEMMs (also reused as NHWC maps / GCN operands)
__device__ __nv_bfloat16 g_Ahi[384*3456];
__device__ __nv_bfloat16 g_Alo[384*3456];
__device__ __nv_bfloat16 g_Bhi[44800000];
__device__ __nv_bfloat16 g_Blo[44800000];

// ---------------- mma / cp.async helpers (baseline PTX, sm_80+) ----------------
__device__ __forceinline__ uint32_t smem_u32(const void* p)
{
    uint32_t a;
    asm("{ .reg .u64 t; cvta.to.shared.u64 t, %1; cvt.u32.u64 %0, t; }" : "=r"(a) : "l"(p));
    return a;
}
__device__ __forceinline__ void ldsm_x4(uint32_t& r0, uint32_t& r1, uint32_t& r2, uint32_t& r3,
                                        uint32_t addr)
{
    asm volatile("ldmatrix.sync.aligned.m8n8.x4.shared.b16 {%0,%1,%2,%3}, [%4];"
                 : "=r"(r0), "=r"(r1), "=r"(r2), "=r"(r3) : "r"(addr));
}
__device__ __forceinline__ void mma16816(float* d, const uint32_t* a, uint32_t b0, uint32_t b1)
{
    asm volatile("mma.sync.aligned.m16n8k16.row.col.f32.bf16.bf16.f32 "
                 "{%0,%1,%2,%3}, {%4,%5,%6,%7}, {%8,%9}, {%0,%1,%2,%3};"
                 : "+f"(d[0]), "+f"(d[1]), "+f"(d[2]), "+f"(d[3])
                 : "r"(a[0]), "r"(a[1]), "r"(a[2]), "r"(a[3]), "r"(b0), "r"(b1));
}
__device__ __forceinline__ void cp16(uint32_t dst, const void* src, bool pred)
{
    int sz = pred ? 16 : 0;
    asm volatile("cp.async.cg.shared.global [%0], [%1], 16, %2;"
                 :: "r"(dst), "l"(src), "r"(sz));
}
#define CP_COMMIT() asm volatile("cp.async.commit_group;" ::: "memory")
#define CP_WAIT(n)  asm volatile("cp.async.wait_group %0;" :: "n"(n) : "memory")

__device__ __forceinline__ void bsplit(float x, __nv_bfloat16& h, __nv_bfloat16& l)
{
    h = __float2bfloat16_rn(x);
    l = __float2bfloat16_rn(x - __bfloat162float(h));
}

// ---------------- prep kernels ----------------
__global__ void wsplit_pad_k(const float* __restrict__ w, __nv_bfloat16* __restrict__ hi,
                             __nv_bfloat16* __restrict__ lo, int M, int Kreal, int KPAD)
{
    int i = blockIdx.x * blockDim.x + threadIdx.x;
    if (i >= M * KPAD) return;
    int m = i / KPAD, k = i - m * KPAD;
    float x = (k < Kreal) ? w[(size_t)m * Kreal + k] : 0.f;
    bsplit(x, hi[i], lo[i]);
}

__global__ void wsplit_reorder_k(const float* __restrict__ w, __nv_bfloat16* __restrict__ hi,
                                 __nv_bfloat16* __restrict__ lo, int M, int CIN, int KK)
{
    int K = CIN * KK;
    int i = blockIdx.x * blockDim.x + threadIdx.x;
    if (i >= M * K) return;
    int m = i / K, kidx = i - m * K;
    int pos = kidx / CIN, ci = kidx - pos * CIN;
    bsplit(w[((size_t)m * CIN + ci) * KK + pos], hi[i], lo[i]);
}

// transpose + split: A[m,k] = w[k*M + m]  (w stored [K, M] row-major)
__global__ void wsplitT_k(const float* __restrict__ w, __nv_bfloat16* __restrict__ hi,
                          __nv_bfloat16* __restrict__ lo, int M, int K)
{
    int i = blockIdx.x * blockDim.x + threadIdx.x;
    if (i >= M * K) return;
    int m = i / K, k = i - m * K;
    bsplit(w[(size_t)k * M + m], hi[i], lo[i]);
}

// gather + split nodes: B[n=m*16+t, d] = p5[t][d][m]
__global__ void gather_nodes_split_k(const float* __restrict__ p5,
                                     __nv_bfloat16* __restrict__ hi, __nv_bfloat16* __restrict__ lo)
{
    int idx = blockIdx.x * blockDim.x + threadIdx.x;
    if (idx >= TMN * 256) return;
    int d = idx % 256;
    int n = idx / 256;
    int t = n % 16, m = n / 16;
    bsplit(p5[((size_t)t * 256 + d) * 88 + m], hi[idx], lo[idx]);
}

__global__ void nchw2nhwc_k(const float* __restrict__ in,
                            __nv_bfloat16* __restrict__ hi, __nv_bfloat16* __restrict__ lo,
                            int C, int NPIX)
{
    __shared__ float t[32][33];
    int img = blockIdx.z;
    int p0 = blockIdx.x * 32, c0 = blockIdx.y * 32;
    int tx = threadIdx.x, ty = threadIdx.y;
    const float* src = in + (size_t)img * C * NPIX;
    #pragma unroll
    for (int i = 0; i < 4; i++) {
        int c = c0 + ty + i * 8, p = p0 + tx;
        if (p < NPIX) t[ty + i * 8][tx] = src[(size_t)c * NPIX + p];
    }
    __syncthreads();
    #pragma unroll
    for (int i = 0; i < 4; i++) {
        int p = p0 + ty + i * 8, c = c0 + tx;
        if (p < NPIX) {
            size_t o = ((size_t)img * NPIX + p) * C + c;
            bsplit(t[tx][ty + i * 8], hi[o], lo[o]);
        }
    }
}

template<int CIN, int KD, int S, int HinP, int WinP, int Hout, int Wout, int KPAD>
__global__ void im2col_v8_t(const float* __restrict__ in,
                            __nv_bfloat16* __restrict__ bhi, __nv_bfloat16* __restrict__ blo)
{
    constexpr int KK = KD * KD;
    constexpr int KREAL = CIN * KK;
    constexpr int HW = Hout * Wout;
    constexpr int NPIX = N_IMG * HW;
    constexpr int KQ = KPAD / 8;
    int idx = blockIdx.x * blockDim.x + threadIdx.x;
    if (idx >= NPIX * KQ) return;
    int p  = idx / KQ;
    int k0 = (idx - p * KQ) * 8;
    int img = p / HW;
    int rr  = p - img * HW;
    int oh  = rr / Wout;
    int ow  = rr - oh * Wout;
    const float* base = in + ((size_t)img * CIN * HinP + oh * S) * WinP + ow * S;

    __nv_bfloat16 hv[8], lv[8];
    #pragma unroll
    for (int j = 0; j < 8; j++) {
        int k = k0 + j;
        float x = 0.f;
        if (k < KREAL) {
            int ci = k / KK;
            int r  = k - ci * KK;
            int kh = r / KD;
            int kw = r - kh * KD;
            x = base[((size_t)ci * HinP + kh) * WinP + kw];
        }
        bsplit(x, hv[j], lv[j]);
    }
    size_t o = (size_t)p * KPAD + k0;
    *(uint4*)(bhi + o) = *(const uint4*)hv;
    *(uint4*)(blo + o) = *(const uint4*)lv;
}

// ---------------- fused-segment tensor-core GEMMs ----------------
#define ASTR 72

// -------- explicit-B GEMM, 64(M) x 128(N) — conv1 --------
#define A1_SZ (64 * ASTR * 2)
#define B1_SZ (128 * ASTR * 2)
#define ST1_SZ (2 * A1_SZ + 2 * B1_SZ)
#define SMEM_G1 (2 * ST1_SZ)
__global__ void __launch_bounds__(256)
mmaconv64_k(const __nv_bfloat16* __restrict__ Ahi, const __nv_bfloat16* __restrict__ Alo,
            const __nv_bfloat16* __restrict__ Bhi, const __nv_bfloat16* __restrict__ Blo,
            const float* __restrict__ bias, float* __restrict__ out,
            int M, int Npix, int K, int Hout, int Wout,
            int HoP, int WoP, int opad)
{
    extern __shared__ char smem[];
    uint32_t sb = smem_u32(smem);
    uint32_t stg[2] = { sb, sb + ST1_SZ };

    int tid  = threadIdx.x;
    int lane = tid & 31;
    int wid  = tid >> 5;
    int wm   = wid & 1;
    int wn   = wid >> 1;

    int m0 = 0;
    int n0 = blockIdx.x * 128;

    float d[2][4][4];
    #pragma unroll
    for (int i = 0; i < 2; i++)
        #pragma unroll
        for (int j = 0; j < 4; j++)
            #pragma unroll
            for (int r = 0; r < 4; r++) d[i][j][r] = 0.f;

    int aj = lane >> 3, ar = lane & 7;
    uint32_t aAddrOff = (uint32_t)(((aj & 1) * 8 + ar) * ASTR + (aj >> 1) * 8) * 2;
    uint32_t bAddrOff = (uint32_t)(((aj >> 1) * 8 + ar) * ASTR + (aj & 1) * 8) * 2;

    int itK = K >> 6;

    int arow[2], aq[2];
    #pragma unroll
    for (int j = 0; j < 2; j++) { int i = tid + j * 256; arow[j] = i >> 3; aq[j] = i & 7; }
    int brow[4], bq[4];
    #pragma unroll
    for (int j = 0; j < 4; j++) { int i = tid + j * 256; brow[j] = i >> 3; bq[j] = i & 7; }

    auto load_stage = [&](int st, int it) {
        int kof = it << 6;
        uint32_t s = stg[st];
        #pragma unroll
        for (int j = 0; j < 2; j++) {
            size_t go = (size_t)(m0 + arow[j]) * K + kof + aq[j] * 8;
            uint32_t so = (uint32_t)(arow[j] * ASTR + aq[j] * 8) * 2;
            bool pr = m0 + arow[j] < M;
            cp16(s + so, Ahi + go, pr);
            cp16(s + A1_SZ + so, Alo + go, pr);
        }
        #pragma unroll
        for (int j = 0; j < 4; j++) {
            size_t go = (size_t)(n0 + brow[j]) * K + kof + bq[j] * 8;
            uint32_t so = (uint32_t)(brow[j] * ASTR + bq[j] * 8) * 2;
            bool pr = n0 + brow[j] < Npix;
            cp16(s + 2 * A1_SZ + so, Bhi + go, pr);
            cp16(s + 2 * A1_SZ + B1_SZ + so, Blo + go, pr);
        }
        CP_COMMIT();
    };

    load_stage(0, 0);

    for (int it = 0; it < itK; it++) {
        int st = it & 1;
        if (it + 1 < itK) { load_stage(st ^ 1, it + 1); CP_WAIT(1); }
        else              { CP_WAIT(0); }
        __syncthreads();
        uint32_t s = stg[st];

        #pragma unroll
        for (int kk = 0; kk < 4; kk++) {
            uint32_t ah[2][4], al[2][4];
            #pragma unroll
            for (int mi = 0; mi < 2; mi++) {
                uint32_t off = aAddrOff + (uint32_t)((wm * 32 + mi * 16) * ASTR + kk * 16) * 2;
                ldsm_x4(ah[mi][0], ah[mi][1], ah[mi][2], ah[mi][3], s + off);
                ldsm_x4(al[mi][0], al[mi][1], al[mi][2], al[mi][3], s + A1_SZ + off);
            }
            uint32_t bh[4][2], bl[4][2];
            #pragma unroll
            for (int q = 0; q < 2; q++) {
                uint32_t off = bAddrOff + (uint32_t)((wn * 32 + q * 16) * ASTR + kk * 16) * 2;
                uint32_t r0, r1, r2, r3;
                ldsm_x4(r0, r1, r2, r3, s + 2 * A1_SZ + off);
                bh[q * 2][0] = r0; bh[q * 2][1] = r1;
                bh[q * 2 + 1][0] = r2; bh[q * 2 + 1][1] = r3;
                ldsm_x4(r0, r1, r2, r3, s + 2 * A1_SZ + B1_SZ + off);
                bl[q * 2][0] = r0; bl[q * 2][1] = r1;
                bl[q * 2 + 1][0] = r2; bl[q * 2 + 1][1] = r3;
            }
            #pragma unroll
            for (int mi = 0; mi < 2; mi++)
                #pragma unroll
                for (int nj = 0; nj < 4; nj++) {
                    mma16816(d[mi][nj], ah[mi], bh[nj][0], bh[nj][1]);
                    mma16816(d[mi][nj], ah[mi], bl[nj][0], bl[nj][1]);
                    mma16816(d[mi][nj], al[mi], bh[nj][0], bh[nj][1]);
                }
        }
        __syncthreads();
    }

    int HW = Hout * Wout;
    #pragma unroll
    for (int mi = 0; mi < 2; mi++) {
        #pragma unroll
        for (int r2 = 0; r2 < 2; r2++) {
            int co = m0 + wm * 32 + mi * 16 + (lane >> 2) + r2 * 8;
            if (co >= M) continue;
            float bv = bias[co];
            #pragma unroll
            for (int nj = 0; nj < 4; nj++) {
                #pragma unroll
                for (int c = 0; c < 2; c++) {
                    int p = n0 + wn * 32 + nj * 8 + (lane & 3) * 2 + c;
                    if (p >= Npix) continue;
                    float v = d[mi][nj][r2 * 2 + c] + bv;
                    int img = p / HW;
                    int rr  = p - img * HW;
                    int oh  = rr / Wout;
                    int ow  = rr - oh * Wout;
                    out[((size_t)(img * M + co) * HoP + oh + opad) * WoP + ow + opad]
                        = fmaxf(v, 0.f);
                }
            }
        }
    }
}

// -------- implicit-B GEMM, 128(M) x 64(N), B gathered from NHWC map --------
#define A2_SZ (128 * ASTR * 2)
#define B2_SZ (64 * ASTR * 2)
#define ST2_SZ (2 * A2_SZ + 2 * B2_SZ)
#define SMEM_G2 (2 * ST2_SZ)
__global__ void __launch_bounds__(256)
mmaconv_imp_k(const __nv_bfloat16* __restrict__ Ahi, const __nv_bfloat16* __restrict__ Alo,
              const __nv_bfloat16* __restrict__ Xhi, const __nv_bfloat16* __restrict__ Xlo,
              const float* __restrict__ bias, float* __restrict__ out,
              int M, int Npix, int K, int CIN, int KD,
              int HinP, int WinP, int Hout, int Wout,
              int HoP, int WoP, int opad)
{
    extern __shared__ char smem[];
    uint32_t sb = smem_u32(smem);
    uint32_t stg[2] = { sb, sb + ST2_SZ };

    int tid  = threadIdx.x;
    int lane = tid & 31;
    int wid  = tid >> 5;
    int wm   = wid & 3;
    int wn   = wid >> 2;

    int m0 = blockIdx.y * 128;
    int n0 = blockIdx.x * 64;

    float d[2][4][4];
    #pragma unroll
    for (int i = 0; i < 2; i++)
        #pragma unroll
        for (int j = 0; j < 4; j++)
            #pragma unroll
            for (int r = 0; r < 4; r++) d[i][j][r] = 0.f;

    int aj = lane >> 3, ar = lane & 7;
    uint32_t aAddrOff = (uint32_t)(((aj & 1) * 8 + ar) * ASTR + (aj >> 1) * 8) * 2;
    uint32_t bAddrOff = (uint32_t)(((aj >> 1) * 8 + ar) * ASTR + (aj & 1) * 8) * 2;

    int itK = K >> 6;
    int cPer = CIN >> 6;
    int HW = Hout * Wout;

    int arow[4], aq[4];
    #pragma unroll
    for (int j = 0; j < 4; j++) { int i = tid + j * 256; arow[j] = i >> 3; aq[j] = i & 7; }
    int brow[2], bq[2];
    long bbase[2];
    bool bval[2];
    #pragma unroll
    for (int j = 0; j < 2; j++) {
        int i = tid + j * 256;
        brow[j] = i >> 3; bq[j] = i & 7;
        int p = n0 + brow[j];
        bval[j] = p < Npix;
        if (!bval[j]) p = 0;
        int img = p / HW;
        int rr  = p - img * HW;
        int oh  = rr / Wout;
        int ow  = rr - oh * Wout;
        bbase[j] = ((long)(img * HinP + oh) * WinP + ow) * CIN;
    }

    auto load_stage = [&](int st, int it) {
        int pos = it / cPer;
        int cioff = (it - pos * cPer) << 6;
        int kh = pos / KD, kw = pos - kh * KD;
        int kofA = it << 6;
        long boff = (long)(kh * WinP + kw) * CIN + cioff;
        uint32_t s = stg[st];
        #pragma unroll
        for (int j = 0; j < 4; j++) {
            size_t go = (size_t)(m0 + arow[j]) * K + kofA + aq[j] * 8;
            uint32_t so = (uint32_t)(arow[j] * ASTR + aq[j] * 8) * 2;
            bool pr = m0 + arow[j] < M;
            cp16(s + so, Ahi + go, pr);
            cp16(s + A2_SZ + so, Alo + go, pr);
        }
        #pragma unroll
        for (int j = 0; j < 2; j++) {
            long go = bbase[j] + boff + bq[j] * 8;
            uint32_t so = (uint32_t)(brow[j] * ASTR + bq[j] * 8) * 2;
            cp16(s + 2 * A2_SZ + so, Xhi + go, bval[j]);
            cp16(s + 2 * A2_SZ + B2_SZ + so, Xlo + go, bval[j]);
        }
        CP_COMMIT();
    };

    load_stage(0, 0);

    for (int it = 0; it < itK; it++) {
        int st = it & 1;
        if (it + 1 < itK) { load_stage(st ^ 1, it + 1); CP_WAIT(1); }
        else              { CP_WAIT(0); }
        __syncthreads();
        uint32_t s = stg[st];

        #pragma unroll
        for (int kk = 0; kk < 4; kk++) {
            uint32_t ah[2][4], al[2][4];
            #pragma unroll
            for (int mi = 0; mi < 2; mi++) {
                uint32_t off = aAddrOff + (uint32_t)((wm * 32 + mi * 16) * ASTR + kk * 16) * 2;
                ldsm_x4(ah[mi][0], ah[mi][1], ah[mi][2], ah[mi][3], s + off);
                ldsm_x4(al[mi][0], al[mi][1], al[mi][2], al[mi][3], s + A2_SZ + off);
            }
            uint32_t bh[4][2], bl[4][2];
            #pragma unroll
            for (int q = 0; q < 2; q++) {
                uint32_t off = bAddrOff + (uint32_t)((wn * 32 + q * 16) * ASTR + kk * 16) * 2;
                uint32_t r0, r1, r2, r3;
                ldsm_x4(r0, r1, r2, r3, s + 2 * A2_SZ + off);
                bh[q * 2][0] = r0; bh[q * 2][1] = r1;
                bh[q * 2 + 1][0] = r2; bh[q * 2 + 1][1] = r3;
                ldsm_x4(r0, r1, r2, r3, s + 2 * A2_SZ + B2_SZ + off);
                bl[q * 2][0] = r0; bl[q * 2][1] = r1;
                bl[q * 2 + 1][0] = r2; bl[q * 2 + 1][1] = r3;
            }
            #pragma unroll
            for (int mi = 0; mi < 2; mi++)
                #pragma unroll
                for (int nj = 0; nj < 4; nj++) {
                    mma16816(d[mi][nj], ah[mi], bh[nj][0], bh[nj][1]);
                    mma16816(d[mi][nj], ah[mi], bl[nj][0], bl[nj][1]);
                    mma16816(d[mi][nj], al[mi], bh[nj][0], bh[nj][1]);
                }
        }
        __syncthreads();
    }

    #pragma unroll
    for (int mi = 0; mi < 2; mi++) {
        #pragma unroll
        for (int r2 = 0; r2 < 2; r2++) {
            int co = m0 + wm * 32 + mi * 16 + (lane >> 2) + r2 * 8;
            if (co >= M) continue;
            float bv = bias[co];
            #pragma unroll
            for (int nj = 0; nj < 4; nj++) {
                #pragma unroll
                for (int c = 0; c < 2; c++) {
                    int p = n0 + wn * 32 + nj * 8 + (lane & 3) * 2 + c;
                    if (p >= Npix) continue;
                    float v = d[mi][nj][r2 * 2 + c] + bv;
                    int img = p / HW;
                    int rr  = p - img * HW;
                    int oh  = rr / Wout;
                    int ow  = rr - oh * Wout;
                    out[((size_t)(img * M + co) * HoP + oh + opad) * WoP + ow + opad]
                        = fmaxf(v, 0.f);
                }
            }
        }
    }
}

// -------- generic explicit GEMM, 128(M) x 64(N), transposed output C[n,m] --------
// D[m,n] = sum_k A[m,k]*B[n,k]; writes out[n*M + m] (no bias/activation).
__global__ void __launch_bounds__(256)
mmagemm_k(const __nv_bfloat16* __restrict__ Ahi, const __nv_bfloat16* __restrict__ Alo,
          const __nv_bfloat16* __restrict__ Bhi, const __nv_bfloat16* __restrict__ Blo,
          float* __restrict__ out, int M, int N, int K)
{
    extern __shared__ char smem[];
    uint32_t sb = smem_u32(smem);
    uint32_t stg[2] = { sb, sb + ST2_SZ };

    int tid  = threadIdx.x;
    int lane = tid & 31;
    int wid  = tid >> 5;
    int wm   = wid & 3;
    int wn   = wid >> 2;

    int m0 = blockIdx.y * 128;
    int n0 = blockIdx.x * 64;

    float d[2][4][4];
    #pragma unroll
    for (int i = 0; i < 2; i++)
        #pragma unroll
        for (int j = 0; j < 4; j++)
            #pragma unroll
            for (int r = 0; r < 4; r++) d[i][j][r] = 0.f;

    int aj = lane >> 3, ar = lane & 7;
    uint32_t aAddrOff = (uint32_t)(((aj & 1) * 8 + ar) * ASTR + (aj >> 1) * 8) * 2;
    uint32_t bAddrOff = (uint32_t)(((aj >> 1) * 8 + ar) * ASTR + (aj & 1) * 8) * 2;

    int itK = K >> 6;

    int arow[4], aq[4];
    #pragma unroll
    for (int j = 0; j < 4; j++) { int i = tid + j * 256; arow[j] = i >> 3; aq[j] = i & 7; }
    int brow[2], bq[2];
    #pragma unroll
    for (int j = 0; j < 2; j++) { int i = tid + j * 256; brow[j] = i >> 3; bq[j] = i & 7; }

    auto load_stage = [&](int st, int it) {
        int kof = it << 6;
        uint32_t s = stg[st];
        #pragma unroll
        for (int j = 0; j < 4; j++) {
            size_t go = (size_t)(m0 + arow[j]) * K + kof + aq[j] * 8;
            uint32_t so = (uint32_t)(arow[j] * ASTR + aq[j] * 8) * 2;
            bool pr = m0 + arow[j] < M;
            cp16(s + so, Ahi + go, pr);
            cp16(s + A2_SZ + so, Alo + go, pr);
        }
        #pragma unroll
        for (int j = 0; j < 2; j++) {
            size_t go = (size_t)(n0 + brow[j]) * K + kof + bq[j] * 8;
            uint32_t so = (uint32_t)(brow[j] * ASTR + bq[j] * 8) * 2;
            bool pr = n0 + brow[j] < N;
            cp16(s + 2 * A2_SZ + so, Bhi + go, pr);
            cp16(s + 2 * A2_SZ + B2_SZ + so, Blo + go, pr);
        }
        CP_COMMIT();
    };

    load_stage(0, 0);

    for (int it = 0; it < itK; it++) {
        int st = it & 1;
        if (it + 1 < itK) { load_stage(st ^ 1, it + 1); CP_WAIT(1); }
        else              { CP_WAIT(0); }
        __syncthreads();
        uint32_t s = stg[st];

        #pragma unroll
        for (int kk = 0; kk < 4; kk++) {
            uint32_t ah[2][4], al[2][4];
            #pragma unroll
            for (int mi = 0; mi < 2; mi++) {
                uint32_t off = aAddrOff + (uint32_t)((wm * 32 + mi * 16) * ASTR + kk * 16) * 2;
                ldsm_x4(ah[mi][0], ah[mi][1], ah[mi][2], ah[mi][3], s + off);
                ldsm_x4(al[mi][0], al[mi][1], al[mi][2], al[mi][3], s + A2_SZ + off);
            }
            uint32_t bh[4][2], bl[4][2];
            #pragma unroll
            for (int q = 0; q < 2; q++) {
                uint32_t off = bAddrOff + (uint32_t)((wn * 32 + q * 16) * ASTR + kk * 16) * 2;
                uint32_t r0, r1, r2, r3;
                ldsm_x4(r0, r1, r2, r3, s + 2 * A2_SZ + off);
                bh[q * 2][0] = r0; bh[q * 2][1] = r1;
                bh[q * 2 + 1][0] = r2; bh[q * 2 + 1][1] = r3;
                ldsm_x4(r0, r1, r2, r3, s + 2 * A2_SZ + B2_SZ + off);
                bl[q * 2][0] = r0; bl[q * 2][1] = r1;
                bl[q * 2 + 1][0] = r2; bl[q * 2 + 1][1] = r3;
            }
            #pragma unroll
            for (int mi = 0; mi < 2; mi++)
                #pragma unroll
                for (int nj = 0; nj < 4; nj++) {
                    mma16816(d[mi][nj], ah[mi], bh[nj][0], bh[nj][1]);
                    mma16816(d[mi][nj], ah[mi], bl[nj][0], bl[nj][1]);
                    mma16816(d[mi][nj], al[mi], bh[nj][0], bh[nj][1]);
                }
        }
        __syncthreads();
    }

    #pragma unroll
    for (int mi = 0; mi < 2; mi++) {
        #pragma unroll
        for (int r2 = 0; r2 < 2; r2++) {
            int co = m0 + wm * 32 + mi * 16 + (lane >> 2) + r2 * 8;
            if (co >= M) continue;
            #pragma unroll
            for (int nj = 0; nj < 4; nj++) {
                #pragma unroll
                for (int c = 0; c < 2; c++) {
                    int p = n0 + wn * 32 + nj * 8 + (lane & 3) * 2 + c;
                    if (p >= N) continue;
                    out[(size_t)p * M + co] = d[mi][nj][r2 * 2 + c];
                }
            }
        }
    }
}

// ---------------- scalar kernels (rest of network) ----------------

__global__ void pad_copy_k(const float* __restrict__ src, float* __restrict__ dst,
                           int nimg, int boff)
{
    int idx = blockIdx.x * blockDim.x + threadIdx.x;
    int total = nimg * 3 * H0 * W0;
    if (idx >= total) return;
    int w = idx % W0; int t = idx / W0;
    int h = t % H0;   t /= H0;
    int c = t % 3;    int n = t / 3;
    dst[(((size_t)(boff + n) * 3 + c) * H0P + h + 2) * W0P + (w + 2)] = src[idx];
}

__global__ void maxpool_k(const float* __restrict__ in, float* __restrict__ out,
                          int NC, int Hin, int Win, int Ho, int Wo,
                          int HoP, int WoP, int opad)
{
    int idx = blockIdx.x * blockDim.x + threadIdx.x;
    int total = NC * Ho * Wo;
    if (idx >= total) return;
    int ow = idx % Wo; int t = idx / Wo;
    int oh = t % Ho;   int nc = t / Ho;
    const float* ip = in + ((size_t)nc * Hin + oh * 2) * Win + ow * 2;
    float m = -INFINITY;
    #pragma unroll
    for (int kh = 0; kh < 3; kh++)
        #pragma unroll
        for (int kw = 0; kw < 3; kw++)
            m = fmaxf(m, ip[kh * Win + kw]);
    out[((size_t)nc * HoP + oh + opad) * WoP + ow + opad] = m;
}

__global__ void cd_conv_k(const float* __restrict__ Xf, const float* __restrict__ wcd,
                          const float* __restrict__ bcd, float* __restrict__ xc)
{
    int p = blockIdx.x;
    int o = threadIdx.x;
    float acc = bcd[o];
    for (int i = 0; i < 256; i++) {
        const float* wr = wcd + (o * 256 + i) * 3;
        const float* xr = Xf + i * 88;
        if (p > 0)  acc += xr[p - 1] * wr[0];
        acc += xr[p] * wr[1];
        if (p < 87) acc += xr[p + 1] * wr[2];
    }
    xc[o * 88 + p] = acc;
}

__global__ void cd_max_k(const float* __restrict__ xc, float* __restrict__ v)
{
    int o = threadIdx.x;
    float m = -INFINITY;
    for (int p = 0; p < 88; p++) m = fmaxf(m, xc[o * 88 + p]);
    v[o] = m;
}

__global__ void xhat_k(const float* __restrict__ v, const float* __restrict__ wt,
                       const float* __restrict__ bt, float* __restrict__ xhat)
{
    __shared__ float sv[256];
    int o = blockIdx.x;
    int k = threadIdx.x;
    for (int i = threadIdx.x; i < 256; i += blockDim.x) sv[i] = v[i];
    __syncthreads();
    float acc = bt[o];
    for (int i = 0; i < 256; i++)
        acc += sv[i] * wt[((size_t)i * 256 + o) * 88 + k];
    xhat[o * 88 + k] = acc;
}

__global__ __launch_bounds__(256)
void rbgemm_k(const float* __restrict__ A, const float* __restrict__ B,
              const float* __restrict__ bias, float* __restrict__ C,
              int M, int N, int K, int flags)
{
    __shared__ float As[16][65];
    __shared__ float Bs[16][64];
    int tid = threadIdx.x;
    int tx = tid & 15;
    int ty = tid >> 4;
    int m0 = blockIdx.y * 64;
    int n0 = blockIdx.x * 64;

    float acc[4][4] = {};

    for (int k0 = 0; k0 < K; k0 += 16) {
        #pragma unroll
        for (int i = 0; i < 4; i++) {
            int e  = tid + i * 256;
            int kk = e & 15;
            int mm = e >> 4;
            int gm = m0 + mm, gk = k0 + kk;
            As[kk][mm] = (gm < M && gk < K) ? A[(size_t)gm * K + gk] : 0.f;
        }
        #pragma unroll
        for (int i = 0; i < 4; i++) {
            int nn = tid & 63;
            int kk = (tid >> 6) + i * 4;
            int gk = k0 + kk, gn = n0 + nn;
            Bs[kk][nn] = (gk < K && gn < N) ? B[(size_t)gk * N + gn] : 0.f;
        }
        __syncthreads();
        #pragma unroll
        for (int kk = 0; kk < 16; kk++) {
            float ra[4], rb[4];
            #pragma unroll
            for (int i = 0; i < 4; i++) ra[i] = As[kk][ty * 4 + i];
            #pragma unroll
            for (int j = 0; j < 4; j++) rb[j] = Bs[kk][tx * 4 + j];
            #pragma unroll
            for (int i = 0; i < 4; i++)
                #pragma unroll
                for (int j = 0; j < 4; j++)
                    acc[i][j] += ra[i] * rb[j];
        }
        __syncthreads();
    }

    #pragma unroll
    for (int i = 0; i < 4; i++) {
        int gm = m0 + ty * 4 + i;
        if (gm >= M) continue;
        #pragma unroll
        for (int j = 0; j < 4; j++) {
            int gn = n0 + tx * 4 + j;
            if (gn >= N) continue;
            float v = acc[i][j];
            if (flags & 1) v += bias[gm];
            if (flags & 2) v += bias[gn];
            if (flags & 4) v = v >= 0.f ? v : 0.01f * v;
            C[(size_t)gm * N + gn] = v;
        }
    }
}

__global__ void a1_reduce_k(const float* __restrict__ Y, float* __restrict__ S, int F)
{
    int f = blockIdx.x * blockDim.x + threadIdx.x;
    int t = blockIdx.y;
    if (f >= F) return;
    float s = 0.f;
    for (int m = 0; m < 88; m++) s += Y[(size_t)(m * 16 + t) * F + f];
    S[t * F + f] = s;
}

// layer-1 apply: h = lrelu(S - (t==0)Y + bias), emitted directly as bf16 hi/lo
__global__ void a1_apply_split_k(const float* __restrict__ Y, const float* __restrict__ S,
                                 const float* __restrict__ bias,
                                 __nv_bfloat16* __restrict__ hi, __nv_bfloat16* __restrict__ lo,
                                 int F)
{
    int idx = blockIdx.x * blockDim.x + threadIdx.x;
    if (idx >= TMN * F) return;
    int f = idx % F;
    int n = idx / F;
    int t = n % 16;
    float val = S[t * F + f] + bias[f];
    if (t == 0) val -= Y[idx];
    val = val >= 0.f ? val : 0.01f * val;
    bsplit(val, hi[idx], lo[idx]);
}

__global__ void a1_apply_k(const float* __restrict__ Y, const float* __restrict__ S,
                           const float* __restrict__ bias, float* __restrict__ h, int F)
{
    int idx = blockIdx.x * blockDim.x + threadIdx.x;
    if (idx >= TMN * F) return;
    int f = idx % F;
    int n = idx / F;
    int t = n % 16;
    float val = S[t * F + f] + bias[f];
    if (t == 0) val -= Y[idx];
    h[idx] = val >= 0.f ? val : 0.01f * val;
}

__global__ void v1_k(const float* __restrict__ h2, const float* __restrict__ xhat,
                     float* __restrict__ V1, float* __restrict__ V1t, float* __restrict__ Vx)
{
    int idx = blockIdx.x * blockDim.x + threadIdx.x;
    if (idx >= 256 * 88) return;
    int d = idx % 256;
    int m = idx / 256;
    float mx = -INFINITY;
    #pragma unroll
    for (int t = 0; t < 16; t++) mx = fmaxf(mx, h2[(size_t)(m * 16 + t) * 256 + d]);
    V1[d * 88 + m] = mx;
    V1t[m * 256 + d] = mx;
    Vx[d * 88 + m] = mx + xhat[d * 88 + m];
}

__global__ void attn_k(const float* __restrict__ G, const float* __restrict__ Hh,
                       float* __restrict__ A2)
{
    __shared__ float red[128];
    int j = blockIdx.x;
    int i = threadIdx.x;
    float s = 0.f;
    if (i < 88) {
        for (int d = 0; d < 256; d++) s += Hh[d * 88 + j] * G[d * 88 + i];
    }
    red[i] = (i < 88) ? s : -INFINITY;
    __syncthreads();
    for (int st = 64; st > 0; st >>= 1) {
        if (i < st) red[i] = fmaxf(red[i], red[i + st]);
        __syncthreads();
    }
    float mx = red[0];
    __syncthreads();
    float e = (i < 88) ? expf(s - mx) : 0.f;
    red[i] = e;
    __syncthreads();
    for (int st = 64; st > 0; st >>= 1) {
        if (i < st) red[i] += red[i + st];
        __syncthreads();
    }
    float sum = red[0];
    if (i < 88) A2[j * 88 + i] = e / sum;
}

__global__ void final_dot_k(const float* __restrict__ Xf, const float* __restrict__ V2t,
                            float* __restrict__ out)
{
    __shared__ float red[256];
    float acc = 0.f;
    for (int e = threadIdx.x; e < 256 * 88; e += 256) {
        int d = e / 88, m = e % 88;
        acc += Xf[e] * V2t[m * 256 + d];
    }
    red[threadIdx.x] = acc;
    __syncthreads();
    for (int st = 128; st > 0; st >>= 1) {
        if (threadIdx.x < st) red[threadIdx.x] += red[threadIdx.x + st];
        __syncthreads();
    }
    if (threadIdx.x == 0) out[0] = red[0];
}

// ---------------- host ----------------
static float* symaddr(const void* s)
{
    void* p = nullptr;
    cudaGetSymbolAddress(&p, s);
    return (float*)p;
}
static __nv_bfloat16* symaddr_bf(const void* s)
{
    void* p = nullptr;
    cudaGetSymbolAddress(&p, s);
    return (__nv_bfloat16*)p;
}

extern "C" void kernel_launch(void* const* d_in, const int* in_sizes, int n_in,
                              void* d_out, int out_size)
{
    const float* search    = (const float*)d_in[0];
    const float* exemplars = (const float*)d_in[1];
    const float* aw1 = (const float*)d_in[2];  const float* ab1 = (const float*)d_in[3];
    const float* aw2 = (const float*)d_in[4];  const float* ab2 = (const float*)d_in[5];
    const float* aw3 = (const float*)d_in[6];  const float* ab3 = (const float*)d_in[7];
    const float* aw4 = (const float*)d_in[8];  const float* ab4 = (const float*)d_in[9];
    const float* aw5 = (const float*)d_in[10]; const float* ab5 = (const float*)d_in[11];
    const float* wcd = (const float*)d_in[12]; const float* bcd = (const float*)d_in[13];
    const float* wt  = (const float*)d_in[14]; const float* bt  = (const float*)d_in[15];
    const float* ws1 = (const float*)d_in[16]; const float* bs1 = (const float*)d_in[17];
    const float* ws2 = (const float*)d_in[18]; const float* bs2 = (const float*)d_in[19];
    const float* wg  = (const float*)d_in[20]; const float* bg  = (const float*)d_in[21];
    const float* wh  = (const float*)d_in[22]; const float* bh  = (const float*)d_in[23];
    const float* wc1 = (const float*)d_in[24]; const float* bc1 = (const float*)d_in[25];
    const float* wc2 = (const float*)d_in[26]; const float* bc2 = (const float*)d_in[27];

    float* p_in  = symaddr(g_in);
    float* p_c1  = symaddr(g_c1);
    float* p_p1  = symaddr(g_p1);
    float* p_c2  = symaddr(g_c2);
    float* p_p2  = symaddr(g_p2);
    float* p_c3  = symaddr(g_c3);
    float* p_c4  = symaddr(g_c4);
    float* p_c5  = symaddr(g_c5);
    float* p_p5  = symaddr(g_p5);
    float* p_xc  = symaddr(g_xc);
    float* p_v   = symaddr(g_v);
    float* p_xh  = symaddr(g_xhat);
    float* p_Y1  = symaddr(g_Y1);
    float* p_S   = symaddr(g_S);
    float* p_Y2  = symaddr(g_Y2);
    float* p_h2  = symaddr(g_h2);
    float* p_V1  = symaddr(g_V1);
    float* p_V1t = symaddr(g_V1t);
    float* p_Vx  = symaddr(g_Vx);
    float* p_G   = symaddr(g_G);
    float* p_Hh  = symaddr(g_Hh);
    float* p_A2  = symaddr(g_A2);
    float* p_xw  = symaddr(g_xw);
    float* p_c1m = symaddr(g_c1m);
    float* p_cw  = symaddr(g_cw);
    float* p_V2t = symaddr(g_V2t);
    __nv_bfloat16* pAhi = symaddr_bf(g_Ahi);
    __nv_bfloat16* pAlo = symaddr_bf(g_Alo);
    __nv_bfloat16* pBhi = symaddr_bf(g_Bhi);
    __nv_bfloat16* pBlo = symaddr_bf(g_Blo);

    cudaFuncSetAttribute(mmaconv64_k, cudaFuncAttributeMaxDynamicSharedMemorySize, SMEM_G1);
    cudaFuncSetAttribute(mmaconv_imp_k, cudaFuncAttributeMaxDynamicSharedMemorySize, SMEM_G2);
    cudaFuncSetAttribute(mmagemm_k, cudaFuncAttributeMaxDynamicSharedMemorySize, SMEM_G2);

    // zero padded buffers (borders must be 0 every replay)
    cudaMemsetAsync(p_in, 0, sizeof(float) * ((size_t)N_IMG * 3 * H0P * W0P + TAILPAD), 0);
    cudaMemsetAsync(p_p1, 0, sizeof(float) * ((size_t)N_IMG * C1o * P1HP * P1WP + TAILPAD), 0);
    cudaMemsetAsync(p_p2, 0, sizeof(float) * ((size_t)N_IMG * C2o * P2HP * P2WP + TAILPAD), 0);
    cudaMemsetAsync(p_c3, 0, sizeof(float) * ((size_t)N_IMG * C3o * P2HP * P2WP + TAILPAD), 0);
    cudaMemsetAsync(p_c4, 0, sizeof(float) * ((size_t)N_IMG * C4o * P2HP * P2WP + TAILPAD), 0);

    // assemble padded input batch
    {
        int tot = 16 * 3 * H0 * W0;
        pad_copy_k<<<(tot + 127) / 128, 128>>>(exemplars, p_in, 16, 0);
        tot = 3 * H0 * W0;
        pad_copy_k<<<(tot + 127) / 128, 128>>>(search, p_in, 1, 16);
    }

    // ---- conv1 (vectorized im2col, fused-segment 64x128 GEMM): M=64, K=384(pad) ----
    {
        const int KP = 384, NP = N_IMG * H1 * W1;
        wsplit_pad_k<<<(C1o * KP + 255) / 256, 256>>>(aw1, pAhi, pAlo, C1o, 363, KP);
        int tot = NP * (KP / 8);
        im2col_v8_t<3, 11, 4, H0P, W0P, H1, W1, 384><<<(tot + 255) / 256, 256>>>(p_in, pBhi, pBlo);
        mmaconv64_k<<<(NP + 127) / 128, 256, SMEM_G1>>>(
            pAhi, pAlo, pBhi, pBlo, ab1, p_c1, C1o, NP, KP, H1, W1, H1, W1, 0);
    }
    {
        int tot = N_IMG * C1o * P1H * P1W;
        maxpool_k<<<(tot + 127) / 128, 128>>>(p_c1, p_p1, N_IMG * C1o, H1, W1, P1H, P1W, P1HP, P1WP, 2);
    }

    // ---- p1 -> NHWC bf16 ----
    {
        const int NPIX = P1HP * P1WP;
        nchw2nhwc_k<<<dim3((NPIX + 31) / 32, C1o / 32, N_IMG), dim3(32, 8)>>>(p_p1, pBhi, pBlo, C1o, NPIX);
    }

    // ---- conv2 (implicit, fused): M=192, K=1600, CIN=64, KD=5 ----
    {
        const int K = 1600, NP = N_IMG * H2 * W2;
        wsplit_reorder_k<<<(C2o * K + 255) / 256, 256>>>(aw2, pAhi, pAlo, C2o, 64, 25);
        mmaconv_imp_k<<<dim3((NP + 63) / 64, 2), 256, SMEM_G2>>>(
            pAhi, pAlo, pBhi, pBlo, ab2, p_c2, C2o, NP, K, 64, 5,
            P1HP, P1WP, H2, W2, H2, W2, 0);
    }
    {
        int tot = N_IMG * C2o * P2H * P2W;
        maxpool_k<<<(tot + 127) / 128, 128>>>(p_c2, p_p2, N_IMG * C2o, H2, W2, P2H, P2W, P2HP, P2WP, 1);
    }

    // ---- p2 -> NHWC ----
    {
        const int NPIX = P2HP * P2WP;
        nchw2nhwc_k<<<dim3((NPIX + 31) / 32, C2o / 32, N_IMG), dim3(32, 8)>>>(p_p2, pBhi, pBlo, C2o, NPIX);
    }

    // ---- conv3 (implicit, fused): M=384, K=1728, CIN=192 ----
    {
        const int K = 1728, NP = N_IMG * P2H * P2W;
        wsplit_reorder_k<<<(C3o * K + 255) / 256, 256>>>(aw3, pAhi, pAlo, C3o, 192, 9);
        mmaconv_imp_k<<<dim3((NP + 63) / 64, 3), 256, SMEM_G2>>>(
            pAhi, pAlo, pBhi, pBlo, ab3, p_c3, C3o, NP, K, 192, 3,
            P2HP, P2WP, P2H, P2W, P2HP, P2WP, 1);
    }

    // ---- c3 -> NHWC ----
    {
        const int NPIX = P2HP * P2WP;
        nchw2nhwc_k<<<dim3((NPIX + 31) / 32, C3o / 32, N_IMG), dim3(32, 8)>>>(p_c3, pBhi, pBlo, C3o, NPIX);
    }

    // ---- conv4 (implicit, fused): M=256, K=3456, CIN=384 ----
    {
        const int K = 3456, NP = N_IMG * P2H * P2W;
        wsplit_reorder_k<<<(C4o * K + 255) / 256, 256>>>(aw4, pAhi, pAlo, C4o, 384, 9);
        mmaconv_imp_k<<<dim3((NP + 63) / 64, 2), 256, SMEM_G2>>>(
            pAhi, pAlo, pBhi, pBlo, ab4, p_c4, C4o, NP, K, 384, 3,
            P2HP, P2WP, P2H, P2W, P2HP, P2WP, 1);
    }

    // ---- c4 -> NHWC ----
    {
        const int NPIX = P2HP * P2WP;
        nchw2nhwc_k<<<dim3((NPIX + 31) / 32, C4o / 32, N_IMG), dim3(32, 8)>>>(p_c4, pBhi, pBlo, C4o, NPIX);
    }

    // ---- conv5 (implicit, fused): M=256, K=2304, CIN=256, out unpadded ----
    {
        const int K = 2304, NP = N_IMG * P2H * P2W;
        wsplit_reorder_k<<<(C5o * K + 255) / 256, 256>>>(aw5, pAhi, pAlo, C5o, 256, 9);
        mmaconv_imp_k<<<dim3((NP + 63) / 64, 2), 256, SMEM_G2>>>(
            pAhi, pAlo, pBhi, pBlo, ab5, p_c5, C5o, NP, K, 256, 3,
            P2HP, P2WP, P2H, P2W, H5, W5, 0);
    }
    {
        int tot = N_IMG * C5o * P5H * P5W;
        maxpool_k<<<(tot + 127) / 128, 128>>>(p_c5, p_p5, N_IMG * C5o, H5, W5, P5H, P5W, P5H, P5W, 0);
    }

    const float* Xf = p_p5 + (size_t)16 * 256 * 88;

    // ---- conv_deconv branch ----
    cd_conv_k<<<88, 256>>>(Xf, wcd, bcd, p_xc);
    cd_max_k<<<1, 256>>>(p_xc, p_v);
    xhat_k<<<256, 88>>>(p_v, wt, bt, p_xh);

    // ---- spatiotemporal GCN (tensor-core, fused split) ----
    // buffers: nodes hi/lo at pB[0..360K); h1 hi/lo at pB + 1<<20; weights in pA
    __nv_bfloat16* nHi = pBhi;
    __nv_bfloat16* nLo = pBlo;
    __nv_bfloat16* h1Hi = pBhi + (1 << 20);
    __nv_bfloat16* h1Lo = pBlo + (1 << 20);
    __nv_bfloat16* w1Hi = pAhi;             // [512, 256]
    __nv_bfloat16* w1Lo = pAlo;
    __nv_bfloat16* w2Hi = pAhi + (512 * 256);  // [256, 512]
    __nv_bfloat16* w2Lo = pAlo + (512 * 256);

    gather_nodes_split_k<<<(TMN * 256 + 255) / 256, 256>>>(p_p5, nHi, nLo);
    wsplitT_k<<<(512 * 256 + 255) / 256, 256>>>(ws1, w1Hi, w1Lo, 512, 256);
    mmagemm_k<<<dim3(TMN / 64, 512 / 128), 256, SMEM_G2>>>(
        w1Hi, w1Lo, nHi, nLo, p_Y1, 512, TMN, 256);
    a1_reduce_k<<<dim3(4, 16), 128>>>(p_Y1, p_S, 512);
    a1_apply_split_k<<<(TMN * 512 + 255) / 256, 256>>>(p_Y1, p_S, bs1, h1Hi, h1Lo, 512);
    wsplitT_k<<<(256 * 512 + 255) / 256, 256>>>(ws2, w2Hi, w2Lo, 256, 512);
    mmagemm_k<<<dim3(TMN / 64, 256 / 128), 256, SMEM_G2>>>(
        w2Hi, w2Lo, h1Hi, h1Lo, p_Y2, 256, TMN, 512);
    a1_reduce_k<<<dim3(2, 16), 128>>>(p_Y2, p_S, 256);
    a1_apply_k<<<(TMN * 256 + 255) / 256, 256>>>(p_Y2, p_S, bs2, p_h2, 256);
    v1_k<<<(256 * 88 + 255) / 256, 256>>>(p_h2, p_xh, p_V1, p_V1t, p_Vx);

    // ---- dynamic cross-track graph ----
    rbgemm_k<<<dim3((88 + 63) / 64, 256 / 64), 256>>>(wg, p_Vx, bg, p_G, 256, 88, 256, 1);
    rbgemm_k<<<dim3((88 + 63) / 64, 256 / 64), 256>>>(wh, p_Vx, bh, p_Hh, 256, 88, 256, 1);
    attn_k<<<88, 128>>>(p_G, p_Hh, p_A2);

    // ---- ct GCN ----
    rbgemm_k<<<dim3(384 / 64, (88 + 63) / 64), 256>>>(p_V1t, wc1, nullptr, p_xw, 88, 384, 256, 0);
    rbgemm_k<<<dim3(384 / 64, (88 + 63) / 64), 256>>>(p_A2, p_xw, bc1, p_c1m, 88, 384, 88, 2 | 4);
    rbgemm_k<<<dim3(256 / 64, (88 + 63) / 64), 256>>>(p_c1m, wc2, nullptr, p_cw, 88, 256, 384, 0);
    rbgemm_k<<<dim3(256 / 64, (88 + 63) / 64), 256>>>(p_A2, p_cw, bc2, p_V2t, 88, 256, 88, 2 | 4);

    // ---- final correlation ----
    final_dot_k<<<1, 256>>>(Xf, p_V2t, (float*)d_out);
}

// round 13
// speedup vs baseline: 1.2998x; 1.0902x over previous
#include <cuda_runtime.h>
#include <cuda_bf16.h>
#include <cstdint>
#include <math.h>

// ---------------- dimensions ----------------
#define N_IMG 17
#define H0 383
#define W0 287
#define H0P 387
#define W0P 291
#define C1o 64
#define H1 95
#define W1 71
#define P1H 47
#define P1W 35
#define P1HP 51
#define P1WP 39
#define C2o 192
#define H2 47
#define W2 35
#define P2H 23
#define P2W 17
#define P2HP 25
#define P2WP 19
#define C3o 384
#define C4o 256
#define C5o 256
#define H5 23
#define W5 17
#define P5H 11
#define P5W 8
#define MM 88
#define TT 16
#define TMN 1408
#define TAILPAD 4096

// ---------------- scratch (device globals; no allocation) ----------------
__device__ float g_in [N_IMG*3*H0P*W0P + TAILPAD];
__device__ float g_c1 [N_IMG*C1o*H1*W1];
__device__ float g_p1 [N_IMG*C1o*P1HP*P1WP + TAILPAD];
__device__ float g_c2 [N_IMG*C2o*H2*W2];
__device__ float g_p2 [N_IMG*C2o*P2HP*P2WP + TAILPAD];
__device__ float g_c3 [N_IMG*C3o*P2HP*P2WP + TAILPAD];
__device__ float g_c4 [N_IMG*C4o*P2HP*P2WP + TAILPAD];
__device__ float g_c5 [N_IMG*C5o*H5*W5];
__device__ float g_p5 [N_IMG*C5o*MM];
__device__ float g_xc [256*88];
__device__ float g_v  [256];
__device__ float g_xhat[256*88];
__device__ float g_Y1 [TMN*512];
__device__ float g_S  [16*512];
__device__ float g_Y2 [TMN*256];
__device__ float g_h2 [TMN*256];
__device__ float g_V1 [256*88];
__device__ float g_V1t[88*256];
__device__ float g_Vx [256*88];
__device__ float g_G  [256*88];
__device__ float g_Hh [256*88];
__device__ float g_A2 [88*88];
__device__ float g_xw [88*384];
__device__ float g_c1m[88*384];
__device__ float g_cw [88*256];
__device__ float g_V2t[88*256];

// bf16 split matrices for tensor-core GEMMs (also reused as NHWC maps / GCN operands)
__device__ __nv_bfloat16 g_Ahi[384*3456];
__device__ __nv_bfloat16 g_Alo[384*3456];
__device__ __nv_bfloat16 g_Bhi[44800000];
__device__ __nv_bfloat16 g_Blo[44800000];

// ---------------- mma / cp.async helpers (baseline PTX, sm_80+) ----------------
__device__ __forceinline__ uint32_t smem_u32(const void* p)
{
    uint32_t a;
    asm("{ .reg .u64 t; cvta.to.shared.u64 t, %1; cvt.u32.u64 %0, t; }" : "=r"(a) : "l"(p));
    return a;
}
__device__ __forceinline__ void ldsm_x4(uint32_t& r0, uint32_t& r1, uint32_t& r2, uint32_t& r3,
                                        uint32_t addr)
{
    asm volatile("ldmatrix.sync.aligned.m8n8.x4.shared.b16 {%0,%1,%2,%3}, [%4];"
                 : "=r"(r0), "=r"(r1), "=r"(r2), "=r"(r3) : "r"(addr));
}
__device__ __forceinline__ void mma16816(float* d, const uint32_t* a, uint32_t b0, uint32_t b1)
{
    asm volatile("mma.sync.aligned.m16n8k16.row.col.f32.bf16.bf16.f32 "
                 "{%0,%1,%2,%3}, {%4,%5,%6,%7}, {%8,%9}, {%0,%1,%2,%3};"
                 : "+f"(d[0]), "+f"(d[1]), "+f"(d[2]), "+f"(d[3])
                 : "r"(a[0]), "r"(a[1]), "r"(a[2]), "r"(a[3]), "r"(b0), "r"(b1));
}
__device__ __forceinline__ void cp16(uint32_t dst, const void* src, bool pred)
{
    int sz = pred ? 16 : 0;
    asm volatile("cp.async.cg.shared.global [%0], [%1], 16, %2;"
                 :: "r"(dst), "l"(src), "r"(sz));
}
#define CP_COMMIT() asm volatile("cp.async.commit_group;" ::: "memory")
#define CP_WAIT(n)  asm volatile("cp.async.wait_group %0;" :: "n"(n) : "memory")

__device__ __forceinline__ void bsplit(float x, __nv_bfloat16& h, __nv_bfloat16& l)
{
    h = __float2bfloat16_rn(x);
    l = __float2bfloat16_rn(x - __bfloat162float(h));
}

// ---------------- prep kernels ----------------
__global__ void wsplit_pad_k(const float* __restrict__ w, __nv_bfloat16* __restrict__ hi,
                             __nv_bfloat16* __restrict__ lo, int M, int Kreal, int KPAD)
{
    int i = blockIdx.x * blockDim.x + threadIdx.x;
    if (i >= M * KPAD) return;
    int m = i / KPAD, k = i - m * KPAD;
    float x = (k < Kreal) ? w[(size_t)m * Kreal + k] : 0.f;
    bsplit(x, hi[i], lo[i]);
}

__global__ void wsplit_reorder_k(const float* __restrict__ w, __nv_bfloat16* __restrict__ hi,
                                 __nv_bfloat16* __restrict__ lo, int M, int CIN, int KK)
{
    int K = CIN * KK;
    int i = blockIdx.x * blockDim.x + threadIdx.x;
    if (i >= M * K) return;
    int m = i / K, kidx = i - m * K;
    int pos = kidx / CIN, ci = kidx - pos * CIN;
    bsplit(w[((size_t)m * CIN + ci) * KK + pos], hi[i], lo[i]);
}

__global__ void wsplitT_k(const float* __restrict__ w, __nv_bfloat16* __restrict__ hi,
                          __nv_bfloat16* __restrict__ lo, int M, int K)
{
    int i = blockIdx.x * blockDim.x + threadIdx.x;
    if (i >= M * K) return;
    int m = i / K, k = i - m * K;
    bsplit(w[(size_t)k * M + m], hi[i], lo[i]);
}

__global__ void gather_nodes_split_k(const float* __restrict__ p5,
                                     __nv_bfloat16* __restrict__ hi, __nv_bfloat16* __restrict__ lo)
{
    int idx = blockIdx.x * blockDim.x + threadIdx.x;
    if (idx >= TMN * 256) return;
    int d = idx % 256;
    int n = idx / 256;
    int t = n % 16, m = n / 16;
    bsplit(p5[((size_t)t * 256 + d) * 88 + m], hi[idx], lo[idx]);
}

__global__ void nchw2nhwc_k(const float* __restrict__ in,
                            __nv_bfloat16* __restrict__ hi, __nv_bfloat16* __restrict__ lo,
                            int C, int NPIX)
{
    __shared__ float t[32][33];
    int img = blockIdx.z;
    int p0 = blockIdx.x * 32, c0 = blockIdx.y * 32;
    int tx = threadIdx.x, ty = threadIdx.y;
    const float* src = in + (size_t)img * C * NPIX;
    #pragma unroll
    for (int i = 0; i < 4; i++) {
        int c = c0 + ty + i * 8, p = p0 + tx;
        if (p < NPIX) t[ty + i * 8][tx] = src[(size_t)c * NPIX + p];
    }
    __syncthreads();
    #pragma unroll
    for (int i = 0; i < 4; i++) {
        int p = p0 + ty + i * 8, c = c0 + tx;
        if (p < NPIX) {
            size_t o = ((size_t)img * NPIX + p) * C + c;
            bsplit(t[tx][ty + i * 8], hi[o], lo[o]);
        }
    }
}

template<int CIN, int KD, int S, int HinP, int WinP, int Hout, int Wout, int KPAD>
__global__ void im2col_v8_t(const float* __restrict__ in,
                            __nv_bfloat16* __restrict__ bhi, __nv_bfloat16* __restrict__ blo)
{
    constexpr int KK = KD * KD;
    constexpr int KREAL = CIN * KK;
    constexpr int HW = Hout * Wout;
    constexpr int NPIX = N_IMG * HW;
    constexpr int KQ = KPAD / 8;
    int idx = blockIdx.x * blockDim.x + threadIdx.x;
    if (idx >= NPIX * KQ) return;
    int p  = idx / KQ;
    int k0 = (idx - p * KQ) * 8;
    int img = p / HW;
    int rr  = p - img * HW;
    int oh  = rr / Wout;
    int ow  = rr - oh * Wout;
    const float* base = in + ((size_t)img * CIN * HinP + oh * S) * WinP + ow * S;

    __nv_bfloat16 hv[8], lv[8];
    #pragma unroll
    for (int j = 0; j < 8; j++) {
        int k = k0 + j;
        float x = 0.f;
        if (k < KREAL) {
            int ci = k / KK;
            int r  = k - ci * KK;
            int kh = r / KD;
            int kw = r - kh * KD;
            x = base[((size_t)ci * HinP + kh) * WinP + kw];
        }
        bsplit(x, hv[j], lv[j]);
    }
    size_t o = (size_t)p * KPAD + k0;
    *(uint4*)(bhi + o) = *(const uint4*)hv;
    *(uint4*)(blo + o) = *(const uint4*)lv;
}

// ---------------- fused-segment tensor-core GEMMs ----------------
#define ASTR 72

// -------- explicit-B GEMM, 64(M) x 128(N) — conv1 (padded-row layout) --------
#define A1_SZ (64 * ASTR * 2)
#define B1_SZ (128 * ASTR * 2)
#define ST1_SZ (2 * A1_SZ + 2 * B1_SZ)
#define SMEM_G1 (2 * ST1_SZ)
__global__ void __launch_bounds__(256)
mmaconv64_k(const __nv_bfloat16* __restrict__ Ahi, const __nv_bfloat16* __restrict__ Alo,
            const __nv_bfloat16* __restrict__ Bhi, const __nv_bfloat16* __restrict__ Blo,
            const float* __restrict__ bias, float* __restrict__ out,
            int M, int Npix, int K, int Hout, int Wout,
            int HoP, int WoP, int opad)
{
    extern __shared__ char smem[];
    uint32_t sb = smem_u32(smem);
    uint32_t stg[2] = { sb, sb + ST1_SZ };

    int tid  = threadIdx.x;
    int lane = tid & 31;
    int wid  = tid >> 5;
    int wm   = wid & 1;
    int wn   = wid >> 1;

    int m0 = 0;
    int n0 = blockIdx.x * 128;

    float d[2][4][4];
    #pragma unroll
    for (int i = 0; i < 2; i++)
        #pragma unroll
        for (int j = 0; j < 4; j++)
            #pragma unroll
            for (int r = 0; r < 4; r++) d[i][j][r] = 0.f;

    int aj = lane >> 3, ar = lane & 7;
    uint32_t aAddrOff = (uint32_t)(((aj & 1) * 8 + ar) * ASTR + (aj >> 1) * 8) * 2;
    uint32_t bAddrOff = (uint32_t)(((aj >> 1) * 8 + ar) * ASTR + (aj & 1) * 8) * 2;

    int itK = K >> 6;

    int arow[2], aq[2];
    #pragma unroll
    for (int j = 0; j < 2; j++) { int i = tid + j * 256; arow[j] = i >> 3; aq[j] = i & 7; }
    int brow[4], bq[4];
    #pragma unroll
    for (int j = 0; j < 4; j++) { int i = tid + j * 256; brow[j] = i >> 3; bq[j] = i & 7; }

    auto load_stage = [&](int st, int it) {
        int kof = it << 6;
        uint32_t s = stg[st];
        #pragma unroll
        for (int j = 0; j < 2; j++) {
            size_t go = (size_t)(m0 + arow[j]) * K + kof + aq[j] * 8;
            uint32_t so = (uint32_t)(arow[j] * ASTR + aq[j] * 8) * 2;
            bool pr = m0 + arow[j] < M;
            cp16(s + so, Ahi + go, pr);
            cp16(s + A1_SZ + so, Alo + go, pr);
        }
        #pragma unroll
        for (int j = 0; j < 4; j++) {
            size_t go = (size_t)(n0 + brow[j]) * K + kof + bq[j] * 8;
            uint32_t so = (uint32_t)(brow[j] * ASTR + bq[j] * 8) * 2;
            bool pr = n0 + brow[j] < Npix;
            cp16(s + 2 * A1_SZ + so, Bhi + go, pr);
            cp16(s + 2 * A1_SZ + B1_SZ + so, Blo + go, pr);
        }
        CP_COMMIT();
    };

    load_stage(0, 0);

    for (int it = 0; it < itK; it++) {
        int st = it & 1;
        if (it + 1 < itK) { load_stage(st ^ 1, it + 1); CP_WAIT(1); }
        else              { CP_WAIT(0); }
        __syncthreads();
        uint32_t s = stg[st];

        #pragma unroll
        for (int kk = 0; kk < 4; kk++) {
            uint32_t ah[2][4], al[2][4];
            #pragma unroll
            for (int mi = 0; mi < 2; mi++) {
                uint32_t off = aAddrOff + (uint32_t)((wm * 32 + mi * 16) * ASTR + kk * 16) * 2;
                ldsm_x4(ah[mi][0], ah[mi][1], ah[mi][2], ah[mi][3], s + off);
                ldsm_x4(al[mi][0], al[mi][1], al[mi][2], al[mi][3], s + A1_SZ + off);
            }
            uint32_t bh[4][2], bl[4][2];
            #pragma unroll
            for (int q = 0; q < 2; q++) {
                uint32_t off = bAddrOff + (uint32_t)((wn * 32 + q * 16) * ASTR + kk * 16) * 2;
                uint32_t r0, r1, r2, r3;
                ldsm_x4(r0, r1, r2, r3, s + 2 * A1_SZ + off);
                bh[q * 2][0] = r0; bh[q * 2][1] = r1;
                bh[q * 2 + 1][0] = r2; bh[q * 2 + 1][1] = r3;
                ldsm_x4(r0, r1, r2, r3, s + 2 * A1_SZ + B1_SZ + off);
                bl[q * 2][0] = r0; bl[q * 2][1] = r1;
                bl[q * 2 + 1][0] = r2; bl[q * 2 + 1][1] = r3;
            }
            #pragma unroll
            for (int mi = 0; mi < 2; mi++)
                #pragma unroll
                for (int nj = 0; nj < 4; nj++) {
                    mma16816(d[mi][nj], ah[mi], bh[nj][0], bh[nj][1]);
                    mma16816(d[mi][nj], ah[mi], bl[nj][0], bl[nj][1]);
                    mma16816(d[mi][nj], al[mi], bh[nj][0], bh[nj][1]);
                }
        }
        __syncthreads();
    }

    int HW = Hout * Wout;
    #pragma unroll
    for (int mi = 0; mi < 2; mi++) {
        #pragma unroll
        for (int r2 = 0; r2 < 2; r2++) {
            int co = m0 + wm * 32 + mi * 16 + (lane >> 2) + r2 * 8;
            if (co >= M) continue;
            float bv = bias[co];
            #pragma unroll
            for (int nj = 0; nj < 4; nj++) {
                #pragma unroll
                for (int c = 0; c < 2; c++) {
                    int p = n0 + wn * 32 + nj * 8 + (lane & 3) * 2 + c;
                    if (p >= Npix) continue;
                    float v = d[mi][nj][r2 * 2 + c] + bv;
                    int img = p / HW;
                    int rr  = p - img * HW;
                    int oh  = rr / Wout;
                    int ow  = rr - oh * Wout;
                    out[((size_t)(img * M + co) * HoP + oh + opad) * WoP + ow + opad]
                        = fmaxf(v, 0.f);
                }
            }
        }
    }
}

// -------- implicit-B GEMM, 128(M) x 64(N), XOR-swizzled 128B rows, 2 blocks/SM --------
#define AR3_SZ 16384        // 128 rows x 128 B (one of hi/lo)
#define BR3_SZ 8192         // 64 rows x 128 B
#define ST3_SZ (2 * AR3_SZ + 2 * BR3_SZ)   // 49152
#define SMEM_G3 (2 * ST3_SZ)               // 98304
__global__ void __launch_bounds__(256, 2)
mmaconv_imp_k(const __nv_bfloat16* __restrict__ Ahi, const __nv_bfloat16* __restrict__ Alo,
              const __nv_bfloat16* __restrict__ Xhi, const __nv_bfloat16* __restrict__ Xlo,
              const float* __restrict__ bias, float* __restrict__ out,
              int M, int Npix, int K, int CIN, int KD,
              int HinP, int WinP, int Hout, int Wout,
              int HoP, int WoP, int opad)
{
    extern __shared__ char smem[];
    uint32_t sb = smem_u32(smem);
    uint32_t stg[2] = { sb, sb + ST3_SZ };

    int tid  = threadIdx.x;
    int lane = tid & 31;
    int wid  = tid >> 5;
    int wm   = wid & 3;
    int wn   = wid >> 2;

    int m0 = blockIdx.y * 128;
    int n0 = blockIdx.x * 64;

    float d[2][4][4];
    #pragma unroll
    for (int i = 0; i < 2; i++)
        #pragma unroll
        for (int j = 0; j < 4; j++)
            #pragma unroll
            for (int r = 0; r < 4; r++) d[i][j][r] = 0.f;

    int aj = lane >> 3, ar = lane & 7;
    // fragment row byte-offsets (row bases are multiples of 8 -> XOR term is exactly ar)
    uint32_t aRowOff[2], bRowOff[2];
    #pragma unroll
    for (int mi = 0; mi < 2; mi++)
        aRowOff[mi] = (uint32_t)((wm * 32 + mi * 16 + (aj & 1) * 8 + ar) * 128);
    #pragma unroll
    for (int q = 0; q < 2; q++)
        bRowOff[q] = (uint32_t)((wn * 32 + q * 16 + (aj >> 1) * 8 + ar) * 128);
    int aColBase = aj >> 1;    // 16B-group within kk pair
    int bColBase = aj & 1;

    int itK = K >> 6;
    int cPer = CIN >> 6;
    int HW = Hout * Wout;

    int arow[4], aq[4];
    #pragma unroll
    for (int j = 0; j < 4; j++) { int i = tid + j * 256; arow[j] = i >> 3; aq[j] = i & 7; }
    int brow[2], bq[2];
    long bbase[2];
    bool bval[2];
    #pragma unroll
    for (int j = 0; j < 2; j++) {
        int i = tid + j * 256;
        brow[j] = i >> 3; bq[j] = i & 7;
        int p = n0 + brow[j];
        bval[j] = p < Npix;
        if (!bval[j]) p = 0;
        int img = p / HW;
        int rr  = p - img * HW;
        int oh  = rr / Wout;
        int ow  = rr - oh * Wout;
        bbase[j] = ((long)(img * HinP + oh) * WinP + ow) * CIN;
    }

    auto load_stage = [&](int st, int it) {
        int pos = it / cPer;
        int cioff = (it - pos * cPer) << 6;
        int kh = pos / KD, kw = pos - kh * KD;
        int kofA = it << 6;
        long boff = (long)(kh * WinP + kw) * CIN + cioff;
        uint32_t s = stg[st];
        #pragma unroll
        for (int j = 0; j < 4; j++) {
            size_t go = (size_t)(m0 + arow[j]) * K + kofA + aq[j] * 8;
            uint32_t so = (uint32_t)(arow[j] * 128 + ((aq[j] ^ (arow[j] & 7)) * 16));
            bool pr = m0 + arow[j] < M;
            cp16(s + so, Ahi + go, pr);
            cp16(s + AR3_SZ + so, Alo + go, pr);
        }
        #pragma unroll
        for (int j = 0; j < 2; j++) {
            long go = bbase[j] + boff + bq[j] * 8;
            uint32_t so = (uint32_t)(brow[j] * 128 + ((bq[j] ^ (brow[j] & 7)) * 16));
            cp16(s + 2 * AR3_SZ + so, Xhi + go, bval[j]);
            cp16(s + 2 * AR3_SZ + BR3_SZ + so, Xlo + go, bval[j]);
        }
        CP_COMMIT();
    };

    load_stage(0, 0);

    for (int it = 0; it < itK; it++) {
        int st = it & 1;
        if (it + 1 < itK) { load_stage(st ^ 1, it + 1); CP_WAIT(1); }
        else              { CP_WAIT(0); }
        __syncthreads();
        uint32_t s = stg[st];

        #pragma unroll
        for (int kk = 0; kk < 4; kk++) {
            uint32_t aCol = (uint32_t)(((kk * 2 + aColBase) ^ ar) * 16);
            uint32_t bCol = (uint32_t)(((kk * 2 + bColBase) ^ ar) * 16);
            uint32_t ah[2][4], al[2][4];
            #pragma unroll
            for (int mi = 0; mi < 2; mi++) {
                uint32_t ad = s + aRowOff[mi] + aCol;
                ldsm_x4(ah[mi][0], ah[mi][1], ah[mi][2], ah[mi][3], ad);
                ldsm_x4(al[mi][0], al[mi][1], al[mi][2], al[mi][3], ad + AR3_SZ);
            }
            uint32_t bh[4][2], bl[4][2];
            #pragma unroll
            for (int q = 0; q < 2; q++) {
                uint32_t bd = s + 2 * AR3_SZ + bRowOff[q] + bCol;
                uint32_t r0, r1, r2, r3;
                ldsm_x4(r0, r1, r2, r3, bd);
                bh[q * 2][0] = r0; bh[q * 2][1] = r1;
                bh[q * 2 + 1][0] = r2; bh[q * 2 + 1][1] = r3;
                ldsm_x4(r0, r1, r2, r3, bd + BR3_SZ);
                bl[q * 2][0] = r0; bl[q * 2][1] = r1;
                bl[q * 2 + 1][0] = r2; bl[q * 2 + 1][1] = r3;
            }
            #pragma unroll
            for (int mi = 0; mi < 2; mi++)
                #pragma unroll
                for (int nj = 0; nj < 4; nj++) {
                    mma16816(d[mi][nj], ah[mi], bh[nj][0], bh[nj][1]);
                    mma16816(d[mi][nj], ah[mi], bl[nj][0], bl[nj][1]);
                    mma16816(d[mi][nj], al[mi], bh[nj][0], bh[nj][1]);
                }
        }
        __syncthreads();
    }

    #pragma unroll
    for (int mi = 0; mi < 2; mi++) {
        #pragma unroll
        for (int r2 = 0; r2 < 2; r2++) {
            int co = m0 + wm * 32 + mi * 16 + (lane >> 2) + r2 * 8;
            if (co >= M) continue;
            float bv = bias[co];
            #pragma unroll
            for (int nj = 0; nj < 4; nj++) {
                #pragma unroll
                for (int c = 0; c < 2; c++) {
                    int p = n0 + wn * 32 + nj * 8 + (lane & 3) * 2 + c;
                    if (p >= Npix) continue;
                    float v = d[mi][nj][r2 * 2 + c] + bv;
                    int img = p / HW;
                    int rr  = p - img * HW;
                    int oh  = rr / Wout;
                    int ow  = rr - oh * Wout;
                    out[((size_t)(img * M + co) * HoP + oh + opad) * WoP + ow + opad]
                        = fmaxf(v, 0.f);
                }
            }
        }
    }
}

// -------- generic explicit GEMM, 128(M) x 64(N), transposed output C[n,m] --------
#define A2_SZ (128 * ASTR * 2)
#define B2_SZ (64 * ASTR * 2)
#define ST2_SZ (2 * A2_SZ + 2 * B2_SZ)
#define SMEM_G2 (2 * ST2_SZ)
__global__ void __launch_bounds__(256)
mmagemm_k(const __nv_bfloat16* __restrict__ Ahi, const __nv_bfloat16* __restrict__ Alo,
          const __nv_bfloat16* __restrict__ Bhi, const __nv_bfloat16* __restrict__ Blo,
          float* __restrict__ out, int M, int N, int K)
{
    extern __shared__ char smem[];
    uint32_t sb = smem_u32(smem);
    uint32_t stg[2] = { sb, sb + ST2_SZ };

    int tid  = threadIdx.x;
    int lane = tid & 31;
    int wid  = tid >> 5;
    int wm   = wid & 3;
    int wn   = wid >> 2;

    int m0 = blockIdx.y * 128;
    int n0 = blockIdx.x * 64;

    float d[2][4][4];
    #pragma unroll
    for (int i = 0; i < 2; i++)
        #pragma unroll
        for (int j = 0; j < 4; j++)
            #pragma unroll
            for (int r = 0; r < 4; r++) d[i][j][r] = 0.f;

    int aj = lane >> 3, ar = lane & 7;
    uint32_t aAddrOff = (uint32_t)(((aj & 1) * 8 + ar) * ASTR + (aj >> 1) * 8) * 2;
    uint32_t bAddrOff = (uint32_t)(((aj >> 1) * 8 + ar) * ASTR + (aj & 1) * 8) * 2;

    int itK = K >> 6;

    int arow[4], aq[4];
    #pragma unroll
    for (int j = 0; j < 4; j++) { int i = tid + j * 256; arow[j] = i >> 3; aq[j] = i & 7; }
    int brow[2], bq[2];
    #pragma unroll
    for (int j = 0; j < 2; j++) { int i = tid + j * 256; brow[j] = i >> 3; bq[j] = i & 7; }

    auto load_stage = [&](int st, int it) {
        int kof = it << 6;
        uint32_t s = stg[st];
        #pragma unroll
        for (int j = 0; j < 4; j++) {
            size_t go = (size_t)(m0 + arow[j]) * K + kof + aq[j] * 8;
            uint32_t so = (uint32_t)(arow[j] * ASTR + aq[j] * 8) * 2;
            bool pr = m0 + arow[j] < M;
            cp16(s + so, Ahi + go, pr);
            cp16(s + A2_SZ + so, Alo + go, pr);
        }
        #pragma unroll
        for (int j = 0; j < 2; j++) {
            size_t go = (size_t)(n0 + brow[j]) * K + kof + bq[j] * 8;
            uint32_t so = (uint32_t)(brow[j] * ASTR + bq[j] * 8) * 2;
            bool pr = n0 + brow[j] < N;
            cp16(s + 2 * A2_SZ + so, Bhi + go, pr);
            cp16(s + 2 * A2_SZ + B2_SZ + so, Blo + go, pr);
        }
        CP_COMMIT();
    };

    load_stage(0, 0);

    for (int it = 0; it < itK; it++) {
        int st = it & 1;
        if (it + 1 < itK) { load_stage(st ^ 1, it + 1); CP_WAIT(1); }
        else              { CP_WAIT(0); }
        __syncthreads();
        uint32_t s = stg[st];

        #pragma unroll
        for (int kk = 0; kk < 4; kk++) {
            uint32_t ah[2][4], al[2][4];
            #pragma unroll
            for (int mi = 0; mi < 2; mi++) {
                uint32_t off = aAddrOff + (uint32_t)((wm * 32 + mi * 16) * ASTR + kk * 16) * 2;
                ldsm_x4(ah[mi][0], ah[mi][1], ah[mi][2], ah[mi][3], s + off);
                ldsm_x4(al[mi][0], al[mi][1], al[mi][2], al[mi][3], s + A2_SZ + off);
            }
            uint32_t bh[4][2], bl[4][2];
            #pragma unroll
            for (int q = 0; q < 2; q++) {
                uint32_t off = bAddrOff + (uint32_t)((wn * 32 + q * 16) * ASTR + kk * 16) * 2;
                uint32_t r0, r1, r2, r3;
                ldsm_x4(r0, r1, r2, r3, s + 2 * A2_SZ + off);
                bh[q * 2][0] = r0; bh[q * 2][1] = r1;
                bh[q * 2 + 1][0] = r2; bh[q * 2 + 1][1] = r3;
                ldsm_x4(r0, r1, r2, r3, s + 2 * A2_SZ + B2_SZ + off);
                bl[q * 2][0] = r0; bl[q * 2][1] = r1;
                bl[q * 2 + 1][0] = r2; bl[q * 2 + 1][1] = r3;
            }
            #pragma unroll
            for (int mi = 0; mi < 2; mi++)
                #pragma unroll
                for (int nj = 0; nj < 4; nj++) {
                    mma16816(d[mi][nj], ah[mi], bh[nj][0], bh[nj][1]);
                    mma16816(d[mi][nj], ah[mi], bl[nj][0], bl[nj][1]);
                    mma16816(d[mi][nj], al[mi], bh[nj][0], bh[nj][1]);
                }
        }
        __syncthreads();
    }

    #pragma unroll
    for (int mi = 0; mi < 2; mi++) {
        #pragma unroll
        for (int r2 = 0; r2 < 2; r2++) {
            int co = m0 + wm * 32 + mi * 16 + (lane >> 2) + r2 * 8;
            if (co >= M) continue;
            #pragma unroll
            for (int nj = 0; nj < 4; nj++) {
                #pragma unroll
                for (int c = 0; c < 2; c++) {
                    int p = n0 + wn * 32 + nj * 8 + (lane & 3) * 2 + c;
                    if (p >= N) continue;
                    out[(size_t)p * M + co] = d[mi][nj][r2 * 2 + c];
                }
            }
        }
    }
}

// ---------------- scalar kernels (rest of network) ----------------

__global__ void pad_copy_k(const float* __restrict__ src, float* __restrict__ dst,
                           int nimg, int boff)
{
    int idx = blockIdx.x * blockDim.x + threadIdx.x;
    int total = nimg * 3 * H0 * W0;
    if (idx >= total) return;
    int w = idx % W0; int t = idx / W0;
    int h = t % H0;   t /= H0;
    int c = t % 3;    int n = t / 3;
    dst[(((size_t)(boff + n) * 3 + c) * H0P + h + 2) * W0P + (w + 2)] = src[idx];
}

__global__ void maxpool_k(const float* __restrict__ in, float* __restrict__ out,
                          int NC, int Hin, int Win, int Ho, int Wo,
                          int HoP, int WoP, int opad)
{
    int idx = blockIdx.x * blockDim.x + threadIdx.x;
    int total = NC * Ho * Wo;
    if (idx >= total) return;
    int ow = idx % Wo; int t = idx / Wo;
    int oh = t % Ho;   int nc = t / Ho;
    const float* ip = in + ((size_t)nc * Hin + oh * 2) * Win + ow * 2;
    float m = -INFINITY;
    #pragma unroll
    for (int kh = 0; kh < 3; kh++)
        #pragma unroll
        for (int kw = 0; kw < 3; kw++)
            m = fmaxf(m, ip[kh * Win + kw]);
    out[((size_t)nc * HoP + oh + opad) * WoP + ow + opad] = m;
}

__global__ void cd_conv_k(const float* __restrict__ Xf, const float* __restrict__ wcd,
                          const float* __restrict__ bcd, float* __restrict__ xc)
{
    int p = blockIdx.x;
    int o = threadIdx.x;
    float acc = bcd[o];
    for (int i = 0; i < 256; i++) {
        const float* wr = wcd + (o * 256 + i) * 3;
        const float* xr = Xf + i * 88;
        if (p > 0)  acc += xr[p - 1] * wr[0];
        acc += xr[p] * wr[1];
        if (p < 87) acc += xr[p + 1] * wr[2];
    }
    xc[o * 88 + p] = acc;
}

__global__ void cd_max_k(const float* __restrict__ xc, float* __restrict__ v)
{
    int o = threadIdx.x;
    float m = -INFINITY;
    for (int p = 0; p < 88; p++) m = fmaxf(m, xc[o * 88 + p]);
    v[o] = m;
}

__global__ void xhat_k(const float* __restrict__ v, const float* __restrict__ wt,
                       const float* __restrict__ bt, float* __restrict__ xhat)
{
    __shared__ float sv[256];
    int o = blockIdx.x;
    int k = threadIdx.x;
    for (int i = threadIdx.x; i < 256; i += blockDim.x) sv[i] = v[i];
    __syncthreads();
    float acc = bt[o];
    for (int i = 0; i < 256; i++)
        acc += sv[i] * wt[((size_t)i * 256 + o) * 88 + k];
    xhat[o * 88 + k] = acc;
}

__global__ __launch_bounds__(256)
void rbgemm_k(const float* __restrict__ A, const float* __restrict__ B,
              const float* __restrict__ bias, float* __restrict__ C,
              int M, int N, int K, int flags)
{
    __shared__ float As[16][65];
    __shared__ float Bs[16][64];
    int tid = threadIdx.x;
    int tx = tid & 15;
    int ty = tid >> 4;
    int m0 = blockIdx.y * 64;
    int n0 = blockIdx.x * 64;

    float acc[4][4] = {};

    for (int k0 = 0; k0 < K; k0 += 16) {
        #pragma unroll
        for (int i = 0; i < 4; i++) {
            int e  = tid + i * 256;
            int kk = e & 15;
            int mm = e >> 4;
            int gm = m0 + mm, gk = k0 + kk;
            As[kk][mm] = (gm < M && gk < K) ? A[(size_t)gm * K + gk] : 0.f;
        }
        #pragma unroll
        for (int i = 0; i < 4; i++) {
            int nn = tid & 63;
            int kk = (tid >> 6) + i * 4;
            int gk = k0 + kk, gn = n0 + nn;
            Bs[kk][nn] = (gk < K && gn < N) ? B[(size_t)gk * N + gn] : 0.f;
        }
        __syncthreads();
        #pragma unroll
        for (int kk = 0; kk < 16; kk++) {
            float ra[4], rb[4];
            #pragma unroll
            for (int i = 0; i < 4; i++) ra[i] = As[kk][ty * 4 + i];
            #pragma unroll
            for (int j = 0; j < 4; j++) rb[j] = Bs[kk][tx * 4 + j];
            #pragma unroll
            for (int i = 0; i < 4; i++)
                #pragma unroll
                for (int j = 0; j < 4; j++)
                    acc[i][j] += ra[i] * rb[j];
        }
        __syncthreads();
    }

    #pragma unroll
    for (int i = 0; i < 4; i++) {
        int gm = m0 + ty * 4 + i;
        if (gm >= M) continue;
        #pragma unroll
        for (int j = 0; j < 4; j++) {
            int gn = n0 + tx * 4 + j;
            if (gn >= N) continue;
            float v = acc[i][j];
            if (flags & 1) v += bias[gm];
            if (flags & 2) v += bias[gn];
            if (flags & 4) v = v >= 0.f ? v : 0.01f * v;
            C[(size_t)gm * N + gn] = v;
        }
    }
}

__global__ void a1_reduce_k(const float* __restrict__ Y, float* __restrict__ S, int F)
{
    int f = blockIdx.x * blockDim.x + threadIdx.x;
    int t = blockIdx.y;
    if (f >= F) return;
    float s = 0.f;
    for (int m = 0; m < 88; m++) s += Y[(size_t)(m * 16 + t) * F + f];
    S[t * F + f] = s;
}

__global__ void a1_apply_split_k(const float* __restrict__ Y, const float* __restrict__ S,
                                 const float* __restrict__ bias,
                                 __nv_bfloat16* __restrict__ hi, __nv_bfloat16* __restrict__ lo,
                                 int F)
{
    int idx = blockIdx.x * blockDim.x + threadIdx.x;
    if (idx >= TMN * F) return;
    int f = idx % F;
    int n = idx / F;
    int t = n % 16;
    float val = S[t * F + f] + bias[f];
    if (t == 0) val -= Y[idx];
    val = val >= 0.f ? val : 0.01f * val;
    bsplit(val, hi[idx], lo[idx]);
}

__global__ void a1_apply_k(const float* __restrict__ Y, const float* __restrict__ S,
                           const float* __restrict__ bias, float* __restrict__ h, int F)
{
    int idx = blockIdx.x * blockDim.x + threadIdx.x;
    if (idx >= TMN * F) return;
    int f = idx % F;
    int n = idx / F;
    int t = n % 16;
    float val = S[t * F + f] + bias[f];
    if (t == 0) val -= Y[idx];
    h[idx] = val >= 0.f ? val : 0.01f * val;
}

__global__ void v1_k(const float* __restrict__ h2, const float* __restrict__ xhat,
                     float* __restrict__ V1, float* __restrict__ V1t, float* __restrict__ Vx)
{
    int idx = blockIdx.x * blockDim.x + threadIdx.x;
    if (idx >= 256 * 88) return;
    int d = idx % 256;
    int m = idx / 256;
    float mx = -INFINITY;
    #pragma unroll
    for (int t = 0; t < 16; t++) mx = fmaxf(mx, h2[(size_t)(m * 16 + t) * 256 + d]);
    V1[d * 88 + m] = mx;
    V1t[m * 256 + d] = mx;
    Vx[d * 88 + m] = mx + xhat[d * 88 + m];
}

__global__ void attn_k(const float* __restrict__ G, const float* __restrict__ Hh,
                       float* __restrict__ A2)
{
    __shared__ float red[128];
    int j = blockIdx.x;
    int i = threadIdx.x;
    float s = 0.f;
    if (i < 88) {
        for (int d = 0; d < 256; d++) s += Hh[d * 88 + j] * G[d * 88 + i];
    }
    red[i] = (i < 88) ? s : -INFINITY;
    __syncthreads();
    for (int st = 64; st > 0; st >>= 1) {
        if (i < st) red[i] = fmaxf(red[i], red[i + st]);
        __syncthreads();
    }
    float mx = red[0];
    __syncthreads();
    float e = (i < 88) ? expf(s - mx) : 0.f;
    red[i] = e;
    __syncthreads();
    for (int st = 64; st > 0; st >>= 1) {
        if (i < st) red[i] += red[i + st];
        __syncthreads();
    }
    float sum = red[0];
    if (i < 88) A2[j * 88 + i] = e / sum;
}

__global__ void final_dot_k(const float* __restrict__ Xf, const float* __restrict__ V2t,
                            float* __restrict__ out)
{
    __shared__ float red[256];
    float acc = 0.f;
    for (int e = threadIdx.x; e < 256 * 88; e += 256) {
        int d = e / 88, m = e % 88;
        acc += Xf[e] * V2t[m * 256 + d];
    }
    red[threadIdx.x] = acc;
    __syncthreads();
    for (int st = 128; st > 0; st >>= 1) {
        if (threadIdx.x < st) red[threadIdx.x] += red[threadIdx.x + st];
        __syncthreads();
    }
    if (threadIdx.x == 0) out[0] = red[0];
}

// ---------------- host ----------------
static float* symaddr(const void* s)
{
    void* p = nullptr;
    cudaGetSymbolAddress(&p, s);
    return (float*)p;
}
static __nv_bfloat16* symaddr_bf(const void* s)
{
    void* p = nullptr;
    cudaGetSymbolAddress(&p, s);
    return (__nv_bfloat16*)p;
}

extern "C" void kernel_launch(void* const* d_in, const int* in_sizes, int n_in,
                              void* d_out, int out_size)
{
    const float* search    = (const float*)d_in[0];
    const float* exemplars = (const float*)d_in[1];
    const float* aw1 = (const float*)d_in[2];  const float* ab1 = (const float*)d_in[3];
    const float* aw2 = (const float*)d_in[4];  const float* ab2 = (const float*)d_in[5];
    const float* aw3 = (const float*)d_in[6];  const float* ab3 = (const float*)d_in[7];
    const float* aw4 = (const float*)d_in[8];  const float* ab4 = (const float*)d_in[9];
    const float* aw5 = (const float*)d_in[10]; const float* ab5 = (const float*)d_in[11];
    const float* wcd = (const float*)d_in[12]; const float* bcd = (const float*)d_in[13];
    const float* wt  = (const float*)d_in[14]; const float* bt  = (const float*)d_in[15];
    const float* ws1 = (const float*)d_in[16]; const float* bs1 = (const float*)d_in[17];
    const float* ws2 = (const float*)d_in[18]; const float* bs2 = (const float*)d_in[19];
    const float* wg  = (const float*)d_in[20]; const float* bg  = (const float*)d_in[21];
    const float* wh  = (const float*)d_in[22]; const float* bh  = (const float*)d_in[23];
    const float* wc1 = (const float*)d_in[24]; const float* bc1 = (const float*)d_in[25];
    const float* wc2 = (const float*)d_in[26]; const float* bc2 = (const float*)d_in[27];

    float* p_in  = symaddr(g_in);
    float* p_c1  = symaddr(g_c1);
    float* p_p1  = symaddr(g_p1);
    float* p_c2  = symaddr(g_c2);
    float* p_p2  = symaddr(g_p2);
    float* p_c3  = symaddr(g_c3);
    float* p_c4  = symaddr(g_c4);
    float* p_c5  = symaddr(g_c5);
    float* p_p5  = symaddr(g_p5);
    float* p_xc  = symaddr(g_xc);
    float* p_v   = symaddr(g_v);
    float* p_xh  = symaddr(g_xhat);
    float* p_Y1  = symaddr(g_Y1);
    float* p_S   = symaddr(g_S);
    float* p_Y2  = symaddr(g_Y2);
    float* p_h2  = symaddr(g_h2);
    float* p_V1  = symaddr(g_V1);
    float* p_V1t = symaddr(g_V1t);
    float* p_Vx  = symaddr(g_Vx);
    float* p_G   = symaddr(g_G);
    float* p_Hh  = symaddr(g_Hh);
    float* p_A2  = symaddr(g_A2);
    float* p_xw  = symaddr(g_xw);
    float* p_c1m = symaddr(g_c1m);
    float* p_cw  = symaddr(g_cw);
    float* p_V2t = symaddr(g_V2t);
    __nv_bfloat16* pAhi = symaddr_bf(g_Ahi);
    __nv_bfloat16* pAlo = symaddr_bf(g_Alo);
    __nv_bfloat16* pBhi = symaddr_bf(g_Bhi);
    __nv_bfloat16* pBlo = symaddr_bf(g_Blo);

    cudaFuncSetAttribute(mmaconv64_k, cudaFuncAttributeMaxDynamicSharedMemorySize, SMEM_G1);
    cudaFuncSetAttribute(mmaconv_imp_k, cudaFuncAttributeMaxDynamicSharedMemorySize, SMEM_G3);
    cudaFuncSetAttribute(mmagemm_k, cudaFuncAttributeMaxDynamicSharedMemorySize, SMEM_G2);

    // zero padded buffers (borders must be 0 every replay)
    cudaMemsetAsync(p_in, 0, sizeof(float) * ((size_t)N_IMG * 3 * H0P * W0P + TAILPAD), 0);
    cudaMemsetAsync(p_p1, 0, sizeof(float) * ((size_t)N_IMG * C1o * P1HP * P1WP + TAILPAD), 0);
    cudaMemsetAsync(p_p2, 0, sizeof(float) * ((size_t)N_IMG * C2o * P2HP * P2WP + TAILPAD), 0);
    cudaMemsetAsync(p_c3, 0, sizeof(float) * ((size_t)N_IMG * C3o * P2HP * P2WP + TAILPAD), 0);
    cudaMemsetAsync(p_c4, 0, sizeof(float) * ((size_t)N_IMG * C4o * P2HP * P2WP + TAILPAD), 0);

    // assemble padded input batch
    {
        int tot = 16 * 3 * H0 * W0;
        pad_copy_k<<<(tot + 127) / 128, 128>>>(exemplars, p_in, 16, 0);
        tot = 3 * H0 * W0;
        pad_copy_k<<<(tot + 127) / 128, 128>>>(search, p_in, 1, 16);
    }

    // ---- conv1 (vectorized im2col, fused-segment 64x128 GEMM): M=64, K=384(pad) ----
    {
        const int KP = 384, NP = N_IMG * H1 * W1;
        wsplit_pad_k<<<(C1o * KP + 255) / 256, 256>>>(aw1, pAhi, pAlo, C1o, 363, KP);
        int tot = NP * (KP / 8);
        im2col_v8_t<3, 11, 4, H0P, W0P, H1, W1, 384><<<(tot + 255) / 256, 256>>>(p_in, pBhi, pBlo);
        mmaconv64_k<<<(NP + 127) / 128, 256, SMEM_G1>>>(
            pAhi, pAlo, pBhi, pBlo, ab1, p_c1, C1o, NP, KP, H1, W1, H1, W1, 0);
    }
    {
        int tot = N_IMG * C1o * P1H * P1W;
        maxpool_k<<<(tot + 127) / 128, 128>>>(p_c1, p_p1, N_IMG * C1o, H1, W1, P1H, P1W, P1HP, P1WP, 2);
    }

    // ---- p1 -> NHWC bf16 ----
    {
        const int NPIX = P1HP * P1WP;
        nchw2nhwc_k<<<dim3((NPIX + 31) / 32, C1o / 32, N_IMG), dim3(32, 8)>>>(p_p1, pBhi, pBlo, C1o, NPIX);
    }

    // ---- conv2 (implicit, fused, swizzled): M=192, K=1600, CIN=64, KD=5 ----
    {
        const int K = 1600, NP = N_IMG * H2 * W2;
        wsplit_reorder_k<<<(C2o * K + 255) / 256, 256>>>(aw2, pAhi, pAlo, C2o, 64, 25);
        mmaconv_imp_k<<<dim3((NP + 63) / 64, 2), 256, SMEM_G3>>>(
            pAhi, pAlo, pBhi, pBlo, ab2, p_c2, C2o, NP, K, 64, 5,
            P1HP, P1WP, H2, W2, H2, W2, 0);
    }
    {
        int tot = N_IMG * C2o * P2H * P2W;
        maxpool_k<<<(tot + 127) / 128, 128>>>(p_c2, p_p2, N_IMG * C2o, H2, W2, P2H, P2W, P2HP, P2WP, 1);
    }

    // ---- p2 -> NHWC ----
    {
        const int NPIX = P2HP * P2WP;
        nchw2nhwc_k<<<dim3((NPIX + 31) / 32, C2o / 32, N_IMG), dim3(32, 8)>>>(p_p2, pBhi, pBlo, C2o, NPIX);
    }

    // ---- conv3 (implicit, fused, swizzled): M=384, K=1728, CIN=192 ----
    {
        const int K = 1728, NP = N_IMG * P2H * P2W;
        wsplit_reorder_k<<<(C3o * K + 255) / 256, 256>>>(aw3, pAhi, pAlo, C3o, 192, 9);
        mmaconv_imp_k<<<dim3((NP + 63) / 64, 3), 256, SMEM_G3>>>(
            pAhi, pAlo, pBhi, pBlo, ab3, p_c3, C3o, NP, K, 192, 3,
            P2HP, P2WP, P2H, P2W, P2HP, P2WP, 1);
    }

    // ---- c3 -> NHWC ----
    {
        const int NPIX = P2HP * P2WP;
        nchw2nhwc_k<<<dim3((NPIX + 31) / 32, C3o / 32, N_IMG), dim3(32, 8)>>>(p_c3, pBhi, pBlo, C3o, NPIX);
    }

    // ---- conv4 (implicit, fused, swizzled): M=256, K=3456, CIN=384 ----
    {
        const int K = 3456, NP = N_IMG * P2H * P2W;
        wsplit_reorder_k<<<(C4o * K + 255) / 256, 256>>>(aw4, pAhi, pAlo, C4o, 384, 9);
        mmaconv_imp_k<<<dim3((NP + 63) / 64, 2), 256, SMEM_G3>>>(
            pAhi, pAlo, pBhi, pBlo, ab4, p_c4, C4o, NP, K, 384, 3,
            P2HP, P2WP, P2H, P2W, P2HP, P2WP, 1);
    }

    // ---- c4 -> NHWC ----
    {
        const int NPIX = P2HP * P2WP;
        nchw2nhwc_k<<<dim3((NPIX + 31) / 32, C4o / 32, N_IMG), dim3(32, 8)>>>(p_c4, pBhi, pBlo, C4o, NPIX);
    }

    // ---- conv5 (implicit, fused, swizzled): M=256, K=2304, CIN=256, out unpadded ----
    {
        const int K = 2304, NP = N_IMG * P2H * P2W;
        wsplit_reorder_k<<<(C5o * K + 255) / 256, 256>>>(aw5, pAhi, pAlo, C5o, 256, 9);
        mmaconv_imp_k<<<dim3((NP + 63) / 64, 2), 256, SMEM_G3>>>(
            pAhi, pAlo, pBhi, pBlo, ab5, p_c5, C5o, NP, K, 256, 3,
            P2HP, P2WP, P2H, P2W, H5, W5, 0);
    }
    {
        int tot = N_IMG * C5o * P5H * P5W;
        maxpool_k<<<(tot + 127) / 128, 128>>>(p_c5, p_p5, N_IMG * C5o, H5, W5, P5H, P5W, P5H, P5W, 0);
    }

    const float* Xf = p_p5 + (size_t)16 * 256 * 88;

    // ---- conv_deconv branch ----
    cd_conv_k<<<88, 256>>>(Xf, wcd, bcd, p_xc);
    cd_max_k<<<1, 256>>>(p_xc, p_v);
    xhat_k<<<256, 88>>>(p_v, wt, bt, p_xh);

    // ---- spatiotemporal GCN (tensor-core, fused split) ----
    __nv_bfloat16* nHi = pBhi;
    __nv_bfloat16* nLo = pBlo;
    __nv_bfloat16* h1Hi = pBhi + (1 << 20);
    __nv_bfloat16* h1Lo = pBlo + (1 << 20);
    __nv_bfloat16* w1Hi = pAhi;
    __nv_bfloat16* w1Lo = pAlo;
    __nv_bfloat16* w2Hi = pAhi + (512 * 256);
    __nv_bfloat16* w2Lo = pAlo + (512 * 256);

    gather_nodes_split_k<<<(TMN * 256 + 255) / 256, 256>>>(p_p5, nHi, nLo);
    wsplitT_k<<<(512 * 256 + 255) / 256, 256>>>(ws1, w1Hi, w1Lo, 512, 256);
    mmagemm_k<<<dim3(TMN / 64, 512 / 128), 256, SMEM_G2>>>(
        w1Hi, w1Lo, nHi, nLo, p_Y1, 512, TMN, 256);
    a1_reduce_k<<<dim3(4, 16), 128>>>(p_Y1, p_S, 512);
    a1_apply_split_k<<<(TMN * 512 + 255) / 256, 256>>>(p_Y1, p_S, bs1, h1Hi, h1Lo, 512);
    wsplitT_k<<<(256 * 512 + 255) / 256, 256>>>(ws2, w2Hi, w2Lo, 256, 512);
    mmagemm_k<<<dim3(TMN / 64, 256 / 128), 256, SMEM_G2>>>(
        w2Hi, w2Lo, h1Hi, h1Lo, p_Y2, 256, TMN, 512);
    a1_reduce_k<<<dim3(2, 16), 128>>>(p_Y2, p_S, 256);
    a1_apply_k<<<(TMN * 256 + 255) / 256, 256>>>(p_Y2, p_S, bs2, p_h2, 256);
    v1_k<<<(256 * 88 + 255) / 256, 256>>>(p_h2, p_xh, p_V1, p_V1t, p_Vx);

    // ---- dynamic cross-track graph ----
    rbgemm_k<<<dim3((88 + 63) / 64, 256 / 64), 256>>>(wg, p_Vx, bg, p_G, 256, 88, 256, 1);
    rbgemm_k<<<dim3((88 + 63) / 64, 256 / 64), 256>>>(wh, p_Vx, bh, p_Hh, 256, 88, 256, 1);
    attn_k<<<88, 128>>>(p_G, p_Hh, p_A2);

    // ---- ct GCN ----
    rbgemm_k<<<dim3(384 / 64, (88 + 63) / 64), 256>>>(p_V1t, wc1, nullptr, p_xw, 88, 384, 256, 0);
    rbgemm_k<<<dim3(384 / 64, (88 + 63) / 64), 256>>>(p_A2, p_xw, bc1, p_c1m, 88, 384, 88, 2 | 4);
    rbgemm_k<<<dim3(256 / 64, (88 + 63) / 64), 256>>>(p_c1m, wc2, nullptr, p_cw, 88, 256, 384, 0);
    rbgemm_k<<<dim3(256 / 64, (88 + 63) / 64), 256>>>(p_A2, p_cw, bc2, p_V2t, 88, 256, 88, 2 | 4);

    // ---- final correlation ----
    final_dot_k<<<1, 256>>>(Xf, p_V2t, (float*)d_out);
}

// round 14
// speedup vs baseline: 1.3108x; 1.0085x over previous
#include <cuda_runtime.h>
#include <cuda_bf16.h>
#include <cstdint>
#include <math.h>

// ---------------- dimensions ----------------
#define N_IMG 17
#define H0 383
#define W0 287
#define H0P 387
#define W0P 291
#define C1o 64
#define H1 95
#define W1 71
#define P1H 47
#define P1W 35
#define P1HP 51
#define P1WP 39
#define C2o 192
#define H2 47
#define W2 35
#define P2H 23
#define P2W 17
#define P2HP 25
#define P2WP 19
#define C3o 384
#define C4o 256
#define C5o 256
#define H5 23
#define W5 17
#define P5H 11
#define P5W 8
#define MM 88
#define TT 16
#define TMN 1408
#define TAILPAD 4096

// ---------------- scratch (device globals; no allocation) ----------------
__device__ float g_in [N_IMG*3*H0P*W0P + TAILPAD];
__device__ float g_c1 [N_IMG*C1o*H1*W1];
__device__ float g_p1 [N_IMG*C1o*P1HP*P1WP + TAILPAD];
__device__ float g_c2 [N_IMG*C2o*H2*W2];
__device__ float g_p2 [N_IMG*C2o*P2HP*P2WP + TAILPAD];
__device__ float g_c3 [N_IMG*C3o*P2HP*P2WP + TAILPAD];
__device__ float g_c4 [N_IMG*C4o*P2HP*P2WP + TAILPAD];
__device__ float g_c5 [N_IMG*C5o*H5*W5];
__device__ float g_p5 [N_IMG*C5o*MM];
__device__ float g_xc [256*88];
__device__ float g_v  [256];
__device__ float g_xhat[256*88];
__device__ float g_Y1 [TMN*512];
__device__ float g_S  [16*512];
__device__ float g_Y2 [TMN*256];
__device__ float g_h2 [TMN*256];
__device__ float g_V1 [256*88];
__device__ float g_V1t[88*256];
__device__ float g_Vx [256*88];
__device__ float g_G  [256*88];
__device__ float g_Hh [256*88];
__device__ float g_A2 [88*88];
__device__ float g_xw [88*384];
__device__ float g_c1m[88*384];
__device__ float g_cw [88*256];
__device__ float g_V2t[88*256];

// bf16 split matrices for tensor-core GEMMs (also reused as NHWC maps / GCN operands)
__device__ __nv_bfloat16 g_Ahi[384*3456];
__device__ __nv_bfloat16 g_Alo[384*3456];
__device__ __nv_bfloat16 g_Bhi[44800000];
__device__ __nv_bfloat16 g_Blo[44800000];

// ---------------- mma / cp.async helpers (baseline PTX, sm_80+) ----------------
__device__ __forceinline__ uint32_t smem_u32(const void* p)
{
    uint32_t a;
    asm("{ .reg .u64 t; cvta.to.shared.u64 t, %1; cvt.u32.u64 %0, t; }" : "=r"(a) : "l"(p));
    return a;
}
__device__ __forceinline__ void ldsm_x4(uint32_t& r0, uint32_t& r1, uint32_t& r2, uint32_t& r3,
                                        uint32_t addr)
{
    asm volatile("ldmatrix.sync.aligned.m8n8.x4.shared.b16 {%0,%1,%2,%3}, [%4];"
                 : "=r"(r0), "=r"(r1), "=r"(r2), "=r"(r3) : "r"(addr));
}
__device__ __forceinline__ void mma16816(float* d, const uint32_t* a, uint32_t b0, uint32_t b1)
{
    asm volatile("mma.sync.aligned.m16n8k16.row.col.f32.bf16.bf16.f32 "
                 "{%0,%1,%2,%3}, {%4,%5,%6,%7}, {%8,%9}, {%0,%1,%2,%3};"
                 : "+f"(d[0]), "+f"(d[1]), "+f"(d[2]), "+f"(d[3])
                 : "r"(a[0]), "r"(a[1]), "r"(a[2]), "r"(a[3]), "r"(b0), "r"(b1));
}
__device__ __forceinline__ void cp16(uint32_t dst, const void* src, bool pred)
{
    int sz = pred ? 16 : 0;
    asm volatile("cp.async.cg.shared.global [%0], [%1], 16, %2;"
                 :: "r"(dst), "l"(src), "r"(sz));
}
#define CP_COMMIT() asm volatile("cp.async.commit_group;" ::: "memory")
#define CP_WAIT(n)  asm volatile("cp.async.wait_group %0;" :: "n"(n) : "memory")

__device__ __forceinline__ void bsplit(float x, __nv_bfloat16& h, __nv_bfloat16& l)
{
    h = __float2bfloat16_rn(x);
    l = __float2bfloat16_rn(x - __bfloat162float(h));
}

// ---------------- prep kernels ----------------
__global__ void wsplit_pad_k(const float* __restrict__ w, __nv_bfloat16* __restrict__ hi,
                             __nv_bfloat16* __restrict__ lo, int M, int Kreal, int KPAD)
{
    int i = blockIdx.x * blockDim.x + threadIdx.x;
    if (i >= M * KPAD) return;
    int m = i / KPAD, k = i - m * KPAD;
    float x = (k < Kreal) ? w[(size_t)m * Kreal + k] : 0.f;
    bsplit(x, hi[i], lo[i]);
}

__global__ void wsplit_reorder_k(const float* __restrict__ w, __nv_bfloat16* __restrict__ hi,
                                 __nv_bfloat16* __restrict__ lo, int M, int CIN, int KK)
{
    int K = CIN * KK;
    int i = blockIdx.x * blockDim.x + threadIdx.x;
    if (i >= M * K) return;
    int m = i / K, kidx = i - m * K;
    int pos = kidx / CIN, ci = kidx - pos * CIN;
    bsplit(w[((size_t)m * CIN + ci) * KK + pos], hi[i], lo[i]);
}

__global__ void wsplitT_k(const float* __restrict__ w, __nv_bfloat16* __restrict__ hi,
                          __nv_bfloat16* __restrict__ lo, int M, int K)
{
    int i = blockIdx.x * blockDim.x + threadIdx.x;
    if (i >= M * K) return;
    int m = i / K, k = i - m * K;
    bsplit(w[(size_t)k * M + m], hi[i], lo[i]);
}

__global__ void gather_nodes_split_k(const float* __restrict__ p5,
                                     __nv_bfloat16* __restrict__ hi, __nv_bfloat16* __restrict__ lo)
{
    int idx = blockIdx.x * blockDim.x + threadIdx.x;
    if (idx >= TMN * 256) return;
    int d = idx % 256;
    int n = idx / 256;
    int t = n % 16, m = n / 16;
    bsplit(p5[((size_t)t * 256 + d) * 88 + m], hi[idx], lo[idx]);
}

__global__ void nchw2nhwc_k(const float* __restrict__ in,
                            __nv_bfloat16* __restrict__ hi, __nv_bfloat16* __restrict__ lo,
                            int C, int NPIX)
{
    __shared__ float t[32][33];
    int img = blockIdx.z;
    int p0 = blockIdx.x * 32, c0 = blockIdx.y * 32;
    int tx = threadIdx.x, ty = threadIdx.y;
    const float* src = in + (size_t)img * C * NPIX;
    #pragma unroll
    for (int i = 0; i < 4; i++) {
        int c = c0 + ty + i * 8, p = p0 + tx;
        if (p < NPIX) t[ty + i * 8][tx] = src[(size_t)c * NPIX + p];
    }
    __syncthreads();
    #pragma unroll
    for (int i = 0; i < 4; i++) {
        int p = p0 + ty + i * 8, c = c0 + tx;
        if (p < NPIX) {
            size_t o = ((size_t)img * NPIX + p) * C + c;
            bsplit(t[tx][ty + i * 8], hi[o], lo[o]);
        }
    }
}

template<int CIN, int KD, int S, int HinP, int WinP, int Hout, int Wout, int KPAD>
__global__ void im2col_v8_t(const float* __restrict__ in,
                            __nv_bfloat16* __restrict__ bhi, __nv_bfloat16* __restrict__ blo)
{
    constexpr int KK = KD * KD;
    constexpr int KREAL = CIN * KK;
    constexpr int HW = Hout * Wout;
    constexpr int NPIX = N_IMG * HW;
    constexpr int KQ = KPAD / 8;
    int idx = blockIdx.x * blockDim.x + threadIdx.x;
    if (idx >= NPIX * KQ) return;
    int p  = idx / KQ;
    int k0 = (idx - p * KQ) * 8;
    int img = p / HW;
    int rr  = p - img * HW;
    int oh  = rr / Wout;
    int ow  = rr - oh * Wout;
    const float* base = in + ((size_t)img * CIN * HinP + oh * S) * WinP + ow * S;

    __nv_bfloat16 hv[8], lv[8];
    #pragma unroll
    for (int j = 0; j < 8; j++) {
        int k = k0 + j;
        float x = 0.f;
        if (k < KREAL) {
            int ci = k / KK;
            int r  = k - ci * KK;
            int kh = r / KD;
            int kw = r - kh * KD;
            x = base[((size_t)ci * HinP + kh) * WinP + kw];
        }
        bsplit(x, hv[j], lv[j]);
    }
    size_t o = (size_t)p * KPAD + k0;
    *(uint4*)(bhi + o) = *(const uint4*)hv;
    *(uint4*)(blo + o) = *(const uint4*)lv;
}

// ---------------- fused-segment tensor-core GEMMs ----------------
#define ASTR 72

// -------- explicit-B GEMM, 64(M) x 128(N) — conv1, XOR-swizzled, 2 blocks/SM --------
#define A1R_SZ 8192         // 64 rows x 128 B (one of hi/lo)
#define B1R_SZ 16384        // 128 rows x 128 B
#define ST1_SZ (2 * A1R_SZ + 2 * B1R_SZ)   // 49152
#define SMEM_G1 (2 * ST1_SZ)               // 98304
__global__ void __launch_bounds__(256, 2)
mmaconv64_k(const __nv_bfloat16* __restrict__ Ahi, const __nv_bfloat16* __restrict__ Alo,
            const __nv_bfloat16* __restrict__ Bhi, const __nv_bfloat16* __restrict__ Blo,
            const float* __restrict__ bias, float* __restrict__ out,
            int M, int Npix, int K, int Hout, int Wout,
            int HoP, int WoP, int opad)
{
    extern __shared__ char smem[];
    uint32_t sb = smem_u32(smem);
    uint32_t stg[2] = { sb, sb + ST1_SZ };

    int tid  = threadIdx.x;
    int lane = tid & 31;
    int wid  = tid >> 5;
    int wm   = wid & 1;
    int wn   = wid >> 1;

    int m0 = 0;
    int n0 = blockIdx.x * 128;

    float d[2][4][4];
    #pragma unroll
    for (int i = 0; i < 2; i++)
        #pragma unroll
        for (int j = 0; j < 4; j++)
            #pragma unroll
            for (int r = 0; r < 4; r++) d[i][j][r] = 0.f;

    int aj = lane >> 3, ar = lane & 7;
    uint32_t aRowOff[2], bRowOff[2];
    #pragma unroll
    for (int mi = 0; mi < 2; mi++)
        aRowOff[mi] = (uint32_t)((wm * 32 + mi * 16 + (aj & 1) * 8 + ar) * 128);
    #pragma unroll
    for (int q = 0; q < 2; q++)
        bRowOff[q] = (uint32_t)((wn * 32 + q * 16 + (aj >> 1) * 8 + ar) * 128);
    int aColBase = aj >> 1;
    int bColBase = aj & 1;

    int itK = K >> 6;

    int arow[2], aq[2];
    #pragma unroll
    for (int j = 0; j < 2; j++) { int i = tid + j * 256; arow[j] = i >> 3; aq[j] = i & 7; }
    int brow[4], bq[4];
    #pragma unroll
    for (int j = 0; j < 4; j++) { int i = tid + j * 256; brow[j] = i >> 3; bq[j] = i & 7; }

    auto load_stage = [&](int st, int it) {
        int kof = it << 6;
        uint32_t s = stg[st];
        #pragma unroll
        for (int j = 0; j < 2; j++) {
            size_t go = (size_t)(m0 + arow[j]) * K + kof + aq[j] * 8;
            uint32_t so = (uint32_t)(arow[j] * 128 + ((aq[j] ^ (arow[j] & 7)) * 16));
            bool pr = m0 + arow[j] < M;
            cp16(s + so, Ahi + go, pr);
            cp16(s + A1R_SZ + so, Alo + go, pr);
        }
        #pragma unroll
        for (int j = 0; j < 4; j++) {
            size_t go = (size_t)(n0 + brow[j]) * K + kof + bq[j] * 8;
            uint32_t so = (uint32_t)(brow[j] * 128 + ((bq[j] ^ (brow[j] & 7)) * 16));
            bool pr = n0 + brow[j] < Npix;
            cp16(s + 2 * A1R_SZ + so, Bhi + go, pr);
            cp16(s + 2 * A1R_SZ + B1R_SZ + so, Blo + go, pr);
        }
        CP_COMMIT();
    };

    load_stage(0, 0);

    for (int it = 0; it < itK; it++) {
        int st = it & 1;
        if (it + 1 < itK) { load_stage(st ^ 1, it + 1); CP_WAIT(1); }
        else              { CP_WAIT(0); }
        __syncthreads();
        uint32_t s = stg[st];

        #pragma unroll
        for (int kk = 0; kk < 4; kk++) {
            uint32_t aCol = (uint32_t)(((kk * 2 + aColBase) ^ ar) * 16);
            uint32_t bCol = (uint32_t)(((kk * 2 + bColBase) ^ ar) * 16);
            uint32_t ah[2][4], al[2][4];
            #pragma unroll
            for (int mi = 0; mi < 2; mi++) {
                uint32_t ad = s + aRowOff[mi] + aCol;
                ldsm_x4(ah[mi][0], ah[mi][1], ah[mi][2], ah[mi][3], ad);
                ldsm_x4(al[mi][0], al[mi][1], al[mi][2], al[mi][3], ad + A1R_SZ);
            }
            uint32_t bh[4][2], bl[4][2];
            #pragma unroll
            for (int q = 0; q < 2; q++) {
                uint32_t bd = s + 2 * A1R_SZ + bRowOff[q] + bCol;
                uint32_t r0, r1, r2, r3;
                ldsm_x4(r0, r1, r2, r3, bd);
                bh[q * 2][0] = r0; bh[q * 2][1] = r1;
                bh[q * 2 + 1][0] = r2; bh[q * 2 + 1][1] = r3;
                ldsm_x4(r0, r1, r2, r3, bd + B1R_SZ);
                bl[q * 2][0] = r0; bl[q * 2][1] = r1;
                bl[q * 2 + 1][0] = r2; bl[q * 2 + 1][1] = r3;
            }
            #pragma unroll
            for (int mi = 0; mi < 2; mi++)
                #pragma unroll
                for (int nj = 0; nj < 4; nj++) {
                    mma16816(d[mi][nj], ah[mi], bh[nj][0], bh[nj][1]);
                    mma16816(d[mi][nj], ah[mi], bl[nj][0], bl[nj][1]);
                    mma16816(d[mi][nj], al[mi], bh[nj][0], bh[nj][1]);
                }
        }
        __syncthreads();
    }

    int HW = Hout * Wout;
    #pragma unroll
    for (int mi = 0; mi < 2; mi++) {
        #pragma unroll
        for (int r2 = 0; r2 < 2; r2++) {
            int co = m0 + wm * 32 + mi * 16 + (lane >> 2) + r2 * 8;
            if (co >= M) continue;
            float bv = bias[co];
            #pragma unroll
            for (int nj = 0; nj < 4; nj++) {
                #pragma unroll
                for (int c = 0; c < 2; c++) {
                    int p = n0 + wn * 32 + nj * 8 + (lane & 3) * 2 + c;
                    if (p >= Npix) continue;
                    float v = d[mi][nj][r2 * 2 + c] + bv;
                    int img = p / HW;
                    int rr  = p - img * HW;
                    int oh  = rr / Wout;
                    int ow  = rr - oh * Wout;
                    out[((size_t)(img * M + co) * HoP + oh + opad) * WoP + ow + opad]
                        = fmaxf(v, 0.f);
                }
            }
        }
    }
}

// -------- implicit-B GEMM, 128(M) x 64(N), XOR-swizzled 128B rows, 2 blocks/SM --------
#define AR3_SZ 16384        // 128 rows x 128 B (one of hi/lo)
#define BR3_SZ 8192         // 64 rows x 128 B
#define ST3_SZ (2 * AR3_SZ + 2 * BR3_SZ)   // 49152
#define SMEM_G3 (2 * ST3_SZ)               // 98304
__global__ void __launch_bounds__(256, 2)
mmaconv_imp_k(const __nv_bfloat16* __restrict__ Ahi, const __nv_bfloat16* __restrict__ Alo,
              const __nv_bfloat16* __restrict__ Xhi, const __nv_bfloat16* __restrict__ Xlo,
              const float* __restrict__ bias, float* __restrict__ out,
              int M, int Npix, int K, int CIN, int KD,
              int HinP, int WinP, int Hout, int Wout,
              int HoP, int WoP, int opad)
{
    extern __shared__ char smem[];
    uint32_t sb = smem_u32(smem);
    uint32_t stg[2] = { sb, sb + ST3_SZ };

    int tid  = threadIdx.x;
    int lane = tid & 31;
    int wid  = tid >> 5;
    int wm   = wid & 3;
    int wn   = wid >> 2;

    int m0 = blockIdx.y * 128;
    int n0 = blockIdx.x * 64;

    float d[2][4][4];
    #pragma unroll
    for (int i = 0; i < 2; i++)
        #pragma unroll
        for (int j = 0; j < 4; j++)
            #pragma unroll
            for (int r = 0; r < 4; r++) d[i][j][r] = 0.f;

    int aj = lane >> 3, ar = lane & 7;
    uint32_t aRowOff[2], bRowOff[2];
    #pragma unroll
    for (int mi = 0; mi < 2; mi++)
        aRowOff[mi] = (uint32_t)((wm * 32 + mi * 16 + (aj & 1) * 8 + ar) * 128);
    #pragma unroll
    for (int q = 0; q < 2; q++)
        bRowOff[q] = (uint32_t)((wn * 32 + q * 16 + (aj >> 1) * 8 + ar) * 128);
    int aColBase = aj >> 1;
    int bColBase = aj & 1;

    int itK = K >> 6;
    int cPer = CIN >> 6;
    int HW = Hout * Wout;

    int arow[4], aq[4];
    #pragma unroll
    for (int j = 0; j < 4; j++) { int i = tid + j * 256; arow[j] = i >> 3; aq[j] = i & 7; }
    int brow[2], bq[2];
    long bbase[2];
    bool bval[2];
    #pragma unroll
    for (int j = 0; j < 2; j++) {
        int i = tid + j * 256;
        brow[j] = i >> 3; bq[j] = i & 7;
        int p = n0 + brow[j];
        bval[j] = p < Npix;
        if (!bval[j]) p = 0;
        int img = p / HW;
        int rr  = p - img * HW;
        int oh  = rr / Wout;
        int ow  = rr - oh * Wout;
        bbase[j] = ((long)(img * HinP + oh) * WinP + ow) * CIN;
    }

    auto load_stage = [&](int st, int it) {
        int pos = it / cPer;
        int cioff = (it - pos * cPer) << 6;
        int kh = pos / KD, kw = pos - kh * KD;
        int kofA = it << 6;
        long boff = (long)(kh * WinP + kw) * CIN + cioff;
        uint32_t s = stg[st];
        #pragma unroll
        for (int j = 0; j < 4; j++) {
            size_t go = (size_t)(m0 + arow[j]) * K + kofA + aq[j] * 8;
            uint32_t so = (uint32_t)(arow[j] * 128 + ((aq[j] ^ (arow[j] & 7)) * 16));
            bool pr = m0 + arow[j] < M;
            cp16(s + so, Ahi + go, pr);
            cp16(s + AR3_SZ + so, Alo + go, pr);
        }
        #pragma unroll
        for (int j = 0; j < 2; j++) {
            long go = bbase[j] + boff + bq[j] * 8;
            uint32_t so = (uint32_t)(brow[j] * 128 + ((bq[j] ^ (brow[j] & 7)) * 16));
            cp16(s + 2 * AR3_SZ + so, Xhi + go, bval[j]);
            cp16(s + 2 * AR3_SZ + BR3_SZ + so, Xlo + go, bval[j]);
        }
        CP_COMMIT();
    };

    load_stage(0, 0);

    for (int it = 0; it < itK; it++) {
        int st = it & 1;
        if (it + 1 < itK) { load_stage(st ^ 1, it + 1); CP_WAIT(1); }
        else              { CP_WAIT(0); }
        __syncthreads();
        uint32_t s = stg[st];

        #pragma unroll
        for (int kk = 0; kk < 4; kk++) {
            uint32_t aCol = (uint32_t)(((kk * 2 + aColBase) ^ ar) * 16);
            uint32_t bCol = (uint32_t)(((kk * 2 + bColBase) ^ ar) * 16);
            uint32_t ah[2][4], al[2][4];
            #pragma unroll
            for (int mi = 0; mi < 2; mi++) {
                uint32_t ad = s + aRowOff[mi] + aCol;
                ldsm_x4(ah[mi][0], ah[mi][1], ah[mi][2], ah[mi][3], ad);
                ldsm_x4(al[mi][0], al[mi][1], al[mi][2], al[mi][3], ad + AR3_SZ);
            }
            uint32_t bh[4][2], bl[4][2];
            #pragma unroll
            for (int q = 0; q < 2; q++) {
                uint32_t bd = s + 2 * AR3_SZ + bRowOff[q] + bCol;
                uint32_t r0, r1, r2, r3;
                ldsm_x4(r0, r1, r2, r3, bd);
                bh[q * 2][0] = r0; bh[q * 2][1] = r1;
                bh[q * 2 + 1][0] = r2; bh[q * 2 + 1][1] = r3;
                ldsm_x4(r0, r1, r2, r3, bd + BR3_SZ);
                bl[q * 2][0] = r0; bl[q * 2][1] = r1;
                bl[q * 2 + 1][0] = r2; bl[q * 2 + 1][1] = r3;
            }
            #pragma unroll
            for (int mi = 0; mi < 2; mi++)
                #pragma unroll
                for (int nj = 0; nj < 4; nj++) {
                    mma16816(d[mi][nj], ah[mi], bh[nj][0], bh[nj][1]);
                    mma16816(d[mi][nj], ah[mi], bl[nj][0], bl[nj][1]);
                    mma16816(d[mi][nj], al[mi], bh[nj][0], bh[nj][1]);
                }
        }
        __syncthreads();
    }

    #pragma unroll
    for (int mi = 0; mi < 2; mi++) {
        #pragma unroll
        for (int r2 = 0; r2 < 2; r2++) {
            int co = m0 + wm * 32 + mi * 16 + (lane >> 2) + r2 * 8;
            if (co >= M) continue;
            float bv = bias[co];
            #pragma unroll
            for (int nj = 0; nj < 4; nj++) {
                #pragma unroll
                for (int c = 0; c < 2; c++) {
                    int p = n0 + wn * 32 + nj * 8 + (lane & 3) * 2 + c;
                    if (p >= Npix) continue;
                    float v = d[mi][nj][r2 * 2 + c] + bv;
                    int img = p / HW;
                    int rr  = p - img * HW;
                    int oh  = rr / Wout;
                    int ow  = rr - oh * Wout;
                    out[((size_t)(img * M + co) * HoP + oh + opad) * WoP + ow + opad]
                        = fmaxf(v, 0.f);
                }
            }
        }
    }
}

// -------- generic explicit GEMM, 128(M) x 64(N), transposed output C[n,m] --------
#define A2_SZ (128 * ASTR * 2)
#define B2_SZ (64 * ASTR * 2)
#define ST2_SZ (2 * A2_SZ + 2 * B2_SZ)
#define SMEM_G2 (2 * ST2_SZ)
__global__ void __launch_bounds__(256)
mmagemm_k(const __nv_bfloat16* __restrict__ Ahi, const __nv_bfloat16* __restrict__ Alo,
          const __nv_bfloat16* __restrict__ Bhi, const __nv_bfloat16* __restrict__ Blo,
          float* __restrict__ out, int M, int N, int K)
{
    extern __shared__ char smem[];
    uint32_t sb = smem_u32(smem);
    uint32_t stg[2] = { sb, sb + ST2_SZ };

    int tid  = threadIdx.x;
    int lane = tid & 31;
    int wid  = tid >> 5;
    int wm   = wid & 3;
    int wn   = wid >> 2;

    int m0 = blockIdx.y * 128;
    int n0 = blockIdx.x * 64;

    float d[2][4][4];
    #pragma unroll
    for (int i = 0; i < 2; i++)
        #pragma unroll
        for (int j = 0; j < 4; j++)
            #pragma unroll
            for (int r = 0; r < 4; r++) d[i][j][r] = 0.f;

    int aj = lane >> 3, ar = lane & 7;
    uint32_t aAddrOff = (uint32_t)(((aj & 1) * 8 + ar) * ASTR + (aj >> 1) * 8) * 2;
    uint32_t bAddrOff = (uint32_t)(((aj >> 1) * 8 + ar) * ASTR + (aj & 1) * 8) * 2;

    int itK = K >> 6;

    int arow[4], aq[4];
    #pragma unroll
    for (int j = 0; j < 4; j++) { int i = tid + j * 256; arow[j] = i >> 3; aq[j] = i & 7; }
    int brow[2], bq[2];
    #pragma unroll
    for (int j = 0; j < 2; j++) { int i = tid + j * 256; brow[j] = i >> 3; bq[j] = i & 7; }

    auto load_stage = [&](int st, int it) {
        int kof = it << 6;
        uint32_t s = stg[st];
        #pragma unroll
        for (int j = 0; j < 4; j++) {
            size_t go = (size_t)(m0 + arow[j]) * K + kof + aq[j] * 8;
            uint32_t so = (uint32_t)(arow[j] * ASTR + aq[j] * 8) * 2;
            bool pr = m0 + arow[j] < M;
            cp16(s + so, Ahi + go, pr);
            cp16(s + A2_SZ + so, Alo + go, pr);
        }
        #pragma unroll
        for (int j = 0; j < 2; j++) {
            size_t go = (size_t)(n0 + brow[j]) * K + kof + bq[j] * 8;
            uint32_t so = (uint32_t)(brow[j] * ASTR + bq[j] * 8) * 2;
            bool pr = n0 + brow[j] < N;
            cp16(s + 2 * A2_SZ + so, Bhi + go, pr);
            cp16(s + 2 * A2_SZ + B2_SZ + so, Blo + go, pr);
        }
        CP_COMMIT();
    };

    load_stage(0, 0);

    for (int it = 0; it < itK; it++) {
        int st = it & 1;
        if (it + 1 < itK) { load_stage(st ^ 1, it + 1); CP_WAIT(1); }
        else              { CP_WAIT(0); }
        __syncthreads();
        uint32_t s = stg[st];

        #pragma unroll
        for (int kk = 0; kk < 4; kk++) {
            uint32_t ah[2][4], al[2][4];
            #pragma unroll
            for (int mi = 0; mi < 2; mi++) {
                uint32_t off = aAddrOff + (uint32_t)((wm * 32 + mi * 16) * ASTR + kk * 16) * 2;
                ldsm_x4(ah[mi][0], ah[mi][1], ah[mi][2], ah[mi][3], s + off);
                ldsm_x4(al[mi][0], al[mi][1], al[mi][2], al[mi][3], s + A2_SZ + off);
            }
            uint32_t bh[4][2], bl[4][2];
            #pragma unroll
            for (int q = 0; q < 2; q++) {
                uint32_t off = bAddrOff + (uint32_t)((wn * 32 + q * 16) * ASTR + kk * 16) * 2;
                uint32_t r0, r1, r2, r3;
                ldsm_x4(r0, r1, r2, r3, s + 2 * A2_SZ + off);
                bh[q * 2][0] = r0; bh[q * 2][1] = r1;
                bh[q * 2 + 1][0] = r2; bh[q * 2 + 1][1] = r3;
                ldsm_x4(r0, r1, r2, r3, s + 2 * A2_SZ + B2_SZ + off);
                bl[q * 2][0] = r0; bl[q * 2][1] = r1;
                bl[q * 2 + 1][0] = r2; bl[q * 2 + 1][1] = r3;
            }
            #pragma unroll
            for (int mi = 0; mi < 2; mi++)
                #pragma unroll
                for (int nj = 0; nj < 4; nj++) {
                    mma16816(d[mi][nj], ah[mi], bh[nj][0], bh[nj][1]);
                    mma16816(d[mi][nj], ah[mi], bl[nj][0], bl[nj][1]);
                    mma16816(d[mi][nj], al[mi], bh[nj][0], bh[nj][1]);
                }
        }
        __syncthreads();
    }

    #pragma unroll
    for (int mi = 0; mi < 2; mi++) {
        #pragma unroll
        for (int r2 = 0; r2 < 2; r2++) {
            int co = m0 + wm * 32 + mi * 16 + (lane >> 2) + r2 * 8;
            if (co >= M) continue;
            #pragma unroll
            for (int nj = 0; nj < 4; nj++) {
                #pragma unroll
                for (int c = 0; c < 2; c++) {
                    int p = n0 + wn * 32 + nj * 8 + (lane & 3) * 2 + c;
                    if (p >= N) continue;
                    out[(size_t)p * M + co] = d[mi][nj][r2 * 2 + c];
                }
            }
        }
    }
}

// ---------------- scalar kernels (rest of network) ----------------

__global__ void pad_copy_k(const float* __restrict__ src, float* __restrict__ dst,
                           int nimg, int boff)
{
    int idx = blockIdx.x * blockDim.x + threadIdx.x;
    int total = nimg * 3 * H0 * W0;
    if (idx >= total) return;
    int w = idx % W0; int t = idx / W0;
    int h = t % H0;   t /= H0;
    int c = t % 3;    int n = t / 3;
    dst[(((size_t)(boff + n) * 3 + c) * H0P + h + 2) * W0P + (w + 2)] = src[idx];
}

__global__ void maxpool_k(const float* __restrict__ in, float* __restrict__ out,
                          int NC, int Hin, int Win, int Ho, int Wo,
                          int HoP, int WoP, int opad)
{
    int idx = blockIdx.x * blockDim.x + threadIdx.x;
    int total = NC * Ho * Wo;
    if (idx >= total) return;
    int ow = idx % Wo; int t = idx / Wo;
    int oh = t % Ho;   int nc = t / Ho;
    const float* ip = in + ((size_t)nc * Hin + oh * 2) * Win + ow * 2;
    float m = -INFINITY;
    #pragma unroll
    for (int kh = 0; kh < 3; kh++)
        #pragma unroll
        for (int kw = 0; kw < 3; kw++)
            m = fmaxf(m, ip[kh * Win + kw]);
    out[((size_t)nc * HoP + oh + opad) * WoP + ow + opad] = m;
}

__global__ void cd_conv_k(const float* __restrict__ Xf, const float* __restrict__ wcd,
                          const float* __restrict__ bcd, float* __restrict__ xc)
{
    int p = blockIdx.x;
    int o = threadIdx.x;
    float acc = bcd[o];
    for (int i = 0; i < 256; i++) {
        const float* wr = wcd + (o * 256 + i) * 3;
        const float* xr = Xf + i * 88;
        if (p > 0)  acc += xr[p - 1] * wr[0];
        acc += xr[p] * wr[1];
        if (p < 87) acc += xr[p + 1] * wr[2];
    }
    xc[o * 88 + p] = acc;
}

__global__ void cd_max_k(const float* __restrict__ xc, float* __restrict__ v)
{
    int o = threadIdx.x;
    float m = -INFINITY;
    for (int p = 0; p < 88; p++) m = fmaxf(m, xc[o * 88 + p]);
    v[o] = m;
}

__global__ void xhat_k(const float* __restrict__ v, const float* __restrict__ wt,
                       const float* __restrict__ bt, float* __restrict__ xhat)
{
    __shared__ float sv[256];
    int o = blockIdx.x;
    int k = threadIdx.x;
    for (int i = threadIdx.x; i < 256; i += blockDim.x) sv[i] = v[i];
    __syncthreads();
    float acc = bt[o];
    for (int i = 0; i < 256; i++)
        acc += sv[i] * wt[((size_t)i * 256 + o) * 88 + k];
    xhat[o * 88 + k] = acc;
}

__global__ __launch_bounds__(256)
void rbgemm_k(const float* __restrict__ A, const float* __restrict__ B,
              const float* __restrict__ bias, float* __restrict__ C,
              int M, int N, int K, int flags)
{
    __shared__ float As[16][65];
    __shared__ float Bs[16][64];
    int tid = threadIdx.x;
    int tx = tid & 15;
    int ty = tid >> 4;
    int m0 = blockIdx.y * 64;
    int n0 = blockIdx.x * 64;

    float acc[4][4] = {};

    for (int k0 = 0; k0 < K; k0 += 16) {
        #pragma unroll
        for (int i = 0; i < 4; i++) {
            int e  = tid + i * 256;
            int kk = e & 15;
            int mm = e >> 4;
            int gm = m0 + mm, gk = k0 + kk;
            As[kk][mm] = (gm < M && gk < K) ? A[(size_t)gm * K + gk] : 0.f;
        }
        #pragma unroll
        for (int i = 0; i < 4; i++) {
            int nn = tid & 63;
            int kk = (tid >> 6) + i * 4;
            int gk = k0 + kk, gn = n0 + nn;
            Bs[kk][nn] = (gk < K && gn < N) ? B[(size_t)gk * N + gn] : 0.f;
        }
        __syncthreads();
        #pragma unroll
        for (int kk = 0; kk < 16; kk++) {
            float ra[4], rb[4];
            #pragma unroll
            for (int i = 0; i < 4; i++) ra[i] = As[kk][ty * 4 + i];
            #pragma unroll
            for (int j = 0; j < 4; j++) rb[j] = Bs[kk][tx * 4 + j];
            #pragma unroll
            for (int i = 0; i < 4; i++)
                #pragma unroll
                for (int j = 0; j < 4; j++)
                    acc[i][j] += ra[i] * rb[j];
        }
        __syncthreads();
    }

    #pragma unroll
    for (int i = 0; i < 4; i++) {
        int gm = m0 + ty * 4 + i;
        if (gm >= M) continue;
        #pragma unroll
        for (int j = 0; j < 4; j++) {
            int gn = n0 + tx * 4 + j;
            if (gn >= N) continue;
            float v = acc[i][j];
            if (flags & 1) v += bias[gm];
            if (flags & 2) v += bias[gn];
            if (flags & 4) v = v >= 0.f ? v : 0.01f * v;
            C[(size_t)gm * N + gn] = v;
        }
    }
}

__global__ void a1_reduce_k(const float* __restrict__ Y, float* __restrict__ S, int F)
{
    int f = blockIdx.x * blockDim.x + threadIdx.x;
    int t = blockIdx.y;
    if (f >= F) return;
    float s = 0.f;
    for (int m = 0; m < 88; m++) s += Y[(size_t)(m * 16 + t) * F + f];
    S[t * F + f] = s;
}

__global__ void a1_apply_split_k(const float* __restrict__ Y, const float* __restrict__ S,
                                 const float* __restrict__ bias,
                                 __nv_bfloat16* __restrict__ hi, __nv_bfloat16* __restrict__ lo,
                                 int F)
{
    int idx = blockIdx.x * blockDim.x + threadIdx.x;
    if (idx >= TMN * F) return;
    int f = idx % F;
    int n = idx / F;
    int t = n % 16;
    float val = S[t * F + f] + bias[f];
    if (t == 0) val -= Y[idx];
    val = val >= 0.f ? val : 0.01f * val;
    bsplit(val, hi[idx], lo[idx]);
}

__global__ void a1_apply_k(const float* __restrict__ Y, const float* __restrict__ S,
                           const float* __restrict__ bias, float* __restrict__ h, int F)
{
    int idx = blockIdx.x * blockDim.x + threadIdx.x;
    if (idx >= TMN * F) return;
    int f = idx % F;
    int n = idx / F;
    int t = n % 16;
    float val = S[t * F + f] + bias[f];
    if (t == 0) val -= Y[idx];
    h[idx] = val >= 0.f ? val : 0.01f * val;
}

__global__ void v1_k(const float* __restrict__ h2, const float* __restrict__ xhat,
                     float* __restrict__ V1, float* __restrict__ V1t, float* __restrict__ Vx)
{
    int idx = blockIdx.x * blockDim.x + threadIdx.x;
    if (idx >= 256 * 88) return;
    int d = idx % 256;
    int m = idx / 256;
    float mx = -INFINITY;
    #pragma unroll
    for (int t = 0; t < 16; t++) mx = fmaxf(mx, h2[(size_t)(m * 16 + t) * 256 + d]);
    V1[d * 88 + m] = mx;
    V1t[m * 256 + d] = mx;
    Vx[d * 88 + m] = mx + xhat[d * 88 + m];
}

__global__ void attn_k(const float* __restrict__ G, const float* __restrict__ Hh,
                       float* __restrict__ A2)
{
    __shared__ float red[128];
    int j = blockIdx.x;
    int i = threadIdx.x;
    float s = 0.f;
    if (i < 88) {
        for (int d = 0; d < 256; d++) s += Hh[d * 88 + j] * G[d * 88 + i];
    }
    red[i] = (i < 88) ? s : -INFINITY;
    __syncthreads();
    for (int st = 64; st > 0; st >>= 1) {
        if (i < st) red[i] = fmaxf(red[i], red[i + st]);
        __syncthreads();
    }
    float mx = red[0];
    __syncthreads();
    float e = (i < 88) ? expf(s - mx) : 0.f;
    red[i] = e;
    __syncthreads();
    for (int st = 64; st > 0; st >>= 1) {
        if (i < st) red[i] += red[i + st];
        __syncthreads();
    }
    float sum = red[0];
    if (i < 88) A2[j * 88 + i] = e / sum;
}

__global__ void final_dot_k(const float* __restrict__ Xf, const float* __restrict__ V2t,
                            float* __restrict__ out)
{
    __shared__ float red[256];
    float acc = 0.f;
    for (int e = threadIdx.x; e < 256 * 88; e += 256) {
        int d = e / 88, m = e % 88;
        acc += Xf[e] * V2t[m * 256 + d];
    }
    red[threadIdx.x] = acc;
    __syncthreads();
    for (int st = 128; st > 0; st >>= 1) {
        if (threadIdx.x < st) red[threadIdx.x] += red[threadIdx.x + st];
        __syncthreads();
    }
    if (threadIdx.x == 0) out[0] = red[0];
}

// ---------------- host ----------------
static float* symaddr(const void* s)
{
    void* p = nullptr;
    cudaGetSymbolAddress(&p, s);
    return (float*)p;
}
static __nv_bfloat16* symaddr_bf(const void* s)
{
    void* p = nullptr;
    cudaGetSymbolAddress(&p, s);
    return (__nv_bfloat16*)p;
}

extern "C" void kernel_launch(void* const* d_in, const int* in_sizes, int n_in,
                              void* d_out, int out_size)
{
    const float* search    = (const float*)d_in[0];
    const float* exemplars = (const float*)d_in[1];
    const float* aw1 = (const float*)d_in[2];  const float* ab1 = (const float*)d_in[3];
    const float* aw2 = (const float*)d_in[4];  const float* ab2 = (const float*)d_in[5];
    const float* aw3 = (const float*)d_in[6];  const float* ab3 = (const float*)d_in[7];
    const float* aw4 = (const float*)d_in[8];  const float* ab4 = (const float*)d_in[9];
    const float* aw5 = (const float*)d_in[10]; const float* ab5 = (const float*)d_in[11];
    const float* wcd = (const float*)d_in[12]; const float* bcd = (const float*)d_in[13];
    const float* wt  = (const float*)d_in[14]; const float* bt  = (const float*)d_in[15];
    const float* ws1 = (const float*)d_in[16]; const float* bs1 = (const float*)d_in[17];
    const float* ws2 = (const float*)d_in[18]; const float* bs2 = (const float*)d_in[19];
    const float* wg  = (const float*)d_in[20]; const float* bg  = (const float*)d_in[21];
    const float* wh  = (const float*)d_in[22]; const float* bh  = (const float*)d_in[23];
    const float* wc1 = (const float*)d_in[24]; const float* bc1 = (const float*)d_in[25];
    const float* wc2 = (const float*)d_in[26]; const float* bc2 = (const float*)d_in[27];

    float* p_in  = symaddr(g_in);
    float* p_c1  = symaddr(g_c1);
    float* p_p1  = symaddr(g_p1);
    float* p_c2  = symaddr(g_c2);
    float* p_p2  = symaddr(g_p2);
    float* p_c3  = symaddr(g_c3);
    float* p_c4  = symaddr(g_c4);
    float* p_c5  = symaddr(g_c5);
    float* p_p5  = symaddr(g_p5);
    float* p_xc  = symaddr(g_xc);
    float* p_v   = symaddr(g_v);
    float* p_xh  = symaddr(g_xhat);
    float* p_Y1  = symaddr(g_Y1);
    float* p_S   = symaddr(g_S);
    float* p_Y2  = symaddr(g_Y2);
    float* p_h2  = symaddr(g_h2);
    float* p_V1  = symaddr(g_V1);
    float* p_V1t = symaddr(g_V1t);
    float* p_Vx  = symaddr(g_Vx);
    float* p_G   = symaddr(g_G);
    float* p_Hh  = symaddr(g_Hh);
    float* p_A2  = symaddr(g_A2);
    float* p_xw  = symaddr(g_xw);
    float* p_c1m = symaddr(g_c1m);
    float* p_cw  = symaddr(g_cw);
    float* p_V2t = symaddr(g_V2t);
    __nv_bfloat16* pAhi = symaddr_bf(g_Ahi);
    __nv_bfloat16* pAlo = symaddr_bf(g_Alo);
    __nv_bfloat16* pBhi = symaddr_bf(g_Bhi);
    __nv_bfloat16* pBlo = symaddr_bf(g_Blo);

    cudaFuncSetAttribute(mmaconv64_k, cudaFuncAttributeMaxDynamicSharedMemorySize, SMEM_G1);
    cudaFuncSetAttribute(mmaconv_imp_k, cudaFuncAttributeMaxDynamicSharedMemorySize, SMEM_G3);
    cudaFuncSetAttribute(mmagemm_k, cudaFuncAttributeMaxDynamicSharedMemorySize, SMEM_G2);

    // zero padded buffers (borders must be 0 every replay)
    cudaMemsetAsync(p_in, 0, sizeof(float) * ((size_t)N_IMG * 3 * H0P * W0P + TAILPAD), 0);
    cudaMemsetAsync(p_p1, 0, sizeof(float) * ((size_t)N_IMG * C1o * P1HP * P1WP + TAILPAD), 0);
    cudaMemsetAsync(p_p2, 0, sizeof(float) * ((size_t)N_IMG * C2o * P2HP * P2WP + TAILPAD), 0);
    cudaMemsetAsync(p_c3, 0, sizeof(float) * ((size_t)N_IMG * C3o * P2HP * P2WP + TAILPAD), 0);
    cudaMemsetAsync(p_c4, 0, sizeof(float) * ((size_t)N_IMG * C4o * P2HP * P2WP + TAILPAD), 0);

    // assemble padded input batch
    {
        int tot = 16 * 3 * H0 * W0;
        pad_copy_k<<<(tot + 127) / 128, 128>>>(exemplars, p_in, 16, 0);
        tot = 3 * H0 * W0;
        pad_copy_k<<<(tot + 127) / 128, 128>>>(search, p_in, 1, 16);
    }

    // ---- conv1 (vectorized im2col, swizzled 64x128 GEMM): M=64, K=384(pad) ----
    {
        const int KP = 384, NP = N_IMG * H1 * W1;
        wsplit_pad_k<<<(C1o * KP + 255) / 256, 256>>>(aw1, pAhi, pAlo, C1o, 363, KP);
        int tot = NP * (KP / 8);
        im2col_v8_t<3, 11, 4, H0P, W0P, H1, W1, 384><<<(tot + 255) / 256, 256>>>(p_in, pBhi, pBlo);
        mmaconv64_k<<<(NP + 127) / 128, 256, SMEM_G1>>>(
            pAhi, pAlo, pBhi, pBlo, ab1, p_c1, C1o, NP, KP, H1, W1, H1, W1, 0);
    }
    {
        int tot = N_IMG * C1o * P1H * P1W;
        maxpool_k<<<(tot + 127) / 128, 128>>>(p_c1, p_p1, N_IMG * C1o, H1, W1, P1H, P1W, P1HP, P1WP, 2);
    }

    // ---- p1 -> NHWC bf16 ----
    {
        const int NPIX = P1HP * P1WP;
        nchw2nhwc_k<<<dim3((NPIX + 31) / 32, C1o / 32, N_IMG), dim3(32, 8)>>>(p_p1, pBhi, pBlo, C1o, NPIX);
    }

    // ---- conv2 (implicit, fused, swizzled): M=192, K=1600, CIN=64, KD=5 ----
    {
        const int K = 1600, NP = N_IMG * H2 * W2;
        wsplit_reorder_k<<<(C2o * K + 255) / 256, 256>>>(aw2, pAhi, pAlo, C2o, 64, 25);
        mmaconv_imp_k<<<dim3((NP + 63) / 64, 2), 256, SMEM_G3>>>(
            pAhi, pAlo, pBhi, pBlo, ab2, p_c2, C2o, NP, K, 64, 5,
            P1HP, P1WP, H2, W2, H2, W2, 0);
    }
    {
        int tot = N_IMG * C2o * P2H * P2W;
        maxpool_k<<<(tot + 127) / 128, 128>>>(p_c2, p_p2, N_IMG * C2o, H2, W2, P2H, P2W, P2HP, P2WP, 1);
    }

    // ---- p2 -> NHWC ----
    {
        const int NPIX = P2HP * P2WP;
        nchw2nhwc_k<<<dim3((NPIX + 31) / 32, C2o / 32, N_IMG), dim3(32, 8)>>>(p_p2, pBhi, pBlo, C2o, NPIX);
    }

    // ---- conv3 (implicit, fused, swizzled): M=384, K=1728, CIN=192 ----
    {
        const int K = 1728, NP = N_IMG * P2H * P2W;
        wsplit_reorder_k<<<(C3o * K + 255) / 256, 256>>>(aw3, pAhi, pAlo, C3o, 192, 9);
        mmaconv_imp_k<<<dim3((NP + 63) / 64, 3), 256, SMEM_G3>>>(
            pAhi, pAlo, pBhi, pBlo, ab3, p_c3, C3o, NP, K, 192, 3,
            P2HP, P2WP, P2H, P2W, P2HP, P2WP, 1);
    }

    // ---- c3 -> NHWC ----
    {
        const int NPIX = P2HP * P2WP;
        nchw2nhwc_k<<<dim3((NPIX + 31) / 32, C3o / 32, N_IMG), dim3(32, 8)>>>(p_c3, pBhi, pBlo, C3o, NPIX);
    }

    // ---- conv4 (implicit, fused, swizzled): M=256, K=3456, CIN=384 ----
    {
        const int K = 3456, NP = N_IMG * P2H * P2W;
        wsplit_reorder_k<<<(C4o * K + 255) / 256, 256>>>(aw4, pAhi, pAlo, C4o, 384, 9);
        mmaconv_imp_k<<<dim3((NP + 63) / 64, 2), 256, SMEM_G3>>>(
            pAhi, pAlo, pBhi, pBlo, ab4, p_c4, C4o, NP, K, 384, 3,
            P2HP, P2WP, P2H, P2W, P2HP, P2WP, 1);
    }

    // ---- c4 -> NHWC ----
    {
        const int NPIX = P2HP * P2WP;
        nchw2nhwc_k<<<dim3((NPIX + 31) / 32, C4o / 32, N_IMG), dim3(32, 8)>>>(p_c4, pBhi, pBlo, C4o, NPIX);
    }

    // ---- conv5 (implicit, fused, swizzled): M=256, K=2304, CIN=256, out unpadded ----
    {
        const int K = 2304, NP = N_IMG * P2H * P2W;
        wsplit_reorder_k<<<(C5o * K + 255) / 256, 256>>>(aw5, pAhi, pAlo, C5o, 256, 9);
        mmaconv_imp_k<<<dim3((NP + 63) / 64, 2), 256, SMEM_G3>>>(
            pAhi, pAlo, pBhi, pBlo, ab5, p_c5, C5o, NP, K, 256, 3,
            P2HP, P2WP, P2H, P2W, H5, W5, 0);
    }
    {
        int tot = N_IMG * C5o * P5H * P5W;
        maxpool_k<<<(tot + 127) / 128, 128>>>(p_c5, p_p5, N_IMG * C5o, H5, W5, P5H, P5W, P5H, P5W, 0);
    }

    const float* Xf = p_p5 + (size_t)16 * 256 * 88;

    // ---- conv_deconv branch ----
    cd_conv_k<<<88, 256>>>(Xf, wcd, bcd, p_xc);
    cd_max_k<<<1, 256>>>(p_xc, p_v);
    xhat_k<<<256, 88>>>(p_v, wt, bt, p_xh);

    // ---- spatiotemporal GCN (tensor-core, fused split) ----
    __nv_bfloat16* nHi = pBhi;
    __nv_bfloat16* nLo = pBlo;
    __nv_bfloat16* h1Hi = pBhi + (1 << 20);
    __nv_bfloat16* h1Lo = pBlo + (1 << 20);
    __nv_bfloat16* w1Hi = pAhi;
    __nv_bfloat16* w1Lo = pAlo;
    __nv_bfloat16* w2Hi = pAhi + (512 * 256);
    __nv_bfloat16* w2Lo = pAlo + (512 * 256);

    gather_nodes_split_k<<<(TMN * 256 + 255) / 256, 256>>>(p_p5, nHi, nLo);
    wsplitT_k<<<(512 * 256 + 255) / 256, 256>>>(ws1, w1Hi, w1Lo, 512, 256);
    mmagemm_k<<<dim3(TMN / 64, 512 / 128), 256, SMEM_G2>>>(
        w1Hi, w1Lo, nHi, nLo, p_Y1, 512, TMN, 256);
    a1_reduce_k<<<dim3(4, 16), 128>>>(p_Y1, p_S, 512);
    a1_apply_split_k<<<(TMN * 512 + 255) / 256, 256>>>(p_Y1, p_S, bs1, h1Hi, h1Lo, 512);
    wsplitT_k<<<(256 * 512 + 255) / 256, 256>>>(ws2, w2Hi, w2Lo, 256, 512);
    mmagemm_k<<<dim3(TMN / 64, 256 / 128), 256, SMEM_G2>>>(
        w2Hi, w2Lo, h1Hi, h1Lo, p_Y2, 256, TMN, 512);
    a1_reduce_k<<<dim3(2, 16), 128>>>(p_Y2, p_S, 256);
    a1_apply_k<<<(TMN * 256 + 255) / 256, 256>>>(p_Y2, p_S, bs2, p_h2, 256);
    v1_k<<<(256 * 88 + 255) / 256, 256>>>(p_h2, p_xh, p_V1, p_V1t, p_Vx);

    // ---- dynamic cross-track graph ----
    rbgemm_k<<<dim3((88 + 63) / 64, 256 / 64), 256>>>(wg, p_Vx, bg, p_G, 256, 88, 256, 1);
    rbgemm_k<<<dim3((88 + 63) / 64, 256 / 64), 256>>>(wh, p_Vx, bh, p_Hh, 256, 88, 256, 1);
    attn_k<<<88, 128>>>(p_G, p_Hh, p_A2);

    // ---- ct GCN ----
    rbgemm_k<<<dim3(384 / 64, (88 + 63) / 64), 256>>>(p_V1t, wc1, nullptr, p_xw, 88, 384, 256, 0);
    rbgemm_k<<<dim3(384 / 64, (88 + 63) / 64), 256>>>(p_A2, p_xw, bc1, p_c1m, 88, 384, 88, 2 | 4);
    rbgemm_k<<<dim3(256 / 64, (88 + 63) / 64), 256>>>(p_c1m, wc2, nullptr, p_cw, 88, 256, 384, 0);
    rbgemm_k<<<dim3(256 / 64, (88 + 63) / 64), 256>>>(p_A2, p_cw, bc2, p_V2t, 88, 256, 88, 2 | 4);

    // ---- final correlation ----
    final_dot_k<<<1, 256>>>(Xf, p_V2t, (float*)d_out);
}

// round 15
// speedup vs baseline: 1.3480x; 1.0283x over previous
#include <cuda_runtime.h>
#include <cuda_bf16.h>
#include <cstdint>
#include <math.h>

// ---------------- dimensions ----------------
#define N_IMG 17
#define H0 383
#define W0 287
#define H0P 387
#define W0P 291
#define C1o 64
#define H1 95
#define W1 71
#define P1H 47
#define P1W 35
#define P1HP 51
#define P1WP 39
#define C2o 192
#define H2 47
#define W2 35
#define P2H 23
#define P2W 17
#define P2HP 25
#define P2WP 19
#define C3o 384
#define C4o 256
#define C5o 256
#define H5 23
#define W5 17
#define P5H 11
#define P5W 8
#define MM 88
#define TT 16
#define TMN 1408
#define TAILPAD 4096

// NHWC bf16 region offsets inside g_Bhi/g_Blo (elements)
#define C3OFF (16u << 20)
#define C4OFF (24u << 20)
#define C3SZ  (N_IMG * P2HP * P2WP * C3o)   // 3,100,800
#define C4SZ  (N_IMG * P2HP * P2WP * C4o)   // 2,067,200

// ---------------- scratch (device globals; no allocation) ----------------
__device__ float g_in [N_IMG*3*H0P*W0P + TAILPAD];
__device__ float g_c1 [N_IMG*C1o*H1*W1];
__device__ float g_p1 [N_IMG*C1o*P1HP*P1WP + TAILPAD];
__device__ float g_c2 [N_IMG*C2o*H2*W2];
__device__ float g_p2 [N_IMG*C2o*P2HP*P2WP + TAILPAD];
__device__ float g_c5 [N_IMG*C5o*H5*W5];
__device__ float g_p5 [N_IMG*C5o*MM];
__device__ float g_xc [256*88];
__device__ float g_v  [256];
__device__ float g_xhat[256*88];
__device__ float g_Y1 [TMN*512];
__device__ float g_S  [16*512];
__device__ float g_Y2 [TMN*256];
__device__ float g_h2 [TMN*256];
__device__ float g_V1 [256*88];
__device__ float g_V1t[88*256];
__device__ float g_Vx [256*88];
__device__ float g_G  [256*88];
__device__ float g_Hh [256*88];
__device__ float g_A2 [88*88];
__device__ float g_xw [88*384];
__device__ float g_c1m[88*384];
__device__ float g_cw [88*256];
__device__ float g_V2t[88*256];

// bf16 split matrices for tensor-core GEMMs (also NHWC maps / GCN operands)
__device__ __nv_bfloat16 g_Ahi[384*3456];
__device__ __nv_bfloat16 g_Alo[384*3456];
__device__ __nv_bfloat16 g_Bhi[44800000];
__device__ __nv_bfloat16 g_Blo[44800000];

// ---------------- mma / cp.async helpers (baseline PTX, sm_80+) ----------------
__device__ __forceinline__ uint32_t smem_u32(const void* p)
{
    uint32_t a;
    asm("{ .reg .u64 t; cvta.to.shared.u64 t, %1; cvt.u32.u64 %0, t; }" : "=r"(a) : "l"(p));
    return a;
}
__device__ __forceinline__ void ldsm_x4(uint32_t& r0, uint32_t& r1, uint32_t& r2, uint32_t& r3,
                                        uint32_t addr)
{
    asm volatile("ldmatrix.sync.aligned.m8n8.x4.shared.b16 {%0,%1,%2,%3}, [%4];"
                 : "=r"(r0), "=r"(r1), "=r"(r2), "=r"(r3) : "r"(addr));
}
__device__ __forceinline__ void mma16816(float* d, const uint32_t* a, uint32_t b0, uint32_t b1)
{
    asm volatile("mma.sync.aligned.m16n8k16.row.col.f32.bf16.bf16.f32 "
                 "{%0,%1,%2,%3}, {%4,%5,%6,%7}, {%8,%9}, {%0,%1,%2,%3};"
                 : "+f"(d[0]), "+f"(d[1]), "+f"(d[2]), "+f"(d[3])
                 : "r"(a[0]), "r"(a[1]), "r"(a[2]), "r"(a[3]), "r"(b0), "r"(b1));
}
__device__ __forceinline__ void cp16(uint32_t dst, const void* src, bool pred)
{
    int sz = pred ? 16 : 0;
    asm volatile("cp.async.cg.shared.global [%0], [%1], 16, %2;"
                 :: "r"(dst), "l"(src), "r"(sz));
}
#define CP_COMMIT() asm volatile("cp.async.commit_group;" ::: "memory")
#define CP_WAIT(n)  asm volatile("cp.async.wait_group %0;" :: "n"(n) : "memory")

__device__ __forceinline__ void bsplit(float x, __nv_bfloat16& h, __nv_bfloat16& l)
{
    h = __float2bfloat16_rn(x);
    l = __float2bfloat16_rn(x - __bfloat162float(h));
}

// ---------------- prep kernels ----------------
__global__ void wsplit_pad_k(const float* __restrict__ w, __nv_bfloat16* __restrict__ hi,
                             __nv_bfloat16* __restrict__ lo, int M, int Kreal, int KPAD)
{
    int i = blockIdx.x * blockDim.x + threadIdx.x;
    if (i >= M * KPAD) return;
    int m = i / KPAD, k = i - m * KPAD;
    float x = (k < Kreal) ? w[(size_t)m * Kreal + k] : 0.f;
    bsplit(x, hi[i], lo[i]);
}

__global__ void wsplit_reorder_k(const float* __restrict__ w, __nv_bfloat16* __restrict__ hi,
                                 __nv_bfloat16* __restrict__ lo, int M, int CIN, int KK)
{
    int K = CIN * KK;
    int i = blockIdx.x * blockDim.x + threadIdx.x;
    if (i >= M * K) return;
    int m = i / K, kidx = i - m * K;
    int pos = kidx / CIN, ci = kidx - pos * CIN;
    bsplit(w[((size_t)m * CIN + ci) * KK + pos], hi[i], lo[i]);
}

__global__ void wsplitT_k(const float* __restrict__ w, __nv_bfloat16* __restrict__ hi,
                          __nv_bfloat16* __restrict__ lo, int M, int K)
{
    int i = blockIdx.x * blockDim.x + threadIdx.x;
    if (i >= M * K) return;
    int m = i / K, k = i - m * K;
    bsplit(w[(size_t)k * M + m], hi[i], lo[i]);
}

__global__ void gather_nodes_split_k(const float* __restrict__ p5,
                                     __nv_bfloat16* __restrict__ hi, __nv_bfloat16* __restrict__ lo)
{
    int idx = blockIdx.x * blockDim.x + threadIdx.x;
    if (idx >= TMN * 256) return;
    int d = idx % 256;
    int n = idx / 256;
    int t = n % 16, m = n / 16;
    bsplit(p5[((size_t)t * 256 + d) * 88 + m], hi[idx], lo[idx]);
}

__global__ void nchw2nhwc_k(const float* __restrict__ in,
                            __nv_bfloat16* __restrict__ hi, __nv_bfloat16* __restrict__ lo,
                            int C, int NPIX)
{
    __shared__ float t[32][33];
    int img = blockIdx.z;
    int p0 = blockIdx.x * 32, c0 = blockIdx.y * 32;
    int tx = threadIdx.x, ty = threadIdx.y;
    const float* src = in + (size_t)img * C * NPIX;
    #pragma unroll
    for (int i = 0; i < 4; i++) {
        int c = c0 + ty + i * 8, p = p0 + tx;
        if (p < NPIX) t[ty + i * 8][tx] = src[(size_t)c * NPIX + p];
    }
    __syncthreads();
    #pragma unroll
    for (int i = 0; i < 4; i++) {
        int p = p0 + ty + i * 8, c = c0 + tx;
        if (p < NPIX) {
            size_t o = ((size_t)img * NPIX + p) * C + c;
            bsplit(t[tx][ty + i * 8], hi[o], lo[o]);
        }
    }
}

template<int CIN, int KD, int S, int HinP, int WinP, int Hout, int Wout, int KPAD>
__global__ void im2col_v8_t(const float* __restrict__ in,
                            __nv_bfloat16* __restrict__ bhi, __nv_bfloat16* __restrict__ blo)
{
    constexpr int KK = KD * KD;
    constexpr int KREAL = CIN * KK;
    constexpr int HW = Hout * Wout;
    constexpr int NPIX = N_IMG * HW;
    constexpr int KQ = KPAD / 8;
    int idx = blockIdx.x * blockDim.x + threadIdx.x;
    if (idx >= NPIX * KQ) return;
    int p  = idx / KQ;
    int k0 = (idx - p * KQ) * 8;
    int img = p / HW;
    int rr  = p - img * HW;
    int oh  = rr / Wout;
    int ow  = rr - oh * Wout;
    const float* base = in + ((size_t)img * CIN * HinP + oh * S) * WinP + ow * S;

    __nv_bfloat16 hv[8], lv[8];
    #pragma unroll
    for (int j = 0; j < 8; j++) {
        int k = k0 + j;
        float x = 0.f;
        if (k < KREAL) {
            int ci = k / KK;
            int r  = k - ci * KK;
            int kh = r / KD;
            int kw = r - kh * KD;
            x = base[((size_t)ci * HinP + kh) * WinP + kw];
        }
        bsplit(x, hv[j], lv[j]);
    }
    size_t o = (size_t)p * KPAD + k0;
    *(uint4*)(bhi + o) = *(const uint4*)hv;
    *(uint4*)(blo + o) = *(const uint4*)lv;
}

// ---------------- fused-segment tensor-core GEMMs ----------------
#define ASTR 72

// -------- explicit-B GEMM, 64(M) x 128(N) — conv1, XOR-swizzled, 2 blocks/SM --------
#define A1R_SZ 8192         // 64 rows x 128 B (one of hi/lo)
#define B1R_SZ 16384        // 128 rows x 128 B
#define ST1_SZ (2 * A1R_SZ + 2 * B1R_SZ)   // 49152
#define SMEM_G1 (2 * ST1_SZ)               // 98304
__global__ void __launch_bounds__(256, 2)
mmaconv64_k(const __nv_bfloat16* __restrict__ Ahi, const __nv_bfloat16* __restrict__ Alo,
            const __nv_bfloat16* __restrict__ Bhi, const __nv_bfloat16* __restrict__ Blo,
            const float* __restrict__ bias, float* __restrict__ out,
            int M, int Npix, int K, int Hout, int Wout,
            int HoP, int WoP, int opad)
{
    extern __shared__ char smem[];
    uint32_t sb = smem_u32(smem);
    uint32_t stg[2] = { sb, sb + ST1_SZ };

    int tid  = threadIdx.x;
    int lane = tid & 31;
    int wid  = tid >> 5;
    int wm   = wid & 1;
    int wn   = wid >> 1;

    int m0 = 0;
    int n0 = blockIdx.x * 128;

    float d[2][4][4];
    #pragma unroll
    for (int i = 0; i < 2; i++)
        #pragma unroll
        for (int j = 0; j < 4; j++)
            #pragma unroll
            for (int r = 0; r < 4; r++) d[i][j][r] = 0.f;

    int aj = lane >> 3, ar = lane & 7;
    uint32_t aRowOff[2], bRowOff[2];
    #pragma unroll
    for (int mi = 0; mi < 2; mi++)
        aRowOff[mi] = (uint32_t)((wm * 32 + mi * 16 + (aj & 1) * 8 + ar) * 128);
    #pragma unroll
    for (int q = 0; q < 2; q++)
        bRowOff[q] = (uint32_t)((wn * 32 + q * 16 + (aj >> 1) * 8 + ar) * 128);
    int aColBase = aj >> 1;
    int bColBase = aj & 1;

    int itK = K >> 6;

    int arow[2], aq[2];
    #pragma unroll
    for (int j = 0; j < 2; j++) { int i = tid + j * 256; arow[j] = i >> 3; aq[j] = i & 7; }
    int brow[4], bq[4];
    #pragma unroll
    for (int j = 0; j < 4; j++) { int i = tid + j * 256; brow[j] = i >> 3; bq[j] = i & 7; }

    auto load_stage = [&](int st, int it) {
        int kof = it << 6;
        uint32_t s = stg[st];
        #pragma unroll
        for (int j = 0; j < 2; j++) {
            size_t go = (size_t)(m0 + arow[j]) * K + kof + aq[j] * 8;
            uint32_t so = (uint32_t)(arow[j] * 128 + ((aq[j] ^ (arow[j] & 7)) * 16));
            bool pr = m0 + arow[j] < M;
            cp16(s + so, Ahi + go, pr);
            cp16(s + A1R_SZ + so, Alo + go, pr);
        }
        #pragma unroll
        for (int j = 0; j < 4; j++) {
            size_t go = (size_t)(n0 + brow[j]) * K + kof + bq[j] * 8;
            uint32_t so = (uint32_t)(brow[j] * 128 + ((bq[j] ^ (brow[j] & 7)) * 16));
            bool pr = n0 + brow[j] < Npix;
            cp16(s + 2 * A1R_SZ + so, Bhi + go, pr);
            cp16(s + 2 * A1R_SZ + B1R_SZ + so, Blo + go, pr);
        }
        CP_COMMIT();
    };

    load_stage(0, 0);

    for (int it = 0; it < itK; it++) {
        int st = it & 1;
        if (it + 1 < itK) { load_stage(st ^ 1, it + 1); CP_WAIT(1); }
        else              { CP_WAIT(0); }
        __syncthreads();
        uint32_t s = stg[st];

        #pragma unroll
        for (int kk = 0; kk < 4; kk++) {
            uint32_t aCol = (uint32_t)(((kk * 2 + aColBase) ^ ar) * 16);
            uint32_t bCol = (uint32_t)(((kk * 2 + bColBase) ^ ar) * 16);
            uint32_t ah[2][4], al[2][4];
            #pragma unroll
            for (int mi = 0; mi < 2; mi++) {
                uint32_t ad = s + aRowOff[mi] + aCol;
                ldsm_x4(ah[mi][0], ah[mi][1], ah[mi][2], ah[mi][3], ad);
                ldsm_x4(al[mi][0], al[mi][1], al[mi][2], al[mi][3], ad + A1R_SZ);
            }
            uint32_t bh[4][2], bl[4][2];
            #pragma unroll
            for (int q = 0; q < 2; q++) {
                uint32_t bd = s + 2 * A1R_SZ + bRowOff[q] + bCol;
                uint32_t r0, r1, r2, r3;
                ldsm_x4(r0, r1, r2, r3, bd);
                bh[q * 2][0] = r0; bh[q * 2][1] = r1;
                bh[q * 2 + 1][0] = r2; bh[q * 2 + 1][1] = r3;
                ldsm_x4(r0, r1, r2, r3, bd + B1R_SZ);
                bl[q * 2][0] = r0; bl[q * 2][1] = r1;
                bl[q * 2 + 1][0] = r2; bl[q * 2 + 1][1] = r3;
            }
            #pragma unroll
            for (int mi = 0; mi < 2; mi++)
                #pragma unroll
                for (int nj = 0; nj < 4; nj++) {
                    mma16816(d[mi][nj], ah[mi], bh[nj][0], bh[nj][1]);
                    mma16816(d[mi][nj], ah[mi], bl[nj][0], bl[nj][1]);
                    mma16816(d[mi][nj], al[mi], bh[nj][0], bh[nj][1]);
                }
        }
        __syncthreads();
    }

    int HW = Hout * Wout;
    #pragma unroll
    for (int mi = 0; mi < 2; mi++) {
        #pragma unroll
        for (int r2 = 0; r2 < 2; r2++) {
            int co = m0 + wm * 32 + mi * 16 + (lane >> 2) + r2 * 8;
            if (co >= M) continue;
            float bv = bias[co];
            #pragma unroll
            for (int nj = 0; nj < 4; nj++) {
                #pragma unroll
                for (int c = 0; c < 2; c++) {
                    int p = n0 + wn * 32 + nj * 8 + (lane & 3) * 2 + c;
                    if (p >= Npix) continue;
                    float v = d[mi][nj][r2 * 2 + c] + bv;
                    int img = p / HW;
                    int rr  = p - img * HW;
                    int oh  = rr / Wout;
                    int ow  = rr - oh * Wout;
                    out[((size_t)(img * M + co) * HoP + oh + opad) * WoP + ow + opad]
                        = fmaxf(v, 0.f);
                }
            }
        }
    }
}

// -------- implicit-B GEMM, 64(M) x 128(N) — conv2 (M=192, no M-pad waste) --------
__global__ void __launch_bounds__(256, 2)
mmaconv64_imp_k(const __nv_bfloat16* __restrict__ Ahi, const __nv_bfloat16* __restrict__ Alo,
                const __nv_bfloat16* __restrict__ Xhi, const __nv_bfloat16* __restrict__ Xlo,
                const float* __restrict__ bias, float* __restrict__ out,
                int M, int Npix, int K, int CIN, int KD,
                int HinP, int WinP, int Hout, int Wout,
                int HoP, int WoP, int opad)
{
    extern __shared__ char smem[];
    uint32_t sb = smem_u32(smem);
    uint32_t stg[2] = { sb, sb + ST1_SZ };

    int tid  = threadIdx.x;
    int lane = tid & 31;
    int wid  = tid >> 5;
    int wm   = wid & 1;
    int wn   = wid >> 1;

    int m0 = blockIdx.y * 64;
    int n0 = blockIdx.x * 128;

    float d[2][4][4];
    #pragma unroll
    for (int i = 0; i < 2; i++)
        #pragma unroll
        for (int j = 0; j < 4; j++)
            #pragma unroll
            for (int r = 0; r < 4; r++) d[i][j][r] = 0.f;

    int aj = lane >> 3, ar = lane & 7;
    uint32_t aRowOff[2], bRowOff[2];
    #pragma unroll
    for (int mi = 0; mi < 2; mi++)
        aRowOff[mi] = (uint32_t)((wm * 32 + mi * 16 + (aj & 1) * 8 + ar) * 128);
    #pragma unroll
    for (int q = 0; q < 2; q++)
        bRowOff[q] = (uint32_t)((wn * 32 + q * 16 + (aj >> 1) * 8 + ar) * 128);
    int aColBase = aj >> 1;
    int bColBase = aj & 1;

    int itK = K >> 6;
    int cPer = CIN >> 6;
    int HW = Hout * Wout;

    int arow[2], aq[2];
    #pragma unroll
    for (int j = 0; j < 2; j++) { int i = tid + j * 256; arow[j] = i >> 3; aq[j] = i & 7; }
    int brow[4], bq[4];
    long bbase[4];
    bool bval[4];
    #pragma unroll
    for (int j = 0; j < 4; j++) {
        int i = tid + j * 256;
        brow[j] = i >> 3; bq[j] = i & 7;
        int p = n0 + brow[j];
        bval[j] = p < Npix;
        if (!bval[j]) p = 0;
        int img = p / HW;
        int rr  = p - img * HW;
        int oh  = rr / Wout;
        int ow  = rr - oh * Wout;
        bbase[j] = ((long)(img * HinP + oh) * WinP + ow) * CIN;
    }

    auto load_stage = [&](int st, int it) {
        int pos = it / cPer;
        int cioff = (it - pos * cPer) << 6;
        int kh = pos / KD, kw = pos - kh * KD;
        int kofA = it << 6;
        long boff = (long)(kh * WinP + kw) * CIN + cioff;
        uint32_t s = stg[st];
        #pragma unroll
        for (int j = 0; j < 2; j++) {
            size_t go = (size_t)(m0 + arow[j]) * K + kofA + aq[j] * 8;
            uint32_t so = (uint32_t)(arow[j] * 128 + ((aq[j] ^ (arow[j] & 7)) * 16));
            bool pr = m0 + arow[j] < M;
            cp16(s + so, Ahi + go, pr);
            cp16(s + A1R_SZ + so, Alo + go, pr);
        }
        #pragma unroll
        for (int j = 0; j < 4; j++) {
            long go = bbase[j] + boff + bq[j] * 8;
            uint32_t so = (uint32_t)(brow[j] * 128 + ((bq[j] ^ (brow[j] & 7)) * 16));
            cp16(s + 2 * A1R_SZ + so, Xhi + go, bval[j]);
            cp16(s + 2 * A1R_SZ + B1R_SZ + so, Xlo + go, bval[j]);
        }
        CP_COMMIT();
    };

    load_stage(0, 0);

    for (int it = 0; it < itK; it++) {
        int st = it & 1;
        if (it + 1 < itK) { load_stage(st ^ 1, it + 1); CP_WAIT(1); }
        else              { CP_WAIT(0); }
        __syncthreads();
        uint32_t s = stg[st];

        #pragma unroll
        for (int kk = 0; kk < 4; kk++) {
            uint32_t aCol = (uint32_t)(((kk * 2 + aColBase) ^ ar) * 16);
            uint32_t bCol = (uint32_t)(((kk * 2 + bColBase) ^ ar) * 16);
            uint32_t ah[2][4], al[2][4];
            #pragma unroll
            for (int mi = 0; mi < 2; mi++) {
                uint32_t ad = s + aRowOff[mi] + aCol;
                ldsm_x4(ah[mi][0], ah[mi][1], ah[mi][2], ah[mi][3], ad);
                ldsm_x4(al[mi][0], al[mi][1], al[mi][2], al[mi][3], ad + A1R_SZ);
            }
            uint32_t bh[4][2], bl[4][2];
            #pragma unroll
            for (int q = 0; q < 2; q++) {
                uint32_t bd = s + 2 * A1R_SZ + bRowOff[q] + bCol;
                uint32_t r0, r1, r2, r3;
                ldsm_x4(r0, r1, r2, r3, bd);
                bh[q * 2][0] = r0; bh[q * 2][1] = r1;
                bh[q * 2 + 1][0] = r2; bh[q * 2 + 1][1] = r3;
                ldsm_x4(r0, r1, r2, r3, bd + B1R_SZ);
                bl[q * 2][0] = r0; bl[q * 2][1] = r1;
                bl[q * 2 + 1][0] = r2; bl[q * 2 + 1][1] = r3;
            }
            #pragma unroll
            for (int mi = 0; mi < 2; mi++)
                #pragma unroll
                for (int nj = 0; nj < 4; nj++) {
                    mma16816(d[mi][nj], ah[mi], bh[nj][0], bh[nj][1]);
                    mma16816(d[mi][nj], ah[mi], bl[nj][0], bl[nj][1]);
                    mma16816(d[mi][nj], al[mi], bh[nj][0], bh[nj][1]);
                }
        }
        __syncthreads();
    }

    #pragma unroll
    for (int mi = 0; mi < 2; mi++) {
        #pragma unroll
        for (int r2 = 0; r2 < 2; r2++) {
            int co = m0 + wm * 32 + mi * 16 + (lane >> 2) + r2 * 8;
            if (co >= M) continue;
            float bv = bias[co];
            #pragma unroll
            for (int nj = 0; nj < 4; nj++) {
                #pragma unroll
                for (int c = 0; c < 2; c++) {
                    int p = n0 + wn * 32 + nj * 8 + (lane & 3) * 2 + c;
                    if (p >= Npix) continue;
                    float v = d[mi][nj][r2 * 2 + c] + bv;
                    int img = p / HW;
                    int rr  = p - img * HW;
                    int oh  = rr / Wout;
                    int ow  = rr - oh * Wout;
                    out[((size_t)(img * M + co) * HoP + oh + opad) * WoP + ow + opad]
                        = fmaxf(v, 0.f);
                }
            }
        }
    }
}

// -------- implicit-B GEMM, 128(M) x 64(N), fp32 NCHW output (conv5) --------
#define AR3_SZ 16384
#define BR3_SZ 8192
#define ST3_SZ (2 * AR3_SZ + 2 * BR3_SZ)   // 49152
#define SMEM_G3 (2 * ST3_SZ)               // 98304
__global__ void __launch_bounds__(256, 2)
mmaconv_imp_k(const __nv_bfloat16* __restrict__ Ahi, const __nv_bfloat16* __restrict__ Alo,
              const __nv_bfloat16* __restrict__ Xhi, const __nv_bfloat16* __restrict__ Xlo,
              const float* __restrict__ bias, float* __restrict__ out,
              int M, int Npix, int K, int CIN, int KD,
              int HinP, int WinP, int Hout, int Wout,
              int HoP, int WoP, int opad)
{
    extern __shared__ char smem[];
    uint32_t sb = smem_u32(smem);
    uint32_t stg[2] = { sb, sb + ST3_SZ };

    int tid  = threadIdx.x;
    int lane = tid & 31;
    int wid  = tid >> 5;
    int wm   = wid & 3;
    int wn   = wid >> 2;

    int m0 = blockIdx.y * 128;
    int n0 = blockIdx.x * 64;

    float d[2][4][4];
    #pragma unroll
    for (int i = 0; i < 2; i++)
        #pragma unroll
        for (int j = 0; j < 4; j++)
            #pragma unroll
            for (int r = 0; r < 4; r++) d[i][j][r] = 0.f;

    int aj = lane >> 3, ar = lane & 7;
    uint32_t aRowOff[2], bRowOff[2];
    #pragma unroll
    for (int mi = 0; mi < 2; mi++)
        aRowOff[mi] = (uint32_t)((wm * 32 + mi * 16 + (aj & 1) * 8 + ar) * 128);
    #pragma unroll
    for (int q = 0; q < 2; q++)
        bRowOff[q] = (uint32_t)((wn * 32 + q * 16 + (aj >> 1) * 8 + ar) * 128);
    int aColBase = aj >> 1;
    int bColBase = aj & 1;

    int itK = K >> 6;
    int cPer = CIN >> 6;
    int HW = Hout * Wout;

    int arow[4], aq[4];
    #pragma unroll
    for (int j = 0; j < 4; j++) { int i = tid + j * 256; arow[j] = i >> 3; aq[j] = i & 7; }
    int brow[2], bq[2];
    long bbase[2];
    bool bval[2];
    #pragma unroll
    for (int j = 0; j < 2; j++) {
        int i = tid + j * 256;
        brow[j] = i >> 3; bq[j] = i & 7;
        int p = n0 + brow[j];
        bval[j] = p < Npix;
        if (!bval[j]) p = 0;
        int img = p / HW;
        int rr  = p - img * HW;
        int oh  = rr / Wout;
        int ow  = rr - oh * Wout;
        bbase[j] = ((long)(img * HinP + oh) * WinP + ow) * CIN;
    }

    auto load_stage = [&](int st, int it) {
        int pos = it / cPer;
        int cioff = (it - pos * cPer) << 6;
        int kh = pos / KD, kw = pos - kh * KD;
        int kofA = it << 6;
        long boff = (long)(kh * WinP + kw) * CIN + cioff;
        uint32_t s = stg[st];
        #pragma unroll
        for (int j = 0; j < 4; j++) {
            size_t go = (size_t)(m0 + arow[j]) * K + kofA + aq[j] * 8;
            uint32_t so = (uint32_t)(arow[j] * 128 + ((aq[j] ^ (arow[j] & 7)) * 16));
            bool pr = m0 + arow[j] < M;
            cp16(s + so, Ahi + go, pr);
            cp16(s + AR3_SZ + so, Alo + go, pr);
        }
        #pragma unroll
        for (int j = 0; j < 2; j++) {
            long go = bbase[j] + boff + bq[j] * 8;
            uint32_t so = (uint32_t)(brow[j] * 128 + ((bq[j] ^ (brow[j] & 7)) * 16));
            cp16(s + 2 * AR3_SZ + so, Xhi + go, bval[j]);
            cp16(s + 2 * AR3_SZ + BR3_SZ + so, Xlo + go, bval[j]);
        }
        CP_COMMIT();
    };

    load_stage(0, 0);

    for (int it = 0; it < itK; it++) {
        int st = it & 1;
        if (it + 1 < itK) { load_stage(st ^ 1, it + 1); CP_WAIT(1); }
        else              { CP_WAIT(0); }
        __syncthreads();
        uint32_t s = stg[st];

        #pragma unroll
        for (int kk = 0; kk < 4; kk++) {
            uint32_t aCol = (uint32_t)(((kk * 2 + aColBase) ^ ar) * 16);
            uint32_t bCol = (uint32_t)(((kk * 2 + bColBase) ^ ar) * 16);
            uint32_t ah[2][4], al[2][4];
            #pragma unroll
            for (int mi = 0; mi < 2; mi++) {
                uint32_t ad = s + aRowOff[mi] + aCol;
                ldsm_x4(ah[mi][0], ah[mi][1], ah[mi][2], ah[mi][3], ad);
                ldsm_x4(al[mi][0], al[mi][1], al[mi][2], al[mi][3], ad + AR3_SZ);
            }
            uint32_t bh[4][2], bl[4][2];
            #pragma unroll
            for (int q = 0; q < 2; q++) {
                uint32_t bd = s + 2 * AR3_SZ + bRowOff[q] + bCol;
                uint32_t r0, r1, r2, r3;
                ldsm_x4(r0, r1, r2, r3, bd);
                bh[q * 2][0] = r0; bh[q * 2][1] = r1;
                bh[q * 2 + 1][0] = r2; bh[q * 2 + 1][1] = r3;
                ldsm_x4(r0, r1, r2, r3, bd + BR3_SZ);
                bl[q * 2][0] = r0; bl[q * 2][1] = r1;
                bl[q * 2 + 1][0] = r2; bl[q * 2 + 1][1] = r3;
            }
            #pragma unroll
            for (int mi = 0; mi < 2; mi++)
                #pragma unroll
                for (int nj = 0; nj < 4; nj++) {
                    mma16816(d[mi][nj], ah[mi], bh[nj][0], bh[nj][1]);
                    mma16816(d[mi][nj], ah[mi], bl[nj][0], bl[nj][1]);
                    mma16816(d[mi][nj], al[mi], bh[nj][0], bh[nj][1]);
                }
        }
        __syncthreads();
    }

    #pragma unroll
    for (int mi = 0; mi < 2; mi++) {
        #pragma unroll
        for (int r2 = 0; r2 < 2; r2++) {
            int co = m0 + wm * 32 + mi * 16 + (lane >> 2) + r2 * 8;
            if (co >= M) continue;
            float bv = bias[co];
            #pragma unroll
            for (int nj = 0; nj < 4; nj++) {
                #pragma unroll
                for (int c = 0; c < 2; c++) {
                    int p = n0 + wn * 32 + nj * 8 + (lane & 3) * 2 + c;
                    if (p >= Npix) continue;
                    float v = d[mi][nj][r2 * 2 + c] + bv;
                    int img = p / HW;
                    int rr  = p - img * HW;
                    int oh  = rr / Wout;
                    int ow  = rr - oh * Wout;
                    out[((size_t)(img * M + co) * HoP + oh + opad) * WoP + ow + opad]
                        = fmaxf(v, 0.f);
                }
            }
        }
    }
}

// -------- implicit-B GEMM, 128(M) x 64(N), split NHWC bf16 output (conv3/conv4) --------
__global__ void __launch_bounds__(256, 2)
mmaconv_imp_split_k(const __nv_bfloat16* __restrict__ Ahi, const __nv_bfloat16* __restrict__ Alo,
                    const __nv_bfloat16* __restrict__ Xhi, const __nv_bfloat16* __restrict__ Xlo,
                    const float* __restrict__ bias,
                    __nv_bfloat16* __restrict__ outHi, __nv_bfloat16* __restrict__ outLo,
                    int M, int Npix, int K, int CIN, int KD,
                    int HinP, int WinP, int Hout, int Wout,
                    int HoP, int WoP, int opad)
{
    extern __shared__ char smem[];
    uint32_t sb = smem_u32(smem);
    uint32_t stg[2] = { sb, sb + ST3_SZ };

    int tid  = threadIdx.x;
    int lane = tid & 31;
    int wid  = tid >> 5;
    int wm   = wid & 3;
    int wn   = wid >> 2;

    int m0 = blockIdx.y * 128;
    int n0 = blockIdx.x * 64;

    float d[2][4][4];
    #pragma unroll
    for (int i = 0; i < 2; i++)
        #pragma unroll
        for (int j = 0; j < 4; j++)
            #pragma unroll
            for (int r = 0; r < 4; r++) d[i][j][r] = 0.f;

    int aj = lane >> 3, ar = lane & 7;
    uint32_t aRowOff[2], bRowOff[2];
    #pragma unroll
    for (int mi = 0; mi < 2; mi++)
        aRowOff[mi] = (uint32_t)((wm * 32 + mi * 16 + (aj & 1) * 8 + ar) * 128);
    #pragma unroll
    for (int q = 0; q < 2; q++)
        bRowOff[q] = (uint32_t)((wn * 32 + q * 16 + (aj >> 1) * 8 + ar) * 128);
    int aColBase = aj >> 1;
    int bColBase = aj & 1;

    int itK = K >> 6;
    int cPer = CIN >> 6;
    int HW = Hout * Wout;

    int arow[4], aq[4];
    #pragma unroll
    for (int j = 0; j < 4; j++) { int i = tid + j * 256; arow[j] = i >> 3; aq[j] = i & 7; }
    int brow[2], bq[2];
    long bbase[2];
    bool bval[2];
    #pragma unroll
    for (int j = 0; j < 2; j++) {
        int i = tid + j * 256;
        brow[j] = i >> 3; bq[j] = i & 7;
        int p = n0 + brow[j];
        bval[j] = p < Npix;
        if (!bval[j]) p = 0;
        int img = p / HW;
        int rr  = p - img * HW;
        int oh  = rr / Wout;
        int ow  = rr - oh * Wout;
        bbase[j] = ((long)(img * HinP + oh) * WinP + ow) * CIN;
    }

    auto load_stage = [&](int st, int it) {
        int pos = it / cPer;
        int cioff = (it - pos * cPer) << 6;
        int kh = pos / KD, kw = pos - kh * KD;
        int kofA = it << 6;
        long boff = (long)(kh * WinP + kw) * CIN + cioff;
        uint32_t s = stg[st];
        #pragma unroll
        for (int j = 0; j < 4; j++) {
            size_t go = (size_t)(m0 + arow[j]) * K + kofA + aq[j] * 8;
            uint32_t so = (uint32_t)(arow[j] * 128 + ((aq[j] ^ (arow[j] & 7)) * 16));
            bool pr = m0 + arow[j] < M;
            cp16(s + so, Ahi + go, pr);
            cp16(s + AR3_SZ + so, Alo + go, pr);
        }
        #pragma unroll
        for (int j = 0; j < 2; j++) {
            long go = bbase[j] + boff + bq[j] * 8;
            uint32_t so = (uint32_t)(brow[j] * 128 + ((bq[j] ^ (brow[j] & 7)) * 16));
            cp16(s + 2 * AR3_SZ + so, Xhi + go, bval[j]);
            cp16(s + 2 * AR3_SZ + BR3_SZ + so, Xlo + go, bval[j]);
        }
        CP_COMMIT();
    };

    load_stage(0, 0);

    for (int it = 0; it < itK; it++) {
        int st = it & 1;
        if (it + 1 < itK) { load_stage(st ^ 1, it + 1); CP_WAIT(1); }
        else              { CP_WAIT(0); }
        __syncthreads();
        uint32_t s = stg[st];

        #pragma unroll
        for (int kk = 0; kk < 4; kk++) {
            uint32_t aCol = (uint32_t)(((kk * 2 + aColBase) ^ ar) * 16);
            uint32_t bCol = (uint32_t)(((kk * 2 + bColBase) ^ ar) * 16);
            uint32_t ah[2][4], al[2][4];
            #pragma unroll
            for (int mi = 0; mi < 2; mi++) {
                uint32_t ad = s + aRowOff[mi] + aCol;
                ldsm_x4(ah[mi][0], ah[mi][1], ah[mi][2], ah[mi][3], ad);
                ldsm_x4(al[mi][0], al[mi][1], al[mi][2], al[mi][3], ad + AR3_SZ);
            }
            uint32_t bh[4][2], bl[4][2];
            #pragma unroll
            for (int q = 0; q < 2; q++) {
                uint32_t bd = s + 2 * AR3_SZ + bRowOff[q] + bCol;
                uint32_t r0, r1, r2, r3;
                ldsm_x4(r0, r1, r2, r3, bd);
                bh[q * 2][0] = r0; bh[q * 2][1] = r1;
                bh[q * 2 + 1][0] = r2; bh[q * 2 + 1][1] = r3;
                ldsm_x4(r0, r1, r2, r3, bd + BR3_SZ);
                bl[q * 2][0] = r0; bl[q * 2][1] = r1;
                bl[q * 2 + 1][0] = r2; bl[q * 2 + 1][1] = r3;
            }
            #pragma unroll
            for (int mi = 0; mi < 2; mi++)
                #pragma unroll
                for (int nj = 0; nj < 4; nj++) {
                    mma16816(d[mi][nj], ah[mi], bh[nj][0], bh[nj][1]);
                    mma16816(d[mi][nj], ah[mi], bl[nj][0], bl[nj][1]);
                    mma16816(d[mi][nj], al[mi], bh[nj][0], bh[nj][1]);
                }
        }
        __syncthreads();
    }

    // epilogue: bias + ReLU + split bf16 hi/lo into padded NHWC map
    #pragma unroll
    for (int mi = 0; mi < 2; mi++) {
        #pragma unroll
        for (int r2 = 0; r2 < 2; r2++) {
            int co = m0 + wm * 32 + mi * 16 + (lane >> 2) + r2 * 8;
            if (co >= M) continue;
            float bv = bias[co];
            #pragma unroll
            for (int nj = 0; nj < 4; nj++) {
                #pragma unroll
                for (int c = 0; c < 2; c++) {
                    int p = n0 + wn * 32 + nj * 8 + (lane & 3) * 2 + c;
                    if (p >= Npix) continue;
                    float v = fmaxf(d[mi][nj][r2 * 2 + c] + bv, 0.f);
                    int img = p / HW;
                    int rr  = p - img * HW;
                    int oh  = rr / Wout;
                    int ow  = rr - oh * Wout;
                    size_t o = ((size_t)img * HoP * WoP + (size_t)(oh + opad) * WoP
                                + (ow + opad)) * (size_t)M + co;
                    bsplit(v, outHi[o], outLo[o]);
                }
            }
        }
    }
}

// -------- generic explicit GEMM, 128(M) x 64(N), transposed output C[n,m] --------
#define A2_SZ (128 * ASTR * 2)
#define B2_SZ (64 * ASTR * 2)
#define ST2_SZ (2 * A2_SZ + 2 * B2_SZ)
#define SMEM_G2 (2 * ST2_SZ)
__global__ void __launch_bounds__(256)
mmagemm_k(const __nv_bfloat16* __restrict__ Ahi, const __nv_bfloat16* __restrict__ Alo,
          const __nv_bfloat16* __restrict__ Bhi, const __nv_bfloat16* __restrict__ Blo,
          float* __restrict__ out, int M, int N, int K)
{
    extern __shared__ char smem[];
    uint32_t sb = smem_u32(smem);
    uint32_t stg[2] = { sb, sb + ST2_SZ };

    int tid  = threadIdx.x;
    int lane = tid & 31;
    int wid  = tid >> 5;
    int wm   = wid & 3;
    int wn   = wid >> 2;

    int m0 = blockIdx.y * 128;
    int n0 = blockIdx.x * 64;

    float d[2][4][4];
    #pragma unroll
    for (int i = 0; i < 2; i++)
        #pragma unroll
        for (int j = 0; j < 4; j++)
            #pragma unroll
            for (int r = 0; r < 4; r++) d[i][j][r] = 0.f;

    int aj = lane >> 3, ar = lane & 7;
    uint32_t aAddrOff = (uint32_t)(((aj & 1) * 8 + ar) * ASTR + (aj >> 1) * 8) * 2;
    uint32_t bAddrOff = (uint32_t)(((aj >> 1) * 8 + ar) * ASTR + (aj & 1) * 8) * 2;

    int itK = K >> 6;

    int arow[4], aq[4];
    #pragma unroll
    for (int j = 0; j < 4; j++) { int i = tid + j * 256; arow[j] = i >> 3; aq[j] = i & 7; }
    int brow[2], bq[2];
    #pragma unroll
    for (int j = 0; j < 2; j++) { int i = tid + j * 256; brow[j] = i >> 3; bq[j] = i & 7; }

    auto load_stage = [&](int st, int it) {
        int kof = it << 6;
        uint32_t s = stg[st];
        #pragma unroll
        for (int j = 0; j < 4; j++) {
            size_t go = (size_t)(m0 + arow[j]) * K + kof + aq[j] * 8;
            uint32_t so = (uint32_t)(arow[j] * ASTR + aq[j] * 8) * 2;
            bool pr = m0 + arow[j] < M;
            cp16(s + so, Ahi + go, pr);
            cp16(s + A2_SZ + so, Alo + go, pr);
        }
        #pragma unroll
        for (int j = 0; j < 2; j++) {
            size_t go = (size_t)(n0 + brow[j]) * K + kof + bq[j] * 8;
            uint32_t so = (uint32_t)(brow[j] * ASTR + bq[j] * 8) * 2;
            bool pr = n0 + brow[j] < N;
            cp16(s + 2 * A2_SZ + so, Bhi + go, pr);
            cp16(s + 2 * A2_SZ + B2_SZ + so, Blo + go, pr);
        }
        CP_COMMIT();
    };

    load_stage(0, 0);

    for (int it = 0; it < itK; it++) {
        int st = it & 1;
        if (it + 1 < itK) { load_stage(st ^ 1, it + 1); CP_WAIT(1); }
        else              { CP_WAIT(0); }
        __syncthreads();
        uint32_t s = stg[st];

        #pragma unroll
        for (int kk = 0; kk < 4; kk++) {
            uint32_t ah[2][4], al[2][4];
            #pragma unroll
            for (int mi = 0; mi < 2; mi++) {
                uint32_t off = aAddrOff + (uint32_t)((wm * 32 + mi * 16) * ASTR + kk * 16) * 2;
                ldsm_x4(ah[mi][0], ah[mi][1], ah[mi][2], ah[mi][3], s + off);
                ldsm_x4(al[mi][0], al[mi][1], al[mi][2], al[mi][3], s + A2_SZ + off);
            }
            uint32_t bh[4][2], bl[4][2];
            #pragma unroll
            for (int q = 0; q < 2; q++) {
                uint32_t off = bAddrOff + (uint32_t)((wn * 32 + q * 16) * ASTR + kk * 16) * 2;
                uint32_t r0, r1, r2, r3;
                ldsm_x4(r0, r1, r2, r3, s + 2 * A2_SZ + off);
                bh[q * 2][0] = r0; bh[q * 2][1] = r1;
                bh[q * 2 + 1][0] = r2; bh[q * 2 + 1][1] = r3;
                ldsm_x4(r0, r1, r2, r3, s + 2 * A2_SZ + B2_SZ + off);
                bl[q * 2][0] = r0; bl[q * 2][1] = r1;
                bl[q * 2 + 1][0] = r2; bl[q * 2 + 1][1] = r3;
            }
            #pragma unroll
            for (int mi = 0; mi < 2; mi++)
                #pragma unroll
                for (int nj = 0; nj < 4; nj++) {
                    mma16816(d[mi][nj], ah[mi], bh[nj][0], bh[nj][1]);
                    mma16816(d[mi][nj], ah[mi], bl[nj][0], bl[nj][1]);
                    mma16816(d[mi][nj], al[mi], bh[nj][0], bh[nj][1]);
                }
        }
        __syncthreads();
    }

    #pragma unroll
    for (int mi = 0; mi < 2; mi++) {
        #pragma unroll
        for (int r2 = 0; r2 < 2; r2++) {
            int co = m0 + wm * 32 + mi * 16 + (lane >> 2) + r2 * 8;
            if (co >= M) continue;
            #pragma unroll
            for (int nj = 0; nj < 4; nj++) {
                #pragma unroll
                for (int c = 0; c < 2; c++) {
                    int p = n0 + wn * 32 + nj * 8 + (lane & 3) * 2 + c;
                    if (p >= N) continue;
                    out[(size_t)p * M + co] = d[mi][nj][r2 * 2 + c];
                }
            }
        }
    }
}

// ---------------- scalar kernels (rest of network) ----------------

__global__ void pad_copy_k(const float* __restrict__ src, float* __restrict__ dst,
                           int nimg, int boff)
{
    int idx = blockIdx.x * blockDim.x + threadIdx.x;
    int total = nimg * 3 * H0 * W0;
    if (idx >= total) return;
    int w = idx % W0; int t = idx / W0;
    int h = t % H0;   t /= H0;
    int c = t % 3;    int n = t / 3;
    dst[(((size_t)(boff + n) * 3 + c) * H0P + h + 2) * W0P + (w + 2)] = src[idx];
}

__global__ void maxpool_k(const float* __restrict__ in, float* __restrict__ out,
                          int NC, int Hin, int Win, int Ho, int Wo,
                          int HoP, int WoP, int opad)
{
    int idx = blockIdx.x * blockDim.x + threadIdx.x;
    int total = NC * Ho * Wo;
    if (idx >= total) return;
    int ow = idx % Wo; int t = idx / Wo;
    int oh = t % Ho;   int nc = t / Ho;
    const float* ip = in + ((size_t)nc * Hin + oh * 2) * Win + ow * 2;
    float m = -INFINITY;
    #pragma unroll
    for (int kh = 0; kh < 3; kh++)
        #pragma unroll
        for (int kw = 0; kw < 3; kw++)
            m = fmaxf(m, ip[kh * Win + kw]);
    out[((size_t)nc * HoP + oh + opad) * WoP + ow + opad] = m;
}

__global__ void cd_conv_k(const float* __restrict__ Xf, const float* __restrict__ wcd,
                          const float* __restrict__ bcd, float* __restrict__ xc)
{
    int p = blockIdx.x;
    int o = threadIdx.x;
    float acc = bcd[o];
    for (int i = 0; i < 256; i++) {
        const float* wr = wcd + (o * 256 + i) * 3;
        const float* xr = Xf + i * 88;
        if (p > 0)  acc += xr[p - 1] * wr[0];
        acc += xr[p] * wr[1];
        if (p < 87) acc += xr[p + 1] * wr[2];
    }
    xc[o * 88 + p] = acc;
}

__global__ void cd_max_k(const float* __restrict__ xc, float* __restrict__ v)
{
    int o = threadIdx.x;
    float m = -INFINITY;
    for (int p = 0; p < 88; p++) m = fmaxf(m, xc[o * 88 + p]);
    v[o] = m;
}

__global__ void xhat_k(const float* __restrict__ v, const float* __restrict__ wt,
                       const float* __restrict__ bt, float* __restrict__ xhat)
{
    __shared__ float sv[256];
    int o = blockIdx.x;
    int k = threadIdx.x;
    for (int i = threadIdx.x; i < 256; i += blockDim.x) sv[i] = v[i];
    __syncthreads();
    float acc = bt[o];
    for (int i = 0; i < 256; i++)
        acc += sv[i] * wt[((size_t)i * 256 + o) * 88 + k];
    xhat[o * 88 + k] = acc;
}

__global__ __launch_bounds__(256)
void rbgemm_k(const float* __restrict__ A, const float* __restrict__ B,
              const float* __restrict__ bias, float* __restrict__ C,
              int M, int N, int K, int flags)
{
    __shared__ float As[16][65];
    __shared__ float Bs[16][64];
    int tid = threadIdx.x;
    int tx = tid & 15;
    int ty = tid >> 4;
    int m0 = blockIdx.y * 64;
    int n0 = blockIdx.x * 64;

    float acc[4][4] = {};

    for (int k0 = 0; k0 < K; k0 += 16) {
        #pragma unroll
        for (int i = 0; i < 4; i++) {
            int e  = tid + i * 256;
            int kk = e & 15;
            int mm = e >> 4;
            int gm = m0 + mm, gk = k0 + kk;
            As[kk][mm] = (gm < M && gk < K) ? A[(size_t)gm * K + gk] : 0.f;
        }
        #pragma unroll
        for (int i = 0; i < 4; i++) {
            int nn = tid & 63;
            int kk = (tid >> 6) + i * 4;
            int gk = k0 + kk, gn = n0 + nn;
            Bs[kk][nn] = (gk < K && gn < N) ? B[(size_t)gk * N + gn] : 0.f;
        }
        __syncthreads();
        #pragma unroll
        for (int kk = 0; kk < 16; kk++) {
            float ra[4], rb[4];
            #pragma unroll
            for (int i = 0; i < 4; i++) ra[i] = As[kk][ty * 4 + i];
            #pragma unroll
            for (int j = 0; j < 4; j++) rb[j] = Bs[kk][tx * 4 + j];
            #pragma unroll
            for (int i = 0; i < 4; i++)
                #pragma unroll
                for (int j = 0; j < 4; j++)
                    acc[i][j] += ra[i] * rb[j];
        }
        __syncthreads();
    }

    #pragma unroll
    for (int i = 0; i < 4; i++) {
        int gm = m0 + ty * 4 + i;
        if (gm >= M) continue;
        #pragma unroll
        for (int j = 0; j < 4; j++) {
            int gn = n0 + tx * 4 + j;
            if (gn >= N) continue;
            float v = acc[i][j];
            if (flags & 1) v += bias[gm];
            if (flags & 2) v += bias[gn];
            if (flags & 4) v = v >= 0.f ? v : 0.01f * v;
            C[(size_t)gm * N + gn] = v;
        }
    }
}

__global__ void a1_reduce_k(const float* __restrict__ Y, float* __restrict__ S, int F)
{
    int f = blockIdx.x * blockDim.x + threadIdx.x;
    int t = blockIdx.y;
    if (f >= F) return;
    float s = 0.f;
    for (int m = 0; m < 88; m++) s += Y[(size_t)(m * 16 + t) * F + f];
    S[t * F + f] = s;
}

__global__ void a1_apply_split_k(const float* __restrict__ Y, const float* __restrict__ S,
                                 const float* __restrict__ bias,
                                 __nv_bfloat16* __restrict__ hi, __nv_bfloat16* __restrict__ lo,
                                 int F)
{
    int idx = blockIdx.x * blockDim.x + threadIdx.x;
    if (idx >= TMN * F) return;
    int f = idx % F;
    int n = idx / F;
    int t = n % 16;
    float val = S[t * F + f] + bias[f];
    if (t == 0) val -= Y[idx];
    val = val >= 0.f ? val : 0.01f * val;
    bsplit(val, hi[idx], lo[idx]);
}

__global__ void a1_apply_k(const float* __restrict__ Y, const float* __restrict__ S,
                           const float* __restrict__ bias, float* __restrict__ h, int F)
{
    int idx = blockIdx.x * blockDim.x + threadIdx.x;
    if (idx >= TMN * F) return;
    int f = idx % F;
    int n = idx / F;
    int t = n % 16;
    float val = S[t * F + f] + bias[f];
    if (t == 0) val -= Y[idx];
    h[idx] = val >= 0.f ? val : 0.01f * val;
}

__global__ void v1_k(const float* __restrict__ h2, const float* __restrict__ xhat,
                     float* __restrict__ V1, float* __restrict__ V1t, float* __restrict__ Vx)
{
    int idx = blockIdx.x * blockDim.x + threadIdx.x;
    if (idx >= 256 * 88) return;
    int d = idx % 256;
    int m = idx / 256;
    float mx = -INFINITY;
    #pragma unroll
    for (int t = 0; t < 16; t++) mx = fmaxf(mx, h2[(size_t)(m * 16 + t) * 256 + d]);
    V1[d * 88 + m] = mx;
    V1t[m * 256 + d] = mx;
    Vx[d * 88 + m] = mx + xhat[d * 88 + m];
}

__global__ void attn_k(const float* __restrict__ G, const float* __restrict__ Hh,
                       float* __restrict__ A2)
{
    __shared__ float red[128];
    int j = blockIdx.x;
    int i = threadIdx.x;
    float s = 0.f;
    if (i < 88) {
        for (int d = 0; d < 256; d++) s += Hh[d * 88 + j] * G[d * 88 + i];
    }
    red[i] = (i < 88) ? s : -INFINITY;
    __syncthreads();
    for (int st = 64; st > 0; st >>= 1) {
        if (i < st) red[i] = fmaxf(red[i], red[i + st]);
        __syncthreads();
    }
    float mx = red[0];
    __syncthreads();
    float e = (i < 88) ? expf(s - mx) : 0.f;
    red[i] = e;
    __syncthreads();
    for (int st = 64; st > 0; st >>= 1) {
        if (i < st) red[i] += red[i + st];
        __syncthreads();
    }
    float sum = red[0];
    if (i < 88) A2[j * 88 + i] = e / sum;
}

__global__ void final_dot_k(const float* __restrict__ Xf, const float* __restrict__ V2t,
                            float* __restrict__ out)
{
    __shared__ float red[256];
    float acc = 0.f;
    for (int e = threadIdx.x; e < 256 * 88; e += 256) {
        int d = e / 88, m = e % 88;
        acc += Xf[e] * V2t[m * 256 + d];
    }
    red[threadIdx.x] = acc;
    __syncthreads();
    for (int st = 128; st > 0; st >>= 1) {
        if (threadIdx.x < st) red[threadIdx.x] += red[threadIdx.x + st];
        __syncthreads();
    }
    if (threadIdx.x == 0) out[0] = red[0];
}

// ---------------- host ----------------
static float* symaddr(const void* s)
{
    void* p = nullptr;
    cudaGetSymbolAddress(&p, s);
    return (float*)p;
}
static __nv_bfloat16* symaddr_bf(const void* s)
{
    void* p = nullptr;
    cudaGetSymbolAddress(&p, s);
    return (__nv_bfloat16*)p;
}

extern "C" void kernel_launch(void* const* d_in, const int* in_sizes, int n_in,
                              void* d_out, int out_size)
{
    const float* search    = (const float*)d_in[0];
    const float* exemplars = (const float*)d_in[1];
    const float* aw1 = (const float*)d_in[2];  const float* ab1 = (const float*)d_in[3];
    const float* aw2 = (const float*)d_in[4];  const float* ab2 = (const float*)d_in[5];
    const float* aw3 = (const float*)d_in[6];  const float* ab3 = (const float*)d_in[7];
    const float* aw4 = (const float*)d_in[8];  const float* ab4 = (const float*)d_in[9];
    const float* aw5 = (const float*)d_in[10]; const float* ab5 = (const float*)d_in[11];
    const float* wcd = (const float*)d_in[12]; const float* bcd = (const float*)d_in[13];
    const float* wt  = (const float*)d_in[14]; const float* bt  = (const float*)d_in[15];
    const float* ws1 = (const float*)d_in[16]; const float* bs1 = (const float*)d_in[17];
    const float* ws2 = (const float*)d_in[18]; const float* bs2 = (const float*)d_in[19];
    const float* wg  = (const float*)d_in[20]; const float* bg  = (const float*)d_in[21];
    const float* wh  = (const float*)d_in[22]; const float* bh  = (const float*)d_in[23];
    const float* wc1 = (const float*)d_in[24]; const float* bc1 = (const float*)d_in[25];
    const float* wc2 = (const float*)d_in[26]; const float* bc2 = (const float*)d_in[27];

    float* p_in  = symaddr(g_in);
    float* p_c1  = symaddr(g_c1);
    float* p_p1  = symaddr(g_p1);
    float* p_c2  = symaddr(g_c2);
    float* p_p2  = symaddr(g_p2);
    float* p_c5  = symaddr(g_c5);
    float* p_p5  = symaddr(g_p5);
    float* p_xc  = symaddr(g_xc);
    float* p_v   = symaddr(g_v);
    float* p_xh  = symaddr(g_xhat);
    float* p_Y1  = symaddr(g_Y1);
    float* p_S   = symaddr(g_S);
    float* p_Y2  = symaddr(g_Y2);
    float* p_h2  = symaddr(g_h2);
    float* p_V1  = symaddr(g_V1);
    float* p_V1t = symaddr(g_V1t);
    float* p_Vx  = symaddr(g_Vx);
    float* p_G   = symaddr(g_G);
    float* p_Hh  = symaddr(g_Hh);
    float* p_A2  = symaddr(g_A2);
    float* p_xw  = symaddr(g_xw);
    float* p_c1m = symaddr(g_c1m);
    float* p_cw  = symaddr(g_cw);
    float* p_V2t = symaddr(g_V2t);
    __nv_bfloat16* pAhi = symaddr_bf(g_Ahi);
    __nv_bfloat16* pAlo = symaddr_bf(g_Alo);
    __nv_bfloat16* pBhi = symaddr_bf(g_Bhi);
    __nv_bfloat16* pBlo = symaddr_bf(g_Blo);

    cudaFuncSetAttribute(mmaconv64_k, cudaFuncAttributeMaxDynamicSharedMemorySize, SMEM_G1);
    cudaFuncSetAttribute(mmaconv64_imp_k, cudaFuncAttributeMaxDynamicSharedMemorySize, SMEM_G1);
    cudaFuncSetAttribute(mmaconv_imp_k, cudaFuncAttributeMaxDynamicSharedMemorySize, SMEM_G3);
    cudaFuncSetAttribute(mmaconv_imp_split_k, cudaFuncAttributeMaxDynamicSharedMemorySize, SMEM_G3);
    cudaFuncSetAttribute(mmagemm_k, cudaFuncAttributeMaxDynamicSharedMemorySize, SMEM_G2);

    // zero padded fp32 buffers (borders must be 0 every replay)
    cudaMemsetAsync(p_in, 0, sizeof(float) * ((size_t)N_IMG * 3 * H0P * W0P + TAILPAD), 0);
    cudaMemsetAsync(p_p1, 0, sizeof(float) * ((size_t)N_IMG * C1o * P1HP * P1WP + TAILPAD), 0);
    cudaMemsetAsync(p_p2, 0, sizeof(float) * ((size_t)N_IMG * C2o * P2HP * P2WP + TAILPAD), 0);

    // assemble padded input batch
    {
        int tot = 16 * 3 * H0 * W0;
        pad_copy_k<<<(tot + 127) / 128, 128>>>(exemplars, p_in, 16, 0);
        tot = 3 * H0 * W0;
        pad_copy_k<<<(tot + 127) / 128, 128>>>(search, p_in, 1, 16);
    }

    // ---- conv1 (vectorized im2col, swizzled 64x128 GEMM): M=64, K=384(pad) ----
    {
        const int KP = 384, NP = N_IMG * H1 * W1;
        wsplit_pad_k<<<(C1o * KP + 255) / 256, 256>>>(aw1, pAhi, pAlo, C1o, 363, KP);
        int tot = NP * (KP / 8);
        im2col_v8_t<3, 11, 4, H0P, W0P, H1, W1, 384><<<(tot + 255) / 256, 256>>>(p_in, pBhi, pBlo);
        mmaconv64_k<<<(NP + 127) / 128, 256, SMEM_G1>>>(
            pAhi, pAlo, pBhi, pBlo, ab1, p_c1, C1o, NP, KP, H1, W1, H1, W1, 0);
    }

    // zero NHWC bf16 regions for conv3/conv4 outputs (stream-ordered: after conv1
    // GEMM has consumed the overlapping im2col B buffer)
    cudaMemsetAsync(pBhi + C3OFF, 0, (size_t)C3SZ * 2, 0);
    cudaMemsetAsync(pBlo + C3OFF, 0, (size_t)C3SZ * 2, 0);
    cudaMemsetAsync(pBhi + C4OFF, 0, (size_t)C4SZ * 2, 0);
    cudaMemsetAsync(pBlo + C4OFF, 0, (size_t)C4SZ * 2, 0);

    {
        int tot = N_IMG * C1o * P1H * P1W;
        maxpool_k<<<(tot + 127) / 128, 128>>>(p_c1, p_p1, N_IMG * C1o, H1, W1, P1H, P1W, P1HP, P1WP, 2);
    }

    // ---- p1 -> NHWC bf16 (offset 0) ----
    {
        const int NPIX = P1HP * P1WP;
        nchw2nhwc_k<<<dim3((NPIX + 31) / 32, C1o / 32, N_IMG), dim3(32, 8)>>>(p_p1, pBhi, pBlo, C1o, NPIX);
    }

    // ---- conv2 (implicit, 64M x 128N — no M-pad waste): M=192, K=1600, CIN=64, KD=5 ----
    {
        const int K = 1600, NP = N_IMG * H2 * W2;
        wsplit_reorder_k<<<(C2o * K + 255) / 256, 256>>>(aw2, pAhi, pAlo, C2o, 64, 25);
        mmaconv64_imp_k<<<dim3((NP + 127) / 128, 3), 256, SMEM_G1>>>(
            pAhi, pAlo, pBhi, pBlo, ab2, p_c2, C2o, NP, K, 64, 5,
            P1HP, P1WP, H2, W2, H2, W2, 0);
    }
    {
        int tot = N_IMG * C2o * P2H * P2W;
        maxpool_k<<<(tot + 127) / 128, 128>>>(p_c2, p_p2, N_IMG * C2o, H2, W2, P2H, P2W, P2HP, P2WP, 1);
    }

    // ---- p2 -> NHWC (offset 0) ----
    {
        const int NPIX = P2HP * P2WP;
        nchw2nhwc_k<<<dim3((NPIX + 31) / 32, C2o / 32, N_IMG), dim3(32, 8)>>>(p_p2, pBhi, pBlo, C2o, NPIX);
    }

    // ---- conv3 (implicit, split NHWC epilogue): M=384, K=1728, CIN=192 ----
    {
        const int K = 1728, NP = N_IMG * P2H * P2W;
        wsplit_reorder_k<<<(C3o * K + 255) / 256, 256>>>(aw3, pAhi, pAlo, C3o, 192, 9);
        mmaconv_imp_split_k<<<dim3((NP + 63) / 64, 3), 256, SMEM_G3>>>(
            pAhi, pAlo, pBhi, pBlo, ab3, pBhi + C3OFF, pBlo + C3OFF,
            C3o, NP, K, 192, 3, P2HP, P2WP, P2H, P2W, P2HP, P2WP, 1);
    }

    // ---- conv4 (implicit, split NHWC epilogue): M=256, K=3456, CIN=384 ----
    {
        const int K = 3456, NP = N_IMG * P2H * P2W;
        wsplit_reorder_k<<<(C4o * K + 255) / 256, 256>>>(aw4, pAhi, pAlo, C4o, 384, 9);
        mmaconv_imp_split_k<<<dim3((NP + 63) / 64, 2), 256, SMEM_G3>>>(
            pAhi, pAlo, pBhi + C3OFF, pBlo + C3OFF, ab4, pBhi + C4OFF, pBlo + C4OFF,
            C4o, NP, K, 384, 3, P2HP, P2WP, P2H, P2W, P2HP, P2WP, 1);
    }

    // ---- conv5 (implicit, NCHW out): M=256, K=2304, CIN=256 ----
    {
        const int K = 2304, NP = N_IMG * P2H * P2W;
        wsplit_reorder_k<<<(C5o * K + 255) / 256, 256>>>(aw5, pAhi, pAlo, C5o, 256, 9);
        mmaconv_imp_k<<<dim3((NP + 63) / 64, 2), 256, SMEM_G3>>>(
            pAhi, pAlo, pBhi + C4OFF, pBlo + C4OFF, ab5, p_c5, C5o, NP, K, 256, 3,
            P2HP, P2WP, P2H, P2W, H5, W5, 0);
    }
    {
        int tot = N_IMG * C5o * P5H * P5W;
        maxpool_k<<<(tot + 127) / 128, 128>>>(p_c5, p_p5, N_IMG * C5o, H5, W5, P5H, P5W, P5H, P5W, 0);
    }

    const float* Xf = p_p5 + (size_t)16 * 256 * 88;

    // ---- conv_deconv branch ----
    cd_conv_k<<<88, 256>>>(Xf, wcd, bcd, p_xc);
    cd_max_k<<<1, 256>>>(p_xc, p_v);
    xhat_k<<<256, 88>>>(p_v, wt, bt, p_xh);

    // ---- spatiotemporal GCN (tensor-core, fused split) ----
    __nv_bfloat16* nHi = pBhi;
    __nv_bfloat16* nLo = pBlo;
    __nv_bfloat16* h1Hi = pBhi + (1 << 20);
    __nv_bfloat16* h1Lo = pBlo + (1 << 20);
    __nv_bfloat16* w1Hi = pAhi;
    __nv_bfloat16* w1Lo = pAlo;
    __nv_bfloat16* w2Hi = pAhi + (512 * 256);
    __nv_bfloat16* w2Lo = pAlo + (512 * 256);

    gather_nodes_split_k<<<(TMN * 256 + 255) / 256, 256>>>(p_p5, nHi, nLo);
    wsplitT_k<<<(512 * 256 + 255) / 256, 256>>>(ws1, w1Hi, w1Lo, 512, 256);
    mmagemm_k<<<dim3(TMN / 64, 512 / 128), 256, SMEM_G2>>>(
        w1Hi, w1Lo, nHi, nLo, p_Y1, 512, TMN, 256);
    a1_reduce_k<<<dim3(4, 16), 128>>>(p_Y1, p_S, 512);
    a1_apply_split_k<<<(TMN * 512 + 255) / 256, 256>>>(p_Y1, p_S, bs1, h1Hi, h1Lo, 512);
    wsplitT_k<<<(256 * 512 + 255) / 256, 256>>>(ws2, w2Hi, w2Lo, 256, 512);
    mmagemm_k<<<dim3(TMN / 64, 256 / 128), 256, SMEM_G2>>>(
        w2Hi, w2Lo, h1Hi, h1Lo, p_Y2, 256, TMN, 512);
    a1_reduce_k<<<dim3(2, 16), 128>>>(p_Y2, p_S, 256);
    a1_apply_k<<<(TMN * 256 + 255) / 256, 256>>>(p_Y2, p_S, bs2, p_h2, 256);
    v1_k<<<(256 * 88 + 255) / 256, 256>>>(p_h2, p_xh, p_V1, p_V1t, p_Vx);

    // ---- dynamic cross-track graph ----
    rbgemm_k<<<dim3((88 + 63) / 64, 256 / 64), 256>>>(wg, p_Vx, bg, p_G, 256, 88, 256, 1);
    rbgemm_k<<<dim3((88 + 63) / 64, 256 / 64), 256>>>(wh, p_Vx, bh, p_Hh, 256, 88, 256, 1);
    attn_k<<<88, 128>>>(p_G, p_Hh, p_A2);

    // ---- ct GCN ----
    rbgemm_k<<<dim3(384 / 64, (88 + 63) / 64), 256>>>(p_V1t, wc1, nullptr, p_xw, 88, 384, 256, 0);
    rbgemm_k<<<dim3(384 / 64, (88 + 63) / 64), 256>>>(p_A2, p_xw, bc1, p_c1m, 88, 384, 88, 2 | 4);
    rbgemm_k<<<dim3(256 / 64, (88 + 63) / 64), 256>>>(p_c1m, wc2, nullptr, p_cw, 88, 256, 384, 0);
    rbgemm_k<<<dim3(256 / 64, (88 + 63) / 64), 256>>>(p_A2, p_cw, bc2, p_V2t, 88, 256, 88, 2 | 4);

    // ---- final correlation ----
    final_dot_k<<<1, 256>>>(Xf, p_V2t, (float*)d_out);
}

// round 16
// speedup vs baseline: 1.4672x; 1.0884x over previous
#include <cuda_runtime.h>
#include <cuda_bf16.h>
#include <cstdint>
#include <math.h>

// ---------------- dimensions ----------------
#define N_IMG 17
#define H0 383
#define W0 287
#define H0P 387
#define W0P 291
#define C1o 64
#define H1 95
#define W1 71
#define P1H 47
#define P1W 35
#define P1HP 51
#define P1WP 39
#define C2o 192
#define H2 47
#define W2 35
#define P2H 23
#define P2W 17
#define P2HP 25
#define P2WP 19
#define C3o 384
#define C4o 256
#define C5o 256
#define H5 23
#define W5 17
#define P5H 11
#define P5W 8
#define MM 88
#define TT 16
#define TMN 1408
#define TAILPAD 4096

// NHWC bf16 region offsets inside g_Bhi/g_Blo (elements)
#define P2OFF (8u << 20)
#define C3OFF (16u << 20)
#define C4OFF (24u << 20)
#define C3SZ  (N_IMG * P2HP * P2WP * C3o)
#define C4SZ  (N_IMG * P2HP * P2WP * C4o)

// ---------------- scratch (device globals; no allocation) ----------------
__device__ float g_in [N_IMG*3*H0P*W0P + TAILPAD];
__device__ float g_c1 [N_IMG*C1o*H1*W1];
__device__ float g_c2 [N_IMG*C2o*H2*W2];
__device__ float g_c5 [N_IMG*C5o*H5*W5];
__device__ float g_p5 [N_IMG*C5o*MM];
__device__ float g_v  [256];
__device__ float g_xhat[256*88];
__device__ float g_Y1 [TMN*512];
__device__ float g_S  [16*512];
__device__ float g_Y2 [TMN*256];
__device__ float g_h2 [TMN*256];
__device__ float g_V1 [256*88];
__device__ float g_V1t[88*256];
__device__ float g_Vx [256*88];
__device__ float g_G  [256*88];
__device__ float g_Hh [256*88];
__device__ float g_A2 [88*88];
__device__ float g_xw [88*384];
__device__ float g_c1m[88*384];
__device__ float g_cw [88*256];
__device__ float g_V2t[88*256];

// bf16 split matrices for tensor-core GEMMs (also NHWC maps / GCN operands)
__device__ __nv_bfloat16 g_Ahi[384*3456];
__device__ __nv_bfloat16 g_Alo[384*3456];
__device__ __nv_bfloat16 g_Bhi[44800000];
__device__ __nv_bfloat16 g_Blo[44800000];

// ---------------- mma / cp.async helpers (baseline PTX, sm_80+) ----------------
__device__ __forceinline__ uint32_t smem_u32(const void* p)
{
    uint32_t a;
    asm("{ .reg .u64 t; cvta.to.shared.u64 t, %1; cvt.u32.u64 %0, t; }" : "=r"(a) : "l"(p));
    return a;
}
__device__ __forceinline__ void ldsm_x4(uint32_t& r0, uint32_t& r1, uint32_t& r2, uint32_t& r3,
                                        uint32_t addr)
{
    asm volatile("ldmatrix.sync.aligned.m8n8.x4.shared.b16 {%0,%1,%2,%3}, [%4];"
                 : "=r"(r0), "=r"(r1), "=r"(r2), "=r"(r3) : "r"(addr));
}
__device__ __forceinline__ void mma16816(float* d, const uint32_t* a, uint32_t b0, uint32_t b1)
{
    asm volatile("mma.sync.aligned.m16n8k16.row.col.f32.bf16.bf16.f32 "
                 "{%0,%1,%2,%3}, {%4,%5,%6,%7}, {%8,%9}, {%0,%1,%2,%3};"
                 : "+f"(d[0]), "+f"(d[1]), "+f"(d[2]), "+f"(d[3])
                 : "r"(a[0]), "r"(a[1]), "r"(a[2]), "r"(a[3]), "r"(b0), "r"(b1));
}
__device__ __forceinline__ void cp16(uint32_t dst, const void* src, bool pred)
{
    int sz = pred ? 16 : 0;
    asm volatile("cp.async.cg.shared.global [%0], [%1], 16, %2;"
                 :: "r"(dst), "l"(src), "r"(sz));
}
#define CP_COMMIT() asm volatile("cp.async.commit_group;" ::: "memory")
#define CP_WAIT(n)  asm volatile("cp.async.wait_group %0;" :: "n"(n) : "memory")

__device__ __forceinline__ void bsplit(float x, __nv_bfloat16& h, __nv_bfloat16& l)
{
    h = __float2bfloat16_rn(x);
    l = __float2bfloat16_rn(x - __bfloat162float(h));
}

// ---------------- prep kernels ----------------
__global__ void wsplit_pad_k(const float* __restrict__ w, __nv_bfloat16* __restrict__ hi,
                             __nv_bfloat16* __restrict__ lo, int M, int Kreal, int KPAD)
{
    int i = blockIdx.x * blockDim.x + threadIdx.x;
    if (i >= M * KPAD) return;
    int m = i / KPAD, k = i - m * KPAD;
    float x = (k < Kreal) ? w[(size_t)m * Kreal + k] : 0.f;
    bsplit(x, hi[i], lo[i]);
}

__global__ void wsplit_reorder_k(const float* __restrict__ w, __nv_bfloat16* __restrict__ hi,
                                 __nv_bfloat16* __restrict__ lo, int M, int CIN, int KK)
{
    int K = CIN * KK;
    int i = blockIdx.x * blockDim.x + threadIdx.x;
    if (i >= M * K) return;
    int m = i / K, kidx = i - m * K;
    int pos = kidx / CIN, ci = kidx - pos * CIN;
    bsplit(w[((size_t)m * CIN + ci) * KK + pos], hi[i], lo[i]);
}

__global__ void wsplitT_k(const float* __restrict__ w, __nv_bfloat16* __restrict__ hi,
                          __nv_bfloat16* __restrict__ lo, int M, int K)
{
    int i = blockIdx.x * blockDim.x + threadIdx.x;
    if (i >= M * K) return;
    int m = i / K, k = i - m * K;
    bsplit(w[(size_t)k * M + m], hi[i], lo[i]);
}

__global__ void gather_nodes_split_k(const float* __restrict__ p5,
                                     __nv_bfloat16* __restrict__ hi, __nv_bfloat16* __restrict__ lo)
{
    int idx = blockIdx.x * blockDim.x + threadIdx.x;
    if (idx >= TMN * 256) return;
    int d = idx % 256;
    int n = idx / 256;
    int t = n % 16, m = n / 16;
    bsplit(p5[((size_t)t * 256 + d) * 88 + m], hi[idx], lo[idx]);
}

// fused 3x3/s2 maxpool + NHWC bf16 hi/lo split via smem transpose.
// Writes zero borders itself (no memset needed). C multiple of 32.
__global__ void maxpool_split_k(const float* __restrict__ in,
                                __nv_bfloat16* __restrict__ hi, __nv_bfloat16* __restrict__ lo,
                                int C, int Hin, int Win, int Ho, int Wo,
                                int HoP, int WoP, int opad)
{
    __shared__ float t[32][33];
    int img = blockIdx.z;
    int p0 = blockIdx.x * 32, c0 = blockIdx.y * 32;
    int tx = threadIdx.x, ty = threadIdx.y;
    int NPIX = HoP * WoP;
    const float* src = in + (size_t)img * C * Hin * Win;
    #pragma unroll
    for (int i = 0; i < 4; i++) {
        int c = c0 + ty + i * 8, pp = p0 + tx;
        float m = 0.f;
        if (pp < NPIX) {
            int ohp = pp / WoP, owp = pp - ohp * WoP;
            int oh = ohp - opad, ow = owp - opad;
            if (oh >= 0 && oh < Ho && ow >= 0 && ow < Wo) {
                const float* ip = src + ((size_t)c * Hin + oh * 2) * Win + ow * 2;
                m = -INFINITY;
                #pragma unroll
                for (int kh = 0; kh < 3; kh++)
                    #pragma unroll
                    for (int kw = 0; kw < 3; kw++)
                        m = fmaxf(m, ip[kh * Win + kw]);
            }
        }
        t[ty + i * 8][tx] = m;
    }
    __syncthreads();
    #pragma unroll
    for (int i = 0; i < 4; i++) {
        int pp = p0 + ty + i * 8, c = c0 + tx;
        if (pp < NPIX) {
            size_t o = ((size_t)img * NPIX + pp) * C + c;
            bsplit(t[tx][ty + i * 8], hi[o], lo[o]);
        }
    }
}

template<int CIN, int KD, int S, int HinP, int WinP, int Hout, int Wout, int KPAD>
__global__ void im2col_v8_t(const float* __restrict__ in,
                            __nv_bfloat16* __restrict__ bhi, __nv_bfloat16* __restrict__ blo)
{
    constexpr int KK = KD * KD;
    constexpr int KREAL = CIN * KK;
    constexpr int HW = Hout * Wout;
    constexpr int NPIX = N_IMG * HW;
    constexpr int KQ = KPAD / 8;
    int idx = blockIdx.x * blockDim.x + threadIdx.x;
    if (idx >= NPIX * KQ) return;
    int p  = idx / KQ;
    int k0 = (idx - p * KQ) * 8;
    int img = p / HW;
    int rr  = p - img * HW;
    int oh  = rr / Wout;
    int ow  = rr - oh * Wout;
    const float* base = in + ((size_t)img * CIN * HinP + oh * S) * WinP + ow * S;

    __nv_bfloat16 hv[8], lv[8];
    #pragma unroll
    for (int j = 0; j < 8; j++) {
        int k = k0 + j;
        float x = 0.f;
        if (k < KREAL) {
            int ci = k / KK;
            int r  = k - ci * KK;
            int kh = r / KD;
            int kw = r - kh * KD;
            x = base[((size_t)ci * HinP + kh) * WinP + kw];
        }
        bsplit(x, hv[j], lv[j]);
    }
    size_t o = (size_t)p * KPAD + k0;
    *(uint4*)(bhi + o) = *(const uint4*)hv;
    *(uint4*)(blo + o) = *(const uint4*)lv;
}

// ---------------- fused-segment tensor-core GEMMs ----------------
#define ASTR 72

// -------- explicit-B GEMM, 64(M) x 128(N) — conv1, XOR-swizzled, 2 blocks/SM --------
#define A1R_SZ 8192
#define B1R_SZ 16384
#define ST1_SZ (2 * A1R_SZ + 2 * B1R_SZ)   // 49152
#define SMEM_G1 (2 * ST1_SZ)               // 98304
__global__ void __launch_bounds__(256, 2)
mmaconv64_k(const __nv_bfloat16* __restrict__ Ahi, const __nv_bfloat16* __restrict__ Alo,
            const __nv_bfloat16* __restrict__ Bhi, const __nv_bfloat16* __restrict__ Blo,
            const float* __restrict__ bias, float* __restrict__ out,
            int M, int Npix, int K, int Hout, int Wout,
            int HoP, int WoP, int opad)
{
    extern __shared__ char smem[];
    uint32_t sb = smem_u32(smem);
    uint32_t stg[2] = { sb, sb + ST1_SZ };

    int tid  = threadIdx.x;
    int lane = tid & 31;
    int wid  = tid >> 5;
    int wm   = wid & 1;
    int wn   = wid >> 1;

    int m0 = 0;
    int n0 = blockIdx.x * 128;

    float d[2][4][4];
    #pragma unroll
    for (int i = 0; i < 2; i++)
        #pragma unroll
        for (int j = 0; j < 4; j++)
            #pragma unroll
            for (int r = 0; r < 4; r++) d[i][j][r] = 0.f;

    int aj = lane >> 3, ar = lane & 7;
    uint32_t aRowOff[2], bRowOff[2];
    #pragma unroll
    for (int mi = 0; mi < 2; mi++)
        aRowOff[mi] = (uint32_t)((wm * 32 + mi * 16 + (aj & 1) * 8 + ar) * 128);
    #pragma unroll
    for (int q = 0; q < 2; q++)
        bRowOff[q] = (uint32_t)((wn * 32 + q * 16 + (aj >> 1) * 8 + ar) * 128);
    int aColBase = aj >> 1;
    int bColBase = aj & 1;

    int itK = K >> 6;

    int arow[2], aq[2];
    #pragma unroll
    for (int j = 0; j < 2; j++) { int i = tid + j * 256; arow[j] = i >> 3; aq[j] = i & 7; }
    int brow[4], bq[4];
    #pragma unroll
    for (int j = 0; j < 4; j++) { int i = tid + j * 256; brow[j] = i >> 3; bq[j] = i & 7; }

    auto load_stage = [&](int st, int it) {
        int kof = it << 6;
        uint32_t s = stg[st];
        #pragma unroll
        for (int j = 0; j < 2; j++) {
            size_t go = (size_t)(m0 + arow[j]) * K + kof + aq[j] * 8;
            uint32_t so = (uint32_t)(arow[j] * 128 + ((aq[j] ^ (arow[j] & 7)) * 16));
            bool pr = m0 + arow[j] < M;
            cp16(s + so, Ahi + go, pr);
            cp16(s + A1R_SZ + so, Alo + go, pr);
        }
        #pragma unroll
        for (int j = 0; j < 4; j++) {
            size_t go = (size_t)(n0 + brow[j]) * K + kof + bq[j] * 8;
            uint32_t so = (uint32_t)(brow[j] * 128 + ((bq[j] ^ (brow[j] & 7)) * 16));
            bool pr = n0 + brow[j] < Npix;
            cp16(s + 2 * A1R_SZ + so, Bhi + go, pr);
            cp16(s + 2 * A1R_SZ + B1R_SZ + so, Blo + go, pr);
        }
        CP_COMMIT();
    };

    load_stage(0, 0);

    for (int it = 0; it < itK; it++) {
        int st = it & 1;
        if (it + 1 < itK) { load_stage(st ^ 1, it + 1); CP_WAIT(1); }
        else              { CP_WAIT(0); }
        __syncthreads();
        uint32_t s = stg[st];

        #pragma unroll
        for (int kk = 0; kk < 4; kk++) {
            uint32_t aCol = (uint32_t)(((kk * 2 + aColBase) ^ ar) * 16);
            uint32_t bCol = (uint32_t)(((kk * 2 + bColBase) ^ ar) * 16);
            uint32_t ah[2][4], al[2][4];
            #pragma unroll
            for (int mi = 0; mi < 2; mi++) {
                uint32_t ad = s + aRowOff[mi] + aCol;
                ldsm_x4(ah[mi][0], ah[mi][1], ah[mi][2], ah[mi][3], ad);
                ldsm_x4(al[mi][0], al[mi][1], al[mi][2], al[mi][3], ad + A1R_SZ);
            }
            uint32_t bh[4][2], bl[4][2];
            #pragma unroll
            for (int q = 0; q < 2; q++) {
                uint32_t bd = s + 2 * A1R_SZ + bRowOff[q] + bCol;
                uint32_t r0, r1, r2, r3;
                ldsm_x4(r0, r1, r2, r3, bd);
                bh[q * 2][0] = r0; bh[q * 2][1] = r1;
                bh[q * 2 + 1][0] = r2; bh[q * 2 + 1][1] = r3;
                ldsm_x4(r0, r1, r2, r3, bd + B1R_SZ);
                bl[q * 2][0] = r0; bl[q * 2][1] = r1;
                bl[q * 2 + 1][0] = r2; bl[q * 2 + 1][1] = r3;
            }
            #pragma unroll
            for (int mi = 0; mi < 2; mi++)
                #pragma unroll
                for (int nj = 0; nj < 4; nj++) {
                    mma16816(d[mi][nj], ah[mi], bh[nj][0], bh[nj][1]);
                    mma16816(d[mi][nj], ah[mi], bl[nj][0], bl[nj][1]);
                    mma16816(d[mi][nj], al[mi], bh[nj][0], bh[nj][1]);
                }
        }
        __syncthreads();
    }

    int HW = Hout * Wout;
    #pragma unroll
    for (int mi = 0; mi < 2; mi++) {
        #pragma unroll
        for (int r2 = 0; r2 < 2; r2++) {
            int co = m0 + wm * 32 + mi * 16 + (lane >> 2) + r2 * 8;
            if (co >= M) continue;
            float bv = bias[co];
            #pragma unroll
            for (int nj = 0; nj < 4; nj++) {
                #pragma unroll
                for (int c = 0; c < 2; c++) {
                    int p = n0 + wn * 32 + nj * 8 + (lane & 3) * 2 + c;
                    if (p >= Npix) continue;
                    float v = d[mi][nj][r2 * 2 + c] + bv;
                    int img = p / HW;
                    int rr  = p - img * HW;
                    int oh  = rr / Wout;
                    int ow  = rr - oh * Wout;
                    out[((size_t)(img * M + co) * HoP + oh + opad) * WoP + ow + opad]
                        = fmaxf(v, 0.f);
                }
            }
        }
    }
}

// -------- implicit-B GEMM, 64(M) x 128(N) — conv2 --------
__global__ void __launch_bounds__(256, 2)
mmaconv64_imp_k(const __nv_bfloat16* __restrict__ Ahi, const __nv_bfloat16* __restrict__ Alo,
                const __nv_bfloat16* __restrict__ Xhi, const __nv_bfloat16* __restrict__ Xlo,
                const float* __restrict__ bias, float* __restrict__ out,
                int M, int Npix, int K, int CIN, int KD,
                int HinP, int WinP, int Hout, int Wout,
                int HoP, int WoP, int opad)
{
    extern __shared__ char smem[];
    uint32_t sb = smem_u32(smem);
    uint32_t stg[2] = { sb, sb + ST1_SZ };

    int tid  = threadIdx.x;
    int lane = tid & 31;
    int wid  = tid >> 5;
    int wm   = wid & 1;
    int wn   = wid >> 1;

    int m0 = blockIdx.y * 64;
    int n0 = blockIdx.x * 128;

    float d[2][4][4];
    #pragma unroll
    for (int i = 0; i < 2; i++)
        #pragma unroll
        for (int j = 0; j < 4; j++)
            #pragma unroll
            for (int r = 0; r < 4; r++) d[i][j][r] = 0.f;

    int aj = lane >> 3, ar = lane & 7;
    uint32_t aRowOff[2], bRowOff[2];
    #pragma unroll
    for (int mi = 0; mi < 2; mi++)
        aRowOff[mi] = (uint32_t)((wm * 32 + mi * 16 + (aj & 1) * 8 + ar) * 128);
    #pragma unroll
    for (int q = 0; q < 2; q++)
        bRowOff[q] = (uint32_t)((wn * 32 + q * 16 + (aj >> 1) * 8 + ar) * 128);
    int aColBase = aj >> 1;
    int bColBase = aj & 1;

    int itK = K >> 6;
    int cPer = CIN >> 6;
    int HW = Hout * Wout;

    int arow[2], aq[2];
    #pragma unroll
    for (int j = 0; j < 2; j++) { int i = tid + j * 256; arow[j] = i >> 3; aq[j] = i & 7; }
    int brow[4], bq[4];
    long bbase[4];
    bool bval[4];
    #pragma unroll
    for (int j = 0; j < 4; j++) {
        int i = tid + j * 256;
        brow[j] = i >> 3; bq[j] = i & 7;
        int p = n0 + brow[j];
        bval[j] = p < Npix;
        if (!bval[j]) p = 0;
        int img = p / HW;
        int rr  = p - img * HW;
        int oh  = rr / Wout;
        int ow  = rr - oh * Wout;
        bbase[j] = ((long)(img * HinP + oh) * WinP + ow) * CIN;
    }

    auto load_stage = [&](int st, int it) {
        int pos = it / cPer;
        int cioff = (it - pos * cPer) << 6;
        int kh = pos / KD, kw = pos - kh * KD;
        int kofA = it << 6;
        long boff = (long)(kh * WinP + kw) * CIN + cioff;
        uint32_t s = stg[st];
        #pragma unroll
        for (int j = 0; j < 2; j++) {
            size_t go = (size_t)(m0 + arow[j]) * K + kofA + aq[j] * 8;
            uint32_t so = (uint32_t)(arow[j] * 128 + ((aq[j] ^ (arow[j] & 7)) * 16));
            bool pr = m0 + arow[j] < M;
            cp16(s + so, Ahi + go, pr);
            cp16(s + A1R_SZ + so, Alo + go, pr);
        }
        #pragma unroll
        for (int j = 0; j < 4; j++) {
            long go = bbase[j] + boff + bq[j] * 8;
            uint32_t so = (uint32_t)(brow[j] * 128 + ((bq[j] ^ (brow[j] & 7)) * 16));
            cp16(s + 2 * A1R_SZ + so, Xhi + go, bval[j]);
            cp16(s + 2 * A1R_SZ + B1R_SZ + so, Xlo + go, bval[j]);
        }
        CP_COMMIT();
    };

    load_stage(0, 0);

    for (int it = 0; it < itK; it++) {
        int st = it & 1;
        if (it + 1 < itK) { load_stage(st ^ 1, it + 1); CP_WAIT(1); }
        else              { CP_WAIT(0); }
        __syncthreads();
        uint32_t s = stg[st];

        #pragma unroll
        for (int kk = 0; kk < 4; kk++) {
            uint32_t aCol = (uint32_t)(((kk * 2 + aColBase) ^ ar) * 16);
            uint32_t bCol = (uint32_t)(((kk * 2 + bColBase) ^ ar) * 16);
            uint32_t ah[2][4], al[2][4];
            #pragma unroll
            for (int mi = 0; mi < 2; mi++) {
                uint32_t ad = s + aRowOff[mi] + aCol;
                ldsm_x4(ah[mi][0], ah[mi][1], ah[mi][2], ah[mi][3], ad);
                ldsm_x4(al[mi][0], al[mi][1], al[mi][2], al[mi][3], ad + A1R_SZ);
            }
            uint32_t bh[4][2], bl[4][2];
            #pragma unroll
            for (int q = 0; q < 2; q++) {
                uint32_t bd = s + 2 * A1R_SZ + bRowOff[q] + bCol;
                uint32_t r0, r1, r2, r3;
                ldsm_x4(r0, r1, r2, r3, bd);
                bh[q * 2][0] = r0; bh[q * 2][1] = r1;
                bh[q * 2 + 1][0] = r2; bh[q * 2 + 1][1] = r3;
                ldsm_x4(r0, r1, r2, r3, bd + B1R_SZ);
                bl[q * 2][0] = r0; bl[q * 2][1] = r1;
                bl[q * 2 + 1][0] = r2; bl[q * 2 + 1][1] = r3;
            }
            #pragma unroll
            for (int mi = 0; mi < 2; mi++)
                #pragma unroll
                for (int nj = 0; nj < 4; nj++) {
                    mma16816(d[mi][nj], ah[mi], bh[nj][0], bh[nj][1]);
                    mma16816(d[mi][nj], ah[mi], bl[nj][0], bl[nj][1]);
                    mma16816(d[mi][nj], al[mi], bh[nj][0], bh[nj][1]);
                }
        }
        __syncthreads();
    }

    #pragma unroll
    for (int mi = 0; mi < 2; mi++) {
        #pragma unroll
        for (int r2 = 0; r2 < 2; r2++) {
            int co = m0 + wm * 32 + mi * 16 + (lane >> 2) + r2 * 8;
            if (co >= M) continue;
            float bv = bias[co];
            #pragma unroll
            for (int nj = 0; nj < 4; nj++) {
                #pragma unroll
                for (int c = 0; c < 2; c++) {
                    int p = n0 + wn * 32 + nj * 8 + (lane & 3) * 2 + c;
                    if (p >= Npix) continue;
                    float v = d[mi][nj][r2 * 2 + c] + bv;
                    int img = p / HW;
                    int rr  = p - img * HW;
                    int oh  = rr / Wout;
                    int ow  = rr - oh * Wout;
                    out[((size_t)(img * M + co) * HoP + oh + opad) * WoP + ow + opad]
                        = fmaxf(v, 0.f);
                }
            }
        }
    }
}

// -------- implicit-B GEMM, 128(M) x 64(N), fp32 NCHW output (conv5) --------
#define AR3_SZ 16384
#define BR3_SZ 8192
#define ST3_SZ (2 * AR3_SZ + 2 * BR3_SZ)
#define SMEM_G3 (2 * ST3_SZ)
__global__ void __launch_bounds__(256, 2)
mmaconv_imp_k(const __nv_bfloat16* __restrict__ Ahi, const __nv_bfloat16* __restrict__ Alo,
              const __nv_bfloat16* __restrict__ Xhi, const __nv_bfloat16* __restrict__ Xlo,
              const float* __restrict__ bias, float* __restrict__ out,
              int M, int Npix, int K, int CIN, int KD,
              int HinP, int WinP, int Hout, int Wout,
              int HoP, int WoP, int opad)
{
    extern __shared__ char smem[];
    uint32_t sb = smem_u32(smem);
    uint32_t stg[2] = { sb, sb + ST3_SZ };

    int tid  = threadIdx.x;
    int lane = tid & 31;
    int wid  = tid >> 5;
    int wm   = wid & 3;
    int wn   = wid >> 2;

    int m0 = blockIdx.y * 128;
    int n0 = blockIdx.x * 64;

    float d[2][4][4];
    #pragma unroll
    for (int i = 0; i < 2; i++)
        #pragma unroll
        for (int j = 0; j < 4; j++)
            #pragma unroll
            for (int r = 0; r < 4; r++) d[i][j][r] = 0.f;

    int aj = lane >> 3, ar = lane & 7;
    uint32_t aRowOff[2], bRowOff[2];
    #pragma unroll
    for (int mi = 0; mi < 2; mi++)
        aRowOff[mi] = (uint32_t)((wm * 32 + mi * 16 + (aj & 1) * 8 + ar) * 128);
    #pragma unroll
    for (int q = 0; q < 2; q++)
        bRowOff[q] = (uint32_t)((wn * 32 + q * 16 + (aj >> 1) * 8 + ar) * 128);
    int aColBase = aj >> 1;
    int bColBase = aj & 1;

    int itK = K >> 6;
    int cPer = CIN >> 6;
    int HW = Hout * Wout;

    int arow[4], aq[4];
    #pragma unroll
    for (int j = 0; j < 4; j++) { int i = tid + j * 256; arow[j] = i >> 3; aq[j] = i & 7; }
    int brow[2], bq[2];
    long bbase[2];
    bool bval[2];
    #pragma unroll
    for (int j = 0; j < 2; j++) {
        int i = tid + j * 256;
        brow[j] = i >> 3; bq[j] = i & 7;
        int p = n0 + brow[j];
        bval[j] = p < Npix;
        if (!bval[j]) p = 0;
        int img = p / HW;
        int rr  = p - img * HW;
        int oh  = rr / Wout;
        int ow  = rr - oh * Wout;
        bbase[j] = ((long)(img * HinP + oh) * WinP + ow) * CIN;
    }

    auto load_stage = [&](int st, int it) {
        int pos = it / cPer;
        int cioff = (it - pos * cPer) << 6;
        int kh = pos / KD, kw = pos - kh * KD;
        int kofA = it << 6;
        long boff = (long)(kh * WinP + kw) * CIN + cioff;
        uint32_t s = stg[st];
        #pragma unroll
        for (int j = 0; j < 4; j++) {
            size_t go = (size_t)(m0 + arow[j]) * K + kofA + aq[j] * 8;
            uint32_t so = (uint32_t)(arow[j] * 128 + ((aq[j] ^ (arow[j] & 7)) * 16));
            bool pr = m0 + arow[j] < M;
            cp16(s + so, Ahi + go, pr);
            cp16(s + AR3_SZ + so, Alo + go, pr);
        }
        #pragma unroll
        for (int j = 0; j < 2; j++) {
            long go = bbase[j] + boff + bq[j] * 8;
            uint32_t so = (uint32_t)(brow[j] * 128 + ((bq[j] ^ (brow[j] & 7)) * 16));
            cp16(s + 2 * AR3_SZ + so, Xhi + go, bval[j]);
            cp16(s + 2 * AR3_SZ + BR3_SZ + so, Xlo + go, bval[j]);
        }
        CP_COMMIT();
    };

    load_stage(0, 0);

    for (int it = 0; it < itK; it++) {
        int st = it & 1;
        if (it + 1 < itK) { load_stage(st ^ 1, it + 1); CP_WAIT(1); }
        else              { CP_WAIT(0); }
        __syncthreads();
        uint32_t s = stg[st];

        #pragma unroll
        for (int kk = 0; kk < 4; kk++) {
            uint32_t aCol = (uint32_t)(((kk * 2 + aColBase) ^ ar) * 16);
            uint32_t bCol = (uint32_t)(((kk * 2 + bColBase) ^ ar) * 16);
            uint32_t ah[2][4], al[2][4];
            #pragma unroll
            for (int mi = 0; mi < 2; mi++) {
                uint32_t ad = s + aRowOff[mi] + aCol;
                ldsm_x4(ah[mi][0], ah[mi][1], ah[mi][2], ah[mi][3], ad);
                ldsm_x4(al[mi][0], al[mi][1], al[mi][2], al[mi][3], ad + AR3_SZ);
            }
            uint32_t bh[4][2], bl[4][2];
            #pragma unroll
            for (int q = 0; q < 2; q++) {
                uint32_t bd = s + 2 * AR3_SZ + bRowOff[q] + bCol;
                uint32_t r0, r1, r2, r3;
                ldsm_x4(r0, r1, r2, r3, bd);
                bh[q * 2][0] = r0; bh[q * 2][1] = r1;
                bh[q * 2 + 1][0] = r2; bh[q * 2 + 1][1] = r3;
                ldsm_x4(r0, r1, r2, r3, bd + BR3_SZ);
                bl[q * 2][0] = r0; bl[q * 2][1] = r1;
                bl[q * 2 + 1][0] = r2; bl[q * 2 + 1][1] = r3;
            }
            #pragma unroll
            for (int mi = 0; mi < 2; mi++)
                #pragma unroll
                for (int nj = 0; nj < 4; nj++) {
                    mma16816(d[mi][nj], ah[mi], bh[nj][0], bh[nj][1]);
                    mma16816(d[mi][nj], ah[mi], bl[nj][0], bl[nj][1]);
                    mma16816(d[mi][nj], al[mi], bh[nj][0], bh[nj][1]);
                }
        }
        __syncthreads();
    }

    #pragma unroll
    for (int mi = 0; mi < 2; mi++) {
        #pragma unroll
        for (int r2 = 0; r2 < 2; r2++) {
            int co = m0 + wm * 32 + mi * 16 + (lane >> 2) + r2 * 8;
            if (co >= M) continue;
            float bv = bias[co];
            #pragma unroll
            for (int nj = 0; nj < 4; nj++) {
                #pragma unroll
                for (int c = 0; c < 2; c++) {
                    int p = n0 + wn * 32 + nj * 8 + (lane & 3) * 2 + c;
                    if (p >= Npix) continue;
                    float v = d[mi][nj][r2 * 2 + c] + bv;
                    int img = p / HW;
                    int rr  = p - img * HW;
                    int oh  = rr / Wout;
                    int ow  = rr - oh * Wout;
                    out[((size_t)(img * M + co) * HoP + oh + opad) * WoP + ow + opad]
                        = fmaxf(v, 0.f);
                }
            }
        }
    }
}

// -------- implicit-B GEMM, 128(M) x 64(N), split NHWC bf16 output (conv3/conv4) --------
__global__ void __launch_bounds__(256, 2)
mmaconv_imp_split_k(const __nv_bfloat16* __restrict__ Ahi, const __nv_bfloat16* __restrict__ Alo,
                    const __nv_bfloat16* __restrict__ Xhi, const __nv_bfloat16* __restrict__ Xlo,
                    const float* __restrict__ bias,
                    __nv_bfloat16* __restrict__ outHi, __nv_bfloat16* __restrict__ outLo,
                    int M, int Npix, int K, int CIN, int KD,
                    int HinP, int WinP, int Hout, int Wout,
                    int HoP, int WoP, int opad)
{
    extern __shared__ char smem[];
    uint32_t sb = smem_u32(smem);
    uint32_t stg[2] = { sb, sb + ST3_SZ };

    int tid  = threadIdx.x;
    int lane = tid & 31;
    int wid  = tid >> 5;
    int wm   = wid & 3;
    int wn   = wid >> 2;

    int m0 = blockIdx.y * 128;
    int n0 = blockIdx.x * 64;

    float d[2][4][4];
    #pragma unroll
    for (int i = 0; i < 2; i++)
        #pragma unroll
        for (int j = 0; j < 4; j++)
            #pragma unroll
            for (int r = 0; r < 4; r++) d[i][j][r] = 0.f;

    int aj = lane >> 3, ar = lane & 7;
    uint32_t aRowOff[2], bRowOff[2];
    #pragma unroll
    for (int mi = 0; mi < 2; mi++)
        aRowOff[mi] = (uint32_t)((wm * 32 + mi * 16 + (aj & 1) * 8 + ar) * 128);
    #pragma unroll
    for (int q = 0; q < 2; q++)
        bRowOff[q] = (uint32_t)((wn * 32 + q * 16 + (aj >> 1) * 8 + ar) * 128);
    int aColBase = aj >> 1;
    int bColBase = aj & 1;

    int itK = K >> 6;
    int cPer = CIN >> 6;
    int HW = Hout * Wout;

    int arow[4], aq[4];
    #pragma unroll
    for (int j = 0; j < 4; j++) { int i = tid + j * 256; arow[j] = i >> 3; aq[j] = i & 7; }
    int brow[2], bq[2];
    long bbase[2];
    bool bval[2];
    #pragma unroll
    for (int j = 0; j < 2; j++) {
        int i = tid + j * 256;
        brow[j] = i >> 3; bq[j] = i & 7;
        int p = n0 + brow[j];
        bval[j] = p < Npix;
        if (!bval[j]) p = 0;
        int img = p / HW;
        int rr  = p - img * HW;
        int oh  = rr / Wout;
        int ow  = rr - oh * Wout;
        bbase[j] = ((long)(img * HinP + oh) * WinP + ow) * CIN;
    }

    auto load_stage = [&](int st, int it) {
        int pos = it / cPer;
        int cioff = (it - pos * cPer) << 6;
        int kh = pos / KD, kw = pos - kh * KD;
        int kofA = it << 6;
        long boff = (long)(kh * WinP + kw) * CIN + cioff;
        uint32_t s = stg[st];
        #pragma unroll
        for (int j = 0; j < 4; j++) {
            size_t go = (size_t)(m0 + arow[j]) * K + kofA + aq[j] * 8;
            uint32_t so = (uint32_t)(arow[j] * 128 + ((aq[j] ^ (arow[j] & 7)) * 16));
            bool pr = m0 + arow[j] < M;
            cp16(s + so, Ahi + go, pr);
            cp16(s + AR3_SZ + so, Alo + go, pr);
        }
        #pragma unroll
        for (int j = 0; j < 2; j++) {
            long go = bbase[j] + boff + bq[j] * 8;
            uint32_t so = (uint32_t)(brow[j] * 128 + ((bq[j] ^ (brow[j] & 7)) * 16));
            cp16(s + 2 * AR3_SZ + so, Xhi + go, bval[j]);
            cp16(s + 2 * AR3_SZ + BR3_SZ + so, Xlo + go, bval[j]);
        }
        CP_COMMIT();
    };

    load_stage(0, 0);

    for (int it = 0; it < itK; it++) {
        int st = it & 1;
        if (it + 1 < itK) { load_stage(st ^ 1, it + 1); CP_WAIT(1); }
        else              { CP_WAIT(0); }
        __syncthreads();
        uint32_t s = stg[st];

        #pragma unroll
        for (int kk = 0; kk < 4; kk++) {
            uint32_t aCol = (uint32_t)(((kk * 2 + aColBase) ^ ar) * 16);
            uint32_t bCol = (uint32_t)(((kk * 2 + bColBase) ^ ar) * 16);
            uint32_t ah[2][4], al[2][4];
            #pragma unroll
            for (int mi = 0; mi < 2; mi++) {
                uint32_t ad = s + aRowOff[mi] + aCol;
                ldsm_x4(ah[mi][0], ah[mi][1], ah[mi][2], ah[mi][3], ad);
                ldsm_x4(al[mi][0], al[mi][1], al[mi][2], al[mi][3], ad + AR3_SZ);
            }
            uint32_t bh[4][2], bl[4][2];
            #pragma unroll
            for (int q = 0; q < 2; q++) {
                uint32_t bd = s + 2 * AR3_SZ + bRowOff[q] + bCol;
                uint32_t r0, r1, r2, r3;
                ldsm_x4(r0, r1, r2, r3, bd);
                bh[q * 2][0] = r0; bh[q * 2][1] = r1;
                bh[q * 2 + 1][0] = r2; bh[q * 2 + 1][1] = r3;
                ldsm_x4(r0, r1, r2, r3, bd + BR3_SZ);
                bl[q * 2][0] = r0; bl[q * 2][1] = r1;
                bl[q * 2 + 1][0] = r2; bl[q * 2 + 1][1] = r3;
            }
            #pragma unroll
            for (int mi = 0; mi < 2; mi++)
                #pragma unroll
                for (int nj = 0; nj < 4; nj++) {
                    mma16816(d[mi][nj], ah[mi], bh[nj][0], bh[nj][1]);
                    mma16816(d[mi][nj], ah[mi], bl[nj][0], bl[nj][1]);
                    mma16816(d[mi][nj], al[mi], bh[nj][0], bh[nj][1]);
                }
        }
        __syncthreads();
    }

    #pragma unroll
    for (int mi = 0; mi < 2; mi++) {
        #pragma unroll
        for (int r2 = 0; r2 < 2; r2++) {
            int co = m0 + wm * 32 + mi * 16 + (lane >> 2) + r2 * 8;
            if (co >= M) continue;
            float bv = bias[co];
            #pragma unroll
            for (int nj = 0; nj < 4; nj++) {
                #pragma unroll
                for (int c = 0; c < 2; c++) {
                    int p = n0 + wn * 32 + nj * 8 + (lane & 3) * 2 + c;
                    if (p >= Npix) continue;
                    float v = fmaxf(d[mi][nj][r2 * 2 + c] + bv, 0.f);
                    int img = p / HW;
                    int rr  = p - img * HW;
                    int oh  = rr / Wout;
                    int ow  = rr - oh * Wout;
                    size_t o = ((size_t)img * HoP * WoP + (size_t)(oh + opad) * WoP
                                + (ow + opad)) * (size_t)M + co;
                    bsplit(v, outHi[o], outLo[o]);
                }
            }
        }
    }
}

// -------- generic explicit GEMM, 128(M) x 64(N), transposed output C[n,m] --------
#define A2_SZ (128 * ASTR * 2)
#define B2_SZ (64 * ASTR * 2)
#define ST2_SZ (2 * A2_SZ + 2 * B2_SZ)
#define SMEM_G2 (2 * ST2_SZ)
__global__ void __launch_bounds__(256)
mmagemm_k(const __nv_bfloat16* __restrict__ Ahi, const __nv_bfloat16* __restrict__ Alo,
          const __nv_bfloat16* __restrict__ Bhi, const __nv_bfloat16* __restrict__ Blo,
          float* __restrict__ out, int M, int N, int K)
{
    extern __shared__ char smem[];
    uint32_t sb = smem_u32(smem);
    uint32_t stg[2] = { sb, sb + ST2_SZ };

    int tid  = threadIdx.x;
    int lane = tid & 31;
    int wid  = tid >> 5;
    int wm   = wid & 3;
    int wn   = wid >> 2;

    int m0 = blockIdx.y * 128;
    int n0 = blockIdx.x * 64;

    float d[2][4][4];
    #pragma unroll
    for (int i = 0; i < 2; i++)
        #pragma unroll
        for (int j = 0; j < 4; j++)
            #pragma unroll
            for (int r = 0; r < 4; r++) d[i][j][r] = 0.f;

    int aj = lane >> 3, ar = lane & 7;
    uint32_t aAddrOff = (uint32_t)(((aj & 1) * 8 + ar) * ASTR + (aj >> 1) * 8) * 2;
    uint32_t bAddrOff = (uint32_t)(((aj >> 1) * 8 + ar) * ASTR + (aj & 1) * 8) * 2;

    int itK = K >> 6;

    int arow[4], aq[4];
    #pragma unroll
    for (int j = 0; j < 4; j++) { int i = tid + j * 256; arow[j] = i >> 3; aq[j] = i & 7; }
    int brow[2], bq[2];
    #pragma unroll
    for (int j = 0; j < 2; j++) { int i = tid + j * 256; brow[j] = i >> 3; bq[j] = i & 7; }

    auto load_stage = [&](int st, int it) {
        int kof = it << 6;
        uint32_t s = stg[st];
        #pragma unroll
        for (int j = 0; j < 4; j++) {
            size_t go = (size_t)(m0 + arow[j]) * K + kof + aq[j] * 8;
            uint32_t so = (uint32_t)(arow[j] * ASTR + aq[j] * 8) * 2;
            bool pr = m0 + arow[j] < M;
            cp16(s + so, Ahi + go, pr);
            cp16(s + A2_SZ + so, Alo + go, pr);
        }
        #pragma unroll
        for (int j = 0; j < 2; j++) {
            size_t go = (size_t)(n0 + brow[j]) * K + kof + bq[j] * 8;
            uint32_t so = (uint32_t)(brow[j] * ASTR + bq[j] * 8) * 2;
            bool pr = n0 + brow[j] < N;
            cp16(s + 2 * A2_SZ + so, Bhi + go, pr);
            cp16(s + 2 * A2_SZ + B2_SZ + so, Blo + go, pr);
        }
        CP_COMMIT();
    };

    load_stage(0, 0);

    for (int it = 0; it < itK; it++) {
        int st = it & 1;
        if (it + 1 < itK) { load_stage(st ^ 1, it + 1); CP_WAIT(1); }
        else              { CP_WAIT(0); }
        __syncthreads();
        uint32_t s = stg[st];

        #pragma unroll
        for (int kk = 0; kk < 4; kk++) {
            uint32_t ah[2][4], al[2][4];
            #pragma unroll
            for (int mi = 0; mi < 2; mi++) {
                uint32_t off = aAddrOff + (uint32_t)((wm * 32 + mi * 16) * ASTR + kk * 16) * 2;
                ldsm_x4(ah[mi][0], ah[mi][1], ah[mi][2], ah[mi][3], s + off);
                ldsm_x4(al[mi][0], al[mi][1], al[mi][2], al[mi][3], s + A2_SZ + off);
            }
            uint32_t bh[4][2], bl[4][2];
            #pragma unroll
            for (int q = 0; q < 2; q++) {
                uint32_t off = bAddrOff + (uint32_t)((wn * 32 + q * 16) * ASTR + kk * 16) * 2;
                uint32_t r0, r1, r2, r3;
                ldsm_x4(r0, r1, r2, r3, s + 2 * A2_SZ + off);
                bh[q * 2][0] = r0; bh[q * 2][1] = r1;
                bh[q * 2 + 1][0] = r2; bh[q * 2 + 1][1] = r3;
                ldsm_x4(r0, r1, r2, r3, s + 2 * A2_SZ + B2_SZ + off);
                bl[q * 2][0] = r0; bl[q * 2][1] = r1;
                bl[q * 2 + 1][0] = r2; bl[q * 2 + 1][1] = r3;
            }
            #pragma unroll
            for (int mi = 0; mi < 2; mi++)
                #pragma unroll
                for (int nj = 0; nj < 4; nj++) {
                    mma16816(d[mi][nj], ah[mi], bh[nj][0], bh[nj][1]);
                    mma16816(d[mi][nj], ah[mi], bl[nj][0], bl[nj][1]);
                    mma16816(d[mi][nj], al[mi], bh[nj][0], bh[nj][1]);
                }
        }
        __syncthreads();
    }

    #pragma unroll
    for (int mi = 0; mi < 2; mi++) {
        #pragma unroll
        for (int r2 = 0; r2 < 2; r2++) {
            int co = m0 + wm * 32 + mi * 16 + (lane >> 2) + r2 * 8;
            if (co >= M) continue;
            #pragma unroll
            for (int nj = 0; nj < 4; nj++) {
                #pragma unroll
                for (int c = 0; c < 2; c++) {
                    int p = n0 + wn * 32 + nj * 8 + (lane & 3) * 2 + c;
                    if (p >= N) continue;
                    out[(size_t)p * M + co] = d[mi][nj][r2 * 2 + c];
                }
            }
        }
    }
}

// ---------------- scalar kernels (rest of network) ----------------

__global__ void pad_copy_k(const float* __restrict__ src, float* __restrict__ dst,
                           int nimg, int boff)
{
    int idx = blockIdx.x * blockDim.x + threadIdx.x;
    int total = nimg * 3 * H0 * W0;
    if (idx >= total) return;
    int w = idx % W0; int t = idx / W0;
    int h = t % H0;   t /= H0;
    int c = t % 3;    int n = t / 3;
    dst[(((size_t)(boff + n) * 3 + c) * H0P + h + 2) * W0P + (w + 2)] = src[idx];
}

__global__ void maxpool_k(const float* __restrict__ in, float* __restrict__ out,
                          int NC, int Hin, int Win, int Ho, int Wo,
                          int HoP, int WoP, int opad)
{
    int idx = blockIdx.x * blockDim.x + threadIdx.x;
    int total = NC * Ho * Wo;
    if (idx >= total) return;
    int ow = idx % Wo; int t = idx / Wo;
    int oh = t % Ho;   int nc = t / Ho;
    const float* ip = in + ((size_t)nc * Hin + oh * 2) * Win + ow * 2;
    float m = -INFINITY;
    #pragma unroll
    for (int kh = 0; kh < 3; kh++)
        #pragma unroll
        for (int kw = 0; kw < 3; kw++)
            m = fmaxf(m, ip[kh * Win + kw]);
    out[((size_t)nc * HoP + oh + opad) * WoP + ow + opad] = m;
}

// fused conv1d(k=3,p=1) + global max over positions: v[o] = max_p xc[o,p]
__global__ void cd_fused_k(const float* __restrict__ Xf, const float* __restrict__ wcd,
                           const float* __restrict__ bcd, float* __restrict__ v)
{
    __shared__ float red[128];
    int o = blockIdx.x;     // 0..255
    int p = threadIdx.x;    // 0..127, active p<88
    float acc = -INFINITY;
    if (p < 88) {
        acc = bcd[o];
        for (int i = 0; i < 256; i++) {
            const float* wr = wcd + (o * 256 + i) * 3;
            const float* xr = Xf + i * 88;
            if (p > 0)  acc += xr[p - 1] * wr[0];
            acc += xr[p] * wr[1];
            if (p < 87) acc += xr[p + 1] * wr[2];
        }
    }
    red[p] = acc;
    __syncthreads();
    for (int st = 64; st > 0; st >>= 1) {
        if (p < st) red[p] = fmaxf(red[p], red[p + st]);
        __syncthreads();
    }
    if (p == 0) v[o] = red[0];
}

__global__ void xhat_k(const float* __restrict__ v, const float* __restrict__ wt,
                       const float* __restrict__ bt, float* __restrict__ xhat)
{
    __shared__ float sv[256];
    int o = blockIdx.x;
    int k = threadIdx.x;
    for (int i = threadIdx.x; i < 256; i += blockDim.x) sv[i] = v[i];
    __syncthreads();
    float acc = bt[o];
    for (int i = 0; i < 256; i++)
        acc += sv[i] * wt[((size_t)i * 256 + o) * 88 + k];
    xhat[o * 88 + k] = acc;
}

__global__ __launch_bounds__(256)
void rbgemm_k(const float* __restrict__ A, const float* __restrict__ B,
              const float* __restrict__ bias, float* __restrict__ C,
              int M, int N, int K, int flags)
{
    __shared__ float As[16][65];
    __shared__ float Bs[16][64];
    int tid = threadIdx.x;
    int tx = tid & 15;
    int ty = tid >> 4;
    int m0 = blockIdx.y * 64;
    int n0 = blockIdx.x * 64;

    float acc[4][4] = {};

    for (int k0 = 0; k0 < K; k0 += 16) {
        #pragma unroll
        for (int i = 0; i < 4; i++) {
            int e  = tid + i * 256;
            int kk = e & 15;
            int mm = e >> 4;
            int gm = m0 + mm, gk = k0 + kk;
            As[kk][mm] = (gm < M && gk < K) ? A[(size_t)gm * K + gk] : 0.f;
        }
        #pragma unroll
        for (int i = 0; i < 4; i++) {
            int nn = tid & 63;
            int kk = (tid >> 6) + i * 4;
            int gk = k0 + kk, gn = n0 + nn;
            Bs[kk][nn] = (gk < K && gn < N) ? B[(size_t)gk * N + gn] : 0.f;
        }
        __syncthreads();
        #pragma unroll
        for (int kk = 0; kk < 16; kk++) {
            float ra[4], rb[4];
            #pragma unroll
            for (int i = 0; i < 4; i++) ra[i] = As[kk][ty * 4 + i];
            #pragma unroll
            for (int j = 0; j < 4; j++) rb[j] = Bs[kk][tx * 4 + j];
            #pragma unroll
            for (int i = 0; i < 4; i++)
                #pragma unroll
                for (int j = 0; j < 4; j++)
                    acc[i][j] += ra[i] * rb[j];
        }
        __syncthreads();
    }

    #pragma unroll
    for (int i = 0; i < 4; i++) {
        int gm = m0 + ty * 4 + i;
        if (gm >= M) continue;
        #pragma unroll
        for (int j = 0; j < 4; j++) {
            int gn = n0 + tx * 4 + j;
            if (gn >= N) continue;
            float v = acc[i][j];
            if (flags & 1) v += bias[gm];
            if (flags & 2) v += bias[gn];
            if (flags & 4) v = v >= 0.f ? v : 0.01f * v;
            C[(size_t)gm * N + gn] = v;
        }
    }
}

__global__ void a1_reduce_k(const float* __restrict__ Y, float* __restrict__ S, int F)
{
    int f = blockIdx.x * blockDim.x + threadIdx.x;
    int t = blockIdx.y;
    if (f >= F) return;
    float s = 0.f;
    for (int m = 0; m < 88; m++) s += Y[(size_t)(m * 16 + t) * F + f];
    S[t * F + f] = s;
}

__global__ void a1_apply_split_k(const float* __restrict__ Y, const float* __restrict__ S,
                                 const float* __restrict__ bias,
                                 __nv_bfloat16* __restrict__ hi, __nv_bfloat16* __restrict__ lo,
                                 int F)
{
    int idx = blockIdx.x * blockDim.x + threadIdx.x;
    if (idx >= TMN * F) return;
    int f = idx % F;
    int n = idx / F;
    int t = n % 16;
    float val = S[t * F + f] + bias[f];
    if (t == 0) val -= Y[idx];
    val = val >= 0.f ? val : 0.01f * val;
    bsplit(val, hi[idx], lo[idx]);
}

__global__ void a1_apply_k(const float* __restrict__ Y, const float* __restrict__ S,
                           const float* __restrict__ bias, float* __restrict__ h, int F)
{
    int idx = blockIdx.x * blockDim.x + threadIdx.x;
    if (idx >= TMN * F) return;
    int f = idx % F;
    int n = idx / F;
    int t = n % 16;
    float val = S[t * F + f] + bias[f];
    if (t == 0) val -= Y[idx];
    h[idx] = val >= 0.f ? val : 0.01f * val;
}

__global__ void v1_k(const float* __restrict__ h2, const float* __restrict__ xhat,
                     float* __restrict__ V1, float* __restrict__ V1t, float* __restrict__ Vx)
{
    int idx = blockIdx.x * blockDim.x + threadIdx.x;
    if (idx >= 256 * 88) return;
    int d = idx % 256;
    int m = idx / 256;
    float mx = -INFINITY;
    #pragma unroll
    for (int t = 0; t < 16; t++) mx = fmaxf(mx, h2[(size_t)(m * 16 + t) * 256 + d]);
    V1[d * 88 + m] = mx;
    V1t[m * 256 + d] = mx;
    Vx[d * 88 + m] = mx + xhat[d * 88 + m];
}

__global__ void attn_k(const float* __restrict__ G, const float* __restrict__ Hh,
                       float* __restrict__ A2)
{
    __shared__ float red[128];
    int j = blockIdx.x;
    int i = threadIdx.x;
    float s = 0.f;
    if (i < 88) {
        for (int d = 0; d < 256; d++) s += Hh[d * 88 + j] * G[d * 88 + i];
    }
    red[i] = (i < 88) ? s : -INFINITY;
    __syncthreads();
    for (int st = 64; st > 0; st >>= 1) {
        if (i < st) red[i] = fmaxf(red[i], red[i + st]);
        __syncthreads();
    }
    float mx = red[0];
    __syncthreads();
    float e = (i < 88) ? expf(s - mx) : 0.f;
    red[i] = e;
    __syncthreads();
    for (int st = 64; st > 0; st >>= 1) {
        if (i < st) red[i] += red[i + st];
        __syncthreads();
    }
    float sum = red[0];
    if (i < 88) A2[j * 88 + i] = e / sum;
}

__global__ void final_dot_k(const float* __restrict__ Xf, const float* __restrict__ V2t,
                            float* __restrict__ out)
{
    __shared__ float red[256];
    float acc = 0.f;
    for (int e = threadIdx.x; e < 256 * 88; e += 256) {
        int d = e / 88, m = e % 88;
        acc += Xf[e] * V2t[m * 256 + d];
    }
    red[threadIdx.x] = acc;
    __syncthreads();
    for (int st = 128; st > 0; st >>= 1) {
        if (threadIdx.x < st) red[threadIdx.x] += red[threadIdx.x + st];
        __syncthreads();
    }
    if (threadIdx.x == 0) out[0] = red[0];
}

// ---------------- host ----------------
static float* symaddr(const void* s)
{
    void* p = nullptr;
    cudaGetSymbolAddress(&p, s);
    return (float*)p;
}
static __nv_bfloat16* symaddr_bf(const void* s)
{
    void* p = nullptr;
    cudaGetSymbolAddress(&p, s);
    return (__nv_bfloat16*)p;
}

extern "C" void kernel_launch(void* const* d_in, const int* in_sizes, int n_in,
                              void* d_out, int out_size)
{
    const float* search    = (const float*)d_in[0];
    const float* exemplars = (const float*)d_in[1];
    const float* aw1 = (const float*)d_in[2];  const float* ab1 = (const float*)d_in[3];
    const float* aw2 = (const float*)d_in[4];  const float* ab2 = (const float*)d_in[5];
    const float* aw3 = (const float*)d_in[6];  const float* ab3 = (const float*)d_in[7];
    const float* aw4 = (const float*)d_in[8];  const float* ab4 = (const float*)d_in[9];
    const float* aw5 = (const float*)d_in[10]; const float* ab5 = (const float*)d_in[11];
    const float* wcd = (const float*)d_in[12]; const float* bcd = (const float*)d_in[13];
    const float* wt  = (const float*)d_in[14]; const float* bt  = (const float*)d_in[15];
    const float* ws1 = (const float*)d_in[16]; const float* bs1 = (const float*)d_in[17];
    const float* ws2 = (const float*)d_in[18]; const float* bs2 = (const float*)d_in[19];
    const float* wg  = (const float*)d_in[20]; const float* bg  = (const float*)d_in[21];
    const float* wh  = (const float*)d_in[22]; const float* bh  = (const float*)d_in[23];
    const float* wc1 = (const float*)d_in[24]; const float* bc1 = (const float*)d_in[25];
    const float* wc2 = (const float*)d_in[26]; const float* bc2 = (const float*)d_in[27];

    float* p_in  = symaddr(g_in);
    float* p_c1  = symaddr(g_c1);
    float* p_c2  = symaddr(g_c2);
    float* p_c5  = symaddr(g_c5);
    float* p_p5  = symaddr(g_p5);
    float* p_v   = symaddr(g_v);
    float* p_xh  = symaddr(g_xhat);
    float* p_Y1  = symaddr(g_Y1);
    float* p_S   = symaddr(g_S);
    float* p_Y2  = symaddr(g_Y2);
    float* p_h2  = symaddr(g_h2);
    float* p_V1  = symaddr(g_V1);
    float* p_V1t = symaddr(g_V1t);
    float* p_Vx  = symaddr(g_Vx);
    float* p_G   = symaddr(g_G);
    float* p_Hh  = symaddr(g_Hh);
    float* p_A2  = symaddr(g_A2);
    float* p_xw  = symaddr(g_xw);
    float* p_c1m = symaddr(g_c1m);
    float* p_cw  = symaddr(g_cw);
    float* p_V2t = symaddr(g_V2t);
    __nv_bfloat16* pAhi = symaddr_bf(g_Ahi);
    __nv_bfloat16* pAlo = symaddr_bf(g_Alo);
    __nv_bfloat16* pBhi = symaddr_bf(g_Bhi);
    __nv_bfloat16* pBlo = symaddr_bf(g_Blo);

    cudaFuncSetAttribute(mmaconv64_k, cudaFuncAttributeMaxDynamicSharedMemorySize, SMEM_G1);
    cudaFuncSetAttribute(mmaconv64_imp_k, cudaFuncAttributeMaxDynamicSharedMemorySize, SMEM_G1);
    cudaFuncSetAttribute(mmaconv_imp_k, cudaFuncAttributeMaxDynamicSharedMemorySize, SMEM_G3);
    cudaFuncSetAttribute(mmaconv_imp_split_k, cudaFuncAttributeMaxDynamicSharedMemorySize, SMEM_G3);
    cudaFuncSetAttribute(mmagemm_k, cudaFuncAttributeMaxDynamicSharedMemorySize, SMEM_G2);

    // zero padded input buffer (borders must be 0 every replay)
    cudaMemsetAsync(p_in, 0, sizeof(float) * ((size_t)N_IMG * 3 * H0P * W0P + TAILPAD), 0);

    // assemble padded input batch
    {
        int tot = 16 * 3 * H0 * W0;
        pad_copy_k<<<(tot + 127) / 128, 128>>>(exemplars, p_in, 16, 0);
        tot = 3 * H0 * W0;
        pad_copy_k<<<(tot + 127) / 128, 128>>>(search, p_in, 1, 16);
    }

    // ---- conv1 (vectorized im2col, swizzled 64x128 GEMM): M=64, K=384(pad) ----
    {
        const int KP = 384, NP = N_IMG * H1 * W1;
        wsplit_pad_k<<<(C1o * KP + 255) / 256, 256>>>(aw1, pAhi, pAlo, C1o, 363, KP);
        int tot = NP * (KP / 8);
        im2col_v8_t<3, 11, 4, H0P, W0P, H1, W1, 384><<<(tot + 255) / 256, 256>>>(p_in, pBhi, pBlo);
        mmaconv64_k<<<(NP + 127) / 128, 256, SMEM_G1>>>(
            pAhi, pAlo, pBhi, pBlo, ab1, p_c1, C1o, NP, KP, H1, W1, H1, W1, 0);
    }

    // zero NHWC bf16 regions for conv3/conv4 outputs (after conv1 GEMM consumed
    // the overlapping im2col B buffer; GEMM split-epilogues only write interiors)
    cudaMemsetAsync(pBhi + C3OFF, 0, (size_t)C3SZ * 2, 0);
    cudaMemsetAsync(pBlo + C3OFF, 0, (size_t)C3SZ * 2, 0);
    cudaMemsetAsync(pBhi + C4OFF, 0, (size_t)C4SZ * 2, 0);
    cudaMemsetAsync(pBlo + C4OFF, 0, (size_t)C4SZ * 2, 0);

    // ---- pool1 fused with NHWC split (writes own zero borders) -> pBhi/pBlo @ 0 ----
    {
        const int NPIX = P1HP * P1WP;
        maxpool_split_k<<<dim3((NPIX + 31) / 32, C1o / 32, N_IMG), dim3(32, 8)>>>(
            p_c1, pBhi, pBlo, C1o, H1, W1, P1H, P1W, P1HP, P1WP, 2);
    }

    // ---- conv2 (implicit, 64M x 128N): M=192, K=1600, CIN=64, KD=5 ----
    {
        const int K = 1600, NP = N_IMG * H2 * W2;
        wsplit_reorder_k<<<(C2o * K + 255) / 256, 256>>>(aw2, pAhi, pAlo, C2o, 64, 25);
        mmaconv64_imp_k<<<dim3((NP + 127) / 128, 3), 256, SMEM_G1>>>(
            pAhi, pAlo, pBhi, pBlo, ab2, p_c2, C2o, NP, K, 64, 5,
            P1HP, P1WP, H2, W2, H2, W2, 0);
    }

    // ---- pool2 fused with NHWC split -> pBhi/pBlo @ P2OFF ----
    {
        const int NPIX = P2HP * P2WP;
        maxpool_split_k<<<dim3((NPIX + 31) / 32, C2o / 32, N_IMG), dim3(32, 8)>>>(
            p_c2, pBhi + P2OFF, pBlo + P2OFF, C2o, H2, W2, P2H, P2W, P2HP, P2WP, 1);
    }

    // ---- conv3 (implicit, split NHWC epilogue): M=384, K=1728, CIN=192 ----
    {
        const int K = 1728, NP = N_IMG * P2H * P2W;
        wsplit_reorder_k<<<(C3o * K + 255) / 256, 256>>>(aw3, pAhi, pAlo, C3o, 192, 9);
        mmaconv_imp_split_k<<<dim3((NP + 63) / 64, 3), 256, SMEM_G3>>>(
            pAhi, pAlo, pBhi + P2OFF, pBlo + P2OFF, ab3, pBhi + C3OFF, pBlo + C3OFF,
            C3o, NP, K, 192, 3, P2HP, P2WP, P2H, P2W, P2HP, P2WP, 1);
    }

    // ---- conv4 (implicit, split NHWC epilogue): M=256, K=3456, CIN=384 ----
    {
        const int K = 3456, NP = N_IMG * P2H * P2W;
        wsplit_reorder_k<<<(C4o * K + 255) / 256, 256>>>(aw4, pAhi, pAlo, C4o, 384, 9);
        mmaconv_imp_split_k<<<dim3((NP + 63) / 64, 2), 256, SMEM_G3>>>(
            pAhi, pAlo, pBhi + C3OFF, pBlo + C3OFF, ab4, pBhi + C4OFF, pBlo + C4OFF,
            C4o, NP, K, 384, 3, P2HP, P2WP, P2H, P2W, P2HP, P2WP, 1);
    }

    // ---- conv5 (implicit, NCHW out): M=256, K=2304, CIN=256 ----
    {
        const int K = 2304, NP = N_IMG * P2H * P2W;
        wsplit_reorder_k<<<(C5o * K + 255) / 256, 256>>>(aw5, pAhi, pAlo, C5o, 256, 9);
        mmaconv_imp_k<<<dim3((NP + 63) / 64, 2), 256, SMEM_G3>>>(
            pAhi, pAlo, pBhi + C4OFF, pBlo + C4OFF, ab5, p_c5, C5o, NP, K, 256, 3,
            P2HP, P2WP, P2H, P2W, H5, W5, 0);
    }
    {
        int tot = N_IMG * C5o * P5H * P5W;
        maxpool_k<<<(tot + 127) / 128, 128>>>(p_c5, p_p5, N_IMG * C5o, H5, W5, P5H, P5W, P5H, P5W, 0);
    }

    const float* Xf = p_p5 + (size_t)16 * 256 * 88;

    // ---- conv_deconv branch (fused conv1d + global max) ----
    cd_fused_k<<<256, 128>>>(Xf, wcd, bcd, p_v);
    xhat_k<<<256, 88>>>(p_v, wt, bt, p_xh);

    // ---- spatiotemporal GCN (tensor-core, fused split) ----
    __nv_bfloat16* nHi = pBhi;
    __nv_bfloat16* nLo = pBlo;
    __nv_bfloat16* h1Hi = pBhi + (1 << 20);
    __nv_bfloat16* h1Lo = pBlo + (1 << 20);
    __nv_bfloat16* w1Hi = pAhi;
    __nv_bfloat16* w1Lo = pAlo;
    __nv_bfloat16* w2Hi = pAhi + (512 * 256);
    __nv_bfloat16* w2Lo = pAlo + (512 * 256);

    gather_nodes_split_k<<<(TMN * 256 + 255) / 256, 256>>>(p_p5, nHi, nLo);
    wsplitT_k<<<(512 * 256 + 255) / 256, 256>>>(ws1, w1Hi, w1Lo, 512, 256);
    mmagemm_k<<<dim3(TMN / 64, 512 / 128), 256, SMEM_G2>>>(
        w1Hi, w1Lo, nHi, nLo, p_Y1, 512, TMN, 256);
    a1_reduce_k<<<dim3(4, 16), 128>>>(p_Y1, p_S, 512);
    a1_apply_split_k<<<(TMN * 512 + 255) / 256, 256>>>(p_Y1, p_S, bs1, h1Hi, h1Lo, 512);
    wsplitT_k<<<(256 * 512 + 255) / 256, 256>>>(ws2, w2Hi, w2Lo, 256, 512);
    mmagemm_k<<<dim3(TMN / 64, 256 / 128), 256, SMEM_G2>>>(
        w2Hi, w2Lo, h1Hi, h1Lo, p_Y2, 256, TMN, 512);
    a1_reduce_k<<<dim3(2, 16), 128>>>(p_Y2, p_S, 256);
    a1_apply_k<<<(TMN * 256 + 255) / 256, 256>>>(p_Y2, p_S, bs2, p_h2, 256);
    v1_k<<<(256 * 88 + 255) / 256, 256>>>(p_h2, p_xh, p_V1, p_V1t, p_Vx);

    // ---- dynamic cross-track graph ----
    rbgemm_k<<<dim3((88 + 63) / 64, 256 / 64), 256>>>(wg, p_Vx, bg, p_G, 256, 88, 256, 1);
    rbgemm_k<<<dim3((88 + 63) / 64, 256 / 64), 256>>>(wh, p_Vx, bh, p_Hh, 256, 88, 256, 1);
    attn_k<<<88, 128>>>(p_G, p_Hh, p_A2);

    // ---- ct GCN ----
    rbgemm_k<<<dim3(384 / 64, (88 + 63) / 64), 256>>>(p_V1t, wc1, nullptr, p_xw, 88, 384, 256, 0);
    rbgemm_k<<<dim3(384 / 64, (88 + 63) / 64), 256>>>(p_A2, p_xw, bc1, p_c1m, 88, 384, 88, 2 | 4);
    rbgemm_k<<<dim3(256 / 64, (88 + 63) / 64), 256>>>(p_c1m, wc2, nullptr, p_cw, 88, 256, 384, 0);
    rbgemm_k<<<dim3(256 / 64, (88 + 63) / 64), 256>>>(p_A2, p_cw, bc2, p_V2t, 88, 256, 88, 2 | 4);

    // ---- final correlation ----
    final_dot_k<<<1, 256>>>(Xf, p_V2t, (float*)d_out);
}